// round 1
// baseline (speedup 1.0000x reference)
#include <cuda_runtime.h>
#include <math.h>

// ---------------- problem constants ----------------
#define TOK   2048      // total tokens (2 halves x 1024)
#define DIMM  1024
#define NH    16
#define HD    64
#define SEQ   2048      // merged (interleaved) sequence
#define NASS  8192      // TOK * K(=4) routed assignments
#define NEXP  32        // 16 p-experts + 16 f-experts
#define FDIM  512       // expert hidden
#define DSH   2048      // shared expert hidden

// ---------------- scratch (device globals; no allocs) ----------------
__device__ float g_xnorm[TOK*DIMM];
__device__ float g_qkv[TOK*3*DIMM];
__device__ float g_qm[NH*SEQ*HD];
__device__ float g_km[NH*SEQ*HD];
__device__ float g_vm[NH*SEQ*HD];
__device__ float g_om[NH*SEQ*HD];
__device__ float g_orows[TOK*DIMM];
__device__ float g_xffni[TOK*DIMM];
__device__ float g_xffn[TOK*DIMM];
__device__ float g_G[NASS*FDIM];
__device__ float g_U[NASS*FDIM];
__device__ float g_slots[(size_t)NASS*DIMM];
__device__ float g_su[(size_t)TOK*2*DSH];
__device__ float g_hs[(size_t)TOK*DSH];
__device__ float g_scales[NASS];
__device__ int   g_eid[NASS];
__device__ int   g_tokof[NASS];
__device__ int   g_posof[NASS];
__device__ int   g_counts[NEXP];
__device__ int   g_offsets[NEXP];
__device__ int   g_cursors[NEXP];

// ---------------- rmsnorm ----------------
__global__ void rmsnorm_kernel(const float* __restrict__ x, const float* __restrict__ w,
                               float* __restrict__ out) {
    int r = blockIdx.x;
    const float* xr = x + (size_t)r*DIMM;
    __shared__ float red[8];
    float s = 0.f;
    for (int d = threadIdx.x; d < DIMM; d += 256) { float v = xr[d]; s += v*v; }
    #pragma unroll
    for (int o = 16; o; o >>= 1) s += __shfl_xor_sync(0xffffffffu, s, o);
    if ((threadIdx.x & 31) == 0) red[threadIdx.x >> 5] = s;
    __syncthreads();
    if (threadIdx.x == 0) {
        float t = 0.f;
        #pragma unroll
        for (int i = 0; i < 8; i++) t += red[i];
        red[0] = rsqrtf(t / (float)DIMM + 1e-5f);
    }
    __syncthreads();
    float rms = red[0];
    for (int d = threadIdx.x; d < DIMM; d += 256)
        out[(size_t)r*DIMM + d] = xr[d] * rms * w[d];
}

// ---------------- dense SGEMM: C[M,N] = A[M,K] @ B[K,N] (+D) ----------------
// 64x64 tile, BK=16, 256 threads, 4x4 microtile. All dims multiples of 64/16.
__global__ void gemm_dense(const float* __restrict__ A, const float* __restrict__ B,
                           float* __restrict__ C, const float* __restrict__ D,
                           int M, int N, int K) {
    __shared__ float As[16][65];
    __shared__ float Bs[16][64];
    int tid = threadIdx.x;
    int tx = tid & 15, ty = tid >> 4;
    int rowBase = blockIdx.y * 64, colBase = blockIdx.x * 64;
    float acc[4][4] = {};
    int ar = tid >> 4, ac = tid & 15;
    int br = tid >> 6, bc = tid & 63;
    for (int kt = 0; kt < K; kt += 16) {
        #pragma unroll
        for (int it = 0; it < 4; it++)
            As[ac][ar + 16*it] = A[(size_t)(rowBase + ar + 16*it)*K + kt + ac];
        #pragma unroll
        for (int it = 0; it < 4; it++)
            Bs[br + 4*it][bc] = B[(size_t)(kt + br + 4*it)*N + colBase + bc];
        __syncthreads();
        #pragma unroll
        for (int k = 0; k < 16; k++) {
            float a[4], b[4];
            #pragma unroll
            for (int i = 0; i < 4; i++) a[i] = As[k][ty*4 + i];
            #pragma unroll
            for (int j = 0; j < 4; j++) b[j] = Bs[k][tx*4 + j];
            #pragma unroll
            for (int i = 0; i < 4; i++)
                #pragma unroll
                for (int j = 0; j < 4; j++) acc[i][j] = fmaf(a[i], b[j], acc[i][j]);
        }
        __syncthreads();
    }
    #pragma unroll
    for (int i = 0; i < 4; i++) {
        int r = rowBase + ty*4 + i;
        #pragma unroll
        for (int j = 0; j < 4; j++) {
            int c = colBase + tx*4 + j;
            float v = acc[i][j];
            if (D) v += D[(size_t)r*N + c];
            C[(size_t)r*N + c] = v;
        }
    }
}

// ---------------- rope + dual interleave ----------------
// merged position t = 2*si + bi ; rope uses original si
__global__ void rope_interleave_kernel() {
    int r = blockIdx.x, h = blockIdx.y, d = threadIdx.x;
    int bi = r >> 10, si = r & 1023;
    int t = 2*si + bi;
    size_t src = (size_t)r*3072 + h*64;
    size_t dst = ((size_t)h*SEQ + t)*64;
    float q = g_qkv[src + d];
    float k = g_qkv[src + 1024 + d];
    float v = g_qkv[src + 2048 + d];
    g_vm[dst + d] = v;
    __shared__ float qs[64], ks[64];
    qs[d] = q; ks[d] = k;
    __syncthreads();
    if (d < 32) {
        float inv = powf(10000.0f, -(float)(2*d) / 64.0f);
        float fr = (float)si * inv;
        float sn, cs;
        sincosf(fr, &sn, &cs);
        float x1 = qs[d], x2 = qs[d+32];
        g_qm[dst + d]      =  x1*cs + x2*sn;
        g_qm[dst + d + 32] = -x1*sn + x2*cs;
        x1 = ks[d]; x2 = ks[d+32];
        g_km[dst + d]      =  x1*cs + x2*sn;
        g_km[dst + d + 32] = -x1*sn + x2*cs;
    }
}

// ---------------- streaming causal attention, 8 queries/block ----------------
#define TQ 8
__global__ void attn_kernel() {
    int h = blockIdx.y;
    int t0 = blockIdx.x * TQ;
    int d = threadIdx.x;   // 64 threads
    __shared__ float qs[TQ][64];
    __shared__ float Ks[64][65];
    __shared__ float Vs[64][64];
    __shared__ float sc[TQ][64];
    __shared__ float sp[TQ][64];
    const float* qb = g_qm + ((size_t)h*SEQ + t0)*64;
    #pragma unroll
    for (int q = 0; q < TQ; q++) qs[q][d] = qb[q*64 + d];
    float m[TQ], l[TQ], acc[TQ];
    #pragma unroll
    for (int q = 0; q < TQ; q++) { m[q] = -1e30f; l[q] = 0.f; acc[q] = 0.f; }
    int tmax = t0 + TQ - 1;
    for (int k0 = 0; k0 <= tmax; k0 += 64) {
        __syncthreads();
        const float* kb = g_km + ((size_t)h*SEQ + k0)*64;
        const float* vb = g_vm + ((size_t)h*SEQ + k0)*64;
        #pragma unroll 4
        for (int i = 0; i < 64; i++) {
            Ks[i][d] = kb[(size_t)i*64 + d];
            Vs[i][d] = vb[(size_t)i*64 + d];
        }
        __syncthreads();
        // scores: this thread = key (k0+d)
        #pragma unroll
        for (int q = 0; q < TQ; q++) {
            float dot = 0.f;
            #pragma unroll 8
            for (int i = 0; i < 64; i++) dot = fmaf(qs[q][i], Ks[d][i], dot);
            sc[q][d] = dot * 0.125f;
        }
        __syncthreads();
        // online softmax update (thread d writes prob of key d)
        #pragma unroll
        for (int q = 0; q < TQ; q++) {
            int lim = (t0 + q) - k0;       // keys valid for index i <= lim
            if (lim < 0) { sp[q][d] = 0.f; continue; }
            int hi = lim < 63 ? lim : 63;
            float tm = -1e30f;
            for (int i = 0; i <= hi; i++) tm = fmaxf(tm, sc[q][i]);
            float newm = fmaxf(m[q], tm);
            float p = (d <= lim) ? __expf(sc[q][d] - newm) : 0.f;
            sp[q][d] = p;
            float corr = __expf(m[q] - newm);
            acc[q] *= corr; l[q] *= corr; m[q] = newm;
        }
        __syncthreads();
        // accumulate: this thread = output dim d
        #pragma unroll
        for (int q = 0; q < TQ; q++) {
            if (t0 + q < k0) continue;
            float a = acc[q], ls = 0.f;
            #pragma unroll 8
            for (int i = 0; i < 64; i++) {
                float p = sp[q][i];
                ls += p;
                a = fmaf(p, Vs[i][d], a);
            }
            acc[q] = a; l[q] += ls;
        }
    }
    #pragma unroll
    for (int q = 0; q < TQ; q++)
        g_om[((size_t)h*SEQ + t0 + q)*64 + d] = acc[q] / l[q];
}

// ---------------- de-interleave attention output back to token rows ----------------
__global__ void deinterleave_kernel() {
    int r = blockIdx.x, h = blockIdx.y, d = threadIdx.x;
    int bi = r >> 10, si = r & 1023;
    int t = 2*si + bi;
    g_orows[(size_t)r*DIMM + h*64 + d] = g_om[((size_t)h*SEQ + t)*64 + d];
}

// ---------------- router: logits + sigmoid-normalized top-k scales ----------------
__global__ void router_kernel(const float* __restrict__ pkeys, const float* __restrict__ fkeys,
                              const float* __restrict__ pbias, const float* __restrict__ fbias,
                              const int* __restrict__ pidx, const float* __restrict__ pval,
                              const int* __restrict__ fidx, const float* __restrict__ fval) {
    int tok = blockIdx.x, tid = threadIdx.x;     // 128 threads
    bool isf = tok >= 1024;
    const float* keys = isf ? fkeys : pkeys;
    const float* x = g_xffn + (size_t)tok*DIMM;
    __shared__ float part[8][16];
    __shared__ float logit[16];
    int e = tid & 15, ch = tid >> 4;
    float s = 0.f;
    int d0 = ch * 128;
    for (int d = d0; d < d0 + 128; d++) s = fmaf(x[d], keys[d*16 + e], s);
    part[ch][e] = s;
    __syncthreads();
    if (tid < 16) {
        float t = 0.f;
        #pragma unroll
        for (int c = 0; c < 8; c++) t += part[c][tid];
        logit[tid] = t;
    }
    __syncthreads();
    if (tid == 0) {
        int lt = isf ? tok - 1024 : tok;
        const int*   idx  = isf ? fidx  : pidx;
        const float* val  = isf ? fval  : pval;
        const float* bias = isf ? fbias : pbias;
        float sc[4]; int id[4]; float sum = 0.f;
        #pragma unroll
        for (int k = 0; k < 4; k++) {
            int ix = idx[lt*4 + k];
            float v = val[lt*4 + k] + logit[ix] + bias[ix];
            float s2 = 1.f / (1.f + expf(-v));
            sc[k] = s2; sum += s2;
            id[k] = ix + (isf ? 16 : 0);
        }
        #pragma unroll
        for (int k = 0; k < 4; k++) {
            g_scales[tok*4 + k] = sc[k] / sum;
            g_eid[tok*4 + k] = id[k];
            atomicAdd(&g_counts[id[k]], 1);
        }
    }
}

__global__ void zero32_kernel() {
    int i = threadIdx.x;
    if (i < NEXP) { g_counts[i] = 0; g_cursors[i] = 0; }
}

__global__ void prefix_kernel() {
    int acc = 0;
    for (int e = 0; e < NEXP; e++) { g_offsets[e] = acc; acc += g_counts[e]; }
}

__global__ void scatter_kernel() {
    int a = blockIdx.x * blockDim.x + threadIdx.x;
    if (a >= NASS) return;
    int e = g_eid[a];
    int p = g_offsets[e] + atomicAdd(&g_cursors[e], 1);
    g_tokof[p] = a >> 2;
    g_posof[a] = p;
}

// ---------------- grouped MoE gate/up GEMM (gathered A rows) ----------------
// sel: 0 -> gate weights -> g_G ; 1 -> up weights -> g_U
__global__ void moe_gemm_gu(const float* __restrict__ pW, const float* __restrict__ fW, int sel) {
    int e = blockIdx.z;
    int cnt = g_counts[e];
    int rowTile = blockIdx.y * 64;
    if (rowTile >= cnt) return;
    int base = g_offsets[e];
    const float* W = (e < 16) ? pW + ((size_t)sel*16 + e)      * (size_t)DIMM*FDIM
                              : fW + ((size_t)sel*16 + (e-16)) * (size_t)DIMM*FDIM;
    float* Out = sel ? g_U : g_G;
    __shared__ float As[16][65];
    __shared__ float Bs[16][64];
    __shared__ int   rows[64];
    int tid = threadIdx.x;
    if (tid < 64) {
        int rr = rowTile + tid;
        rows[tid] = (rr < cnt) ? g_tokof[base + rr] : -1;
    }
    __syncthreads();
    int tx = tid & 15, ty = tid >> 4;
    int ar = tid >> 4, ac = tid & 15;
    int br = tid >> 6, bc = tid & 63;
    int colBase = blockIdx.x * 64;
    float acc[4][4] = {};
    for (int kt = 0; kt < DIMM; kt += 16) {
        #pragma unroll
        for (int it = 0; it < 4; it++) {
            int tokr = rows[ar + 16*it];
            As[ac][ar + 16*it] = (tokr >= 0) ? g_xffn[(size_t)tokr*DIMM + kt + ac] : 0.f;
        }
        #pragma unroll
        for (int it = 0; it < 4; it++)
            Bs[br + 4*it][bc] = W[(size_t)(kt + br + 4*it)*FDIM + colBase + bc];
        __syncthreads();
        #pragma unroll
        for (int k = 0; k < 16; k++) {
            float a[4], b[4];
            #pragma unroll
            for (int i = 0; i < 4; i++) a[i] = As[k][ty*4 + i];
            #pragma unroll
            for (int j = 0; j < 4; j++) b[j] = Bs[k][tx*4 + j];
            #pragma unroll
            for (int i = 0; i < 4; i++)
                #pragma unroll
                for (int j = 0; j < 4; j++) acc[i][j] = fmaf(a[i], b[j], acc[i][j]);
        }
        __syncthreads();
    }
    #pragma unroll
    for (int i = 0; i < 4; i++) {
        int r = rowTile + ty*4 + i;
        if (r < cnt)
            #pragma unroll
            for (int j = 0; j < 4; j++)
                Out[(size_t)(base + r)*FDIM + colBase + tx*4 + j] = acc[i][j];
    }
}

__global__ void swiglu_moe_kernel() {
    size_t i = (size_t)blockIdx.x * blockDim.x + threadIdx.x;   // NASS*FDIM total
    float g = g_G[i], u = g_U[i];
    g_G[i] = (g / (1.f + expf(-g))) * u;
}

// ---------------- grouped MoE down GEMM: out[t,d] = sum_f H[t,f] * W2[d,f] ----------------
__global__ void moe_gemm_down(const float* __restrict__ pW, const float* __restrict__ fW) {
    int e = blockIdx.z;
    int cnt = g_counts[e];
    int rowTile = blockIdx.y * 64;
    if (rowTile >= cnt) return;
    int base = g_offsets[e];
    const float* W = (e < 16) ? pW + ((size_t)2*16 + e)      * (size_t)DIMM*FDIM
                              : fW + ((size_t)2*16 + (e-16)) * (size_t)DIMM*FDIM;
    __shared__ float As[16][65];
    __shared__ float Bs[16][65];
    int tid = threadIdx.x;
    int tx = tid & 15, ty = tid >> 4;
    int ar = tid >> 4, ac = tid & 15;
    int colBase = blockIdx.x * 64;
    float acc[4][4] = {};
    for (int kt = 0; kt < FDIM; kt += 16) {
        #pragma unroll
        for (int it = 0; it < 4; it++) {
            int rr = rowTile + ar + 16*it;
            As[ac][ar + 16*it] = (rr < cnt) ? g_G[(size_t)(base + rr)*FDIM + kt + ac] : 0.f;
        }
        // B is [N=1024 rows d][K=512 cols f]: load transposed, coalesced in f
        #pragma unroll
        for (int it = 0; it < 4; it++) {
            int nl = (tid >> 4) + 16*it;       // 0..63 local col (=d)
            int kl = tid & 15;                 // 0..15 local k (=f)
            Bs[kl][nl] = W[(size_t)(colBase + nl)*FDIM + kt + kl];
        }
        __syncthreads();
        #pragma unroll
        for (int k = 0; k < 16; k++) {
            float a[4], b[4];
            #pragma unroll
            for (int i = 0; i < 4; i++) a[i] = As[k][ty*4 + i];
            #pragma unroll
            for (int j = 0; j < 4; j++) b[j] = Bs[k][tx*4 + j];
            #pragma unroll
            for (int i = 0; i < 4; i++)
                #pragma unroll
                for (int j = 0; j < 4; j++) acc[i][j] = fmaf(a[i], b[j], acc[i][j]);
        }
        __syncthreads();
    }
    #pragma unroll
    for (int i = 0; i < 4; i++) {
        int r = rowTile + ty*4 + i;
        if (r < cnt)
            #pragma unroll
            for (int j = 0; j < 4; j++)
                g_slots[(size_t)(base + r)*DIMM + colBase + tx*4 + j] = acc[i][j];
    }
}

// ---------------- combine: y = x_ffn_input + sum_k scale_k * slot_k ----------------
__global__ void combine_kernel(float* __restrict__ y) {
    int tok = blockIdx.x;
    __shared__ int pos[4];
    __shared__ float sc[4];
    if (threadIdx.x < 4) {
        pos[threadIdx.x] = g_posof[tok*4 + threadIdx.x];
        sc[threadIdx.x]  = g_scales[tok*4 + threadIdx.x];
    }
    __syncthreads();
    for (int d = threadIdx.x; d < DIMM; d += 256) {
        float v = g_xffni[(size_t)tok*DIMM + d];
        #pragma unroll
        for (int k = 0; k < 4; k++) v = fmaf(sc[k], g_slots[(size_t)pos[k]*DIMM + d], v);
        y[(size_t)tok*DIMM + d] = v;
    }
}

// ---------------- shared expert swiglu ----------------
__global__ void swiglu_shared_kernel() {
    int t = blockIdx.x;
    for (int j = threadIdx.x; j < DSH; j += 256) {
        float a = g_su[(size_t)t*2*DSH + j];
        float b = g_su[(size_t)t*2*DSH + DSH + j];
        g_hs[(size_t)t*DSH + j] = (a / (1.f + expf(-a))) * b;
    }
}

// ---------------- launch ----------------
extern "C" void kernel_launch(void* const* d_in, const int* in_sizes, int n_in,
                              void* d_out, int out_size) {
    const float* x_input  = (const float*)d_in[0];
    const int*   p_idx    = (const int*)  d_in[1];
    const float* p_val    = (const float*)d_in[2];
    const int*   f_idx    = (const int*)  d_in[3];
    const float* f_val    = (const float*)d_in[4];
    const float* attn_nw  = (const float*)d_in[5];
    const float* ffn_nw   = (const float*)d_in[6];
    const float* W_attn   = (const float*)d_in[7];
    const float* W_attn_o = (const float*)d_in[8];
    const float* ffn_up   = (const float*)d_in[9];
    const float* ffn_down = (const float*)d_in[10];
    const float* pW       = (const float*)d_in[11];
    const float* fW       = (const float*)d_in[12];
    const float* pkeys    = (const float*)d_in[13];
    const float* fkeys    = (const float*)d_in[14];
    const float* pbias    = (const float*)d_in[15];
    const float* fbias    = (const float*)d_in[16];
    float* out = (float*)d_out;

    float *xnorm, *qkv, *orows, *xffni, *xffn, *su, *hs;
    cudaGetSymbolAddress((void**)&xnorm, g_xnorm);
    cudaGetSymbolAddress((void**)&qkv,   g_qkv);
    cudaGetSymbolAddress((void**)&orows, g_orows);
    cudaGetSymbolAddress((void**)&xffni, g_xffni);
    cudaGetSymbolAddress((void**)&xffn,  g_xffn);
    cudaGetSymbolAddress((void**)&su,    g_su);
    cudaGetSymbolAddress((void**)&hs,    g_hs);

    // attention block
    rmsnorm_kernel<<<TOK, 256>>>(x_input, attn_nw, xnorm);
    gemm_dense<<<dim3(48, 32), 256>>>(xnorm, W_attn, qkv, nullptr, TOK, 3*DIMM, DIMM);
    rope_interleave_kernel<<<dim3(TOK, NH), 64>>>();
    attn_kernel<<<dim3(SEQ/TQ, NH), 64>>>();
    deinterleave_kernel<<<dim3(TOK, NH), 64>>>();
    gemm_dense<<<dim3(16, 32), 256>>>(orows, W_attn_o, xffni, x_input, TOK, DIMM, DIMM);
    rmsnorm_kernel<<<TOK, 256>>>(xffni, ffn_nw, xffn);

    // routing
    zero32_kernel<<<1, 32>>>();
    router_kernel<<<TOK, 128>>>(pkeys, fkeys, pbias, fbias, p_idx, p_val, f_idx, f_val);
    prefix_kernel<<<1, 1>>>();
    scatter_kernel<<<32, 256>>>();

    // grouped MoE
    moe_gemm_gu<<<dim3(FDIM/64, 64, NEXP), 256>>>(pW, fW, 0);
    moe_gemm_gu<<<dim3(FDIM/64, 64, NEXP), 256>>>(pW, fW, 1);
    swiglu_moe_kernel<<<(NASS*FDIM)/256, 256>>>();
    moe_gemm_down<<<dim3(DIMM/64, 64, NEXP), 256>>>(pW, fW);
    combine_kernel<<<TOK, 256>>>(out);

    // shared expert (adds into out)
    gemm_dense<<<dim3(64, 32), 256>>>(xffn, ffn_up, su, nullptr, TOK, 2*DSH, DIMM);
    swiglu_shared_kernel<<<TOK, 256>>>();
    gemm_dense<<<dim3(16, 32), 256>>>(hs, ffn_down, out, out, TOK, DIMM, DSH);
}

// round 2
// speedup vs baseline: 2.8217x; 2.8217x over previous
#include <cuda_runtime.h>
#include <math.h>

// ---------------- problem constants ----------------
#define TOK   2048
#define DIMM  1024
#define NH    16
#define HD    64
#define SEQ   2048
#define NASS  8192
#define NEXP  32
#define FDIM  512
#define DSH   2048

// ---------------- scratch ----------------
__device__ float g_xnorm[TOK*DIMM];
__device__ float g_qkv[TOK*3*DIMM];
__device__ float g_qm[NH*SEQ*HD];
__device__ float g_km[NH*SEQ*HD];
__device__ float g_vm[NH*SEQ*HD];
__device__ float g_om[NH*SEQ*HD];
__device__ float g_orows[TOK*DIMM];
__device__ float g_xffni[TOK*DIMM];
__device__ float g_xffn[TOK*DIMM];
__device__ float g_G[NASS*FDIM];
__device__ float g_U[NASS*FDIM];
__device__ float g_slots[(size_t)NASS*DIMM];
__device__ float g_su[(size_t)TOK*2*DSH];
__device__ float g_hs[(size_t)TOK*DSH];
__device__ float g_scales[NASS];
__device__ int   g_eid[NASS];
__device__ int   g_tokof[NASS];
__device__ int   g_posof[NASS];
__device__ int   g_counts[NEXP];
__device__ int   g_offsets[NEXP];
__device__ int   g_cursors[NEXP];

// ---------------- tf32 helpers ----------------
__device__ __forceinline__ unsigned f2tf(float x) {
    unsigned r; asm("cvt.rna.tf32.f32 %0, %1;" : "=r"(r) : "f"(x)); return r;
}
__device__ __forceinline__ void st4tf(unsigned* dst, float4 v) {
    uint4 u; u.x = f2tf(v.x); u.y = f2tf(v.y); u.z = f2tf(v.z); u.w = f2tf(v.w);
    *(uint4*)dst = u;
}
__device__ __forceinline__ void mma8(float c[4], const unsigned a[4], const unsigned b[2]) {
    asm volatile("mma.sync.aligned.m16n8k8.row.col.f32.tf32.tf32.f32 "
                 "{%0,%1,%2,%3},{%4,%5,%6,%7},{%8,%9},{%0,%1,%2,%3};"
                 : "+f"(c[0]), "+f"(c[1]), "+f"(c[2]), "+f"(c[3])
                 : "r"(a[0]), "r"(a[1]), "r"(a[2]), "r"(a[3]), "r"(b[0]), "r"(b[1]));
}

// As layout: [row 0..127][k 0..15], stride 20 words (conflict-free frags)
// Bs (standard): [k 0..15][n 0..127], stride 136 words
// Bs (transposed): [n 0..127][k 0..15], stride 20 words
template<bool BT>
__device__ __forceinline__ void compute_tile(const unsigned* __restrict__ As,
                                             const unsigned* __restrict__ Bs,
                                             int wm, int wn, int g, int t4,
                                             float acc[16][4]) {
    #pragma unroll
    for (int ks = 0; ks < 2; ks++) {
        int kc = ks*8 + t4;
        unsigned af[2][4];
        #pragma unroll
        for (int mi = 0; mi < 2; mi++) {
            int r = wm + mi*16 + g;
            af[mi][0] = As[r*20 + kc];
            af[mi][1] = As[(r+8)*20 + kc];
            af[mi][2] = As[r*20 + kc + 4];
            af[mi][3] = As[(r+8)*20 + kc + 4];
        }
        #pragma unroll
        for (int ni = 0; ni < 8; ni++) {
            unsigned bf[2];
            int n = wn + ni*8 + g;
            if (BT) { bf[0] = Bs[n*20 + kc];  bf[1] = Bs[n*20 + kc + 4]; }
            else    { bf[0] = Bs[kc*136 + n]; bf[1] = Bs[(kc+4)*136 + n]; }
            #pragma unroll
            for (int mi = 0; mi < 2; mi++) mma8(acc[mi*8+ni], af[mi], bf);
        }
    }
}

// ---------------- dense tf32 GEMM: C = A[M,K] @ B[K,N] (+D) ----------------
__global__ void __launch_bounds__(256) gemm_nn(const float* __restrict__ A,
                                               const float* __restrict__ B,
                                               float* __restrict__ C,
                                               const float* __restrict__ D,
                                               int M, int N, int K) {
    __shared__ __align__(16) unsigned As[2][2560];
    __shared__ __align__(16) unsigned Bs[2][2176];
    int tid = threadIdx.x, lane = tid & 31, wid = tid >> 5;
    int g = lane >> 2, t4 = lane & 3;
    int wm = (wid & 3)*32, wn = (wid >> 2)*64;
    size_t rowBase = (size_t)blockIdx.y * 128, colBase = (size_t)blockIdx.x * 128;
    int a_r = tid >> 2, a_c = (tid & 3)*4;
    int b_r = tid >> 5, b_c = (tid & 31)*4;
    const float* Ap0 = A + (rowBase + a_r)*K + a_c;
    const float* Ap1 = Ap0 + (size_t)64*K;
    const float* Bp0 = B + (size_t)b_r*N + colBase + b_c;
    const float* Bp1 = Bp0 + (size_t)8*N;
    float acc[16][4];
    #pragma unroll
    for (int i = 0; i < 16; i++)
        #pragma unroll
        for (int j = 0; j < 4; j++) acc[i][j] = 0.f;
    float4 ra0 = *(const float4*)Ap0;
    float4 ra1 = *(const float4*)Ap1;
    float4 rb0 = *(const float4*)Bp0;
    float4 rb1 = *(const float4*)Bp1;
    int buf = 0;
    st4tf(&As[0][a_r*20 + a_c], ra0);
    st4tf(&As[0][(a_r+64)*20 + a_c], ra1);
    st4tf(&Bs[0][b_r*136 + b_c], rb0);
    st4tf(&Bs[0][(b_r+8)*136 + b_c], rb1);
    __syncthreads();
    for (int kt = 0; kt < K; kt += 16) {
        int nxt = kt + 16;
        if (nxt < K) {
            ra0 = *(const float4*)(Ap0 + nxt);
            ra1 = *(const float4*)(Ap1 + nxt);
            rb0 = *(const float4*)(Bp0 + (size_t)nxt*N);
            rb1 = *(const float4*)(Bp1 + (size_t)nxt*N);
        }
        compute_tile<false>(As[buf], Bs[buf], wm, wn, g, t4, acc);
        if (nxt < K) {
            st4tf(&As[buf^1][a_r*20 + a_c], ra0);
            st4tf(&As[buf^1][(a_r+64)*20 + a_c], ra1);
            st4tf(&Bs[buf^1][b_r*136 + b_c], rb0);
            st4tf(&Bs[buf^1][(b_r+8)*136 + b_c], rb1);
        }
        __syncthreads();
        buf ^= 1;
    }
    #pragma unroll
    for (int mi = 0; mi < 2; mi++)
        #pragma unroll
        for (int ni = 0; ni < 8; ni++) {
            float* c = acc[mi*8+ni];
            size_t r0 = rowBase + wm + mi*16 + g;
            size_t c0 = colBase + wn + ni*8 + 2*t4;
            size_t o0 = r0*N + c0, o1 = (r0+8)*N + c0;
            if (D) {
                C[o0] = c[0] + D[o0]; C[o0+1] = c[1] + D[o0+1];
                C[o1] = c[2] + D[o1]; C[o1+1] = c[3] + D[o1+1];
            } else {
                C[o0] = c[0]; C[o0+1] = c[1];
                C[o1] = c[2]; C[o1+1] = c[3];
            }
        }
}

// ---------------- MoE gate+up fused grouped GEMM ----------------
__global__ void __launch_bounds__(256) moe_gu_tf32(const float* __restrict__ pW,
                                                   const float* __restrict__ fW) {
    int e = blockIdx.z;
    int cnt = g_counts[e];
    int rowTile = blockIdx.y * 128;
    if (rowTile >= cnt) return;
    int base = g_offsets[e];
    int colBase = blockIdx.x * 128;        // 0..1023: [0,512) gate, [512,1024) up
    int sel = colBase >> 9;
    int wcol = colBase & 511;
    const float* W = (e < 16) ? pW + ((size_t)sel*16 + e)      * (size_t)DIMM*FDIM
                              : fW + ((size_t)sel*16 + (e-16)) * (size_t)DIMM*FDIM;
    float* Out = sel ? g_U : g_G;
    __shared__ int rows[128];
    __shared__ __align__(16) unsigned As[2][2560];
    __shared__ __align__(16) unsigned Bs[2][2176];
    int tid = threadIdx.x;
    if (tid < 128) {
        int rr = rowTile + tid;
        rows[tid] = (rr < cnt) ? g_tokof[base + rr] : -1;
    }
    __syncthreads();
    int lane = tid & 31, wid = tid >> 5;
    int g = lane >> 2, t4 = lane & 3;
    int wm = (wid & 3)*32, wn = (wid >> 2)*64;
    int a_r = tid >> 2, a_c = (tid & 3)*4;
    int b_r = tid >> 5, b_c = (tid & 31)*4;
    int tk0 = rows[a_r], tk1 = rows[a_r + 64];
    const float4 z4 = make_float4(0.f, 0.f, 0.f, 0.f);
    const float* Ap0 = g_xffn + (size_t)(tk0 < 0 ? 0 : tk0)*DIMM + a_c;
    const float* Ap1 = g_xffn + (size_t)(tk1 < 0 ? 0 : tk1)*DIMM + a_c;
    const float* Bp0 = W + (size_t)b_r*FDIM + wcol + b_c;
    const float* Bp1 = Bp0 + (size_t)8*FDIM;
    float acc[16][4];
    #pragma unroll
    for (int i = 0; i < 16; i++)
        #pragma unroll
        for (int j = 0; j < 4; j++) acc[i][j] = 0.f;
    float4 ra0 = (tk0 >= 0) ? *(const float4*)Ap0 : z4;
    float4 ra1 = (tk1 >= 0) ? *(const float4*)Ap1 : z4;
    float4 rb0 = *(const float4*)Bp0;
    float4 rb1 = *(const float4*)Bp1;
    int buf = 0;
    st4tf(&As[0][a_r*20 + a_c], ra0);
    st4tf(&As[0][(a_r+64)*20 + a_c], ra1);
    st4tf(&Bs[0][b_r*136 + b_c], rb0);
    st4tf(&Bs[0][(b_r+8)*136 + b_c], rb1);
    __syncthreads();
    for (int kt = 0; kt < DIMM; kt += 16) {
        int nxt = kt + 16;
        if (nxt < DIMM) {
            ra0 = (tk0 >= 0) ? *(const float4*)(Ap0 + nxt) : z4;
            ra1 = (tk1 >= 0) ? *(const float4*)(Ap1 + nxt) : z4;
            rb0 = *(const float4*)(Bp0 + (size_t)nxt*FDIM);
            rb1 = *(const float4*)(Bp1 + (size_t)nxt*FDIM);
        }
        compute_tile<false>(As[buf], Bs[buf], wm, wn, g, t4, acc);
        if (nxt < DIMM) {
            st4tf(&As[buf^1][a_r*20 + a_c], ra0);
            st4tf(&As[buf^1][(a_r+64)*20 + a_c], ra1);
            st4tf(&Bs[buf^1][b_r*136 + b_c], rb0);
            st4tf(&Bs[buf^1][(b_r+8)*136 + b_c], rb1);
        }
        __syncthreads();
        buf ^= 1;
    }
    #pragma unroll
    for (int mi = 0; mi < 2; mi++)
        #pragma unroll
        for (int ni = 0; ni < 8; ni++) {
            float* c = acc[mi*8+ni];
            int r = rowTile + wm + mi*16 + g;
            int cc = wcol + wn + ni*8 + 2*t4;
            if (r < cnt) {
                Out[(size_t)(base+r)*FDIM + cc]     = c[0];
                Out[(size_t)(base+r)*FDIM + cc + 1] = c[1];
            }
            if (r + 8 < cnt) {
                Out[(size_t)(base+r+8)*FDIM + cc]     = c[2];
                Out[(size_t)(base+r+8)*FDIM + cc + 1] = c[3];
            }
        }
}

// ---------------- MoE down grouped GEMM (B transposed: W2 is [d][f]) ----------------
__global__ void __launch_bounds__(256) moe_down_tf32(const float* __restrict__ pW,
                                                     const float* __restrict__ fW) {
    int e = blockIdx.z;
    int cnt = g_counts[e];
    int rowTile = blockIdx.y * 128;
    if (rowTile >= cnt) return;
    int base = g_offsets[e];
    int colBase = blockIdx.x * 128;
    const float* W = (e < 16) ? pW + ((size_t)2*16 + e)      * (size_t)DIMM*FDIM
                              : fW + ((size_t)2*16 + (e-16)) * (size_t)DIMM*FDIM;
    __shared__ __align__(16) unsigned As[2][2560];
    __shared__ __align__(16) unsigned Bs[2][2560];
    int tid = threadIdx.x, lane = tid & 31, wid = tid >> 5;
    int g = lane >> 2, t4 = lane & 3;
    int wm = (wid & 3)*32, wn = (wid >> 2)*64;
    int a_r = tid >> 2, a_c = (tid & 3)*4;
    bool v0 = (rowTile + a_r) < cnt, v1 = (rowTile + a_r + 64) < cnt;
    const float4 z4 = make_float4(0.f, 0.f, 0.f, 0.f);
    const float* Ap0 = g_G + (size_t)(base + rowTile + a_r)*FDIM + a_c;
    const float* Ap1 = g_G + (size_t)(base + rowTile + a_r + 64)*FDIM + a_c;
    const float* Bp0 = W + (size_t)(colBase + a_r)*FDIM + a_c;
    const float* Bp1 = W + (size_t)(colBase + a_r + 64)*FDIM + a_c;
    float acc[16][4];
    #pragma unroll
    for (int i = 0; i < 16; i++)
        #pragma unroll
        for (int j = 0; j < 4; j++) acc[i][j] = 0.f;
    float4 ra0 = v0 ? *(const float4*)Ap0 : z4;
    float4 ra1 = v1 ? *(const float4*)Ap1 : z4;
    float4 rb0 = *(const float4*)Bp0;
    float4 rb1 = *(const float4*)Bp1;
    int buf = 0;
    st4tf(&As[0][a_r*20 + a_c], ra0);
    st4tf(&As[0][(a_r+64)*20 + a_c], ra1);
    st4tf(&Bs[0][a_r*20 + a_c], rb0);
    st4tf(&Bs[0][(a_r+64)*20 + a_c], rb1);
    __syncthreads();
    for (int kt = 0; kt < FDIM; kt += 16) {
        int nxt = kt + 16;
        if (nxt < FDIM) {
            ra0 = v0 ? *(const float4*)(Ap0 + nxt) : z4;
            ra1 = v1 ? *(const float4*)(Ap1 + nxt) : z4;
            rb0 = *(const float4*)(Bp0 + nxt);
            rb1 = *(const float4*)(Bp1 + nxt);
        }
        compute_tile<true>(As[buf], Bs[buf], wm, wn, g, t4, acc);
        if (nxt < FDIM) {
            st4tf(&As[buf^1][a_r*20 + a_c], ra0);
            st4tf(&As[buf^1][(a_r+64)*20 + a_c], ra1);
            st4tf(&Bs[buf^1][a_r*20 + a_c], rb0);
            st4tf(&Bs[buf^1][(a_r+64)*20 + a_c], rb1);
        }
        __syncthreads();
        buf ^= 1;
    }
    #pragma unroll
    for (int mi = 0; mi < 2; mi++)
        #pragma unroll
        for (int ni = 0; ni < 8; ni++) {
            float* c = acc[mi*8+ni];
            int r = rowTile + wm + mi*16 + g;
            int cc = colBase + wn + ni*8 + 2*t4;
            if (r < cnt) {
                g_slots[(size_t)(base+r)*DIMM + cc]     = c[0];
                g_slots[(size_t)(base+r)*DIMM + cc + 1] = c[1];
            }
            if (r + 8 < cnt) {
                g_slots[(size_t)(base+r+8)*DIMM + cc]     = c[2];
                g_slots[(size_t)(base+r+8)*DIMM + cc + 1] = c[3];
            }
        }
}

// ---------------- rmsnorm ----------------
__global__ void rmsnorm_kernel(const float* __restrict__ x, const float* __restrict__ w,
                               float* __restrict__ out) {
    int r = blockIdx.x;
    const float* xr = x + (size_t)r*DIMM;
    __shared__ float red[8];
    float s = 0.f;
    for (int d = threadIdx.x; d < DIMM; d += 256) { float v = xr[d]; s += v*v; }
    #pragma unroll
    for (int o = 16; o; o >>= 1) s += __shfl_xor_sync(0xffffffffu, s, o);
    if ((threadIdx.x & 31) == 0) red[threadIdx.x >> 5] = s;
    __syncthreads();
    if (threadIdx.x == 0) {
        float t = 0.f;
        #pragma unroll
        for (int i = 0; i < 8; i++) t += red[i];
        red[0] = rsqrtf(t / (float)DIMM + 1e-5f);
    }
    __syncthreads();
    float rms = red[0];
    for (int d = threadIdx.x; d < DIMM; d += 256)
        out[(size_t)r*DIMM + d] = xr[d] * rms * w[d];
}

// ---------------- rope + dual interleave ----------------
__global__ void rope_interleave_kernel() {
    int r = blockIdx.x, h = blockIdx.y, d = threadIdx.x;
    int bi = r >> 10, si = r & 1023;
    int t = 2*si + bi;
    size_t src = (size_t)r*3072 + h*64;
    size_t dst = ((size_t)h*SEQ + t)*64;
    float q = g_qkv[src + d];
    float k = g_qkv[src + 1024 + d];
    float v = g_qkv[src + 2048 + d];
    g_vm[dst + d] = v;
    __shared__ float qs[64], ks[64];
    qs[d] = q; ks[d] = k;
    __syncthreads();
    if (d < 32) {
        float inv = powf(10000.0f, -(float)(2*d) / 64.0f);
        float fr = (float)si * inv;
        float sn, cs;
        sincosf(fr, &sn, &cs);
        float x1 = qs[d], x2 = qs[d+32];
        g_qm[dst + d]      =  x1*cs + x2*sn;
        g_qm[dst + d + 32] = -x1*sn + x2*cs;
        x1 = ks[d]; x2 = ks[d+32];
        g_km[dst + d]      =  x1*cs + x2*sn;
        g_km[dst + d + 32] = -x1*sn + x2*cs;
    }
}

// ---------------- attention: TQ=16, 128 threads, shuffle reductions ----------------
__global__ void __launch_bounds__(128) attn_kernel() {
    int h = blockIdx.y;
    int t0 = blockIdx.x * 16;
    int tid = threadIdx.x;
    int d = tid & 63;
    int qg = tid >> 6;               // query group 0/1
    int wid = tid >> 5;
    int lane = tid & 31;
    __shared__ __align__(16) float qs[16][64];
    __shared__ __align__(16) float Ks[64][66];
    __shared__ __align__(16) float Vs[64][66];
    __shared__ __align__(16) float sp[16][64];
    __shared__ float wredM[4][8];
    __shared__ float wredS[4][8];
    const float* qb = g_qm + ((size_t)h*SEQ + t0)*64;
    for (int i = tid; i < 16*64; i += 128) qs[i>>6][i&63] = qb[i];
    float m[8], l[8], acc[8];
    #pragma unroll
    for (int q = 0; q < 8; q++) { m[q] = -1e30f; l[q] = 0.f; acc[q] = 0.f; }
    int qoff = t0 + qg*8;
    for (int k0 = 0; k0 <= t0 + 15; k0 += 64) {
        __syncthreads();
        const float* kb = g_km + ((size_t)h*SEQ + k0)*64;
        const float* vb = g_vm + ((size_t)h*SEQ + k0)*64;
        for (int i = qg; i < 64; i += 2) {
            Ks[i][d] = kb[(size_t)i*64 + d];
            Vs[i][d] = vb[(size_t)i*64 + d];
        }
        __syncthreads();
        float sc[8];
        #pragma unroll
        for (int q = 0; q < 8; q++) sc[q] = 0.f;
        for (int i = 0; i < 64; i += 2) {
            float2 kk = *(const float2*)&Ks[d][i];
            #pragma unroll
            for (int q = 0; q < 8; q++) {
                float2 qq = *(const float2*)&qs[qg*8 + q][i];
                sc[q] = fmaf(qq.x, kk.x, sc[q]);
                sc[q] = fmaf(qq.y, kk.y, sc[q]);
            }
        }
        #pragma unroll
        for (int q = 0; q < 8; q++) {
            int lim = qoff + q - k0;
            sc[q] = (d <= lim) ? sc[q]*0.125f : -1e30f;
            float mx = sc[q];
            #pragma unroll
            for (int o = 16; o; o >>= 1) mx = fmaxf(mx, __shfl_xor_sync(0xffffffffu, mx, o));
            if (lane == 0) wredM[wid][q] = mx;
        }
        __syncthreads();
        #pragma unroll
        for (int q = 0; q < 8; q++) {
            float newm = fmaxf(m[q], fmaxf(wredM[qg*2][q], wredM[qg*2+1][q]));
            float pv = (sc[q] > -1e29f) ? __expf(sc[q] - newm) : 0.f;
            float corr = __expf(m[q] - newm);
            acc[q] *= corr; l[q] *= corr; m[q] = newm;
            sp[qg*8 + q][d] = pv;
            float s = pv;
            #pragma unroll
            for (int o = 16; o; o >>= 1) s += __shfl_xor_sync(0xffffffffu, s, o);
            if (lane == 0) wredS[wid][q] = s;
        }
        __syncthreads();
        #pragma unroll
        for (int q = 0; q < 8; q++) l[q] += wredS[qg*2][q] + wredS[qg*2+1][q];
        for (int i = 0; i < 64; i += 2) {
            float v0 = Vs[i][d], v1 = Vs[i+1][d];
            #pragma unroll
            for (int q = 0; q < 8; q++) {
                float2 pp = *(const float2*)&sp[qg*8 + q][i];
                acc[q] = fmaf(pp.x, v0, acc[q]);
                acc[q] = fmaf(pp.y, v1, acc[q]);
            }
        }
    }
    #pragma unroll
    for (int q = 0; q < 8; q++)
        g_om[((size_t)h*SEQ + qoff + q)*64 + d] = acc[q] / l[q];
}

// ---------------- de-interleave ----------------
__global__ void deinterleave_kernel() {
    int r = blockIdx.x, h = blockIdx.y, d = threadIdx.x;
    int bi = r >> 10, si = r & 1023;
    int t = 2*si + bi;
    g_orows[(size_t)r*DIMM + h*64 + d] = g_om[((size_t)h*SEQ + t)*64 + d];
}

// ---------------- router ----------------
__global__ void router_kernel(const float* __restrict__ pkeys, const float* __restrict__ fkeys,
                              const float* __restrict__ pbias, const float* __restrict__ fbias,
                              const int* __restrict__ pidx, const float* __restrict__ pval,
                              const int* __restrict__ fidx, const float* __restrict__ fval) {
    int tok = blockIdx.x, tid = threadIdx.x;
    bool isf = tok >= 1024;
    const float* keys = isf ? fkeys : pkeys;
    const float* x = g_xffn + (size_t)tok*DIMM;
    __shared__ float part[8][16];
    __shared__ float logit[16];
    int e = tid & 15, ch = tid >> 4;
    float s = 0.f;
    int d0 = ch * 128;
    for (int d = d0; d < d0 + 128; d++) s = fmaf(x[d], keys[d*16 + e], s);
    part[ch][e] = s;
    __syncthreads();
    if (tid < 16) {
        float t = 0.f;
        #pragma unroll
        for (int c = 0; c < 8; c++) t += part[c][tid];
        logit[tid] = t;
    }
    __syncthreads();
    if (tid == 0) {
        int lt = isf ? tok - 1024 : tok;
        const int*   idx  = isf ? fidx  : pidx;
        const float* val  = isf ? fval  : pval;
        const float* bias = isf ? fbias : pbias;
        float sc[4]; int id[4]; float sum = 0.f;
        #pragma unroll
        for (int k = 0; k < 4; k++) {
            int ix = idx[lt*4 + k];
            float v = val[lt*4 + k] + logit[ix] + bias[ix];
            float s2 = 1.f / (1.f + expf(-v));
            sc[k] = s2; sum += s2;
            id[k] = ix + (isf ? 16 : 0);
        }
        #pragma unroll
        for (int k = 0; k < 4; k++) {
            g_scales[tok*4 + k] = sc[k] / sum;
            g_eid[tok*4 + k] = id[k];
            atomicAdd(&g_counts[id[k]], 1);
        }
    }
}

__global__ void zero32_kernel() {
    int i = threadIdx.x;
    if (i < NEXP) { g_counts[i] = 0; g_cursors[i] = 0; }
}

__global__ void prefix_kernel() {
    int acc = 0;
    for (int e = 0; e < NEXP; e++) { g_offsets[e] = acc; acc += g_counts[e]; }
}

__global__ void scatter_kernel() {
    int a = blockIdx.x * blockDim.x + threadIdx.x;
    if (a >= NASS) return;
    int e = g_eid[a];
    int p = g_offsets[e] + atomicAdd(&g_cursors[e], 1);
    g_tokof[p] = a >> 2;
    g_posof[a] = p;
}

__global__ void swiglu_moe_kernel() {
    size_t i = (size_t)blockIdx.x * blockDim.x + threadIdx.x;
    float g = g_G[i], u = g_U[i];
    g_G[i] = (g / (1.f + expf(-g))) * u;
}

__global__ void combine_kernel(float* __restrict__ y) {
    int tok = blockIdx.x;
    __shared__ int pos[4];
    __shared__ float sc[4];
    if (threadIdx.x < 4) {
        pos[threadIdx.x] = g_posof[tok*4 + threadIdx.x];
        sc[threadIdx.x]  = g_scales[tok*4 + threadIdx.x];
    }
    __syncthreads();
    for (int d = threadIdx.x; d < DIMM; d += 256) {
        float v = g_xffni[(size_t)tok*DIMM + d];
        #pragma unroll
        for (int k = 0; k < 4; k++) v = fmaf(sc[k], g_slots[(size_t)pos[k]*DIMM + d], v);
        y[(size_t)tok*DIMM + d] = v;
    }
}

__global__ void swiglu_shared_kernel() {
    int t = blockIdx.x;
    for (int j = threadIdx.x; j < DSH; j += 256) {
        float a = g_su[(size_t)t*2*DSH + j];
        float b = g_su[(size_t)t*2*DSH + DSH + j];
        g_hs[(size_t)t*DSH + j] = (a / (1.f + expf(-a))) * b;
    }
}

// ---------------- launch ----------------
extern "C" void kernel_launch(void* const* d_in, const int* in_sizes, int n_in,
                              void* d_out, int out_size) {
    const float* x_input  = (const float*)d_in[0];
    const int*   p_idx    = (const int*)  d_in[1];
    const float* p_val    = (const float*)d_in[2];
    const int*   f_idx    = (const int*)  d_in[3];
    const float* f_val    = (const float*)d_in[4];
    const float* attn_nw  = (const float*)d_in[5];
    const float* ffn_nw   = (const float*)d_in[6];
    const float* W_attn   = (const float*)d_in[7];
    const float* W_attn_o = (const float*)d_in[8];
    const float* ffn_up   = (const float*)d_in[9];
    const float* ffn_down = (const float*)d_in[10];
    const float* pW       = (const float*)d_in[11];
    const float* fW       = (const float*)d_in[12];
    const float* pkeys    = (const float*)d_in[13];
    const float* fkeys    = (const float*)d_in[14];
    const float* pbias    = (const float*)d_in[15];
    const float* fbias    = (const float*)d_in[16];
    float* out = (float*)d_out;

    float *xnorm, *qkv, *orows, *xffni, *xffn, *su, *hs;
    cudaGetSymbolAddress((void**)&xnorm, g_xnorm);
    cudaGetSymbolAddress((void**)&qkv,   g_qkv);
    cudaGetSymbolAddress((void**)&orows, g_orows);
    cudaGetSymbolAddress((void**)&xffni, g_xffni);
    cudaGetSymbolAddress((void**)&xffn,  g_xffn);
    cudaGetSymbolAddress((void**)&su,    g_su);
    cudaGetSymbolAddress((void**)&hs,    g_hs);

    // attention block
    rmsnorm_kernel<<<TOK, 256>>>(x_input, attn_nw, xnorm);
    gemm_nn<<<dim3(24, 16), 256>>>(xnorm, W_attn, qkv, nullptr, TOK, 3*DIMM, DIMM);
    rope_interleave_kernel<<<dim3(TOK, NH), 64>>>();
    attn_kernel<<<dim3(SEQ/16, NH), 128>>>();
    deinterleave_kernel<<<dim3(TOK, NH), 64>>>();
    gemm_nn<<<dim3(8, 16), 256>>>(orows, W_attn_o, xffni, x_input, TOK, DIMM, DIMM);
    rmsnorm_kernel<<<TOK, 256>>>(xffni, ffn_nw, xffn);

    // routing
    zero32_kernel<<<1, 32>>>();
    router_kernel<<<TOK, 128>>>(pkeys, fkeys, pbias, fbias, p_idx, p_val, f_idx, f_val);
    prefix_kernel<<<1, 1>>>();
    scatter_kernel<<<32, 256>>>();

    // grouped MoE
    moe_gu_tf32<<<dim3(8, 16, NEXP), 256>>>(pW, fW);
    swiglu_moe_kernel<<<(NASS*FDIM)/256, 256>>>();
    moe_down_tf32<<<dim3(8, 16, NEXP), 256>>>(pW, fW);
    combine_kernel<<<TOK, 256>>>(out);

    // shared expert (adds into out)
    gemm_nn<<<dim3(32, 16), 256>>>(xffn, ffn_up, su, nullptr, TOK, 2*DSH, DIMM);
    swiglu_shared_kernel<<<TOK, 256>>>();
    gemm_nn<<<dim3(8, 16), 256>>>(hs, ffn_down, out, out, TOK, DIMM, DSH);
}

// round 3
// speedup vs baseline: 4.0968x; 1.4519x over previous
#include <cuda_runtime.h>
#include <math.h>

// ---------------- problem constants ----------------
#define TOK   2048
#define DIMM  1024
#define NH    16
#define HD    64
#define SEQ   2048
#define NASS  8192
#define NEXP  32
#define FDIM  512
#define DSH   2048

// ---------------- scratch ----------------
__device__ float g_xnorm[TOK*DIMM];
__device__ float g_qkv[TOK*3*DIMM];
__device__ float g_qm[NH*SEQ*HD];
__device__ float g_km[NH*SEQ*HD];
__device__ float g_vm[NH*SEQ*HD];
__device__ float g_orows[TOK*DIMM];
__device__ float g_xffni[TOK*DIMM];
__device__ float g_xffn[TOK*DIMM];
__device__ float g_G[NASS*FDIM];
__device__ float g_U[NASS*FDIM];
__device__ float g_slots[(size_t)NASS*DIMM];
__device__ float g_su[(size_t)TOK*2*DSH];
__device__ float g_hs[(size_t)TOK*DSH];
__device__ float g_scales[NASS];
__device__ int   g_eid[NASS];
__device__ int   g_tokof[NASS];
__device__ int   g_posof[NASS];
__device__ int   g_counts[NEXP];
__device__ int   g_offsets[NEXP];
__device__ int   g_cursors[NEXP];

// ---------------- tf32 helpers ----------------
__device__ __forceinline__ unsigned f2tf(float x) {
    unsigned r; asm("cvt.rna.tf32.f32 %0, %1;" : "=r"(r) : "f"(x)); return r;
}
__device__ __forceinline__ void st4tf(unsigned* dst, float4 v) {
    uint4 u; u.x = f2tf(v.x); u.y = f2tf(v.y); u.z = f2tf(v.z); u.w = f2tf(v.w);
    *(uint4*)dst = u;
}
__device__ __forceinline__ void mma8(float c[4], const unsigned a[4], const unsigned b[2]) {
    asm volatile("mma.sync.aligned.m16n8k8.row.col.f32.tf32.tf32.f32 "
                 "{%0,%1,%2,%3},{%4,%5,%6,%7},{%8,%9},{%0,%1,%2,%3};"
                 : "+f"(c[0]), "+f"(c[1]), "+f"(c[2]), "+f"(c[3])
                 : "r"(a[0]), "r"(a[1]), "r"(a[2]), "r"(a[3]), "r"(b[0]), "r"(b[1]));
}

// ---------------- dense GEMM infrastructure (unchanged from R2) ----------------
template<bool BT>
__device__ __forceinline__ void compute_tile(const unsigned* __restrict__ As,
                                             const unsigned* __restrict__ Bs,
                                             int wm, int wn, int g, int t4,
                                             float acc[16][4]) {
    #pragma unroll
    for (int ks = 0; ks < 2; ks++) {
        int kc = ks*8 + t4;
        unsigned af[2][4];
        #pragma unroll
        for (int mi = 0; mi < 2; mi++) {
            int r = wm + mi*16 + g;
            af[mi][0] = As[r*20 + kc];
            af[mi][1] = As[(r+8)*20 + kc];
            af[mi][2] = As[r*20 + kc + 4];
            af[mi][3] = As[(r+8)*20 + kc + 4];
        }
        #pragma unroll
        for (int ni = 0; ni < 8; ni++) {
            unsigned bf[2];
            int n = wn + ni*8 + g;
            if (BT) { bf[0] = Bs[n*20 + kc];  bf[1] = Bs[n*20 + kc + 4]; }
            else    { bf[0] = Bs[kc*136 + n]; bf[1] = Bs[(kc+4)*136 + n]; }
            #pragma unroll
            for (int mi = 0; mi < 2; mi++) mma8(acc[mi*8+ni], af[mi], bf);
        }
    }
}

__global__ void __launch_bounds__(256) gemm_nn(const float* __restrict__ A,
                                               const float* __restrict__ B,
                                               float* __restrict__ C,
                                               const float* __restrict__ D,
                                               int M, int N, int K) {
    __shared__ __align__(16) unsigned As[2][2560];
    __shared__ __align__(16) unsigned Bs[2][2176];
    int tid = threadIdx.x, lane = tid & 31, wid = tid >> 5;
    int g = lane >> 2, t4 = lane & 3;
    int wm = (wid & 3)*32, wn = (wid >> 2)*64;
    size_t rowBase = (size_t)blockIdx.y * 128, colBase = (size_t)blockIdx.x * 128;
    int a_r = tid >> 2, a_c = (tid & 3)*4;
    int b_r = tid >> 5, b_c = (tid & 31)*4;
    const float* Ap0 = A + (rowBase + a_r)*K + a_c;
    const float* Ap1 = Ap0 + (size_t)64*K;
    const float* Bp0 = B + (size_t)b_r*N + colBase + b_c;
    const float* Bp1 = Bp0 + (size_t)8*N;
    float acc[16][4];
    #pragma unroll
    for (int i = 0; i < 16; i++)
        #pragma unroll
        for (int j = 0; j < 4; j++) acc[i][j] = 0.f;
    float4 ra0 = *(const float4*)Ap0;
    float4 ra1 = *(const float4*)Ap1;
    float4 rb0 = *(const float4*)Bp0;
    float4 rb1 = *(const float4*)Bp1;
    int buf = 0;
    st4tf(&As[0][a_r*20 + a_c], ra0);
    st4tf(&As[0][(a_r+64)*20 + a_c], ra1);
    st4tf(&Bs[0][b_r*136 + b_c], rb0);
    st4tf(&Bs[0][(b_r+8)*136 + b_c], rb1);
    __syncthreads();
    for (int kt = 0; kt < K; kt += 16) {
        int nxt = kt + 16;
        if (nxt < K) {
            ra0 = *(const float4*)(Ap0 + nxt);
            ra1 = *(const float4*)(Ap1 + nxt);
            rb0 = *(const float4*)(Bp0 + (size_t)nxt*N);
            rb1 = *(const float4*)(Bp1 + (size_t)nxt*N);
        }
        compute_tile<false>(As[buf], Bs[buf], wm, wn, g, t4, acc);
        if (nxt < K) {
            st4tf(&As[buf^1][a_r*20 + a_c], ra0);
            st4tf(&As[buf^1][(a_r+64)*20 + a_c], ra1);
            st4tf(&Bs[buf^1][b_r*136 + b_c], rb0);
            st4tf(&Bs[buf^1][(b_r+8)*136 + b_c], rb1);
        }
        __syncthreads();
        buf ^= 1;
    }
    #pragma unroll
    for (int mi = 0; mi < 2; mi++)
        #pragma unroll
        for (int ni = 0; ni < 8; ni++) {
            float* c = acc[mi*8+ni];
            size_t r0 = rowBase + wm + mi*16 + g;
            size_t c0 = colBase + wn + ni*8 + 2*t4;
            size_t o0 = r0*N + c0, o1 = (r0+8)*N + c0;
            if (D) {
                C[o0] = c[0] + D[o0]; C[o0+1] = c[1] + D[o0+1];
                C[o1] = c[2] + D[o1]; C[o1+1] = c[3] + D[o1+1];
            } else {
                C[o0] = c[0]; C[o0+1] = c[1];
                C[o1] = c[2]; C[o1+1] = c[3];
            }
        }
}

// ---------------- MoE gate+up fused grouped GEMM ----------------
__global__ void __launch_bounds__(256) moe_gu_tf32(const float* __restrict__ pW,
                                                   const float* __restrict__ fW) {
    int e = blockIdx.z;
    int cnt = g_counts[e];
    int rowTile = blockIdx.y * 128;
    if (rowTile >= cnt) return;
    int base = g_offsets[e];
    int colBase = blockIdx.x * 128;
    int sel = colBase >> 9;
    int wcol = colBase & 511;
    const float* W = (e < 16) ? pW + ((size_t)sel*16 + e)      * (size_t)DIMM*FDIM
                              : fW + ((size_t)sel*16 + (e-16)) * (size_t)DIMM*FDIM;
    float* Out = sel ? g_U : g_G;
    __shared__ int rows[128];
    __shared__ __align__(16) unsigned As[2][2560];
    __shared__ __align__(16) unsigned Bs[2][2176];
    int tid = threadIdx.x;
    if (tid < 128) {
        int rr = rowTile + tid;
        rows[tid] = (rr < cnt) ? g_tokof[base + rr] : -1;
    }
    __syncthreads();
    int lane = tid & 31, wid = tid >> 5;
    int g = lane >> 2, t4 = lane & 3;
    int wm = (wid & 3)*32, wn = (wid >> 2)*64;
    int a_r = tid >> 2, a_c = (tid & 3)*4;
    int b_r = tid >> 5, b_c = (tid & 31)*4;
    int tk0 = rows[a_r], tk1 = rows[a_r + 64];
    const float4 z4 = make_float4(0.f, 0.f, 0.f, 0.f);
    const float* Ap0 = g_xffn + (size_t)(tk0 < 0 ? 0 : tk0)*DIMM + a_c;
    const float* Ap1 = g_xffn + (size_t)(tk1 < 0 ? 0 : tk1)*DIMM + a_c;
    const float* Bp0 = W + (size_t)b_r*FDIM + wcol + b_c;
    const float* Bp1 = Bp0 + (size_t)8*FDIM;
    float acc[16][4];
    #pragma unroll
    for (int i = 0; i < 16; i++)
        #pragma unroll
        for (int j = 0; j < 4; j++) acc[i][j] = 0.f;
    float4 ra0 = (tk0 >= 0) ? *(const float4*)Ap0 : z4;
    float4 ra1 = (tk1 >= 0) ? *(const float4*)Ap1 : z4;
    float4 rb0 = *(const float4*)Bp0;
    float4 rb1 = *(const float4*)Bp1;
    int buf = 0;
    st4tf(&As[0][a_r*20 + a_c], ra0);
    st4tf(&As[0][(a_r+64)*20 + a_c], ra1);
    st4tf(&Bs[0][b_r*136 + b_c], rb0);
    st4tf(&Bs[0][(b_r+8)*136 + b_c], rb1);
    __syncthreads();
    for (int kt = 0; kt < DIMM; kt += 16) {
        int nxt = kt + 16;
        if (nxt < DIMM) {
            ra0 = (tk0 >= 0) ? *(const float4*)(Ap0 + nxt) : z4;
            ra1 = (tk1 >= 0) ? *(const float4*)(Ap1 + nxt) : z4;
            rb0 = *(const float4*)(Bp0 + (size_t)nxt*FDIM);
            rb1 = *(const float4*)(Bp1 + (size_t)nxt*FDIM);
        }
        compute_tile<false>(As[buf], Bs[buf], wm, wn, g, t4, acc);
        if (nxt < DIMM) {
            st4tf(&As[buf^1][a_r*20 + a_c], ra0);
            st4tf(&As[buf^1][(a_r+64)*20 + a_c], ra1);
            st4tf(&Bs[buf^1][b_r*136 + b_c], rb0);
            st4tf(&Bs[buf^1][(b_r+8)*136 + b_c], rb1);
        }
        __syncthreads();
        buf ^= 1;
    }
    #pragma unroll
    for (int mi = 0; mi < 2; mi++)
        #pragma unroll
        for (int ni = 0; ni < 8; ni++) {
            float* c = acc[mi*8+ni];
            int r = rowTile + wm + mi*16 + g;
            int cc = wcol + wn + ni*8 + 2*t4;
            if (r < cnt) {
                Out[(size_t)(base+r)*FDIM + cc]     = c[0];
                Out[(size_t)(base+r)*FDIM + cc + 1] = c[1];
            }
            if (r + 8 < cnt) {
                Out[(size_t)(base+r+8)*FDIM + cc]     = c[2];
                Out[(size_t)(base+r+8)*FDIM + cc + 1] = c[3];
            }
        }
}

// ---------------- MoE down grouped GEMM ----------------
__global__ void __launch_bounds__(256) moe_down_tf32(const float* __restrict__ pW,
                                                     const float* __restrict__ fW) {
    int e = blockIdx.z;
    int cnt = g_counts[e];
    int rowTile = blockIdx.y * 128;
    if (rowTile >= cnt) return;
    int base = g_offsets[e];
    int colBase = blockIdx.x * 128;
    const float* W = (e < 16) ? pW + ((size_t)2*16 + e)      * (size_t)DIMM*FDIM
                              : fW + ((size_t)2*16 + (e-16)) * (size_t)DIMM*FDIM;
    __shared__ __align__(16) unsigned As[2][2560];
    __shared__ __align__(16) unsigned Bs[2][2560];
    int tid = threadIdx.x, lane = tid & 31, wid = tid >> 5;
    int g = lane >> 2, t4 = lane & 3;
    int wm = (wid & 3)*32, wn = (wid >> 2)*64;
    int a_r = tid >> 2, a_c = (tid & 3)*4;
    bool v0 = (rowTile + a_r) < cnt, v1 = (rowTile + a_r + 64) < cnt;
    const float4 z4 = make_float4(0.f, 0.f, 0.f, 0.f);
    const float* Ap0 = g_G + (size_t)(base + rowTile + a_r)*FDIM + a_c;
    const float* Ap1 = g_G + (size_t)(base + rowTile + a_r + 64)*FDIM + a_c;
    const float* Bp0 = W + (size_t)(colBase + a_r)*FDIM + a_c;
    const float* Bp1 = W + (size_t)(colBase + a_r + 64)*FDIM + a_c;
    float acc[16][4];
    #pragma unroll
    for (int i = 0; i < 16; i++)
        #pragma unroll
        for (int j = 0; j < 4; j++) acc[i][j] = 0.f;
    float4 ra0 = v0 ? *(const float4*)Ap0 : z4;
    float4 ra1 = v1 ? *(const float4*)Ap1 : z4;
    float4 rb0 = *(const float4*)Bp0;
    float4 rb1 = *(const float4*)Bp1;
    int buf = 0;
    st4tf(&As[0][a_r*20 + a_c], ra0);
    st4tf(&As[0][(a_r+64)*20 + a_c], ra1);
    st4tf(&Bs[0][a_r*20 + a_c], rb0);
    st4tf(&Bs[0][(a_r+64)*20 + a_c], rb1);
    __syncthreads();
    for (int kt = 0; kt < FDIM; kt += 16) {
        int nxt = kt + 16;
        if (nxt < FDIM) {
            ra0 = v0 ? *(const float4*)(Ap0 + nxt) : z4;
            ra1 = v1 ? *(const float4*)(Ap1 + nxt) : z4;
            rb0 = *(const float4*)(Bp0 + nxt);
            rb1 = *(const float4*)(Bp1 + nxt);
        }
        compute_tile<true>(As[buf], Bs[buf], wm, wn, g, t4, acc);
        if (nxt < FDIM) {
            st4tf(&As[buf^1][a_r*20 + a_c], ra0);
            st4tf(&As[buf^1][(a_r+64)*20 + a_c], ra1);
            st4tf(&Bs[buf^1][a_r*20 + a_c], rb0);
            st4tf(&Bs[buf^1][(a_r+64)*20 + a_c], rb1);
        }
        __syncthreads();
        buf ^= 1;
    }
    #pragma unroll
    for (int mi = 0; mi < 2; mi++)
        #pragma unroll
        for (int ni = 0; ni < 8; ni++) {
            float* c = acc[mi*8+ni];
            int r = rowTile + wm + mi*16 + g;
            int cc = colBase + wn + ni*8 + 2*t4;
            if (r < cnt) {
                g_slots[(size_t)(base+r)*DIMM + cc]     = c[0];
                g_slots[(size_t)(base+r)*DIMM + cc + 1] = c[1];
            }
            if (r + 8 < cnt) {
                g_slots[(size_t)(base+r+8)*DIMM + cc]     = c[2];
                g_slots[(size_t)(base+r+8)*DIMM + cc + 1] = c[3];
            }
        }
}

// ---------------- rmsnorm ----------------
__global__ void rmsnorm_kernel(const float* __restrict__ x, const float* __restrict__ w,
                               float* __restrict__ out) {
    int r = blockIdx.x;
    const float* xr = x + (size_t)r*DIMM;
    __shared__ float red[8];
    float s = 0.f;
    for (int d = threadIdx.x; d < DIMM; d += 256) { float v = xr[d]; s += v*v; }
    #pragma unroll
    for (int o = 16; o; o >>= 1) s += __shfl_xor_sync(0xffffffffu, s, o);
    if ((threadIdx.x & 31) == 0) red[threadIdx.x >> 5] = s;
    __syncthreads();
    if (threadIdx.x == 0) {
        float t = 0.f;
        #pragma unroll
        for (int i = 0; i < 8; i++) t += red[i];
        red[0] = rsqrtf(t / (float)DIMM + 1e-5f);
    }
    __syncthreads();
    float rms = red[0];
    for (int d = threadIdx.x; d < DIMM; d += 256)
        out[(size_t)r*DIMM + d] = xr[d] * rms * w[d];
}

// ---------------- rope + dual interleave ----------------
__global__ void rope_interleave_kernel() {
    int r = blockIdx.x, h = blockIdx.y, d = threadIdx.x;
    int bi = r >> 10, si = r & 1023;
    int t = 2*si + bi;
    size_t src = (size_t)r*3072 + h*64;
    size_t dst = ((size_t)h*SEQ + t)*64;
    float q = g_qkv[src + d];
    float k = g_qkv[src + 1024 + d];
    float v = g_qkv[src + 2048 + d];
    g_vm[dst + d] = v;
    __shared__ float qs[64], ks[64];
    qs[d] = q; ks[d] = k;
    __syncthreads();
    if (d < 32) {
        float inv = powf(10000.0f, -(float)(2*d) / 64.0f);
        float fr = (float)si * inv;
        float sn, cs;
        sincosf(fr, &sn, &cs);
        float x1 = qs[d], x2 = qs[d+32];
        g_qm[dst + d]      =  x1*cs + x2*sn;
        g_qm[dst + d + 32] = -x1*sn + x2*cs;
        x1 = ks[d]; x2 = ks[d+32];
        g_km[dst + d]      =  x1*cs + x2*sn;
        g_km[dst + d + 32] = -x1*sn + x2*cs;
    }
}

// ---------------- tensor-core flash attention ----------------
// Block: 64 queries x 1 head, 4 warps (16 query rows each), tf32 mma for S and PV.
// Smem (dynamic, words): Qs[64*68], Ks[64*68], Ps[64*68], Vt[64*69]
#define ATT_SMEM_WORDS (4352*3 + 64*69)
__global__ void __launch_bounds__(128) attn_tc() {
    extern __shared__ __align__(16) unsigned smem[];
    unsigned* Qs = smem;               // [row][k]  stride 68
    unsigned* Ks = smem + 4352;        // [key][k]  stride 68
    unsigned* Ps = smem + 8704;        // [row][key] stride 68 (tf32)
    unsigned* Vt = smem + 13056;       // [dim][key] stride 69
    int h = blockIdx.y;
    int t0 = ((int)gridDim.x - 1 - (int)blockIdx.x) * 64;   // heavy blocks first
    int tid = threadIdx.x, lane = tid & 31, wid = tid >> 5;
    int g = lane >> 2, t4 = lane & 3;
    int wm = wid * 16;

    const float* qb = g_qm + ((size_t)h*SEQ + t0)*64;
    for (int i = tid; i < 64*16; i += 128) {
        int r = i >> 4, c = (i & 15) * 4;
        st4tf(&Qs[r*68 + c], *(const float4*)(qb + r*64 + c));
    }

    float o[8][4];
    #pragma unroll
    for (int n = 0; n < 8; n++)
        #pragma unroll
        for (int j = 0; j < 4; j++) o[n][j] = 0.f;
    float m0 = -1e30f, m1 = -1e30f, l0 = 0.f, l1 = 0.f;
    int row0 = t0 + wm + g, row1 = row0 + 8;

    for (int kt = 0; kt <= t0; kt += 64) {
        __syncthreads();
        const float* kb = g_km + ((size_t)h*SEQ + kt)*64;
        const float* vb = g_vm + ((size_t)h*SEQ + kt)*64;
        for (int i = tid; i < 64*16; i += 128) {
            int r = i >> 4, c = (i & 15) * 4;
            st4tf(&Ks[r*68 + c], *(const float4*)(kb + r*64 + c));
            float4 v = *(const float4*)(vb + r*64 + c);
            Vt[(c    )*69 + r] = f2tf(v.x);
            Vt[(c + 1)*69 + r] = f2tf(v.y);
            Vt[(c + 2)*69 + r] = f2tf(v.z);
            Vt[(c + 3)*69 + r] = f2tf(v.w);
        }
        __syncthreads();

        // S = Q K^T  (per warp: 16 rows x 64 keys)
        float s[8][4];
        #pragma unroll
        for (int n = 0; n < 8; n++)
            #pragma unroll
            for (int j = 0; j < 4; j++) s[n][j] = 0.f;
        #pragma unroll
        for (int ks = 0; ks < 8; ks++) {
            int kc = ks*8 + t4;
            unsigned af[4];
            af[0] = Qs[(wm+g)*68 + kc];
            af[1] = Qs[(wm+g+8)*68 + kc];
            af[2] = Qs[(wm+g)*68 + kc + 4];
            af[3] = Qs[(wm+g+8)*68 + kc + 4];
            #pragma unroll
            for (int n = 0; n < 8; n++) {
                unsigned bf[2];
                bf[0] = Ks[(n*8+g)*68 + kc];
                bf[1] = Ks[(n*8+g)*68 + kc + 4];
                mma8(s[n], af, bf);
            }
        }
        // causal mask + scale + row max
        float mx0 = -1e30f, mx1 = -1e30f;
        #pragma unroll
        for (int n = 0; n < 8; n++) {
            int c0 = kt + n*8 + 2*t4, c1 = c0 + 1;
            s[n][0] = (c0 <= row0) ? s[n][0]*0.125f : -1e30f;
            s[n][1] = (c1 <= row0) ? s[n][1]*0.125f : -1e30f;
            s[n][2] = (c0 <= row1) ? s[n][2]*0.125f : -1e30f;
            s[n][3] = (c1 <= row1) ? s[n][3]*0.125f : -1e30f;
            mx0 = fmaxf(mx0, fmaxf(s[n][0], s[n][1]));
            mx1 = fmaxf(mx1, fmaxf(s[n][2], s[n][3]));
        }
        mx0 = fmaxf(mx0, __shfl_xor_sync(0xffffffffu, mx0, 1));
        mx0 = fmaxf(mx0, __shfl_xor_sync(0xffffffffu, mx0, 2));
        mx1 = fmaxf(mx1, __shfl_xor_sync(0xffffffffu, mx1, 1));
        mx1 = fmaxf(mx1, __shfl_xor_sync(0xffffffffu, mx1, 2));
        float nm0 = fmaxf(m0, mx0), nm1 = fmaxf(m1, mx1);
        float cor0 = __expf(m0 - nm0), cor1 = __expf(m1 - nm1);
        m0 = nm0; m1 = nm1;
        l0 *= cor0; l1 *= cor1;
        float sum0 = 0.f, sum1 = 0.f;
        #pragma unroll
        for (int n = 0; n < 8; n++) {
            float p00 = __expf(s[n][0] - nm0), p01 = __expf(s[n][1] - nm0);
            float p10 = __expf(s[n][2] - nm1), p11 = __expf(s[n][3] - nm1);
            sum0 += p00 + p01; sum1 += p10 + p11;
            uint2 u0 = make_uint2(f2tf(p00), f2tf(p01));
            uint2 u1 = make_uint2(f2tf(p10), f2tf(p11));
            *(uint2*)&Ps[(wm+g)*68 + n*8 + 2*t4]   = u0;
            *(uint2*)&Ps[(wm+g+8)*68 + n*8 + 2*t4] = u1;
            #pragma unroll
            for (int j = 0; j < 2; j++) { o[n][j] *= cor0; o[n][2+j] *= cor1; }
        }
        sum0 += __shfl_xor_sync(0xffffffffu, sum0, 1);
        sum0 += __shfl_xor_sync(0xffffffffu, sum0, 2);
        sum1 += __shfl_xor_sync(0xffffffffu, sum1, 1);
        sum1 += __shfl_xor_sync(0xffffffffu, sum1, 2);
        l0 += sum0; l1 += sum1;
        __syncwarp();

        // O += P V   (A = Ps rows of this warp, B = Vt)
        #pragma unroll
        for (int ks = 0; ks < 8; ks++) {
            int kc = ks*8 + t4;
            unsigned af[4];
            af[0] = Ps[(wm+g)*68 + kc];
            af[1] = Ps[(wm+g+8)*68 + kc];
            af[2] = Ps[(wm+g)*68 + kc + 4];
            af[3] = Ps[(wm+g+8)*68 + kc + 4];
            #pragma unroll
            for (int n = 0; n < 8; n++) {
                unsigned bf[2];
                bf[0] = Vt[(n*8+g)*69 + kc];
                bf[1] = Vt[(n*8+g)*69 + kc + 4];
                mma8(o[n], af, bf);
            }
        }
    }

    // epilogue: divide by l, de-interleave directly into token rows
    float inv0 = 1.f / l0, inv1 = 1.f / l1;
    int tok0 = (row0 & 1)*1024 + (row0 >> 1);
    int tok1 = (row1 & 1)*1024 + (row1 >> 1);
    #pragma unroll
    for (int n = 0; n < 8; n++) {
        int col = h*64 + n*8 + 2*t4;
        *(float2*)&g_orows[(size_t)tok0*DIMM + col] = make_float2(o[n][0]*inv0, o[n][1]*inv0);
        *(float2*)&g_orows[(size_t)tok1*DIMM + col] = make_float2(o[n][2]*inv1, o[n][3]*inv1);
    }
}

// ---------------- router ----------------
__global__ void router_kernel(const float* __restrict__ pkeys, const float* __restrict__ fkeys,
                              const float* __restrict__ pbias, const float* __restrict__ fbias,
                              const int* __restrict__ pidx, const float* __restrict__ pval,
                              const int* __restrict__ fidx, const float* __restrict__ fval) {
    int tok = blockIdx.x, tid = threadIdx.x;
    bool isf = tok >= 1024;
    const float* keys = isf ? fkeys : pkeys;
    const float* x = g_xffn + (size_t)tok*DIMM;
    __shared__ float part[8][16];
    __shared__ float logit[16];
    int e = tid & 15, ch = tid >> 4;
    float s = 0.f;
    int d0 = ch * 128;
    for (int d = d0; d < d0 + 128; d++) s = fmaf(x[d], keys[d*16 + e], s);
    part[ch][e] = s;
    __syncthreads();
    if (tid < 16) {
        float t = 0.f;
        #pragma unroll
        for (int c = 0; c < 8; c++) t += part[c][tid];
        logit[tid] = t;
    }
    __syncthreads();
    if (tid == 0) {
        int lt = isf ? tok - 1024 : tok;
        const int*   idx  = isf ? fidx  : pidx;
        const float* val  = isf ? fval  : pval;
        const float* bias = isf ? fbias : pbias;
        float sc[4]; int id[4]; float sum = 0.f;
        #pragma unroll
        for (int k = 0; k < 4; k++) {
            int ix = idx[lt*4 + k];
            float v = val[lt*4 + k] + logit[ix] + bias[ix];
            float s2 = 1.f / (1.f + expf(-v));
            sc[k] = s2; sum += s2;
            id[k] = ix + (isf ? 16 : 0);
        }
        #pragma unroll
        for (int k = 0; k < 4; k++) {
            g_scales[tok*4 + k] = sc[k] / sum;
            g_eid[tok*4 + k] = id[k];
            atomicAdd(&g_counts[id[k]], 1);
        }
    }
}

__global__ void zero32_kernel() {
    int i = threadIdx.x;
    if (i < NEXP) { g_counts[i] = 0; g_cursors[i] = 0; }
}

__global__ void prefix_kernel() {
    int acc = 0;
    for (int e = 0; e < NEXP; e++) { g_offsets[e] = acc; acc += g_counts[e]; }
}

__global__ void scatter_kernel() {
    int a = blockIdx.x * blockDim.x + threadIdx.x;
    if (a >= NASS) return;
    int e = g_eid[a];
    int p = g_offsets[e] + atomicAdd(&g_cursors[e], 1);
    g_tokof[p] = a >> 2;
    g_posof[a] = p;
}

__global__ void swiglu_moe_kernel() {
    size_t i = (size_t)blockIdx.x * blockDim.x + threadIdx.x;
    float g = g_G[i], u = g_U[i];
    g_G[i] = (g / (1.f + expf(-g))) * u;
}

__global__ void combine_kernel(float* __restrict__ y) {
    int tok = blockIdx.x;
    __shared__ int pos[4];
    __shared__ float sc[4];
    if (threadIdx.x < 4) {
        pos[threadIdx.x] = g_posof[tok*4 + threadIdx.x];
        sc[threadIdx.x]  = g_scales[tok*4 + threadIdx.x];
    }
    __syncthreads();
    for (int d = threadIdx.x; d < DIMM; d += 256) {
        float v = g_xffni[(size_t)tok*DIMM + d];
        #pragma unroll
        for (int k = 0; k < 4; k++) v = fmaf(sc[k], g_slots[(size_t)pos[k]*DIMM + d], v);
        y[(size_t)tok*DIMM + d] = v;
    }
}

__global__ void swiglu_shared_kernel() {
    int t = blockIdx.x;
    for (int j = threadIdx.x; j < DSH; j += 256) {
        float a = g_su[(size_t)t*2*DSH + j];
        float b = g_su[(size_t)t*2*DSH + DSH + j];
        g_hs[(size_t)t*DSH + j] = (a / (1.f + expf(-a))) * b;
    }
}

// ---------------- launch ----------------
extern "C" void kernel_launch(void* const* d_in, const int* in_sizes, int n_in,
                              void* d_out, int out_size) {
    const float* x_input  = (const float*)d_in[0];
    const int*   p_idx    = (const int*)  d_in[1];
    const float* p_val    = (const float*)d_in[2];
    const int*   f_idx    = (const int*)  d_in[3];
    const float* f_val    = (const float*)d_in[4];
    const float* attn_nw  = (const float*)d_in[5];
    const float* ffn_nw   = (const float*)d_in[6];
    const float* W_attn   = (const float*)d_in[7];
    const float* W_attn_o = (const float*)d_in[8];
    const float* ffn_up   = (const float*)d_in[9];
    const float* ffn_down = (const float*)d_in[10];
    const float* pW       = (const float*)d_in[11];
    const float* fW       = (const float*)d_in[12];
    const float* pkeys    = (const float*)d_in[13];
    const float* fkeys    = (const float*)d_in[14];
    const float* pbias    = (const float*)d_in[15];
    const float* fbias    = (const float*)d_in[16];
    float* out = (float*)d_out;

    float *xnorm, *qkv, *orows, *xffni, *xffn, *su, *hs;
    cudaGetSymbolAddress((void**)&xnorm, g_xnorm);
    cudaGetSymbolAddress((void**)&qkv,   g_qkv);
    cudaGetSymbolAddress((void**)&orows, g_orows);
    cudaGetSymbolAddress((void**)&xffni, g_xffni);
    cudaGetSymbolAddress((void**)&xffn,  g_xffn);
    cudaGetSymbolAddress((void**)&su,    g_su);
    cudaGetSymbolAddress((void**)&hs,    g_hs);

    static bool attr_set = false;
    if (!attr_set) {
        cudaFuncSetAttribute(attn_tc, cudaFuncAttributeMaxDynamicSharedMemorySize,
                             ATT_SMEM_WORDS * 4);
        attr_set = true;
    }

    // attention block
    rmsnorm_kernel<<<TOK, 256>>>(x_input, attn_nw, xnorm);
    gemm_nn<<<dim3(24, 16), 256>>>(xnorm, W_attn, qkv, nullptr, TOK, 3*DIMM, DIMM);
    rope_interleave_kernel<<<dim3(TOK, NH), 64>>>();
    attn_tc<<<dim3(SEQ/64, NH), 128, ATT_SMEM_WORDS*4>>>();
    gemm_nn<<<dim3(8, 16), 256>>>(orows, W_attn_o, xffni, x_input, TOK, DIMM, DIMM);
    rmsnorm_kernel<<<TOK, 256>>>(xffni, ffn_nw, xffn);

    // routing
    zero32_kernel<<<1, 32>>>();
    router_kernel<<<TOK, 128>>>(pkeys, fkeys, pbias, fbias, p_idx, p_val, f_idx, f_val);
    prefix_kernel<<<1, 1>>>();
    scatter_kernel<<<32, 256>>>();

    // grouped MoE
    moe_gu_tf32<<<dim3(8, 16, NEXP), 256>>>(pW, fW);
    swiglu_moe_kernel<<<(NASS*FDIM)/256, 256>>>();
    moe_down_tf32<<<dim3(8, 16, NEXP), 256>>>(pW, fW);
    combine_kernel<<<TOK, 256>>>(out);

    // shared expert (adds into out)
    gemm_nn<<<dim3(32, 16), 256>>>(xffn, ffn_up, su, nullptr, TOK, 2*DSH, DIMM);
    swiglu_shared_kernel<<<TOK, 256>>>();
    gemm_nn<<<dim3(8, 16), 256>>>(hs, ffn_down, out, out, TOK, DIMM, DSH);
}

// round 6
// speedup vs baseline: 4.2695x; 1.0422x over previous
#include <cuda_runtime.h>
#include <cuda_fp16.h>
#include <math.h>
#include <stdint.h>

// ---------------- problem constants ----------------
#define TOK   2048
#define DIMM  1024
#define NH    16
#define HD    64
#define SEQ   2048
#define NASS  8192
#define NEXP  32
#define FDIM  512
#define DSH   2048

// ---------------- scratch ----------------
__device__ float g_xnorm[TOK*DIMM];
__device__ float g_qkv[TOK*3*DIMM];
__device__ float g_qm[NH*SEQ*HD];
__device__ float g_km[NH*SEQ*HD];
__device__ float g_vm[NH*SEQ*HD];
__device__ float g_orows[TOK*DIMM];
__device__ float g_xffni[TOK*DIMM];
__device__ float g_xffn[TOK*DIMM];
__device__ float g_G[NASS*FDIM];
__device__ float g_U[NASS*FDIM];
__device__ float g_slots[(size_t)NASS*DIMM];
__device__ float g_su[(size_t)TOK*2*DSH];
__device__ float g_hs[(size_t)TOK*DSH];
__device__ float g_scales[NASS];
__device__ int   g_eid[NASS];
__device__ int   g_tokof[NASS];
__device__ int   g_posof[NASS];
__device__ int   g_counts[NEXP];
__device__ int   g_offsets[NEXP];
__device__ int   g_cursors[NEXP];
// K-major transposed weights
__device__ float g_wqkvT[3*DIMM*DIMM];
__device__ float g_woT[DIMM*DIMM];
__device__ float g_wupT[2*DSH*DIMM];
__device__ float g_wdnT[(size_t)DIMM*DSH];
__device__ float g_wguT[(size_t)64*FDIM*DIMM];   // [sel*32+e][f][d]

// ---------------- fp16 helpers ----------------
__device__ __forceinline__ unsigned f2h2(float a, float b) {
    __half2 h = __floats2half2_rn(a, b);
    return *reinterpret_cast<unsigned*>(&h);
}
__device__ __forceinline__ void mma16(float c[4], const unsigned a[4], const unsigned b[2]) {
    asm volatile("mma.sync.aligned.m16n8k16.row.col.f32.f16.f16.f32 "
                 "{%0,%1,%2,%3},{%4,%5,%6,%7},{%8,%9},{%0,%1,%2,%3};"
                 : "+f"(c[0]), "+f"(c[1]), "+f"(c[2]), "+f"(c[3])
                 : "r"(a[0]), "r"(a[1]), "r"(a[2]), "r"(a[3]), "r"(b[0]), "r"(b[1]));
}

// As/Bs layout: [row 0..127][kpair 0..15], stride 20 words (half2), conflict-free frags.
// Covers K=32 elements (2 fp16 k16-steps) per call.
__device__ __forceinline__ void compute_tile_h(const unsigned* __restrict__ As,
                                               const unsigned* __restrict__ Bs,
                                               int wm, int wn, int g, int t4,
                                               float acc[16][4]) {
    #pragma unroll
    for (int ks = 0; ks < 2; ks++) {
        int kc = ks*8 + t4;
        unsigned af[2][4];
        #pragma unroll
        for (int mi = 0; mi < 2; mi++) {
            int r = wm + mi*16 + g;
            af[mi][0] = As[r*20 + kc];
            af[mi][1] = As[(r+8)*20 + kc];
            af[mi][2] = As[r*20 + kc + 4];
            af[mi][3] = As[(r+8)*20 + kc + 4];
        }
        #pragma unroll
        for (int ni = 0; ni < 8; ni++) {
            int n = wn + ni*8 + g;
            unsigned bf[2];
            bf[0] = Bs[n*20 + kc];
            bf[1] = Bs[n*20 + kc + 4];
            #pragma unroll
            for (int mi = 0; mi < 2; mi++) mma16(acc[mi*8+ni], af[mi], bf);
        }
    }
}

#define STAGE4(Sarr, sidx, rv) do { \
    (Sarr)[(sidx) + 0] = f2h2((rv)[0].x, (rv)[0].y); \
    (Sarr)[(sidx) + 1] = f2h2((rv)[0].z, (rv)[0].w); \
    (Sarr)[(sidx) + 2] = f2h2((rv)[1].x, (rv)[1].y); \
    (Sarr)[(sidx) + 3] = f2h2((rv)[1].z, (rv)[1].w); \
    (Sarr)[(sidx) + 4] = f2h2((rv)[2].x, (rv)[2].y); \
    (Sarr)[(sidx) + 5] = f2h2((rv)[2].z, (rv)[2].w); \
    (Sarr)[(sidx) + 6] = f2h2((rv)[3].x, (rv)[3].y); \
    (Sarr)[(sidx) + 7] = f2h2((rv)[3].z, (rv)[3].w); \
} while (0)

// ---------------- weight transposes ----------------
__global__ void __launch_bounds__(256) transpose32(const float* __restrict__ W,
                                                   float* __restrict__ Wt, int K, int N) {
    __shared__ float t[32][33];
    int n0 = blockIdx.x * 32, k0 = blockIdx.y * 32;
    int tx = threadIdx.x & 31, ty = threadIdx.x >> 5;
    #pragma unroll
    for (int i = 0; i < 32; i += 8)
        t[ty + i][tx] = W[(size_t)(k0 + ty + i)*N + n0 + tx];
    __syncthreads();
    #pragma unroll
    for (int i = 0; i < 32; i += 8)
        Wt[(size_t)(n0 + ty + i)*K + k0 + tx] = t[tx][ty + i];
}

__global__ void __launch_bounds__(256) moe_transpose(const float* __restrict__ pW,
                                                     const float* __restrict__ fW) {
    int z = blockIdx.z;              // sel*32 + expert
    int sel = z >> 5, eg = z & 31;
    const float* W = (eg < 16) ? pW + ((size_t)sel*16 + eg)      * (size_t)DIMM*FDIM
                               : fW + ((size_t)sel*16 + (eg-16)) * (size_t)DIMM*FDIM;
    float* Wt = g_wguT + (size_t)z * FDIM * DIMM;
    __shared__ float t[32][33];
    int n0 = blockIdx.x * 32;        // over FDIM
    int k0 = blockIdx.y * 32;        // over DIMM
    int tx = threadIdx.x & 31, ty = threadIdx.x >> 5;
    #pragma unroll
    for (int i = 0; i < 32; i += 8)
        t[ty + i][tx] = W[(size_t)(k0 + ty + i)*FDIM + n0 + tx];
    __syncthreads();
    #pragma unroll
    for (int i = 0; i < 32; i += 8)
        Wt[(size_t)(n0 + ty + i)*DIMM + k0 + tx] = t[tx][ty + i];
}

// ---------------- dense fp16 GEMM: C[M,N] = A[M,K] @ Bt[N,K]^T (+D) ----------------
__global__ void __launch_bounds__(256) gemm_h(const float* __restrict__ A,
                                              const float* __restrict__ Bt,
                                              float* __restrict__ C,
                                              const float* __restrict__ D,
                                              int M, int N, int K) {
    __shared__ __align__(16) unsigned As[2][2560];
    __shared__ __align__(16) unsigned Bs[2][2560];
    int tid = threadIdx.x, lane = tid & 31, wid = tid >> 5;
    int g = lane >> 2, t4 = lane & 3;
    int wm = (wid & 3)*32, wn = (wid >> 2)*64;
    size_t rowBase = (size_t)blockIdx.y * 128, colBase = (size_t)blockIdx.x * 128;
    int r_ = tid >> 1, co = (tid & 1)*16;
    int sidx = r_*20 + (tid & 1)*8;
    const float* Ap = A + (rowBase + r_)*K + co;
    const float* Bp = Bt + (colBase + r_)*K + co;
    float acc[16][4];
    #pragma unroll
    for (int i = 0; i < 16; i++)
        #pragma unroll
        for (int j = 0; j < 4; j++) acc[i][j] = 0.f;
    float4 ra[4], rb[4];
    #pragma unroll
    for (int j = 0; j < 4; j++) { ra[j] = ((const float4*)Ap)[j]; rb[j] = ((const float4*)Bp)[j]; }
    int buf = 0;
    STAGE4(As[0], sidx, ra);
    STAGE4(Bs[0], sidx, rb);
    __syncthreads();
    for (int kt = 0; kt < K; kt += 32) {
        int nxt = kt + 32;
        if (nxt < K) {
            #pragma unroll
            for (int j = 0; j < 4; j++) {
                ra[j] = ((const float4*)(Ap + nxt))[j];
                rb[j] = ((const float4*)(Bp + nxt))[j];
            }
        }
        compute_tile_h(As[buf], Bs[buf], wm, wn, g, t4, acc);
        if (nxt < K) {
            STAGE4(As[buf^1], sidx, ra);
            STAGE4(Bs[buf^1], sidx, rb);
        }
        __syncthreads();
        buf ^= 1;
    }
    #pragma unroll
    for (int mi = 0; mi < 2; mi++)
        #pragma unroll
        for (int ni = 0; ni < 8; ni++) {
            float* c = acc[mi*8+ni];
            size_t r0 = rowBase + wm + mi*16 + g;
            size_t c0 = colBase + wn + ni*8 + 2*t4;
            size_t o0 = r0*N + c0, o1 = (r0+8)*N + c0;
            if (D) {
                C[o0] = c[0] + D[o0]; C[o0+1] = c[1] + D[o0+1];
                C[o1] = c[2] + D[o1]; C[o1+1] = c[3] + D[o1+1];
            } else {
                C[o0] = c[0]; C[o0+1] = c[1];
                C[o1] = c[2]; C[o1+1] = c[3];
            }
        }
}

// ---------------- MoE gate+up fused grouped GEMM (fp16, weights from g_wguT) ----------------
__global__ void __launch_bounds__(256) moe_gu_h() {
    int e = blockIdx.z;
    int cnt = g_counts[e];
    int rowTile = blockIdx.y * 128;
    if (rowTile >= cnt) return;
    int base = g_offsets[e];
    int colBase = blockIdx.x * 128;
    int sel = colBase >> 9;
    int wcol = colBase & 511;
    const float* W = g_wguT + ((size_t)(sel*32 + e)) * FDIM * DIMM;
    float* Out = sel ? g_U : g_G;
    __shared__ int rows[128];
    __shared__ __align__(16) unsigned As[2][2560];
    __shared__ __align__(16) unsigned Bs[2][2560];
    int tid = threadIdx.x;
    if (tid < 128) {
        int rr = rowTile + tid;
        rows[tid] = (rr < cnt) ? g_tokof[base + rr] : -1;
    }
    __syncthreads();
    int lane = tid & 31, wid = tid >> 5;
    int g = lane >> 2, t4 = lane & 3;
    int wm = (wid & 3)*32, wn = (wid >> 2)*64;
    int r_ = tid >> 1, co = (tid & 1)*16;
    int sidx = r_*20 + (tid & 1)*8;
    int tk = rows[r_];
    const float4 z4 = make_float4(0.f, 0.f, 0.f, 0.f);
    const float* Ap = g_xffn + (size_t)(tk < 0 ? 0 : tk)*DIMM + co;
    const float* Bp = W + (size_t)(wcol + r_)*DIMM + co;
    float acc[16][4];
    #pragma unroll
    for (int i = 0; i < 16; i++)
        #pragma unroll
        for (int j = 0; j < 4; j++) acc[i][j] = 0.f;
    float4 ra[4], rb[4];
    #pragma unroll
    for (int j = 0; j < 4; j++) {
        ra[j] = (tk >= 0) ? ((const float4*)Ap)[j] : z4;
        rb[j] = ((const float4*)Bp)[j];
    }
    int buf = 0;
    STAGE4(As[0], sidx, ra);
    STAGE4(Bs[0], sidx, rb);
    __syncthreads();
    for (int kt = 0; kt < DIMM; kt += 32) {
        int nxt = kt + 32;
        if (nxt < DIMM) {
            #pragma unroll
            for (int j = 0; j < 4; j++) {
                ra[j] = (tk >= 0) ? ((const float4*)(Ap + nxt))[j] : z4;
                rb[j] = ((const float4*)(Bp + nxt))[j];
            }
        }
        compute_tile_h(As[buf], Bs[buf], wm, wn, g, t4, acc);
        if (nxt < DIMM) {
            STAGE4(As[buf^1], sidx, ra);
            STAGE4(Bs[buf^1], sidx, rb);
        }
        __syncthreads();
        buf ^= 1;
    }
    #pragma unroll
    for (int mi = 0; mi < 2; mi++)
        #pragma unroll
        for (int ni = 0; ni < 8; ni++) {
            float* c = acc[mi*8+ni];
            int r = rowTile + wm + mi*16 + g;
            int cc = wcol + wn + ni*8 + 2*t4;
            if (r < cnt) {
                Out[(size_t)(base+r)*FDIM + cc]     = c[0];
                Out[(size_t)(base+r)*FDIM + cc + 1] = c[1];
            }
            if (r + 8 < cnt) {
                Out[(size_t)(base+r+8)*FDIM + cc]     = c[2];
                Out[(size_t)(base+r+8)*FDIM + cc + 1] = c[3];
            }
        }
}

// ---------------- MoE down grouped GEMM (fp16, W2 already [N][K]) ----------------
__global__ void __launch_bounds__(256) moe_down_h(const float* __restrict__ pW,
                                                  const float* __restrict__ fW) {
    int e = blockIdx.z;
    int cnt = g_counts[e];
    int rowTile = blockIdx.y * 128;
    if (rowTile >= cnt) return;
    int base = g_offsets[e];
    int colBase = blockIdx.x * 128;
    const float* W = (e < 16) ? pW + ((size_t)2*16 + e)      * (size_t)DIMM*FDIM
                              : fW + ((size_t)2*16 + (e-16)) * (size_t)DIMM*FDIM;
    __shared__ __align__(16) unsigned As[2][2560];
    __shared__ __align__(16) unsigned Bs[2][2560];
    int tid = threadIdx.x, lane = tid & 31, wid = tid >> 5;
    int g = lane >> 2, t4 = lane & 3;
    int wm = (wid & 3)*32, wn = (wid >> 2)*64;
    int r_ = tid >> 1, co = (tid & 1)*16;
    int sidx = r_*20 + (tid & 1)*8;
    bool valid = (rowTile + r_) < cnt;
    int arow = base + rowTile + r_;
    if (arow > NASS - 1) arow = NASS - 1;
    const float4 z4 = make_float4(0.f, 0.f, 0.f, 0.f);
    const float* Ap = g_G + (size_t)arow*FDIM + co;
    const float* Bp = W + (size_t)(colBase + r_)*FDIM + co;
    float acc[16][4];
    #pragma unroll
    for (int i = 0; i < 16; i++)
        #pragma unroll
        for (int j = 0; j < 4; j++) acc[i][j] = 0.f;
    float4 ra[4], rb[4];
    #pragma unroll
    for (int j = 0; j < 4; j++) {
        ra[j] = valid ? ((const float4*)Ap)[j] : z4;
        rb[j] = ((const float4*)Bp)[j];
    }
    int buf = 0;
    STAGE4(As[0], sidx, ra);
    STAGE4(Bs[0], sidx, rb);
    __syncthreads();
    for (int kt = 0; kt < FDIM; kt += 32) {
        int nxt = kt + 32;
        if (nxt < FDIM) {
            #pragma unroll
            for (int j = 0; j < 4; j++) {
                ra[j] = valid ? ((const float4*)(Ap + nxt))[j] : z4;
                rb[j] = ((const float4*)(Bp + nxt))[j];
            }
        }
        compute_tile_h(As[buf], Bs[buf], wm, wn, g, t4, acc);
        if (nxt < FDIM) {
            STAGE4(As[buf^1], sidx, ra);
            STAGE4(Bs[buf^1], sidx, rb);
        }
        __syncthreads();
        buf ^= 1;
    }
    #pragma unroll
    for (int mi = 0; mi < 2; mi++)
        #pragma unroll
        for (int ni = 0; ni < 8; ni++) {
            float* c = acc[mi*8+ni];
            int r = rowTile + wm + mi*16 + g;
            int cc = colBase + wn + ni*8 + 2*t4;
            if (r < cnt) {
                g_slots[(size_t)(base+r)*DIMM + cc]     = c[0];
                g_slots[(size_t)(base+r)*DIMM + cc + 1] = c[1];
            }
            if (r + 8 < cnt) {
                g_slots[(size_t)(base+r+8)*DIMM + cc]     = c[2];
                g_slots[(size_t)(base+r+8)*DIMM + cc + 1] = c[3];
            }
        }
}

// ---------------- rmsnorm ----------------
__global__ void rmsnorm_kernel(const float* __restrict__ x, const float* __restrict__ w,
                               float* __restrict__ out) {
    int r = blockIdx.x;
    const float* xr = x + (size_t)r*DIMM;
    __shared__ float red[8];
    float s = 0.f;
    for (int d = threadIdx.x; d < DIMM; d += 256) { float v = xr[d]; s += v*v; }
    #pragma unroll
    for (int o = 16; o; o >>= 1) s += __shfl_xor_sync(0xffffffffu, s, o);
    if ((threadIdx.x & 31) == 0) red[threadIdx.x >> 5] = s;
    __syncthreads();
    if (threadIdx.x == 0) {
        float t = 0.f;
        #pragma unroll
        for (int i = 0; i < 8; i++) t += red[i];
        red[0] = rsqrtf(t / (float)DIMM + 1e-5f);
    }
    __syncthreads();
    float rms = red[0];
    for (int d = threadIdx.x; d < DIMM; d += 256)
        out[(size_t)r*DIMM + d] = xr[d] * rms * w[d];
}

// ---------------- rope + dual interleave ----------------
__global__ void rope_interleave_kernel() {
    int r = blockIdx.x, h = blockIdx.y, d = threadIdx.x;
    int bi = r >> 10, si = r & 1023;
    int t = 2*si + bi;
    size_t src = (size_t)r*3072 + h*64;
    size_t dst = ((size_t)h*SEQ + t)*64;
    float q = g_qkv[src + d];
    float k = g_qkv[src + 1024 + d];
    float v = g_qkv[src + 2048 + d];
    g_vm[dst + d] = v;
    __shared__ float qs[64], ks[64];
    qs[d] = q; ks[d] = k;
    __syncthreads();
    if (d < 32) {
        float inv = powf(10000.0f, -(float)(2*d) / 64.0f);
        float fr = (float)si * inv;
        float sn, cs;
        sincosf(fr, &sn, &cs);
        float x1 = qs[d], x2 = qs[d+32];
        g_qm[dst + d]      =  x1*cs + x2*sn;
        g_qm[dst + d + 32] = -x1*sn + x2*cs;
        x1 = ks[d]; x2 = ks[d+32];
        g_km[dst + d]      =  x1*cs + x2*sn;
        g_km[dst + d + 32] = -x1*sn + x2*cs;
    }
}

// ---------------- fp16 tensor-core flash attention ----------------
// 64 queries x 1 head per block, 4 warps, half2 smem stride 36 words.
__global__ void __launch_bounds__(128) attn_h() {
    __shared__ __align__(16) unsigned Qs[64*36];
    __shared__ __align__(16) unsigned Ks[64*36];
    __shared__ __align__(16) unsigned Ps[64*36];
    __shared__ __align__(16) unsigned Vt[64*36];
    int h = blockIdx.y;
    int t0 = ((int)gridDim.x - 1 - (int)blockIdx.x) * 64;
    int tid = threadIdx.x, lane = tid & 31, wid = tid >> 5;
    int g = lane >> 2, t4 = lane & 3;
    int wm = wid * 16;

    const float* qb = g_qm + ((size_t)h*SEQ + t0)*64;
    for (int i = tid; i < 64*16; i += 128) {
        int r = i >> 4, c = (i & 15) * 4;
        float4 q = *(const float4*)(qb + r*64 + c);
        Qs[r*36 + c/2]     = f2h2(q.x, q.y);
        Qs[r*36 + c/2 + 1] = f2h2(q.z, q.w);
    }

    float o[8][4];
    #pragma unroll
    for (int n = 0; n < 8; n++)
        #pragma unroll
        for (int j = 0; j < 4; j++) o[n][j] = 0.f;
    float m0 = -1e30f, m1 = -1e30f, l0 = 0.f, l1 = 0.f;
    int row0 = t0 + wm + g, row1 = row0 + 8;

    for (int kt = 0; kt <= t0; kt += 64) {
        __syncthreads();
        const float* kb = g_km + ((size_t)h*SEQ + kt)*64;
        const float* vb = g_vm + ((size_t)h*SEQ + kt)*64;
        for (int i = tid; i < 64*16; i += 128) {
            int r = i >> 4, c = (i & 15) * 4;
            float4 k = *(const float4*)(kb + r*64 + c);
            Ks[r*36 + c/2]     = f2h2(k.x, k.y);
            Ks[r*36 + c/2 + 1] = f2h2(k.z, k.w);
        }
        for (int w = tid; w < 64*32; w += 128) {
            int d = w & 63, p = w >> 6;
            Vt[d*36 + p] = f2h2(vb[(size_t)(2*p)*64 + d], vb[(size_t)(2*p+1)*64 + d]);
        }
        __syncthreads();

        // S = Q K^T : 4 fp16 k16-steps over d=64
        float s[8][4];
        #pragma unroll
        for (int n = 0; n < 8; n++)
            #pragma unroll
            for (int j = 0; j < 4; j++) s[n][j] = 0.f;
        #pragma unroll
        for (int ks = 0; ks < 4; ks++) {
            int kc = ks*8 + t4;
            unsigned af[4];
            af[0] = Qs[(wm+g)*36 + kc];
            af[1] = Qs[(wm+g+8)*36 + kc];
            af[2] = Qs[(wm+g)*36 + kc + 4];
            af[3] = Qs[(wm+g+8)*36 + kc + 4];
            #pragma unroll
            for (int n = 0; n < 8; n++) {
                unsigned bf[2];
                bf[0] = Ks[(n*8+g)*36 + kc];
                bf[1] = Ks[(n*8+g)*36 + kc + 4];
                mma16(s[n], af, bf);
            }
        }
        // causal mask + scale + online softmax
        float mx0 = -1e30f, mx1 = -1e30f;
        #pragma unroll
        for (int n = 0; n < 8; n++) {
            int c0 = kt + n*8 + 2*t4, c1 = c0 + 1;
            s[n][0] = (c0 <= row0) ? s[n][0]*0.125f : -1e30f;
            s[n][1] = (c1 <= row0) ? s[n][1]*0.125f : -1e30f;
            s[n][2] = (c0 <= row1) ? s[n][2]*0.125f : -1e30f;
            s[n][3] = (c1 <= row1) ? s[n][3]*0.125f : -1e30f;
            mx0 = fmaxf(mx0, fmaxf(s[n][0], s[n][1]));
            mx1 = fmaxf(mx1, fmaxf(s[n][2], s[n][3]));
        }
        mx0 = fmaxf(mx0, __shfl_xor_sync(0xffffffffu, mx0, 1));
        mx0 = fmaxf(mx0, __shfl_xor_sync(0xffffffffu, mx0, 2));
        mx1 = fmaxf(mx1, __shfl_xor_sync(0xffffffffu, mx1, 1));
        mx1 = fmaxf(mx1, __shfl_xor_sync(0xffffffffu, mx1, 2));
        float nm0 = fmaxf(m0, mx0), nm1 = fmaxf(m1, mx1);
        float cor0 = __expf(m0 - nm0), cor1 = __expf(m1 - nm1);
        m0 = nm0; m1 = nm1;
        l0 *= cor0; l1 *= cor1;
        float sum0 = 0.f, sum1 = 0.f;
        #pragma unroll
        for (int n = 0; n < 8; n++) {
            float p00 = __expf(s[n][0] - nm0), p01 = __expf(s[n][1] - nm0);
            float p10 = __expf(s[n][2] - nm1), p11 = __expf(s[n][3] - nm1);
            sum0 += p00 + p01; sum1 += p10 + p11;
            Ps[(wm+g)*36 + n*4 + t4]   = f2h2(p00, p01);
            Ps[(wm+g+8)*36 + n*4 + t4] = f2h2(p10, p11);
            #pragma unroll
            for (int j = 0; j < 2; j++) { o[n][j] *= cor0; o[n][2+j] *= cor1; }
        }
        sum0 += __shfl_xor_sync(0xffffffffu, sum0, 1);
        sum0 += __shfl_xor_sync(0xffffffffu, sum0, 2);
        sum1 += __shfl_xor_sync(0xffffffffu, sum1, 1);
        sum1 += __shfl_xor_sync(0xffffffffu, sum1, 2);
        l0 += sum0; l1 += sum1;
        __syncwarp();

        // O += P V : 4 fp16 k16-steps over 64 keys
        #pragma unroll
        for (int ks = 0; ks < 4; ks++) {
            int kc = ks*8 + t4;
            unsigned af[4];
            af[0] = Ps[(wm+g)*36 + kc];
            af[1] = Ps[(wm+g+8)*36 + kc];
            af[2] = Ps[(wm+g)*36 + kc + 4];
            af[3] = Ps[(wm+g+8)*36 + kc + 4];
            #pragma unroll
            for (int n = 0; n < 8; n++) {
                unsigned bf[2];
                bf[0] = Vt[(n*8+g)*36 + kc];
                bf[1] = Vt[(n*8+g)*36 + kc + 4];
                mma16(o[n], af, bf);
            }
        }
    }

    float inv0 = 1.f / l0, inv1 = 1.f / l1;
    int tok0 = (row0 & 1)*1024 + (row0 >> 1);
    int tok1 = (row1 & 1)*1024 + (row1 >> 1);
    #pragma unroll
    for (int n = 0; n < 8; n++) {
        int col = h*64 + n*8 + 2*t4;
        *(float2*)&g_orows[(size_t)tok0*DIMM + col] = make_float2(o[n][0]*inv0, o[n][1]*inv0);
        *(float2*)&g_orows[(size_t)tok1*DIMM + col] = make_float2(o[n][2]*inv1, o[n][3]*inv1);
    }
}

// ---------------- router ----------------
__global__ void router_kernel(const float* __restrict__ pkeys, const float* __restrict__ fkeys,
                              const float* __restrict__ pbias, const float* __restrict__ fbias,
                              const int* __restrict__ pidx, const float* __restrict__ pval,
                              const int* __restrict__ fidx, const float* __restrict__ fval) {
    int tok = blockIdx.x, tid = threadIdx.x;
    bool isf = tok >= 1024;
    const float* keys = isf ? fkeys : pkeys;
    const float* x = g_xffn + (size_t)tok*DIMM;
    __shared__ float part[8][16];
    __shared__ float logit[16];
    int e = tid & 15, ch = tid >> 4;
    float s = 0.f;
    int d0 = ch * 128;
    for (int d = d0; d < d0 + 128; d++) s = fmaf(x[d], keys[d*16 + e], s);
    part[ch][e] = s;
    __syncthreads();
    if (tid < 16) {
        float t = 0.f;
        #pragma unroll
        for (int c = 0; c < 8; c++) t += part[c][tid];
        logit[tid] = t;
    }
    __syncthreads();
    if (tid == 0) {
        int lt = isf ? tok - 1024 : tok;
        const int*   idx  = isf ? fidx  : pidx;
        const float* val  = isf ? fval  : pval;
        const float* bias = isf ? fbias : pbias;
        float sc[4]; int id[4]; float sum = 0.f;
        #pragma unroll
        for (int k = 0; k < 4; k++) {
            int ix = idx[lt*4 + k];
            float v = val[lt*4 + k] + logit[ix] + bias[ix];
            float s2 = 1.f / (1.f + expf(-v));
            sc[k] = s2; sum += s2;
            id[k] = ix + (isf ? 16 : 0);
        }
        #pragma unroll
        for (int k = 0; k < 4; k++) {
            g_scales[tok*4 + k] = sc[k] / sum;
            g_eid[tok*4 + k] = id[k];
            atomicAdd(&g_counts[id[k]], 1);
        }
    }
}

__global__ void zero32_kernel() {
    int i = threadIdx.x;
    if (i < NEXP) { g_counts[i] = 0; g_cursors[i] = 0; }
}

__global__ void prefix_kernel() {
    int acc = 0;
    for (int e = 0; e < NEXP; e++) { g_offsets[e] = acc; acc += g_counts[e]; }
}

__global__ void scatter_kernel() {
    int a = blockIdx.x * blockDim.x + threadIdx.x;
    if (a >= NASS) return;
    int e = g_eid[a];
    int p = g_offsets[e] + atomicAdd(&g_cursors[e], 1);
    g_tokof[p] = a >> 2;
    g_posof[a] = p;
}

__global__ void swiglu_moe_kernel() {
    size_t i = (size_t)blockIdx.x * blockDim.x + threadIdx.x;
    float g = g_G[i], u = g_U[i];
    g_G[i] = (g / (1.f + expf(-g))) * u;
}

__global__ void combine_kernel(float* __restrict__ y) {
    int tok = blockIdx.x;
    __shared__ int pos[4];
    __shared__ float sc[4];
    if (threadIdx.x < 4) {
        pos[threadIdx.x] = g_posof[tok*4 + threadIdx.x];
        sc[threadIdx.x]  = g_scales[tok*4 + threadIdx.x];
    }
    __syncthreads();
    for (int d = threadIdx.x; d < DIMM; d += 256) {
        float v = g_xffni[(size_t)tok*DIMM + d];
        #pragma unroll
        for (int k = 0; k < 4; k++) v = fmaf(sc[k], g_slots[(size_t)pos[k]*DIMM + d], v);
        y[(size_t)tok*DIMM + d] = v;
    }
}

__global__ void swiglu_shared_kernel() {
    int t = blockIdx.x;
    for (int j = threadIdx.x; j < DSH; j += 256) {
        float a = g_su[(size_t)t*2*DSH + j];
        float b = g_su[(size_t)t*2*DSH + DSH + j];
        g_hs[(size_t)t*DSH + j] = (a / (1.f + expf(-a))) * b;
    }
}

// ---------------- launch ----------------
extern "C" void kernel_launch(void* const* d_in, const int* in_sizes, int n_in,
                              void* d_out, int out_size) {
    const float* x_input  = (const float*)d_in[0];
    const int*   p_idx    = (const int*)  d_in[1];
    const float* p_val    = (const float*)d_in[2];
    const int*   f_idx    = (const int*)  d_in[3];
    const float* f_val    = (const float*)d_in[4];
    const float* attn_nw  = (const float*)d_in[5];
    const float* ffn_nw   = (const float*)d_in[6];
    const float* W_attn   = (const float*)d_in[7];
    const float* W_attn_o = (const float*)d_in[8];
    const float* ffn_up   = (const float*)d_in[9];
    const float* ffn_down = (const float*)d_in[10];
    const float* pW       = (const float*)d_in[11];
    const float* fW       = (const float*)d_in[12];
    const float* pkeys    = (const float*)d_in[13];
    const float* fkeys    = (const float*)d_in[14];
    const float* pbias    = (const float*)d_in[15];
    const float* fbias    = (const float*)d_in[16];
    float* out = (float*)d_out;

    float *xnorm, *qkv, *orows, *xffni, *xffn, *su, *hs;
    float *wqkvT, *woT, *wupT, *wdnT;
    cudaGetSymbolAddress((void**)&xnorm, g_xnorm);
    cudaGetSymbolAddress((void**)&qkv,   g_qkv);
    cudaGetSymbolAddress((void**)&orows, g_orows);
    cudaGetSymbolAddress((void**)&xffni, g_xffni);
    cudaGetSymbolAddress((void**)&xffn,  g_xffn);
    cudaGetSymbolAddress((void**)&su,    g_su);
    cudaGetSymbolAddress((void**)&hs,    g_hs);
    cudaGetSymbolAddress((void**)&wqkvT, g_wqkvT);
    cudaGetSymbolAddress((void**)&woT,   g_woT);
    cudaGetSymbolAddress((void**)&wupT,  g_wupT);
    cudaGetSymbolAddress((void**)&wdnT,  g_wdnT);

    // weight transposes to K-major
    transpose32<<<dim3(3*DIMM/32, DIMM/32), 256>>>(W_attn,   wqkvT, DIMM, 3*DIMM);
    transpose32<<<dim3(DIMM/32,   DIMM/32), 256>>>(W_attn_o, woT,   DIMM, DIMM);
    transpose32<<<dim3(2*DSH/32,  DIMM/32), 256>>>(ffn_up,   wupT,  DIMM, 2*DSH);
    transpose32<<<dim3(DIMM/32,   DSH/32),  256>>>(ffn_down, wdnT,  DSH,  DIMM);
    moe_transpose<<<dim3(FDIM/32, DIMM/32, 64), 256>>>(pW, fW);

    // attention block
    rmsnorm_kernel<<<TOK, 256>>>(x_input, attn_nw, xnorm);
    gemm_h<<<dim3(24, 16), 256>>>(xnorm, wqkvT, qkv, nullptr, TOK, 3*DIMM, DIMM);
    rope_interleave_kernel<<<dim3(TOK, NH), 64>>>();
    attn_h<<<dim3(SEQ/64, NH), 128>>>();
    gemm_h<<<dim3(8, 16), 256>>>(orows, woT, xffni, x_input, TOK, DIMM, DIMM);
    rmsnorm_kernel<<<TOK, 256>>>(xffni, ffn_nw, xffn);

    // routing
    zero32_kernel<<<1, 32>>>();
    router_kernel<<<TOK, 128>>>(pkeys, fkeys, pbias, fbias, p_idx, p_val, f_idx, f_val);
    prefix_kernel<<<1, 1>>>();
    scatter_kernel<<<32, 256>>>();

    // grouped MoE (fp16)
    moe_gu_h<<<dim3(8, 16, NEXP), 256>>>();
    swiglu_moe_kernel<<<(NASS*FDIM)/256, 256>>>();
    moe_down_h<<<dim3(8, 16, NEXP), 256>>>(pW, fW);
    combine_kernel<<<TOK, 256>>>(out);

    // shared expert (adds into out)
    gemm_h<<<dim3(32, 16), 256>>>(xffn, wupT, su, nullptr, TOK, 2*DSH, DIMM);
    swiglu_shared_kernel<<<TOK, 256>>>();
    gemm_h<<<dim3(8, 16), 256>>>(hs, wdnT, out, out, TOK, DIMM, DSH);
}

// round 7
// speedup vs baseline: 5.1943x; 1.2166x over previous
#include <cuda_runtime.h>
#include <cuda_fp16.h>
#include <math.h>
#include <stdint.h>

// ---------------- problem constants ----------------
#define TOK   2048
#define DIMM  1024
#define NH    16
#define HD    64
#define SEQ   2048
#define NASS  8192
#define NEXP  32
#define FDIM  512
#define DSH   2048

// ---------------- scratch ----------------
__device__ float g_xnorm[TOK*DIMM];
__device__ float g_qkv[TOK*3*DIMM];
__device__ float g_qm[NH*SEQ*HD];
__device__ float g_km[NH*SEQ*HD];
__device__ float g_vm[NH*SEQ*HD];
__device__ float g_orows[TOK*DIMM];
__device__ float g_xffni[TOK*DIMM];
__device__ float g_xffn[TOK*DIMM];
__device__ float g_G[NASS*FDIM];
__device__ float g_U[NASS*FDIM];
__device__ float g_slots[(size_t)NASS*DIMM];
__device__ float g_su[(size_t)TOK*2*DSH];
__device__ float g_hs[(size_t)TOK*DSH];
__device__ float g_scales[NASS];
__device__ int   g_eid[NASS];
__device__ int   g_tokof[NASS];
__device__ int   g_posof[NASS];
__device__ int   g_counts[NEXP];
__device__ int   g_offsets[NEXP];
__device__ int   g_cursors[NEXP];

// ---------------- fp16 helpers ----------------
__device__ __forceinline__ unsigned f2h2(float a, float b) {
    __half2 h = __floats2half2_rn(a, b);
    return *reinterpret_cast<unsigned*>(&h);
}
__device__ __forceinline__ void mma16(float c[4], const unsigned a[4], const unsigned b[2]) {
    asm volatile("mma.sync.aligned.m16n8k16.row.col.f32.f16.f16.f32 "
                 "{%0,%1,%2,%3},{%4,%5,%6,%7},{%8,%9},{%0,%1,%2,%3};"
                 : "+f"(c[0]), "+f"(c[1]), "+f"(c[2]), "+f"(c[3])
                 : "r"(a[0]), "r"(a[1]), "r"(a[2]), "r"(a[3]), "r"(b[0]), "r"(b[1]));
}

// As: [row 0..127][kpair 0..15] stride 20 words (half2).
// Bs (NN layout): [kpair 0..15][n 0..127] stride 136 words; word = half2(B[2kp][n],B[2kp+1][n]).
__device__ __forceinline__ void compute_tile_nn(const unsigned* __restrict__ As,
                                                const unsigned* __restrict__ Bs,
                                                int wm, int wn, int g, int t4,
                                                float acc[16][4]) {
    #pragma unroll
    for (int ks = 0; ks < 2; ks++) {
        int kc = ks*8 + t4;
        unsigned af[2][4];
        #pragma unroll
        for (int mi = 0; mi < 2; mi++) {
            int r = wm + mi*16 + g;
            af[mi][0] = As[r*20 + kc];
            af[mi][1] = As[(r+8)*20 + kc];
            af[mi][2] = As[r*20 + kc + 4];
            af[mi][3] = As[(r+8)*20 + kc + 4];
        }
        #pragma unroll
        for (int ni = 0; ni < 8; ni++) {
            int n = wn + ni*8 + g;
            unsigned bf[2];
            bf[0] = Bs[kc*136 + n];
            bf[1] = Bs[(kc+4)*136 + n];
            #pragma unroll
            for (int mi = 0; mi < 2; mi++) mma16(acc[mi*8+ni], af[mi], bf);
        }
    }
}

// B_T variant: Bs [n][kpair] stride 20 (K-major source, used by moe_down)
__device__ __forceinline__ void compute_tile_tt(const unsigned* __restrict__ As,
                                                const unsigned* __restrict__ Bs,
                                                int wm, int wn, int g, int t4,
                                                float acc[16][4]) {
    #pragma unroll
    for (int ks = 0; ks < 2; ks++) {
        int kc = ks*8 + t4;
        unsigned af[2][4];
        #pragma unroll
        for (int mi = 0; mi < 2; mi++) {
            int r = wm + mi*16 + g;
            af[mi][0] = As[r*20 + kc];
            af[mi][1] = As[(r+8)*20 + kc];
            af[mi][2] = As[r*20 + kc + 4];
            af[mi][3] = As[(r+8)*20 + kc + 4];
        }
        #pragma unroll
        for (int ni = 0; ni < 8; ni++) {
            int n = wn + ni*8 + g;
            unsigned bf[2];
            bf[0] = Bs[n*20 + kc];
            bf[1] = Bs[n*20 + kc + 4];
            #pragma unroll
            for (int mi = 0; mi < 2; mi++) mma16(acc[mi*8+ni], af[mi], bf);
        }
    }
}

// Stage A rows (k-major source): thread covers 16 consecutive k of one row.
#define STAGE_A(Sarr, sidx, rv) do { \
    (Sarr)[(sidx) + 0] = f2h2((rv)[0].x, (rv)[0].y); \
    (Sarr)[(sidx) + 1] = f2h2((rv)[0].z, (rv)[0].w); \
    (Sarr)[(sidx) + 2] = f2h2((rv)[1].x, (rv)[1].y); \
    (Sarr)[(sidx) + 3] = f2h2((rv)[1].z, (rv)[1].w); \
    (Sarr)[(sidx) + 4] = f2h2((rv)[2].x, (rv)[2].y); \
    (Sarr)[(sidx) + 5] = f2h2((rv)[2].z, (rv)[2].w); \
    (Sarr)[(sidx) + 6] = f2h2((rv)[3].x, (rv)[3].y); \
    (Sarr)[(sidx) + 7] = f2h2((rv)[3].z, (rv)[3].w); \
} while (0)

// Stage B from [K][N]: pack rows 2kp/2kp+1 element-wise into half2.
#define STAGE_B_NN(Bsb, bsidx, r00, r10, r01, r11) do { \
    *(uint4*)&(Bsb)[(bsidx)] = make_uint4( \
        f2h2((r00).x, (r10).x), f2h2((r00).y, (r10).y), \
        f2h2((r00).z, (r10).z), f2h2((r00).w, (r10).w)); \
    *(uint4*)&(Bsb)[(bsidx) + 64] = make_uint4( \
        f2h2((r01).x, (r11).x), f2h2((r01).y, (r11).y), \
        f2h2((r01).z, (r11).z), f2h2((r01).w, (r11).w)); \
} while (0)

// ---------------- dense fp16 GEMM: C[M,N] = A[M,K] @ B[K,N] (+D) ----------------
__global__ void __launch_bounds__(256) gemm_nn_h(const float* __restrict__ A,
                                                 const float* __restrict__ B,
                                                 float* __restrict__ C,
                                                 const float* __restrict__ D,
                                                 int M, int N, int K) {
    __shared__ __align__(16) unsigned As[2][2560];
    __shared__ __align__(16) unsigned Bs[2][2176];
    int tid = threadIdx.x, lane = tid & 31, wid = tid >> 5;
    int g = lane >> 2, t4 = lane & 3;
    int wm = (wid & 3)*32, wn = (wid >> 2)*64;
    size_t rowBase = (size_t)blockIdx.y * 128, colBase = (size_t)blockIdx.x * 128;
    // A staging indices
    int a_r = tid >> 1, a_co = (tid & 1)*16;
    int a_sidx = a_r*20 + (tid & 1)*8;
    const float* Ap = A + (rowBase + a_r)*K + a_co;
    // B staging indices
    int kp = tid >> 4, q = tid & 15;
    int bsidx = kp*136 + q*4;
    const float* Bp0 = B + (size_t)(2*kp)*N + colBase + q*4;     // row 2kp
    float acc[16][4];
    #pragma unroll
    for (int i = 0; i < 16; i++)
        #pragma unroll
        for (int j = 0; j < 4; j++) acc[i][j] = 0.f;
    float4 ra[4], r00, r01, r10, r11;
    #pragma unroll
    for (int j = 0; j < 4; j++) ra[j] = ((const float4*)Ap)[j];
    r00 = *(const float4*)(Bp0);
    r01 = *(const float4*)(Bp0 + 64);
    r10 = *(const float4*)(Bp0 + N);
    r11 = *(const float4*)(Bp0 + N + 64);
    int buf = 0;
    STAGE_A(As[0], a_sidx, ra);
    STAGE_B_NN(Bs[0], bsidx, r00, r10, r01, r11);
    __syncthreads();
    for (int kt = 0; kt < K; kt += 32) {
        int nxt = kt + 32;
        if (nxt < K) {
            #pragma unroll
            for (int j = 0; j < 4; j++) ra[j] = ((const float4*)(Ap + nxt))[j];
            const float* bp = Bp0 + (size_t)nxt*N;
            r00 = *(const float4*)(bp);
            r01 = *(const float4*)(bp + 64);
            r10 = *(const float4*)(bp + N);
            r11 = *(const float4*)(bp + N + 64);
        }
        compute_tile_nn(As[buf], Bs[buf], wm, wn, g, t4, acc);
        if (nxt < K) {
            STAGE_A(As[buf^1], a_sidx, ra);
            STAGE_B_NN(Bs[buf^1], bsidx, r00, r10, r01, r11);
        }
        __syncthreads();
        buf ^= 1;
    }
    #pragma unroll
    for (int mi = 0; mi < 2; mi++)
        #pragma unroll
        for (int ni = 0; ni < 8; ni++) {
            float* c = acc[mi*8+ni];
            size_t r0 = rowBase + wm + mi*16 + g;
            size_t c0 = colBase + wn + ni*8 + 2*t4;
            size_t o0 = r0*N + c0, o1 = (r0+8)*N + c0;
            if (D) {
                C[o0] = c[0] + D[o0]; C[o0+1] = c[1] + D[o0+1];
                C[o1] = c[2] + D[o1]; C[o1+1] = c[3] + D[o1+1];
            } else {
                C[o0] = c[0]; C[o0+1] = c[1];
                C[o1] = c[2]; C[o1+1] = c[3];
            }
        }
}

// ---------------- MoE gate+up fused grouped GEMM (fp16, native [d][f] weights) ----------------
__global__ void __launch_bounds__(256) moe_gu_h(const float* __restrict__ pW,
                                                const float* __restrict__ fW) {
    int e = blockIdx.z;
    int cnt = g_counts[e];
    int rowTile = blockIdx.y * 128;
    if (rowTile >= cnt) return;
    int base = g_offsets[e];
    int colBase = blockIdx.x * 128;         // 0..1023: [0,512) gate, [512,1024) up
    int sel = colBase >> 9;
    int wcol = colBase & 511;
    const float* W = (e < 16) ? pW + ((size_t)sel*16 + e)      * (size_t)DIMM*FDIM
                              : fW + ((size_t)sel*16 + (e-16)) * (size_t)DIMM*FDIM;
    float* Out = sel ? g_U : g_G;
    __shared__ int rows[128];
    __shared__ __align__(16) unsigned As[2][2560];
    __shared__ __align__(16) unsigned Bs[2][2176];
    int tid = threadIdx.x;
    if (tid < 128) {
        int rr = rowTile + tid;
        rows[tid] = (rr < cnt) ? g_tokof[base + rr] : -1;
    }
    __syncthreads();
    int lane = tid & 31, wid = tid >> 5;
    int g = lane >> 2, t4 = lane & 3;
    int wm = (wid & 3)*32, wn = (wid >> 2)*64;
    int a_r = tid >> 1, a_co = (tid & 1)*16;
    int a_sidx = a_r*20 + (tid & 1)*8;
    int tk = rows[a_r];
    const float4 z4 = make_float4(0.f, 0.f, 0.f, 0.f);
    const float* Ap = g_xffn + (size_t)(tk < 0 ? 0 : tk)*DIMM + a_co;
    int kp = tid >> 4, q = tid & 15;
    int bsidx = kp*136 + q*4;
    const float* Bp0 = W + (size_t)(2*kp)*FDIM + wcol + q*4;
    float acc[16][4];
    #pragma unroll
    for (int i = 0; i < 16; i++)
        #pragma unroll
        for (int j = 0; j < 4; j++) acc[i][j] = 0.f;
    float4 ra[4], r00, r01, r10, r11;
    #pragma unroll
    for (int j = 0; j < 4; j++) ra[j] = (tk >= 0) ? ((const float4*)Ap)[j] : z4;
    r00 = *(const float4*)(Bp0);
    r01 = *(const float4*)(Bp0 + 64);
    r10 = *(const float4*)(Bp0 + FDIM);
    r11 = *(const float4*)(Bp0 + FDIM + 64);
    int buf = 0;
    STAGE_A(As[0], a_sidx, ra);
    STAGE_B_NN(Bs[0], bsidx, r00, r10, r01, r11);
    __syncthreads();
    for (int kt = 0; kt < DIMM; kt += 32) {
        int nxt = kt + 32;
        if (nxt < DIMM) {
            #pragma unroll
            for (int j = 0; j < 4; j++)
                ra[j] = (tk >= 0) ? ((const float4*)(Ap + nxt))[j] : z4;
            const float* bp = Bp0 + (size_t)nxt*FDIM;
            r00 = *(const float4*)(bp);
            r01 = *(const float4*)(bp + 64);
            r10 = *(const float4*)(bp + FDIM);
            r11 = *(const float4*)(bp + FDIM + 64);
        }
        compute_tile_nn(As[buf], Bs[buf], wm, wn, g, t4, acc);
        if (nxt < DIMM) {
            STAGE_A(As[buf^1], a_sidx, ra);
            STAGE_B_NN(Bs[buf^1], bsidx, r00, r10, r01, r11);
        }
        __syncthreads();
        buf ^= 1;
    }
    #pragma unroll
    for (int mi = 0; mi < 2; mi++)
        #pragma unroll
        for (int ni = 0; ni < 8; ni++) {
            float* c = acc[mi*8+ni];
            int r = rowTile + wm + mi*16 + g;
            int cc = wcol + wn + ni*8 + 2*t4;
            if (r < cnt) {
                Out[(size_t)(base+r)*FDIM + cc]     = c[0];
                Out[(size_t)(base+r)*FDIM + cc + 1] = c[1];
            }
            if (r + 8 < cnt) {
                Out[(size_t)(base+r+8)*FDIM + cc]     = c[2];
                Out[(size_t)(base+r+8)*FDIM + cc + 1] = c[3];
            }
        }
}

// ---------------- MoE down grouped GEMM (fp16, W2 native [N][K]) ----------------
__global__ void __launch_bounds__(256) moe_down_h(const float* __restrict__ pW,
                                                  const float* __restrict__ fW) {
    int e = blockIdx.z;
    int cnt = g_counts[e];
    int rowTile = blockIdx.y * 128;
    if (rowTile >= cnt) return;
    int base = g_offsets[e];
    int colBase = blockIdx.x * 128;
    const float* W = (e < 16) ? pW + ((size_t)2*16 + e)      * (size_t)DIMM*FDIM
                              : fW + ((size_t)2*16 + (e-16)) * (size_t)DIMM*FDIM;
    __shared__ __align__(16) unsigned As[2][2560];
    __shared__ __align__(16) unsigned Bs[2][2560];
    int tid = threadIdx.x, lane = tid & 31, wid = tid >> 5;
    int g = lane >> 2, t4 = lane & 3;
    int wm = (wid & 3)*32, wn = (wid >> 2)*64;
    int r_ = tid >> 1, co = (tid & 1)*16;
    int sidx = r_*20 + (tid & 1)*8;
    bool valid = (rowTile + r_) < cnt;
    int arow = base + rowTile + r_;
    if (arow > NASS - 1) arow = NASS - 1;
    const float4 z4 = make_float4(0.f, 0.f, 0.f, 0.f);
    const float* Ap = g_G + (size_t)arow*FDIM + co;
    const float* Bp = W + (size_t)(colBase + r_)*FDIM + co;
    float acc[16][4];
    #pragma unroll
    for (int i = 0; i < 16; i++)
        #pragma unroll
        for (int j = 0; j < 4; j++) acc[i][j] = 0.f;
    float4 ra[4], rb[4];
    #pragma unroll
    for (int j = 0; j < 4; j++) {
        ra[j] = valid ? ((const float4*)Ap)[j] : z4;
        rb[j] = ((const float4*)Bp)[j];
    }
    int buf = 0;
    STAGE_A(As[0], sidx, ra);
    STAGE_A(Bs[0], sidx, rb);
    __syncthreads();
    for (int kt = 0; kt < FDIM; kt += 32) {
        int nxt = kt + 32;
        if (nxt < FDIM) {
            #pragma unroll
            for (int j = 0; j < 4; j++) {
                ra[j] = valid ? ((const float4*)(Ap + nxt))[j] : z4;
                rb[j] = ((const float4*)(Bp + nxt))[j];
            }
        }
        compute_tile_tt(As[buf], Bs[buf], wm, wn, g, t4, acc);
        if (nxt < FDIM) {
            STAGE_A(As[buf^1], sidx, ra);
            STAGE_A(Bs[buf^1], sidx, rb);
        }
        __syncthreads();
        buf ^= 1;
    }
    #pragma unroll
    for (int mi = 0; mi < 2; mi++)
        #pragma unroll
        for (int ni = 0; ni < 8; ni++) {
            float* c = acc[mi*8+ni];
            int r = rowTile + wm + mi*16 + g;
            int cc = colBase + wn + ni*8 + 2*t4;
            if (r < cnt) {
                g_slots[(size_t)(base+r)*DIMM + cc]     = c[0];
                g_slots[(size_t)(base+r)*DIMM + cc + 1] = c[1];
            }
            if (r + 8 < cnt) {
                g_slots[(size_t)(base+r+8)*DIMM + cc]     = c[2];
                g_slots[(size_t)(base+r+8)*DIMM + cc + 1] = c[3];
            }
        }
}

// ---------------- rmsnorm ----------------
__global__ void rmsnorm_kernel(const float* __restrict__ x, const float* __restrict__ w,
                               float* __restrict__ out) {
    int r = blockIdx.x;
    const float* xr = x + (size_t)r*DIMM;
    __shared__ float red[8];
    float s = 0.f;
    for (int d = threadIdx.x; d < DIMM; d += 256) { float v = xr[d]; s += v*v; }
    #pragma unroll
    for (int o = 16; o; o >>= 1) s += __shfl_xor_sync(0xffffffffu, s, o);
    if ((threadIdx.x & 31) == 0) red[threadIdx.x >> 5] = s;
    __syncthreads();
    if (threadIdx.x == 0) {
        float t = 0.f;
        #pragma unroll
        for (int i = 0; i < 8; i++) t += red[i];
        red[0] = rsqrtf(t / (float)DIMM + 1e-5f);
    }
    __syncthreads();
    float rms = red[0];
    for (int d = threadIdx.x; d < DIMM; d += 256)
        out[(size_t)r*DIMM + d] = xr[d] * rms * w[d];
}

// ---------------- rope + dual interleave ----------------
__global__ void rope_interleave_kernel() {
    int r = blockIdx.x, h = blockIdx.y, d = threadIdx.x;
    int bi = r >> 10, si = r & 1023;
    int t = 2*si + bi;
    size_t src = (size_t)r*3072 + h*64;
    size_t dst = ((size_t)h*SEQ + t)*64;
    float q = g_qkv[src + d];
    float k = g_qkv[src + 1024 + d];
    float v = g_qkv[src + 2048 + d];
    g_vm[dst + d] = v;
    __shared__ float qs[64], ks[64];
    qs[d] = q; ks[d] = k;
    __syncthreads();
    if (d < 32) {
        float inv = powf(10000.0f, -(float)(2*d) / 64.0f);
        float fr = (float)si * inv;
        float sn, cs;
        sincosf(fr, &sn, &cs);
        float x1 = qs[d], x2 = qs[d+32];
        g_qm[dst + d]      =  x1*cs + x2*sn;
        g_qm[dst + d + 32] = -x1*sn + x2*cs;
        x1 = ks[d]; x2 = ks[d+32];
        g_km[dst + d]      =  x1*cs + x2*sn;
        g_km[dst + d + 32] = -x1*sn + x2*cs;
    }
}

// ---------------- fp16 tensor-core flash attention ----------------
__global__ void __launch_bounds__(128) attn_h() {
    __shared__ __align__(16) unsigned Qs[64*36];
    __shared__ __align__(16) unsigned Ks[64*36];
    __shared__ __align__(16) unsigned Ps[64*36];
    __shared__ __align__(16) unsigned Vt[64*36];
    int h = blockIdx.y;
    int t0 = ((int)gridDim.x - 1 - (int)blockIdx.x) * 64;
    int tid = threadIdx.x, lane = tid & 31, wid = tid >> 5;
    int g = lane >> 2, t4 = lane & 3;
    int wm = wid * 16;

    const float* qb = g_qm + ((size_t)h*SEQ + t0)*64;
    for (int i = tid; i < 64*16; i += 128) {
        int r = i >> 4, c = (i & 15) * 4;
        float4 q = *(const float4*)(qb + r*64 + c);
        Qs[r*36 + c/2]     = f2h2(q.x, q.y);
        Qs[r*36 + c/2 + 1] = f2h2(q.z, q.w);
    }

    float o[8][4];
    #pragma unroll
    for (int n = 0; n < 8; n++)
        #pragma unroll
        for (int j = 0; j < 4; j++) o[n][j] = 0.f;
    float m0 = -1e30f, m1 = -1e30f, l0 = 0.f, l1 = 0.f;
    int row0 = t0 + wm + g, row1 = row0 + 8;

    for (int kt = 0; kt <= t0; kt += 64) {
        __syncthreads();
        const float* kb = g_km + ((size_t)h*SEQ + kt)*64;
        const float* vb = g_vm + ((size_t)h*SEQ + kt)*64;
        for (int i = tid; i < 64*16; i += 128) {
            int r = i >> 4, c = (i & 15) * 4;
            float4 k = *(const float4*)(kb + r*64 + c);
            Ks[r*36 + c/2]     = f2h2(k.x, k.y);
            Ks[r*36 + c/2 + 1] = f2h2(k.z, k.w);
        }
        for (int w = tid; w < 64*32; w += 128) {
            int d = w & 63, p = w >> 6;
            Vt[d*36 + p] = f2h2(vb[(size_t)(2*p)*64 + d], vb[(size_t)(2*p+1)*64 + d]);
        }
        __syncthreads();

        float s[8][4];
        #pragma unroll
        for (int n = 0; n < 8; n++)
            #pragma unroll
            for (int j = 0; j < 4; j++) s[n][j] = 0.f;
        #pragma unroll
        for (int ks = 0; ks < 4; ks++) {
            int kc = ks*8 + t4;
            unsigned af[4];
            af[0] = Qs[(wm+g)*36 + kc];
            af[1] = Qs[(wm+g+8)*36 + kc];
            af[2] = Qs[(wm+g)*36 + kc + 4];
            af[3] = Qs[(wm+g+8)*36 + kc + 4];
            #pragma unroll
            for (int n = 0; n < 8; n++) {
                unsigned bf[2];
                bf[0] = Ks[(n*8+g)*36 + kc];
                bf[1] = Ks[(n*8+g)*36 + kc + 4];
                mma16(s[n], af, bf);
            }
        }
        float mx0 = -1e30f, mx1 = -1e30f;
        #pragma unroll
        for (int n = 0; n < 8; n++) {
            int c0 = kt + n*8 + 2*t4, c1 = c0 + 1;
            s[n][0] = (c0 <= row0) ? s[n][0]*0.125f : -1e30f;
            s[n][1] = (c1 <= row0) ? s[n][1]*0.125f : -1e30f;
            s[n][2] = (c0 <= row1) ? s[n][2]*0.125f : -1e30f;
            s[n][3] = (c1 <= row1) ? s[n][3]*0.125f : -1e30f;
            mx0 = fmaxf(mx0, fmaxf(s[n][0], s[n][1]));
            mx1 = fmaxf(mx1, fmaxf(s[n][2], s[n][3]));
        }
        mx0 = fmaxf(mx0, __shfl_xor_sync(0xffffffffu, mx0, 1));
        mx0 = fmaxf(mx0, __shfl_xor_sync(0xffffffffu, mx0, 2));
        mx1 = fmaxf(mx1, __shfl_xor_sync(0xffffffffu, mx1, 1));
        mx1 = fmaxf(mx1, __shfl_xor_sync(0xffffffffu, mx1, 2));
        float nm0 = fmaxf(m0, mx0), nm1 = fmaxf(m1, mx1);
        float cor0 = __expf(m0 - nm0), cor1 = __expf(m1 - nm1);
        m0 = nm0; m1 = nm1;
        l0 *= cor0; l1 *= cor1;
        float sum0 = 0.f, sum1 = 0.f;
        #pragma unroll
        for (int n = 0; n < 8; n++) {
            float p00 = __expf(s[n][0] - nm0), p01 = __expf(s[n][1] - nm0);
            float p10 = __expf(s[n][2] - nm1), p11 = __expf(s[n][3] - nm1);
            sum0 += p00 + p01; sum1 += p10 + p11;
            Ps[(wm+g)*36 + n*4 + t4]   = f2h2(p00, p01);
            Ps[(wm+g+8)*36 + n*4 + t4] = f2h2(p10, p11);
            #pragma unroll
            for (int j = 0; j < 2; j++) { o[n][j] *= cor0; o[n][2+j] *= cor1; }
        }
        sum0 += __shfl_xor_sync(0xffffffffu, sum0, 1);
        sum0 += __shfl_xor_sync(0xffffffffu, sum0, 2);
        sum1 += __shfl_xor_sync(0xffffffffu, sum1, 1);
        sum1 += __shfl_xor_sync(0xffffffffu, sum1, 2);
        l0 += sum0; l1 += sum1;
        __syncwarp();

        #pragma unroll
        for (int ks = 0; ks < 4; ks++) {
            int kc = ks*8 + t4;
            unsigned af[4];
            af[0] = Ps[(wm+g)*36 + kc];
            af[1] = Ps[(wm+g+8)*36 + kc];
            af[2] = Ps[(wm+g)*36 + kc + 4];
            af[3] = Ps[(wm+g+8)*36 + kc + 4];
            #pragma unroll
            for (int n = 0; n < 8; n++) {
                unsigned bf[2];
                bf[0] = Vt[(n*8+g)*36 + kc];
                bf[1] = Vt[(n*8+g)*36 + kc + 4];
                mma16(o[n], af, bf);
            }
        }
    }

    float inv0 = 1.f / l0, inv1 = 1.f / l1;
    int tok0 = (row0 & 1)*1024 + (row0 >> 1);
    int tok1 = (row1 & 1)*1024 + (row1 >> 1);
    #pragma unroll
    for (int n = 0; n < 8; n++) {
        int col = h*64 + n*8 + 2*t4;
        *(float2*)&g_orows[(size_t)tok0*DIMM + col] = make_float2(o[n][0]*inv0, o[n][1]*inv0);
        *(float2*)&g_orows[(size_t)tok1*DIMM + col] = make_float2(o[n][2]*inv1, o[n][3]*inv1);
    }
}

// ---------------- router ----------------
__global__ void router_kernel(const float* __restrict__ pkeys, const float* __restrict__ fkeys,
                              const float* __restrict__ pbias, const float* __restrict__ fbias,
                              const int* __restrict__ pidx, const float* __restrict__ pval,
                              const int* __restrict__ fidx, const float* __restrict__ fval) {
    int tok = blockIdx.x, tid = threadIdx.x;
    bool isf = tok >= 1024;
    const float* keys = isf ? fkeys : pkeys;
    const float* x = g_xffn + (size_t)tok*DIMM;
    __shared__ float part[8][16];
    __shared__ float logit[16];
    int e = tid & 15, ch = tid >> 4;
    float s = 0.f;
    int d0 = ch * 128;
    for (int d = d0; d < d0 + 128; d++) s = fmaf(x[d], keys[d*16 + e], s);
    part[ch][e] = s;
    __syncthreads();
    if (tid < 16) {
        float t = 0.f;
        #pragma unroll
        for (int c = 0; c < 8; c++) t += part[c][tid];
        logit[tid] = t;
    }
    __syncthreads();
    if (tid == 0) {
        int lt = isf ? tok - 1024 : tok;
        const int*   idx  = isf ? fidx  : pidx;
        const float* val  = isf ? fval  : pval;
        const float* bias = isf ? fbias : pbias;
        float sc[4]; int id[4]; float sum = 0.f;
        #pragma unroll
        for (int k = 0; k < 4; k++) {
            int ix = idx[lt*4 + k];
            float v = val[lt*4 + k] + logit[ix] + bias[ix];
            float s2 = 1.f / (1.f + expf(-v));
            sc[k] = s2; sum += s2;
            id[k] = ix + (isf ? 16 : 0);
        }
        #pragma unroll
        for (int k = 0; k < 4; k++) {
            g_scales[tok*4 + k] = sc[k] / sum;
            g_eid[tok*4 + k] = id[k];
            atomicAdd(&g_counts[id[k]], 1);
        }
    }
}

__global__ void zero32_kernel() {
    int i = threadIdx.x;
    if (i < NEXP) { g_counts[i] = 0; g_cursors[i] = 0; }
}

__global__ void prefix_kernel() {
    int acc = 0;
    for (int e = 0; e < NEXP; e++) { g_offsets[e] = acc; acc += g_counts[e]; }
}

__global__ void scatter_kernel() {
    int a = blockIdx.x * blockDim.x + threadIdx.x;
    if (a >= NASS) return;
    int e = g_eid[a];
    int p = g_offsets[e] + atomicAdd(&g_cursors[e], 1);
    g_tokof[p] = a >> 2;
    g_posof[a] = p;
}

__global__ void swiglu_moe_kernel() {
    size_t i = (size_t)blockIdx.x * blockDim.x + threadIdx.x;
    float g = g_G[i], u = g_U[i];
    g_G[i] = (g / (1.f + expf(-g))) * u;
}

__global__ void combine_kernel(float* __restrict__ y) {
    int tok = blockIdx.x;
    __shared__ int pos[4];
    __shared__ float sc[4];
    if (threadIdx.x < 4) {
        pos[threadIdx.x] = g_posof[tok*4 + threadIdx.x];
        sc[threadIdx.x]  = g_scales[tok*4 + threadIdx.x];
    }
    __syncthreads();
    for (int d = threadIdx.x; d < DIMM; d += 256) {
        float v = g_xffni[(size_t)tok*DIMM + d];
        #pragma unroll
        for (int k = 0; k < 4; k++) v = fmaf(sc[k], g_slots[(size_t)pos[k]*DIMM + d], v);
        y[(size_t)tok*DIMM + d] = v;
    }
}

__global__ void swiglu_shared_kernel() {
    int t = blockIdx.x;
    for (int j = threadIdx.x; j < DSH; j += 256) {
        float a = g_su[(size_t)t*2*DSH + j];
        float b = g_su[(size_t)t*2*DSH + DSH + j];
        g_hs[(size_t)t*DSH + j] = (a / (1.f + expf(-a))) * b;
    }
}

// ---------------- launch ----------------
extern "C" void kernel_launch(void* const* d_in, const int* in_sizes, int n_in,
                              void* d_out, int out_size) {
    const float* x_input  = (const float*)d_in[0];
    const int*   p_idx    = (const int*)  d_in[1];
    const float* p_val    = (const float*)d_in[2];
    const int*   f_idx    = (const int*)  d_in[3];
    const float* f_val    = (const float*)d_in[4];
    const float* attn_nw  = (const float*)d_in[5];
    const float* ffn_nw   = (const float*)d_in[6];
    const float* W_attn   = (const float*)d_in[7];
    const float* W_attn_o = (const float*)d_in[8];
    const float* ffn_up   = (const float*)d_in[9];
    const float* ffn_down = (const float*)d_in[10];
    const float* pW       = (const float*)d_in[11];
    const float* fW       = (const float*)d_in[12];
    const float* pkeys    = (const float*)d_in[13];
    const float* fkeys    = (const float*)d_in[14];
    const float* pbias    = (const float*)d_in[15];
    const float* fbias    = (const float*)d_in[16];
    float* out = (float*)d_out;

    float *xnorm, *qkv, *orows, *xffni, *xffn, *su, *hs;
    cudaGetSymbolAddress((void**)&xnorm, g_xnorm);
    cudaGetSymbolAddress((void**)&qkv,   g_qkv);
    cudaGetSymbolAddress((void**)&orows, g_orows);
    cudaGetSymbolAddress((void**)&xffni, g_xffni);
    cudaGetSymbolAddress((void**)&xffn,  g_xffn);
    cudaGetSymbolAddress((void**)&su,    g_su);
    cudaGetSymbolAddress((void**)&hs,    g_hs);

    // attention block
    rmsnorm_kernel<<<TOK, 256>>>(x_input, attn_nw, xnorm);
    gemm_nn_h<<<dim3(24, 16), 256>>>(xnorm, W_attn, qkv, nullptr, TOK, 3*DIMM, DIMM);
    rope_interleave_kernel<<<dim3(TOK, NH), 64>>>();
    attn_h<<<dim3(SEQ/64, NH), 128>>>();
    gemm_nn_h<<<dim3(8, 16), 256>>>(orows, W_attn_o, xffni, x_input, TOK, DIMM, DIMM);
    rmsnorm_kernel<<<TOK, 256>>>(xffni, ffn_nw, xffn);

    // routing
    zero32_kernel<<<1, 32>>>();
    router_kernel<<<TOK, 128>>>(pkeys, fkeys, pbias, fbias, p_idx, p_val, f_idx, f_val);
    prefix_kernel<<<1, 1>>>();
    scatter_kernel<<<32, 256>>>();

    // grouped MoE (fp16, native weight layouts)
    moe_gu_h<<<dim3(8, 16, NEXP), 256>>>(pW, fW);
    swiglu_moe_kernel<<<(NASS*FDIM)/256, 256>>>();
    moe_down_h<<<dim3(8, 16, NEXP), 256>>>(pW, fW);
    combine_kernel<<<TOK, 256>>>(out);

    // shared expert (adds into out)
    gemm_nn_h<<<dim3(32, 16), 256>>>(xffn, ffn_up, su, nullptr, TOK, 2*DSH, DIMM);
    swiglu_shared_kernel<<<TOK, 256>>>();
    gemm_nn_h<<<dim3(8, 16), 256>>>(hs, ffn_down, out, out, TOK, DIMM, DSH);
}

// round 9
// speedup vs baseline: 6.0082x; 1.1567x over previous
#include <cuda_runtime.h>
#include <cuda_fp16.h>
#include <math.h>
#include <stdint.h>

// ---------------- problem constants ----------------
#define TOK   2048
#define DIMM  1024
#define NH    16
#define HD    64
#define SEQ   2048
#define NASS  8192
#define NEXP  32
#define FDIM  512
#define DSH   2048

// ---------------- scratch ----------------
__device__ __align__(16) __half g_xnormh[TOK*DIMM];
__device__ __align__(16) __half g_qkvh[TOK*3*DIMM];
__device__ __align__(16) __half g_qmh[NH*SEQ*HD];
__device__ __align__(16) __half g_kmh[NH*SEQ*HD];
__device__ __align__(16) unsigned g_vmP[NH*(SEQ/2)*HD];   // half2(V[2t],V[2t+1]) pairs
__device__ __align__(16) __half g_orowsh[TOK*DIMM];
__device__ float g_xffni[TOK*DIMM];
__device__ __align__(16) __half g_xffnh[TOK*DIMM];
__device__ float g_G[NASS*FDIM];
__device__ float g_U[NASS*FDIM];
__device__ __align__(16) __half g_Gh[NASS*FDIM];
__device__ float g_slots[(size_t)NASS*DIMM];
__device__ __align__(16) __half g_suh[(size_t)TOK*2*DSH];
__device__ __align__(16) __half g_hsh[(size_t)TOK*DSH];
__device__ float g_scales[NASS];
__device__ int   g_eid[NASS];
__device__ int   g_tokof[NASS];
__device__ int   g_posof[NASS];
__device__ int   g_counts[NEXP];
__device__ int   g_offsets[NEXP];
__device__ int   g_cursors[NEXP];
// packed fp16 weights
__device__ __align__(16) unsigned g_wqkvP[512*3072];
__device__ __align__(16) unsigned g_woP[512*1024];
__device__ __align__(16) unsigned g_wupP[512*4096];
__device__ __align__(16) unsigned g_wdnP[1024*1024];
__device__ __align__(16) unsigned g_wguP[(size_t)64*512*512];
__device__ __align__(16) __half  g_wdnM[(size_t)32*1024*512];

// ---------------- fp16 helpers ----------------
__device__ __forceinline__ unsigned f2h2(float a, float b) {
    __half2 h = __floats2half2_rn(a, b);
    return *reinterpret_cast<unsigned*>(&h);
}
__device__ __forceinline__ void mma16(float c[4], const unsigned a[4], const unsigned b[2]) {
    asm volatile("mma.sync.aligned.m16n8k16.row.col.f32.f16.f16.f32 "
                 "{%0,%1,%2,%3},{%4,%5,%6,%7},{%8,%9},{%0,%1,%2,%3};"
                 : "+f"(c[0]), "+f"(c[1]), "+f"(c[2]), "+f"(c[3])
                 : "r"(a[0]), "r"(a[1]), "r"(a[2]), "r"(a[3]), "r"(b[0]), "r"(b[1]));
}

// As: [row][kpair] stride 20.  Bs NN: [kpair][n] stride 136.
__device__ __forceinline__ void compute_tile_nn(const unsigned* __restrict__ As,
                                                const unsigned* __restrict__ Bs,
                                                int wm, int wn, int g, int t4,
                                                float acc[16][4]) {
    #pragma unroll
    for (int ks = 0; ks < 2; ks++) {
        int kc = ks*8 + t4;
        unsigned af[2][4];
        #pragma unroll
        for (int mi = 0; mi < 2; mi++) {
            int r = wm + mi*16 + g;
            af[mi][0] = As[r*20 + kc];
            af[mi][1] = As[(r+8)*20 + kc];
            af[mi][2] = As[r*20 + kc + 4];
            af[mi][3] = As[(r+8)*20 + kc + 4];
        }
        #pragma unroll
        for (int ni = 0; ni < 8; ni++) {
            int n = wn + ni*8 + g;
            unsigned bf[2];
            bf[0] = Bs[kc*136 + n];
            bf[1] = Bs[(kc+4)*136 + n];
            #pragma unroll
            for (int mi = 0; mi < 2; mi++) mma16(acc[mi*8+ni], af[mi], bf);
        }
    }
}

// Bs TT: [n][kpair] stride 20.
__device__ __forceinline__ void compute_tile_tt(const unsigned* __restrict__ As,
                                                const unsigned* __restrict__ Bs,
                                                int wm, int wn, int g, int t4,
                                                float acc[16][4]) {
    #pragma unroll
    for (int ks = 0; ks < 2; ks++) {
        int kc = ks*8 + t4;
        unsigned af[2][4];
        #pragma unroll
        for (int mi = 0; mi < 2; mi++) {
            int r = wm + mi*16 + g;
            af[mi][0] = As[r*20 + kc];
            af[mi][1] = As[(r+8)*20 + kc];
            af[mi][2] = As[r*20 + kc + 4];
            af[mi][3] = As[(r+8)*20 + kc + 4];
        }
        #pragma unroll
        for (int ni = 0; ni < 8; ni++) {
            int n = wn + ni*8 + g;
            unsigned bf[2];
            bf[0] = Bs[n*20 + kc];
            bf[1] = Bs[n*20 + kc + 4];
            #pragma unroll
            for (int mi = 0; mi < 2; mi++) mma16(acc[mi*8+ni], af[mi], bf);
        }
    }
}

// ---------------- weight packing ----------------
__global__ void __launch_bounds__(256) pack_nn(const float* __restrict__ W,
                                               unsigned* __restrict__ Wp, int N4) {
    int idx = blockIdx.x*256 + threadIdx.x;
    int kp = idx / N4, nq = idx - kp*N4;
    int N = N4*4;
    float4 a = *(const float4*)(W + (size_t)(2*kp)*N + nq*4);
    float4 b = *(const float4*)(W + (size_t)(2*kp+1)*N + nq*4);
    ((uint4*)Wp)[idx] = make_uint4(f2h2(a.x,b.x), f2h2(a.y,b.y), f2h2(a.z,b.z), f2h2(a.w,b.w));
}

__global__ void __launch_bounds__(256) pack_moe_gu(const float* __restrict__ pW,
                                                   const float* __restrict__ fW) {
    int z = blockIdx.z;                 // sel*32 + expert
    int sel = z >> 5, e = z & 31;
    const float* W = (e < 16) ? pW + ((size_t)sel*16 + e)      * (size_t)DIMM*FDIM
                              : fW + ((size_t)sel*16 + (e-16)) * (size_t)DIMM*FDIM;
    unsigned* Wp = g_wguP + (size_t)z*512*512;
    int idx = blockIdx.x*256 + threadIdx.x;   // 65536 per z
    int kp = idx >> 7, nq = idx & 127;
    float4 a = *(const float4*)(W + (size_t)(2*kp)*FDIM + nq*4);
    float4 b = *(const float4*)(W + (size_t)(2*kp+1)*FDIM + nq*4);
    ((uint4*)Wp)[idx] = make_uint4(f2h2(a.x,b.x), f2h2(a.y,b.y), f2h2(a.z,b.z), f2h2(a.w,b.w));
}

__global__ void __launch_bounds__(256) conv_moe_down(const float* __restrict__ pW,
                                                     const float* __restrict__ fW) {
    int z = blockIdx.z;
    const float* W = (z < 16) ? pW + ((size_t)2*16 + z)      * (size_t)DIMM*FDIM
                              : fW + ((size_t)2*16 + (z-16)) * (size_t)DIMM*FDIM;
    __half* Wh = g_wdnM + (size_t)z*1024*512;
    int idx = blockIdx.x*256 + threadIdx.x;
    float4 a = ((const float4*)W)[idx];
    ((uint2*)Wh)[idx] = make_uint2(f2h2(a.x,a.y), f2h2(a.z,a.w));
}

// ---------------- dense fp16 GEMM: C[M,N] = A[M,K] @ B[K,N] (+D) ----------------
// OUT: 0 -> float C with optional D residual; 1 -> half C
template<int OUT>
__global__ void __launch_bounds__(256) gemm_h(const __half* __restrict__ A,
                                              const unsigned* __restrict__ Bp,
                                              void* __restrict__ Cv,
                                              const float* __restrict__ D,
                                              int M, int N, int K) {
    __shared__ __align__(16) unsigned As[2][2560];
    __shared__ __align__(16) unsigned Bs[2][2176];
    int tid = threadIdx.x, lane = tid & 31, wid = tid >> 5;
    int g = lane >> 2, t4 = lane & 3;
    int wm = (wid & 3)*32, wn = (wid >> 2)*64;
    size_t rowBase = (size_t)blockIdx.y * 128, colBase = (size_t)blockIdx.x * 128;
    int a_r = tid >> 1, a_half = tid & 1;
    int a_sidx = a_r*20 + a_half*8;
    const uint4* Ap = (const uint4*)(A + (rowBase + a_r)*K + a_half*16);
    int kp = tid >> 4, q = tid & 15;
    int bsidx = kp*136 + q*4;
    const unsigned* Brow = Bp + (size_t)kp*N + colBase + q*4;
    float acc[16][4];
    #pragma unroll
    for (int i = 0; i < 16; i++)
        #pragma unroll
        for (int j = 0; j < 4; j++) acc[i][j] = 0.f;
    uint4 ra0 = Ap[0], ra1 = Ap[1];
    uint4 rb0 = *(const uint4*)(Brow);
    uint4 rb1 = *(const uint4*)(Brow + 64);
    int NC = K >> 5;
    int buf = 0;
    As[0][a_sidx+0]=ra0.x; As[0][a_sidx+1]=ra0.y; As[0][a_sidx+2]=ra0.z; As[0][a_sidx+3]=ra0.w;
    As[0][a_sidx+4]=ra1.x; As[0][a_sidx+5]=ra1.y; As[0][a_sidx+6]=ra1.z; As[0][a_sidx+7]=ra1.w;
    *(uint4*)&Bs[0][bsidx] = rb0;
    *(uint4*)&Bs[0][bsidx+64] = rb1;
    __syncthreads();
    for (int c = 0; c < NC; c++) {
        if (c + 1 < NC) {
            ra0 = Ap[(c+1)*4];
            ra1 = Ap[(c+1)*4 + 1];
            const unsigned* b = Brow + (size_t)(c+1)*16*N;
            rb0 = *(const uint4*)(b);
            rb1 = *(const uint4*)(b + 64);
        }
        compute_tile_nn(As[buf], Bs[buf], wm, wn, g, t4, acc);
        if (c + 1 < NC) {
            unsigned* a = &As[buf^1][a_sidx];
            a[0]=ra0.x; a[1]=ra0.y; a[2]=ra0.z; a[3]=ra0.w;
            a[4]=ra1.x; a[5]=ra1.y; a[6]=ra1.z; a[7]=ra1.w;
            *(uint4*)&Bs[buf^1][bsidx] = rb0;
            *(uint4*)&Bs[buf^1][bsidx+64] = rb1;
        }
        __syncthreads();
        buf ^= 1;
    }
    #pragma unroll
    for (int mi = 0; mi < 2; mi++)
        #pragma unroll
        for (int ni = 0; ni < 8; ni++) {
            float* c = acc[mi*8+ni];
            size_t r0 = rowBase + wm + mi*16 + g;
            size_t c0 = colBase + wn + ni*8 + 2*t4;
            if (OUT == 0) {
                float* C = (float*)Cv;
                size_t o0 = r0*N + c0, o1 = (r0+8)*N + c0;
                if (D) {
                    C[o0] = c[0] + D[o0]; C[o0+1] = c[1] + D[o0+1];
                    C[o1] = c[2] + D[o1]; C[o1+1] = c[3] + D[o1+1];
                } else {
                    C[o0] = c[0]; C[o0+1] = c[1];
                    C[o1] = c[2]; C[o1+1] = c[3];
                }
            } else {
                __half* C = (__half*)Cv;
                *(unsigned*)&C[r0*N + c0]     = f2h2(c[0], c[1]);
                *(unsigned*)&C[(r0+8)*N + c0] = f2h2(c[2], c[3]);
            }
        }
}

// ---------------- MoE gate+up fused grouped GEMM (fp16 packed weights) ----------------
__global__ void __launch_bounds__(256) moe_gu_h() {
    int e = blockIdx.z;
    int cnt = g_counts[e];
    int rowTile = blockIdx.y * 128;
    if (rowTile >= cnt) return;
    int base = g_offsets[e];
    int colBase = blockIdx.x * 128;
    int sel = colBase >> 9;
    int wcol = colBase & 511;
    const unsigned* Wp = g_wguP + (size_t)(sel*32 + e)*512*512;
    float* Out = sel ? g_U : g_G;
    __shared__ int rows[128];
    __shared__ __align__(16) unsigned As[2][2560];
    __shared__ __align__(16) unsigned Bs[2][2176];
    int tid = threadIdx.x;
    if (tid < 128) {
        int rr = rowTile + tid;
        rows[tid] = (rr < cnt) ? g_tokof[base + rr] : -1;
    }
    __syncthreads();
    int lane = tid & 31, wid = tid >> 5;
    int g = lane >> 2, t4 = lane & 3;
    int wm = (wid & 3)*32, wn = (wid >> 2)*64;
    int a_r = tid >> 1, a_half = tid & 1;
    int a_sidx = a_r*20 + a_half*8;
    int tk = rows[a_r];
    const uint4* Ap = (const uint4*)(g_xffnh + (size_t)(tk < 0 ? 0 : tk)*DIMM + a_half*16);
    const uint4 z4 = make_uint4(0,0,0,0);
    int kp = tid >> 4, q = tid & 15;
    int bsidx = kp*136 + q*4;
    const unsigned* Brow = Wp + (size_t)kp*512 + wcol + q*4;
    float acc[16][4];
    #pragma unroll
    for (int i = 0; i < 16; i++)
        #pragma unroll
        for (int j = 0; j < 4; j++) acc[i][j] = 0.f;
    uint4 ra0 = (tk >= 0) ? Ap[0] : z4;
    uint4 ra1 = (tk >= 0) ? Ap[1] : z4;
    uint4 rb0 = *(const uint4*)(Brow);
    uint4 rb1 = *(const uint4*)(Brow + 64);
    int buf = 0;
    {
        unsigned* a = &As[0][a_sidx];
        a[0]=ra0.x; a[1]=ra0.y; a[2]=ra0.z; a[3]=ra0.w;
        a[4]=ra1.x; a[5]=ra1.y; a[6]=ra1.z; a[7]=ra1.w;
        *(uint4*)&Bs[0][bsidx] = rb0;
        *(uint4*)&Bs[0][bsidx+64] = rb1;
    }
    __syncthreads();
    for (int c = 0; c < 32; c++) {
        if (c + 1 < 32) {
            ra0 = (tk >= 0) ? Ap[(c+1)*4]     : z4;
            ra1 = (tk >= 0) ? Ap[(c+1)*4 + 1] : z4;
            const unsigned* b = Brow + (size_t)(c+1)*16*512;
            rb0 = *(const uint4*)(b);
            rb1 = *(const uint4*)(b + 64);
        }
        compute_tile_nn(As[buf], Bs[buf], wm, wn, g, t4, acc);
        if (c + 1 < 32) {
            unsigned* a = &As[buf^1][a_sidx];
            a[0]=ra0.x; a[1]=ra0.y; a[2]=ra0.z; a[3]=ra0.w;
            a[4]=ra1.x; a[5]=ra1.y; a[6]=ra1.z; a[7]=ra1.w;
            *(uint4*)&Bs[buf^1][bsidx] = rb0;
            *(uint4*)&Bs[buf^1][bsidx+64] = rb1;
        }
        __syncthreads();
        buf ^= 1;
    }
    #pragma unroll
    for (int mi = 0; mi < 2; mi++)
        #pragma unroll
        for (int ni = 0; ni < 8; ni++) {
            float* c = acc[mi*8+ni];
            int r = rowTile + wm + mi*16 + g;
            int cc = wcol + wn + ni*8 + 2*t4;
            if (r < cnt) {
                Out[(size_t)(base+r)*FDIM + cc]     = c[0];
                Out[(size_t)(base+r)*FDIM + cc + 1] = c[1];
            }
            if (r + 8 < cnt) {
                Out[(size_t)(base+r+8)*FDIM + cc]     = c[2];
                Out[(size_t)(base+r+8)*FDIM + cc + 1] = c[3];
            }
        }
}

// ---------------- MoE down grouped GEMM (fp16 A and W) ----------------
__global__ void __launch_bounds__(256) moe_down_h() {
    int e = blockIdx.z;
    int cnt = g_counts[e];
    int rowTile = blockIdx.y * 128;
    if (rowTile >= cnt) return;
    int base = g_offsets[e];
    int colBase = blockIdx.x * 128;
    const __half* W = g_wdnM + (size_t)e*1024*512;
    __shared__ __align__(16) unsigned As[2][2560];
    __shared__ __align__(16) unsigned Bs[2][2560];
    int tid = threadIdx.x, lane = tid & 31, wid = tid >> 5;
    int g = lane >> 2, t4 = lane & 3;
    int wm = (wid & 3)*32, wn = (wid >> 2)*64;
    int r_ = tid >> 1, a_half = tid & 1;
    int sidx = r_*20 + a_half*8;
    bool valid = (rowTile + r_) < cnt;
    int arow = base + rowTile + r_;
    if (arow > NASS - 1) arow = NASS - 1;
    const uint4 z4 = make_uint4(0,0,0,0);
    const uint4* Ap = (const uint4*)(g_Gh + (size_t)arow*FDIM + a_half*16);
    const uint4* Bq = (const uint4*)(W + (size_t)(colBase + r_)*FDIM + a_half*16);
    float acc[16][4];
    #pragma unroll
    for (int i = 0; i < 16; i++)
        #pragma unroll
        for (int j = 0; j < 4; j++) acc[i][j] = 0.f;
    uint4 ra0 = valid ? Ap[0] : z4, ra1 = valid ? Ap[1] : z4;
    uint4 rb0 = Bq[0], rb1 = Bq[1];
    int buf = 0;
    {
        unsigned* a = &As[0][sidx];
        a[0]=ra0.x; a[1]=ra0.y; a[2]=ra0.z; a[3]=ra0.w;
        a[4]=ra1.x; a[5]=ra1.y; a[6]=ra1.z; a[7]=ra1.w;
        unsigned* b = &Bs[0][sidx];
        b[0]=rb0.x; b[1]=rb0.y; b[2]=rb0.z; b[3]=rb0.w;
        b[4]=rb1.x; b[5]=rb1.y; b[6]=rb1.z; b[7]=rb1.w;
    }
    __syncthreads();
    for (int c = 0; c < 16; c++) {
        if (c + 1 < 16) {
            ra0 = valid ? Ap[(c+1)*4]     : z4;
            ra1 = valid ? Ap[(c+1)*4 + 1] : z4;
            rb0 = Bq[(c+1)*4];
            rb1 = Bq[(c+1)*4 + 1];
        }
        compute_tile_tt(As[buf], Bs[buf], wm, wn, g, t4, acc);
        if (c + 1 < 16) {
            unsigned* a = &As[buf^1][sidx];
            a[0]=ra0.x; a[1]=ra0.y; a[2]=ra0.z; a[3]=ra0.w;
            a[4]=ra1.x; a[5]=ra1.y; a[6]=ra1.z; a[7]=ra1.w;
            unsigned* b = &Bs[buf^1][sidx];
            b[0]=rb0.x; b[1]=rb0.y; b[2]=rb0.z; b[3]=rb0.w;
            b[4]=rb1.x; b[5]=rb1.y; b[6]=rb1.z; b[7]=rb1.w;
        }
        __syncthreads();
        buf ^= 1;
    }
    #pragma unroll
    for (int mi = 0; mi < 2; mi++)
        #pragma unroll
        for (int ni = 0; ni < 8; ni++) {
            float* c = acc[mi*8+ni];
            int r = rowTile + wm + mi*16 + g;
            int cc = colBase + wn + ni*8 + 2*t4;
            if (r < cnt) {
                g_slots[(size_t)(base+r)*DIMM + cc]     = c[0];
                g_slots[(size_t)(base+r)*DIMM + cc + 1] = c[1];
            }
            if (r + 8 < cnt) {
                g_slots[(size_t)(base+r+8)*DIMM + cc]     = c[2];
                g_slots[(size_t)(base+r+8)*DIMM + cc + 1] = c[3];
            }
        }
}

// ---------------- rmsnorm (half out) ----------------
__global__ void rmsnorm_h(const float* __restrict__ x, const float* __restrict__ w,
                          __half* __restrict__ out) {
    int r = blockIdx.x;
    const float* xr = x + (size_t)r*DIMM;
    __shared__ float red[8];
    float s = 0.f;
    for (int d = threadIdx.x; d < DIMM; d += 256) { float v = xr[d]; s += v*v; }
    #pragma unroll
    for (int o = 16; o; o >>= 1) s += __shfl_xor_sync(0xffffffffu, s, o);
    if ((threadIdx.x & 31) == 0) red[threadIdx.x >> 5] = s;
    __syncthreads();
    if (threadIdx.x == 0) {
        float t = 0.f;
        #pragma unroll
        for (int i = 0; i < 8; i++) t += red[i];
        red[0] = rsqrtf(t / (float)DIMM + 1e-5f);
    }
    __syncthreads();
    float rms = red[0];
    for (int d = threadIdx.x; d < DIMM; d += 256)
        out[(size_t)r*DIMM + d] = __float2half(xr[d] * rms * w[d]);
}

// ---------------- rope + dual interleave (half in/out, V packed) ----------------
__global__ void rope_interleave_kernel() {
    int r = blockIdx.x, h = blockIdx.y, d = threadIdx.x;
    int bi = r >> 10, si = r & 1023;
    int t = 2*si + bi;
    size_t src = (size_t)r*3072 + h*64;
    float q = __half2float(g_qkvh[src + d]);
    float k = __half2float(g_qkvh[src + 1024 + d]);
    float v = __half2float(g_qkvh[src + 2048 + d]);
    ((__half*)g_vmP)[(((size_t)h*1024 + (t >> 1))*64 + d)*2 + (t & 1)] = __float2half(v);
    __shared__ float qs[64], ks[64];
    qs[d] = q; ks[d] = k;
    __syncthreads();
    if (d < 32) {
        float inv = powf(10000.0f, -(float)(2*d) / 64.0f);
        float fr = (float)si * inv;
        float sn, cs;
        sincosf(fr, &sn, &cs);
        size_t dst = ((size_t)h*SEQ + t)*64;
        float x1 = qs[d], x2 = qs[d+32];
        g_qmh[dst + d]      = __float2half( x1*cs + x2*sn);
        g_qmh[dst + d + 32] = __float2half(-x1*sn + x2*cs);
        x1 = ks[d]; x2 = ks[d+32];
        g_kmh[dst + d]      = __float2half( x1*cs + x2*sn);
        g_kmh[dst + d + 32] = __float2half(-x1*sn + x2*cs);
    }
}

// ---------------- fp16 flash attention: 128 queries x 256 threads ----------------
#define ATT_SMEM_W (4608 + 2304 + 4608 + 2304)
__global__ void __launch_bounds__(256) attn_h() {
    extern __shared__ __align__(16) unsigned asm_[];
    unsigned* Qs = asm_;            // 128 x 36
    unsigned* Ks = asm_ + 4608;     // 64 x 36
    unsigned* Ps = asm_ + 6912;     // 128 x 36
    unsigned* Vt = asm_ + 11520;    // 64 x 36
    int h = blockIdx.y;
    int t0 = ((int)gridDim.x - 1 - (int)blockIdx.x) * 128;
    int tid = threadIdx.x, lane = tid & 31, wid = tid >> 5;
    int g = lane >> 2, t4 = lane & 3;
    int wm = wid * 16;

    const __half* qb = g_qmh + ((size_t)h*SEQ + t0)*64;
    for (int i = tid; i < 128*8; i += 256) {
        int r = i >> 3, j = i & 7;
        *(uint4*)&Qs[r*36 + j*4] = ((const uint4*)(qb + (size_t)r*64))[j];
    }

    float o[8][4];
    #pragma unroll
    for (int n = 0; n < 8; n++)
        #pragma unroll
        for (int j = 0; j < 4; j++) o[n][j] = 0.f;
    float m0 = -1e30f, m1 = -1e30f, l0 = 0.f, l1 = 0.f;
    int row0 = t0 + wm + g, row1 = row0 + 8;
    int wmax = t0 + wm + 15;

    for (int kt = 0; kt <= t0 + 127; kt += 64) {
        __syncthreads();
        const __half* kb = g_kmh + ((size_t)h*SEQ + kt)*64;
        for (int i = tid; i < 64*8; i += 256) {
            int r = i >> 3, j = i & 7;
            *(uint4*)&Ks[r*36 + j*4] = ((const uint4*)(kb + (size_t)r*64))[j];
        }
        const unsigned* vp = g_vmP + ((size_t)h*1024 + (kt >> 1))*64;
        for (int w = tid; w < 64*32; w += 256) {
            int d = w & 63, p = w >> 6;
            Vt[d*36 + p] = vp[(size_t)p*64 + d];
        }
        __syncthreads();
        if (kt > wmax) continue;

        float s[8][4];
        #pragma unroll
        for (int n = 0; n < 8; n++)
            #pragma unroll
            for (int j = 0; j < 4; j++) s[n][j] = 0.f;
        #pragma unroll
        for (int ks = 0; ks < 4; ks++) {
            int kc = ks*8 + t4;
            unsigned af[4];
            af[0] = Qs[(wm+g)*36 + kc];
            af[1] = Qs[(wm+g+8)*36 + kc];
            af[2] = Qs[(wm+g)*36 + kc + 4];
            af[3] = Qs[(wm+g+8)*36 + kc + 4];
            #pragma unroll
            for (int n = 0; n < 8; n++) {
                unsigned bf[2];
                bf[0] = Ks[(n*8+g)*36 + kc];
                bf[1] = Ks[(n*8+g)*36 + kc + 4];
                mma16(s[n], af, bf);
            }
        }
        float mx0 = -1e30f, mx1 = -1e30f;
        #pragma unroll
        for (int n = 0; n < 8; n++) {
            int c0 = kt + n*8 + 2*t4, c1 = c0 + 1;
            s[n][0] = (c0 <= row0) ? s[n][0]*0.125f : -1e30f;
            s[n][1] = (c1 <= row0) ? s[n][1]*0.125f : -1e30f;
            s[n][2] = (c0 <= row1) ? s[n][2]*0.125f : -1e30f;
            s[n][3] = (c1 <= row1) ? s[n][3]*0.125f : -1e30f;
            mx0 = fmaxf(mx0, fmaxf(s[n][0], s[n][1]));
            mx1 = fmaxf(mx1, fmaxf(s[n][2], s[n][3]));
        }
        mx0 = fmaxf(mx0, __shfl_xor_sync(0xffffffffu, mx0, 1));
        mx0 = fmaxf(mx0, __shfl_xor_sync(0xffffffffu, mx0, 2));
        mx1 = fmaxf(mx1, __shfl_xor_sync(0xffffffffu, mx1, 1));
        mx1 = fmaxf(mx1, __shfl_xor_sync(0xffffffffu, mx1, 2));
        float nm0 = fmaxf(m0, mx0), nm1 = fmaxf(m1, mx1);
        float cor0 = __expf(m0 - nm0), cor1 = __expf(m1 - nm1);
        m0 = nm0; m1 = nm1;
        l0 *= cor0; l1 *= cor1;
        float sum0 = 0.f, sum1 = 0.f;
        #pragma unroll
        for (int n = 0; n < 8; n++) {
            float p00 = __expf(s[n][0] - nm0), p01 = __expf(s[n][1] - nm0);
            float p10 = __expf(s[n][2] - nm1), p11 = __expf(s[n][3] - nm1);
            sum0 += p00 + p01; sum1 += p10 + p11;
            Ps[(wm+g)*36 + n*4 + t4]   = f2h2(p00, p01);
            Ps[(wm+g+8)*36 + n*4 + t4] = f2h2(p10, p11);
            #pragma unroll
            for (int j = 0; j < 2; j++) { o[n][j] *= cor0; o[n][2+j] *= cor1; }
        }
        sum0 += __shfl_xor_sync(0xffffffffu, sum0, 1);
        sum0 += __shfl_xor_sync(0xffffffffu, sum0, 2);
        sum1 += __shfl_xor_sync(0xffffffffu, sum1, 1);
        sum1 += __shfl_xor_sync(0xffffffffu, sum1, 2);
        l0 += sum0; l1 += sum1;
        __syncwarp();

        #pragma unroll
        for (int ks = 0; ks < 4; ks++) {
            int kc = ks*8 + t4;
            unsigned af[4];
            af[0] = Ps[(wm+g)*36 + kc];
            af[1] = Ps[(wm+g+8)*36 + kc];
            af[2] = Ps[(wm+g)*36 + kc + 4];
            af[3] = Ps[(wm+g+8)*36 + kc + 4];
            #pragma unroll
            for (int n = 0; n < 8; n++) {
                unsigned bf[2];
                bf[0] = Vt[(n*8+g)*36 + kc];
                bf[1] = Vt[(n*8+g)*36 + kc + 4];
                mma16(o[n], af, bf);
            }
        }
    }

    float inv0 = 1.f / l0, inv1 = 1.f / l1;
    int tok0 = (row0 & 1)*1024 + (row0 >> 1);
    int tok1 = (row1 & 1)*1024 + (row1 >> 1);
    #pragma unroll
    for (int n = 0; n < 8; n++) {
        int col = h*64 + n*8 + 2*t4;
        *(unsigned*)&g_orowsh[(size_t)tok0*DIMM + col] = f2h2(o[n][0]*inv0, o[n][1]*inv0);
        *(unsigned*)&g_orowsh[(size_t)tok1*DIMM + col] = f2h2(o[n][2]*inv1, o[n][3]*inv1);
    }
}

// ---------------- router (reads half xffn) ----------------
__global__ void router_kernel(const float* __restrict__ pkeys, const float* __restrict__ fkeys,
                              const float* __restrict__ pbias, const float* __restrict__ fbias,
                              const int* __restrict__ pidx, const float* __restrict__ pval,
                              const int* __restrict__ fidx, const float* __restrict__ fval) {
    int tok = blockIdx.x, tid = threadIdx.x;
    bool isf = tok >= 1024;
    const float* keys = isf ? fkeys : pkeys;
    const __half* x = g_xffnh + (size_t)tok*DIMM;
    __shared__ float part[8][16];
    __shared__ float logit[16];
    int e = tid & 15, ch = tid >> 4;
    float s = 0.f;
    int d0 = ch * 128;
    for (int d = d0; d < d0 + 128; d++)
        s = fmaf(__half2float(x[d]), keys[d*16 + e], s);
    part[ch][e] = s;
    __syncthreads();
    if (tid < 16) {
        float t = 0.f;
        #pragma unroll
        for (int c = 0; c < 8; c++) t += part[c][tid];
        logit[tid] = t;
    }
    __syncthreads();
    if (tid == 0) {
        int lt = isf ? tok - 1024 : tok;
        const int*   idx  = isf ? fidx  : pidx;
        const float* val  = isf ? fval  : pval;
        const float* bias = isf ? fbias : pbias;
        float sc[4]; int id[4]; float sum = 0.f;
        #pragma unroll
        for (int k = 0; k < 4; k++) {
            int ix = idx[lt*4 + k];
            float v = val[lt*4 + k] + logit[ix] + bias[ix];
            float s2 = 1.f / (1.f + expf(-v));
            sc[k] = s2; sum += s2;
            id[k] = ix + (isf ? 16 : 0);
        }
        #pragma unroll
        for (int k = 0; k < 4; k++) {
            g_scales[tok*4 + k] = sc[k] / sum;
            g_eid[tok*4 + k] = id[k];
            atomicAdd(&g_counts[id[k]], 1);
        }
    }
}

__global__ void zero32_kernel() {
    int i = threadIdx.x;
    if (i < NEXP) { g_counts[i] = 0; g_cursors[i] = 0; }
}

__global__ void prefix_kernel() {
    int acc = 0;
    for (int e = 0; e < NEXP; e++) { g_offsets[e] = acc; acc += g_counts[e]; }
}

__global__ void scatter_kernel() {
    int a = blockIdx.x * blockDim.x + threadIdx.x;
    if (a >= NASS) return;
    int e = g_eid[a];
    int p = g_offsets[e] + atomicAdd(&g_cursors[e], 1);
    g_tokof[p] = a >> 2;
    g_posof[a] = p;
}

__global__ void swiglu_moe_kernel() {
    size_t i = (size_t)blockIdx.x * blockDim.x + threadIdx.x;
    float g = g_G[i], u = g_U[i];
    g_Gh[i] = __float2half((g / (1.f + expf(-g))) * u);
}

__global__ void combine_kernel(float* __restrict__ y) {
    int tok = blockIdx.x;
    __shared__ int pos[4];
    __shared__ float sc[4];
    if (threadIdx.x < 4) {
        pos[threadIdx.x] = g_posof[tok*4 + threadIdx.x];
        sc[threadIdx.x]  = g_scales[tok*4 + threadIdx.x];
    }
    __syncthreads();
    for (int d = threadIdx.x; d < DIMM; d += 256) {
        float v = g_xffni[(size_t)tok*DIMM + d];
        #pragma unroll
        for (int k = 0; k < 4; k++) v = fmaf(sc[k], g_slots[(size_t)pos[k]*DIMM + d], v);
        y[(size_t)tok*DIMM + d] = v;
    }
}

__global__ void swiglu_shared_kernel() {
    int t = blockIdx.x;
    for (int j = threadIdx.x; j < DSH; j += 256) {
        float a = __half2float(g_suh[(size_t)t*2*DSH + j]);
        float b = __half2float(g_suh[(size_t)t*2*DSH + DSH + j]);
        g_hsh[(size_t)t*DSH + j] = __float2half((a / (1.f + expf(-a))) * b);
    }
}

// ---------------- launch ----------------
extern "C" void kernel_launch(void* const* d_in, const int* in_sizes, int n_in,
                              void* d_out, int out_size) {
    const float* x_input  = (const float*)d_in[0];
    const int*   p_idx    = (const int*)  d_in[1];
    const float* p_val    = (const float*)d_in[2];
    const int*   f_idx    = (const int*)  d_in[3];
    const float* f_val    = (const float*)d_in[4];
    const float* attn_nw  = (const float*)d_in[5];
    const float* ffn_nw   = (const float*)d_in[6];
    const float* W_attn   = (const float*)d_in[7];
    const float* W_attn_o = (const float*)d_in[8];
    const float* ffn_up   = (const float*)d_in[9];
    const float* ffn_down = (const float*)d_in[10];
    const float* pW       = (const float*)d_in[11];
    const float* fW       = (const float*)d_in[12];
    const float* pkeys    = (const float*)d_in[13];
    const float* fkeys    = (const float*)d_in[14];
    const float* pbias    = (const float*)d_in[15];
    const float* fbias    = (const float*)d_in[16];
    float* out = (float*)d_out;

    __half *xnormh, *qkvh, *orowsh, *xffnh, *suh, *hsh;
    float *xffni;
    unsigned *wqkvP, *woP, *wupP, *wdnP;
    cudaGetSymbolAddress((void**)&xnormh, g_xnormh);
    cudaGetSymbolAddress((void**)&qkvh,   g_qkvh);
    cudaGetSymbolAddress((void**)&orowsh, g_orowsh);
    cudaGetSymbolAddress((void**)&xffni,  g_xffni);
    cudaGetSymbolAddress((void**)&xffnh,  g_xffnh);
    cudaGetSymbolAddress((void**)&suh,    g_suh);
    cudaGetSymbolAddress((void**)&hsh,    g_hsh);
    cudaGetSymbolAddress((void**)&wqkvP,  g_wqkvP);
    cudaGetSymbolAddress((void**)&woP,    g_woP);
    cudaGetSymbolAddress((void**)&wupP,   g_wupP);
    cudaGetSymbolAddress((void**)&wdnP,   g_wdnP);

    static bool attr_set = false;
    if (!attr_set) {
        cudaFuncSetAttribute(attn_h, cudaFuncAttributeMaxDynamicSharedMemorySize,
                             ATT_SMEM_W * 4);
        attr_set = true;
    }

    // weight packing (fp16)
    pack_nn<<<1536, 256>>>(W_attn,   wqkvP, 768);
    pack_nn<<<512,  256>>>(W_attn_o, woP,   256);
    pack_nn<<<2048, 256>>>(ffn_up,   wupP, 1024);
    pack_nn<<<1024, 256>>>(ffn_down, wdnP,  256);
    pack_moe_gu<<<dim3(256, 1, 64), 256>>>(pW, fW);
    conv_moe_down<<<dim3(512, 1, 32), 256>>>(pW, fW);

    // attention block
    rmsnorm_h<<<TOK, 256>>>(x_input, attn_nw, xnormh);
    gemm_h<1><<<dim3(24, 16), 256>>>(xnormh, wqkvP, qkvh, nullptr, TOK, 3*DIMM, DIMM);
    rope_interleave_kernel<<<dim3(TOK, NH), 64>>>();
    attn_h<<<dim3(SEQ/128, NH), 256, ATT_SMEM_W*4>>>();
    gemm_h<0><<<dim3(8, 16), 256>>>(orowsh, woP, xffni, x_input, TOK, DIMM, DIMM);
    rmsnorm_h<<<TOK, 256>>>(xffni, ffn_nw, xffnh);

    // routing
    zero32_kernel<<<1, 32>>>();
    router_kernel<<<TOK, 128>>>(pkeys, fkeys, pbias, fbias, p_idx, p_val, f_idx, f_val);
    prefix_kernel<<<1, 1>>>();
    scatter_kernel<<<32, 256>>>();

    // grouped MoE
    moe_gu_h<<<dim3(8, 16, NEXP), 256>>>();
    swiglu_moe_kernel<<<(NASS*FDIM)/256, 256>>>();
    moe_down_h<<<dim3(8, 16, NEXP), 256>>>();
    combine_kernel<<<TOK, 256>>>(out);

    // shared expert (adds into out)
    gemm_h<1><<<dim3(32, 16), 256>>>(xffnh, wupP, suh, nullptr, TOK, 2*DSH, DIMM);
    swiglu_shared_kernel<<<TOK, 256>>>();
    gemm_h<0><<<dim3(8, 16), 256>>>(hsh, wdnP, out, out, TOK, DIMM, DSH);
}

// round 10
// speedup vs baseline: 6.3647x; 1.0593x over previous
#include <cuda_runtime.h>
#include <cuda_fp16.h>
#include <math.h>
#include <stdint.h>

// ---------------- problem constants ----------------
#define TOK   2048
#define DIMM  1024
#define NH    16
#define HD    64
#define SEQ   2048
#define NASS  8192
#define NEXP  32
#define FDIM  512
#define DSH   2048

// ---------------- scratch ----------------
__device__ __align__(16) __half g_xnormh[TOK*DIMM];
__device__ __align__(16) __half g_qkvh[TOK*3*DIMM];
__device__ __align__(16) __half g_qmh[NH*SEQ*HD];
__device__ __align__(16) __half g_kmh[NH*SEQ*HD];
__device__ __align__(16) unsigned g_vmP[NH*(SEQ/2)*HD];
__device__ __align__(16) __half g_orowsh[TOK*DIMM];
__device__ float g_xffni[TOK*DIMM];
__device__ __align__(16) __half g_xffnh[TOK*DIMM];
__device__ __align__(16) __half g_gateh[NASS*FDIM];
__device__ __align__(16) __half g_uph[NASS*FDIM];
__device__ __align__(16) __half g_Gh[NASS*FDIM];
__device__ __align__(16) __half g_slotsh[(size_t)NASS*DIMM];
__device__ __align__(16) __half g_suh[(size_t)TOK*2*DSH];
__device__ __align__(16) __half g_hsh[(size_t)TOK*DSH];
__device__ float g_scales[NASS];
__device__ int   g_eid[NASS];
__device__ int   g_tokof[NASS];
__device__ int   g_posof[NASS];
__device__ int   g_counts[NEXP];
__device__ int   g_offsets[NEXP];
__device__ int   g_cursors[NEXP];
// packed fp16 weights
__device__ __align__(16) unsigned g_wqkvP[512*3072];
__device__ __align__(16) unsigned g_woP[512*1024];
__device__ __align__(16) unsigned g_wupP[512*4096];
__device__ __align__(16) unsigned g_wdnP[1024*1024];
__device__ __align__(16) unsigned g_wguP[(size_t)64*512*512];
__device__ __align__(16) __half  g_wdnM[(size_t)32*1024*512];

// ---------------- helpers ----------------
__device__ __forceinline__ unsigned f2h2(float a, float b) {
    __half2 h = __floats2half2_rn(a, b);
    return *reinterpret_cast<unsigned*>(&h);
}
__device__ __forceinline__ void mma16(float c[4], const unsigned a[4], const unsigned b[2]) {
    asm volatile("mma.sync.aligned.m16n8k16.row.col.f32.f16.f16.f32 "
                 "{%0,%1,%2,%3},{%4,%5,%6,%7},{%8,%9},{%0,%1,%2,%3};"
                 : "+f"(c[0]), "+f"(c[1]), "+f"(c[2]), "+f"(c[3])
                 : "r"(a[0]), "r"(a[1]), "r"(a[2]), "r"(a[3]), "r"(b[0]), "r"(b[1]));
}
__device__ __forceinline__ uint32_t s2u(const void* p) {
    uint32_t a;
    asm("{ .reg .u64 t; cvta.to.shared.u64 t, %1; cvt.u32.u64 %0, t; }" : "=r"(a) : "l"(p));
    return a;
}
__device__ __forceinline__ void cpa16(uint32_t dst, const void* src) {
    asm volatile("cp.async.ca.shared.global [%0], [%1], 16;" :: "r"(dst), "l"(src));
}
#define CPA_COMMIT() asm volatile("cp.async.commit_group;")
#define CPA_WAIT1()  asm volatile("cp.async.wait_group 1;")
#define CPA_WAIT0()  asm volatile("cp.async.wait_group 0;")

// As: [row][kpair] stride 20.  Bs NN: [kpair][n] stride 136.
__device__ __forceinline__ void compute_tile_nn(const unsigned* __restrict__ As,
                                                const unsigned* __restrict__ Bs,
                                                int wm, int wn, int g, int t4,
                                                float acc[16][4]) {
    #pragma unroll
    for (int ks = 0; ks < 2; ks++) {
        int kc = ks*8 + t4;
        unsigned af[2][4];
        #pragma unroll
        for (int mi = 0; mi < 2; mi++) {
            int r = wm + mi*16 + g;
            af[mi][0] = As[r*20 + kc];
            af[mi][1] = As[(r+8)*20 + kc];
            af[mi][2] = As[r*20 + kc + 4];
            af[mi][3] = As[(r+8)*20 + kc + 4];
        }
        #pragma unroll
        for (int ni = 0; ni < 8; ni++) {
            int n = wn + ni*8 + g;
            unsigned bf[2];
            bf[0] = Bs[kc*136 + n];
            bf[1] = Bs[(kc+4)*136 + n];
            #pragma unroll
            for (int mi = 0; mi < 2; mi++) mma16(acc[mi*8+ni], af[mi], bf);
        }
    }
}

// Bs TT: [n][kpair] stride 20.
__device__ __forceinline__ void compute_tile_tt(const unsigned* __restrict__ As,
                                                const unsigned* __restrict__ Bs,
                                                int wm, int wn, int g, int t4,
                                                float acc[16][4]) {
    #pragma unroll
    for (int ks = 0; ks < 2; ks++) {
        int kc = ks*8 + t4;
        unsigned af[2][4];
        #pragma unroll
        for (int mi = 0; mi < 2; mi++) {
            int r = wm + mi*16 + g;
            af[mi][0] = As[r*20 + kc];
            af[mi][1] = As[(r+8)*20 + kc];
            af[mi][2] = As[r*20 + kc + 4];
            af[mi][3] = As[(r+8)*20 + kc + 4];
        }
        #pragma unroll
        for (int ni = 0; ni < 8; ni++) {
            int n = wn + ni*8 + g;
            unsigned bf[2];
            bf[0] = Bs[n*20 + kc];
            bf[1] = Bs[n*20 + kc + 4];
            #pragma unroll
            for (int mi = 0; mi < 2; mi++) mma16(acc[mi*8+ni], af[mi], bf);
        }
    }
}

// ---------------- weight packing ----------------
__global__ void __launch_bounds__(256) pack_nn(const float* __restrict__ W,
                                               unsigned* __restrict__ Wp, int N4) {
    int idx = blockIdx.x*256 + threadIdx.x;
    int kp = idx / N4, nq = idx - kp*N4;
    int N = N4*4;
    float4 a = *(const float4*)(W + (size_t)(2*kp)*N + nq*4);
    float4 b = *(const float4*)(W + (size_t)(2*kp+1)*N + nq*4);
    ((uint4*)Wp)[idx] = make_uint4(f2h2(a.x,b.x), f2h2(a.y,b.y), f2h2(a.z,b.z), f2h2(a.w,b.w));
}

__global__ void __launch_bounds__(256) pack_moe_gu(const float* __restrict__ pW,
                                                   const float* __restrict__ fW) {
    int z = blockIdx.z;
    int sel = z >> 5, e = z & 31;
    const float* W = (e < 16) ? pW + ((size_t)sel*16 + e)      * (size_t)DIMM*FDIM
                              : fW + ((size_t)sel*16 + (e-16)) * (size_t)DIMM*FDIM;
    unsigned* Wp = g_wguP + (size_t)z*512*512;
    int idx = blockIdx.x*256 + threadIdx.x;
    int kp = idx >> 7, nq = idx & 127;
    float4 a = *(const float4*)(W + (size_t)(2*kp)*FDIM + nq*4);
    float4 b = *(const float4*)(W + (size_t)(2*kp+1)*FDIM + nq*4);
    ((uint4*)Wp)[idx] = make_uint4(f2h2(a.x,b.x), f2h2(a.y,b.y), f2h2(a.z,b.z), f2h2(a.w,b.w));
}

__global__ void __launch_bounds__(256) conv_moe_down(const float* __restrict__ pW,
                                                     const float* __restrict__ fW) {
    int z = blockIdx.z;
    const float* W = (z < 16) ? pW + ((size_t)2*16 + z)      * (size_t)DIMM*FDIM
                              : fW + ((size_t)2*16 + (z-16)) * (size_t)DIMM*FDIM;
    __half* Wh = g_wdnM + (size_t)z*1024*512;
    int idx = blockIdx.x*256 + threadIdx.x;
    float4 a = ((const float4*)W)[idx];
    ((uint2*)Wh)[idx] = make_uint2(f2h2(a.x,a.y), f2h2(a.z,a.w));
}

// ---------------- dense fp16 GEMM, 3-stage cp.async: C = A @ B (+D) ----------------
#define GEMM_SMEM ((2560 + 2176) * 3 * 4)
template<int OUT>
__global__ void __launch_bounds__(256) gemm_h(const __half* __restrict__ A,
                                              const unsigned* __restrict__ Bp,
                                              void* __restrict__ Cv,
                                              const float* __restrict__ D,
                                              int M, int N, int K) {
    extern __shared__ __align__(16) unsigned smem[];
    unsigned* As = smem;             // 3 x 2560
    unsigned* Bs = smem + 3*2560;    // 3 x 2176
    int tid = threadIdx.x, lane = tid & 31, wid = tid >> 5;
    int g = lane >> 2, t4 = lane & 3;
    int wm = (wid & 3)*32, wn = (wid >> 2)*64;
    size_t rowBase = (size_t)blockIdx.y * 128, colBase = (size_t)blockIdx.x * 128;
    int a_r = tid >> 1, a_half = tid & 1;
    int a_sidx = a_r*20 + a_half*8;
    const __half* Ag = A + (rowBase + a_r)*K + a_half*16;
    int kp = tid >> 4, q = tid & 15;
    int bsidx = kp*136 + q*4;
    const unsigned* Bg = Bp + (size_t)kp*N + colBase + q*4;
    uint32_t aB = s2u(As), bB = s2u(Bs);
    int NC = K >> 5;

    auto issue = [&](int cc, int s) {
        uint32_t ad = aB + (s*2560 + a_sidx)*4;
        const __half* ag = Ag + cc*32;
        cpa16(ad, ag);
        cpa16(ad + 16, ag + 8);
        uint32_t bd = bB + (s*2176 + bsidx)*4;
        const unsigned* bg = Bg + (size_t)cc*16*N;
        cpa16(bd, bg);
        cpa16(bd + 256, bg + 64);
        CPA_COMMIT();
    };

    float acc[16][4];
    #pragma unroll
    for (int i = 0; i < 16; i++)
        #pragma unroll
        for (int j = 0; j < 4; j++) acc[i][j] = 0.f;

    issue(0, 0);
    issue(1, 1);
    for (int c = 0; c < NC; c++) {
        if (c + 2 < NC) CPA_WAIT1(); else CPA_WAIT0();
        __syncthreads();
        int s = c - (c/3)*3;
        compute_tile_nn(As + s*2560, Bs + s*2176, wm, wn, g, t4, acc);
        if (c + 2 < NC) issue(c + 2, (c+2) - ((c+2)/3)*3);
    }
    #pragma unroll
    for (int mi = 0; mi < 2; mi++)
        #pragma unroll
        for (int ni = 0; ni < 8; ni++) {
            float* c = acc[mi*8+ni];
            size_t r0 = rowBase + wm + mi*16 + g;
            size_t c0 = colBase + wn + ni*8 + 2*t4;
            if (OUT == 0) {
                float* C = (float*)Cv;
                size_t o0 = r0*N + c0, o1 = (r0+8)*N + c0;
                if (D) {
                    C[o0] = c[0] + D[o0]; C[o0+1] = c[1] + D[o0+1];
                    C[o1] = c[2] + D[o1]; C[o1+1] = c[3] + D[o1+1];
                } else {
                    C[o0] = c[0]; C[o0+1] = c[1];
                    C[o1] = c[2]; C[o1+1] = c[3];
                }
            } else {
                __half* C = (__half*)Cv;
                *(unsigned*)&C[r0*N + c0]     = f2h2(c[0], c[1]);
                *(unsigned*)&C[(r0+8)*N + c0] = f2h2(c[2], c[3]);
            }
        }
}

// ---------------- MoE gate+up grouped GEMM (3-stage cp.async, half out) ----------------
__global__ void __launch_bounds__(256) moe_gu_h() {
    extern __shared__ __align__(16) unsigned smem[];
    unsigned* As = smem;
    unsigned* Bs = smem + 3*2560;
    __shared__ int rows[128];
    int e = blockIdx.z;
    int cnt = g_counts[e];
    int rowTile = blockIdx.y * 128;
    if (rowTile >= cnt) return;
    int base = g_offsets[e];
    int colBase = blockIdx.x * 128;
    int sel = colBase >> 9;
    int wcol = colBase & 511;
    const unsigned* Wp = g_wguP + (size_t)(sel*32 + e)*512*512;
    __half* Out = sel ? g_uph : g_gateh;
    int tid = threadIdx.x;
    if (tid < 128) {
        int rr = rowTile + tid;
        rows[tid] = (rr < cnt) ? g_tokof[base + rr] : 0;   // row 0 as harmless filler
    }
    __syncthreads();
    int lane = tid & 31, wid = tid >> 5;
    int g = lane >> 2, t4 = lane & 3;
    int wm = (wid & 3)*32, wn = (wid >> 2)*64;
    int a_r = tid >> 1, a_half = tid & 1;
    int a_sidx = a_r*20 + a_half*8;
    const __half* Ag = g_xffnh + (size_t)rows[a_r]*DIMM + a_half*16;
    int kp = tid >> 4, q = tid & 15;
    int bsidx = kp*136 + q*4;
    const unsigned* Bg = Wp + (size_t)kp*512 + wcol + q*4;
    uint32_t aB = s2u(As), bB = s2u(Bs);

    auto issue = [&](int cc, int s) {
        uint32_t ad = aB + (s*2560 + a_sidx)*4;
        const __half* ag = Ag + cc*32;
        cpa16(ad, ag);
        cpa16(ad + 16, ag + 8);
        uint32_t bd = bB + (s*2176 + bsidx)*4;
        const unsigned* bg = Bg + (size_t)cc*16*512;
        cpa16(bd, bg);
        cpa16(bd + 256, bg + 64);
        CPA_COMMIT();
    };

    float acc[16][4];
    #pragma unroll
    for (int i = 0; i < 16; i++)
        #pragma unroll
        for (int j = 0; j < 4; j++) acc[i][j] = 0.f;

    issue(0, 0);
    issue(1, 1);
    for (int c = 0; c < 32; c++) {
        if (c + 2 < 32) CPA_WAIT1(); else CPA_WAIT0();
        __syncthreads();
        int s = c - (c/3)*3;
        compute_tile_nn(As + s*2560, Bs + s*2176, wm, wn, g, t4, acc);
        if (c + 2 < 32) issue(c + 2, (c+2) - ((c+2)/3)*3);
    }
    #pragma unroll
    for (int mi = 0; mi < 2; mi++)
        #pragma unroll
        for (int ni = 0; ni < 8; ni++) {
            float* c = acc[mi*8+ni];
            int r = rowTile + wm + mi*16 + g;
            int cc = wcol + wn + ni*8 + 2*t4;
            if (r < cnt)
                *(unsigned*)&Out[(size_t)(base+r)*FDIM + cc] = f2h2(c[0], c[1]);
            if (r + 8 < cnt)
                *(unsigned*)&Out[(size_t)(base+r+8)*FDIM + cc] = f2h2(c[2], c[3]);
        }
}

// ---------------- MoE down grouped GEMM (3-stage cp.async, half out) ----------------
#define MDN_SMEM ((2560 + 2560) * 3 * 4)
__global__ void __launch_bounds__(256) moe_down_h() {
    extern __shared__ __align__(16) unsigned smem[];
    unsigned* As = smem;
    unsigned* Bs = smem + 3*2560;
    int e = blockIdx.z;
    int cnt = g_counts[e];
    int rowTile = blockIdx.y * 128;
    if (rowTile >= cnt) return;
    int base = g_offsets[e];
    int colBase = blockIdx.x * 128;
    const __half* W = g_wdnM + (size_t)e*1024*512;
    int tid = threadIdx.x, lane = tid & 31, wid = tid >> 5;
    int g = lane >> 2, t4 = lane & 3;
    int wm = (wid & 3)*32, wn = (wid >> 2)*64;
    int r_ = tid >> 1, a_half = tid & 1;
    int sidx = r_*20 + a_half*8;
    int arow = base + rowTile + r_;
    if (arow > NASS - 1) arow = NASS - 1;
    const __half* Ag = g_Gh + (size_t)arow*FDIM + a_half*16;
    const __half* Bg = W + (size_t)(colBase + r_)*FDIM + a_half*16;
    uint32_t aB = s2u(As), bB = s2u(Bs);

    auto issue = [&](int cc, int s) {
        uint32_t ad = aB + (s*2560 + sidx)*4;
        const __half* ag = Ag + cc*32;
        cpa16(ad, ag);
        cpa16(ad + 16, ag + 8);
        uint32_t bd = bB + (s*2560 + sidx)*4;
        const __half* bg = Bg + cc*32;
        cpa16(bd, bg);
        cpa16(bd + 16, bg + 8);
        CPA_COMMIT();
    };

    float acc[16][4];
    #pragma unroll
    for (int i = 0; i < 16; i++)
        #pragma unroll
        for (int j = 0; j < 4; j++) acc[i][j] = 0.f;

    issue(0, 0);
    issue(1, 1);
    for (int c = 0; c < 16; c++) {
        if (c + 2 < 16) CPA_WAIT1(); else CPA_WAIT0();
        __syncthreads();
        int s = c - (c/3)*3;
        compute_tile_tt(As + s*2560, Bs + s*2560, wm, wn, g, t4, acc);
        if (c + 2 < 16) issue(c + 2, (c+2) - ((c+2)/3)*3);
    }
    #pragma unroll
    for (int mi = 0; mi < 2; mi++)
        #pragma unroll
        for (int ni = 0; ni < 8; ni++) {
            float* c = acc[mi*8+ni];
            int r = rowTile + wm + mi*16 + g;
            int cc = colBase + wn + ni*8 + 2*t4;
            if (r < cnt)
                *(unsigned*)&g_slotsh[(size_t)(base+r)*DIMM + cc] = f2h2(c[0], c[1]);
            if (r + 8 < cnt)
                *(unsigned*)&g_slotsh[(size_t)(base+r+8)*DIMM + cc] = f2h2(c[2], c[3]);
        }
}

// ---------------- rmsnorm (half out) ----------------
__global__ void rmsnorm_h(const float* __restrict__ x, const float* __restrict__ w,
                          __half* __restrict__ out) {
    int r = blockIdx.x;
    const float* xr = x + (size_t)r*DIMM;
    __shared__ float red[8];
    float s = 0.f;
    for (int d = threadIdx.x; d < DIMM; d += 256) { float v = xr[d]; s += v*v; }
    #pragma unroll
    for (int o = 16; o; o >>= 1) s += __shfl_xor_sync(0xffffffffu, s, o);
    if ((threadIdx.x & 31) == 0) red[threadIdx.x >> 5] = s;
    __syncthreads();
    if (threadIdx.x == 0) {
        float t = 0.f;
        #pragma unroll
        for (int i = 0; i < 8; i++) t += red[i];
        red[0] = rsqrtf(t / (float)DIMM + 1e-5f);
    }
    __syncthreads();
    float rms = red[0];
    for (int d = threadIdx.x; d < DIMM; d += 256)
        out[(size_t)r*DIMM + d] = __float2half(xr[d] * rms * w[d]);
}

// ---------------- rope + dual interleave ----------------
__global__ void rope_interleave_kernel() {
    int r = blockIdx.x, h = blockIdx.y, d = threadIdx.x;
    int bi = r >> 10, si = r & 1023;
    int t = 2*si + bi;
    size_t src = (size_t)r*3072 + h*64;
    float q = __half2float(g_qkvh[src + d]);
    float k = __half2float(g_qkvh[src + 1024 + d]);
    float v = __half2float(g_qkvh[src + 2048 + d]);
    ((__half*)g_vmP)[(((size_t)h*1024 + (t >> 1))*64 + d)*2 + (t & 1)] = __float2half(v);
    __shared__ float qs[64], ks[64];
    qs[d] = q; ks[d] = k;
    __syncthreads();
    if (d < 32) {
        float inv = powf(10000.0f, -(float)(2*d) / 64.0f);
        float fr = (float)si * inv;
        float sn, cs;
        sincosf(fr, &sn, &cs);
        size_t dst = ((size_t)h*SEQ + t)*64;
        float x1 = qs[d], x2 = qs[d+32];
        g_qmh[dst + d]      = __float2half( x1*cs + x2*sn);
        g_qmh[dst + d + 32] = __float2half(-x1*sn + x2*cs);
        x1 = ks[d]; x2 = ks[d+32];
        g_kmh[dst + d]      = __float2half( x1*cs + x2*sn);
        g_kmh[dst + d + 32] = __float2half(-x1*sn + x2*cs);
    }
}

// ---------------- fp16 flash attention: 128 queries x 256 threads ----------------
#define ATT_SMEM_W (4608 + 2304 + 4608 + 2304)
__global__ void __launch_bounds__(256) attn_h() {
    extern __shared__ __align__(16) unsigned asm_[];
    unsigned* Qs = asm_;
    unsigned* Ks = asm_ + 4608;
    unsigned* Ps = asm_ + 6912;
    unsigned* Vt = asm_ + 11520;
    int h = blockIdx.y;
    int t0 = ((int)gridDim.x - 1 - (int)blockIdx.x) * 128;
    int tid = threadIdx.x, lane = tid & 31, wid = tid >> 5;
    int g = lane >> 2, t4 = lane & 3;
    int wm = wid * 16;

    const __half* qb = g_qmh + ((size_t)h*SEQ + t0)*64;
    for (int i = tid; i < 128*8; i += 256) {
        int r = i >> 3, j = i & 7;
        *(uint4*)&Qs[r*36 + j*4] = ((const uint4*)(qb + (size_t)r*64))[j];
    }

    float o[8][4];
    #pragma unroll
    for (int n = 0; n < 8; n++)
        #pragma unroll
        for (int j = 0; j < 4; j++) o[n][j] = 0.f;
    float m0 = -1e30f, m1 = -1e30f, l0 = 0.f, l1 = 0.f;
    int row0 = t0 + wm + g, row1 = row0 + 8;
    int wmax = t0 + wm + 15;

    for (int kt = 0; kt <= t0 + 127; kt += 64) {
        __syncthreads();
        const __half* kb = g_kmh + ((size_t)h*SEQ + kt)*64;
        for (int i = tid; i < 64*8; i += 256) {
            int r = i >> 3, j = i & 7;
            *(uint4*)&Ks[r*36 + j*4] = ((const uint4*)(kb + (size_t)r*64))[j];
        }
        const unsigned* vp = g_vmP + ((size_t)h*1024 + (kt >> 1))*64;
        for (int w = tid; w < 64*32; w += 256) {
            int d = w & 63, p = w >> 6;
            Vt[d*36 + p] = vp[(size_t)p*64 + d];
        }
        __syncthreads();
        if (kt > wmax) continue;

        float s[8][4];
        #pragma unroll
        for (int n = 0; n < 8; n++)
            #pragma unroll
            for (int j = 0; j < 4; j++) s[n][j] = 0.f;
        #pragma unroll
        for (int ks = 0; ks < 4; ks++) {
            int kc = ks*8 + t4;
            unsigned af[4];
            af[0] = Qs[(wm+g)*36 + kc];
            af[1] = Qs[(wm+g+8)*36 + kc];
            af[2] = Qs[(wm+g)*36 + kc + 4];
            af[3] = Qs[(wm+g+8)*36 + kc + 4];
            #pragma unroll
            for (int n = 0; n < 8; n++) {
                unsigned bf[2];
                bf[0] = Ks[(n*8+g)*36 + kc];
                bf[1] = Ks[(n*8+g)*36 + kc + 4];
                mma16(s[n], af, bf);
            }
        }
        float mx0 = -1e30f, mx1 = -1e30f;
        #pragma unroll
        for (int n = 0; n < 8; n++) {
            int c0 = kt + n*8 + 2*t4, c1 = c0 + 1;
            s[n][0] = (c0 <= row0) ? s[n][0]*0.125f : -1e30f;
            s[n][1] = (c1 <= row0) ? s[n][1]*0.125f : -1e30f;
            s[n][2] = (c0 <= row1) ? s[n][2]*0.125f : -1e30f;
            s[n][3] = (c1 <= row1) ? s[n][3]*0.125f : -1e30f;
            mx0 = fmaxf(mx0, fmaxf(s[n][0], s[n][1]));
            mx1 = fmaxf(mx1, fmaxf(s[n][2], s[n][3]));
        }
        mx0 = fmaxf(mx0, __shfl_xor_sync(0xffffffffu, mx0, 1));
        mx0 = fmaxf(mx0, __shfl_xor_sync(0xffffffffu, mx0, 2));
        mx1 = fmaxf(mx1, __shfl_xor_sync(0xffffffffu, mx1, 1));
        mx1 = fmaxf(mx1, __shfl_xor_sync(0xffffffffu, mx1, 2));
        float nm0 = fmaxf(m0, mx0), nm1 = fmaxf(m1, mx1);
        float cor0 = __expf(m0 - nm0), cor1 = __expf(m1 - nm1);
        m0 = nm0; m1 = nm1;
        l0 *= cor0; l1 *= cor1;
        float sum0 = 0.f, sum1 = 0.f;
        #pragma unroll
        for (int n = 0; n < 8; n++) {
            float p00 = __expf(s[n][0] - nm0), p01 = __expf(s[n][1] - nm0);
            float p10 = __expf(s[n][2] - nm1), p11 = __expf(s[n][3] - nm1);
            sum0 += p00 + p01; sum1 += p10 + p11;
            Ps[(wm+g)*36 + n*4 + t4]   = f2h2(p00, p01);
            Ps[(wm+g+8)*36 + n*4 + t4] = f2h2(p10, p11);
            #pragma unroll
            for (int j = 0; j < 2; j++) { o[n][j] *= cor0; o[n][2+j] *= cor1; }
        }
        sum0 += __shfl_xor_sync(0xffffffffu, sum0, 1);
        sum0 += __shfl_xor_sync(0xffffffffu, sum0, 2);
        sum1 += __shfl_xor_sync(0xffffffffu, sum1, 1);
        sum1 += __shfl_xor_sync(0xffffffffu, sum1, 2);
        l0 += sum0; l1 += sum1;
        __syncwarp();

        #pragma unroll
        for (int ks = 0; ks < 4; ks++) {
            int kc = ks*8 + t4;
            unsigned af[4];
            af[0] = Ps[(wm+g)*36 + kc];
            af[1] = Ps[(wm+g+8)*36 + kc];
            af[2] = Ps[(wm+g)*36 + kc + 4];
            af[3] = Ps[(wm+g+8)*36 + kc + 4];
            #pragma unroll
            for (int n = 0; n < 8; n++) {
                unsigned bf[2];
                bf[0] = Vt[(n*8+g)*36 + kc];
                bf[1] = Vt[(n*8+g)*36 + kc + 4];
                mma16(o[n], af, bf);
            }
        }
    }

    float inv0 = 1.f / l0, inv1 = 1.f / l1;
    int tok0 = (row0 & 1)*1024 + (row0 >> 1);
    int tok1 = (row1 & 1)*1024 + (row1 >> 1);
    #pragma unroll
    for (int n = 0; n < 8; n++) {
        int col = h*64 + n*8 + 2*t4;
        *(unsigned*)&g_orowsh[(size_t)tok0*DIMM + col] = f2h2(o[n][0]*inv0, o[n][1]*inv0);
        *(unsigned*)&g_orowsh[(size_t)tok1*DIMM + col] = f2h2(o[n][2]*inv1, o[n][3]*inv1);
    }
}

// ---------------- router ----------------
__global__ void router_kernel(const float* __restrict__ pkeys, const float* __restrict__ fkeys,
                              const float* __restrict__ pbias, const float* __restrict__ fbias,
                              const int* __restrict__ pidx, const float* __restrict__ pval,
                              const int* __restrict__ fidx, const float* __restrict__ fval) {
    int tok = blockIdx.x, tid = threadIdx.x;
    bool isf = tok >= 1024;
    const float* keys = isf ? fkeys : pkeys;
    const __half* x = g_xffnh + (size_t)tok*DIMM;
    __shared__ float part[8][16];
    __shared__ float logit[16];
    int e = tid & 15, ch = tid >> 4;
    float s = 0.f;
    int d0 = ch * 128;
    for (int d = d0; d < d0 + 128; d++)
        s = fmaf(__half2float(x[d]), keys[d*16 + e], s);
    part[ch][e] = s;
    __syncthreads();
    if (tid < 16) {
        float t = 0.f;
        #pragma unroll
        for (int c = 0; c < 8; c++) t += part[c][tid];
        logit[tid] = t;
    }
    __syncthreads();
    if (tid == 0) {
        int lt = isf ? tok - 1024 : tok;
        const int*   idx  = isf ? fidx  : pidx;
        const float* val  = isf ? fval  : pval;
        const float* bias = isf ? fbias : pbias;
        float sc[4]; int id[4]; float sum = 0.f;
        #pragma unroll
        for (int k = 0; k < 4; k++) {
            int ix = idx[lt*4 + k];
            float v = val[lt*4 + k] + logit[ix] + bias[ix];
            float s2 = 1.f / (1.f + expf(-v));
            sc[k] = s2; sum += s2;
            id[k] = ix + (isf ? 16 : 0);
        }
        #pragma unroll
        for (int k = 0; k < 4; k++) {
            g_scales[tok*4 + k] = sc[k] / sum;
            g_eid[tok*4 + k] = id[k];
            atomicAdd(&g_counts[id[k]], 1);
        }
    }
}

__global__ void zero32_kernel() {
    int i = threadIdx.x;
    if (i < NEXP) { g_counts[i] = 0; g_cursors[i] = 0; }
}

__global__ void prefix_kernel() {
    int acc = 0;
    for (int e = 0; e < NEXP; e++) { g_offsets[e] = acc; acc += g_counts[e]; }
}

__global__ void scatter_kernel() {
    int a = blockIdx.x * blockDim.x + threadIdx.x;
    if (a >= NASS) return;
    int e = g_eid[a];
    int p = g_offsets[e] + atomicAdd(&g_cursors[e], 1);
    g_tokof[p] = a >> 2;
    g_posof[a] = p;
}

__global__ void swiglu_moe_kernel() {
    int i = blockIdx.x*256 + threadIdx.x;    // over NASS*FDIM/2
    __half2 g2 = ((const __half2*)g_gateh)[i];
    __half2 u2 = ((const __half2*)g_uph)[i];
    float2 gf = __half22float2(g2), uf = __half22float2(u2);
    float a = gf.x / (1.f + __expf(-gf.x)) * uf.x;
    float b = gf.y / (1.f + __expf(-gf.y)) * uf.y;
    ((__half2*)g_Gh)[i] = __floats2half2_rn(a, b);
}

__global__ void combine_kernel(float* __restrict__ y) {
    int tok = blockIdx.x;
    __shared__ int pos[4];
    __shared__ float sc[4];
    if (threadIdx.x < 4) {
        pos[threadIdx.x] = g_posof[tok*4 + threadIdx.x];
        sc[threadIdx.x]  = g_scales[tok*4 + threadIdx.x];
    }
    __syncthreads();
    for (int d = threadIdx.x; d < DIMM; d += 256) {
        float v = g_xffni[(size_t)tok*DIMM + d];
        #pragma unroll
        for (int k = 0; k < 4; k++)
            v = fmaf(sc[k], __half2float(g_slotsh[(size_t)pos[k]*DIMM + d]), v);
        y[(size_t)tok*DIMM + d] = v;
    }
}

__global__ void swiglu_shared_kernel() {
    int t = blockIdx.x;
    for (int j = threadIdx.x; j < DSH; j += 256) {
        float a = __half2float(g_suh[(size_t)t*2*DSH + j]);
        float b = __half2float(g_suh[(size_t)t*2*DSH + DSH + j]);
        g_hsh[(size_t)t*DSH + j] = __float2half((a / (1.f + __expf(-a))) * b);
    }
}

// ---------------- launch ----------------
extern "C" void kernel_launch(void* const* d_in, const int* in_sizes, int n_in,
                              void* d_out, int out_size) {
    const float* x_input  = (const float*)d_in[0];
    const int*   p_idx    = (const int*)  d_in[1];
    const float* p_val    = (const float*)d_in[2];
    const int*   f_idx    = (const int*)  d_in[3];
    const float* f_val    = (const float*)d_in[4];
    const float* attn_nw  = (const float*)d_in[5];
    const float* ffn_nw   = (const float*)d_in[6];
    const float* W_attn   = (const float*)d_in[7];
    const float* W_attn_o = (const float*)d_in[8];
    const float* ffn_up   = (const float*)d_in[9];
    const float* ffn_down = (const float*)d_in[10];
    const float* pW       = (const float*)d_in[11];
    const float* fW       = (const float*)d_in[12];
    const float* pkeys    = (const float*)d_in[13];
    const float* fkeys    = (const float*)d_in[14];
    const float* pbias    = (const float*)d_in[15];
    const float* fbias    = (const float*)d_in[16];
    float* out = (float*)d_out;

    __half *xnormh, *qkvh, *orowsh, *xffnh, *suh, *hsh;
    float *xffni;
    unsigned *wqkvP, *woP, *wupP, *wdnP;
    cudaGetSymbolAddress((void**)&xnormh, g_xnormh);
    cudaGetSymbolAddress((void**)&qkvh,   g_qkvh);
    cudaGetSymbolAddress((void**)&orowsh, g_orowsh);
    cudaGetSymbolAddress((void**)&xffni,  g_xffni);
    cudaGetSymbolAddress((void**)&xffnh,  g_xffnh);
    cudaGetSymbolAddress((void**)&suh,    g_suh);
    cudaGetSymbolAddress((void**)&hsh,    g_hsh);
    cudaGetSymbolAddress((void**)&wqkvP,  g_wqkvP);
    cudaGetSymbolAddress((void**)&woP,    g_woP);
    cudaGetSymbolAddress((void**)&wupP,   g_wupP);
    cudaGetSymbolAddress((void**)&wdnP,   g_wdnP);

    static bool attr_set = false;
    if (!attr_set) {
        cudaFuncSetAttribute(attn_h, cudaFuncAttributeMaxDynamicSharedMemorySize,
                             ATT_SMEM_W * 4);
        cudaFuncSetAttribute(gemm_h<0>, cudaFuncAttributeMaxDynamicSharedMemorySize,
                             GEMM_SMEM);
        cudaFuncSetAttribute(gemm_h<1>, cudaFuncAttributeMaxDynamicSharedMemorySize,
                             GEMM_SMEM);
        cudaFuncSetAttribute(moe_gu_h, cudaFuncAttributeMaxDynamicSharedMemorySize,
                             GEMM_SMEM);
        cudaFuncSetAttribute(moe_down_h, cudaFuncAttributeMaxDynamicSharedMemorySize,
                             MDN_SMEM);
        attr_set = true;
    }

    // weight packing (fp16)
    pack_nn<<<1536, 256>>>(W_attn,   wqkvP, 768);
    pack_nn<<<512,  256>>>(W_attn_o, woP,   256);
    pack_nn<<<2048, 256>>>(ffn_up,   wupP, 1024);
    pack_nn<<<1024, 256>>>(ffn_down, wdnP,  256);
    pack_moe_gu<<<dim3(256, 1, 64), 256>>>(pW, fW);
    conv_moe_down<<<dim3(512, 1, 32), 256>>>(pW, fW);

    // attention block
    rmsnorm_h<<<TOK, 256>>>(x_input, attn_nw, xnormh);
    gemm_h<1><<<dim3(24, 16), 256, GEMM_SMEM>>>(xnormh, wqkvP, qkvh, nullptr, TOK, 3*DIMM, DIMM);
    rope_interleave_kernel<<<dim3(TOK, NH), 64>>>();
    attn_h<<<dim3(SEQ/128, NH), 256, ATT_SMEM_W*4>>>();
    gemm_h<0><<<dim3(8, 16), 256, GEMM_SMEM>>>(orowsh, woP, xffni, x_input, TOK, DIMM, DIMM);
    rmsnorm_h<<<TOK, 256>>>(xffni, ffn_nw, xffnh);

    // routing
    zero32_kernel<<<1, 32>>>();
    router_kernel<<<TOK, 128>>>(pkeys, fkeys, pbias, fbias, p_idx, p_val, f_idx, f_val);
    prefix_kernel<<<1, 1>>>();
    scatter_kernel<<<32, 256>>>();

    // grouped MoE
    moe_gu_h<<<dim3(8, 16, NEXP), 256, GEMM_SMEM>>>();
    swiglu_moe_kernel<<<(NASS*FDIM/2)/256, 256>>>();
    moe_down_h<<<dim3(8, 16, NEXP), 256, MDN_SMEM>>>();
    combine_kernel<<<TOK, 256>>>(out);

    // shared expert (adds into out)
    gemm_h<1><<<dim3(32, 16), 256, GEMM_SMEM>>>(xffnh, wupP, suh, nullptr, TOK, 2*DSH, DIMM);
    swiglu_shared_kernel<<<TOK, 256>>>();
    gemm_h<0><<<dim3(8, 16), 256, GEMM_SMEM>>>(hsh, wdnP, out, out, TOK, DIMM, DSH);
}

// round 11
// speedup vs baseline: 6.3876x; 1.0036x over previous
#include <cuda_runtime.h>
#include <cuda_fp16.h>
#include <math.h>
#include <stdint.h>

// ---------------- problem constants ----------------
#define TOK   2048
#define DIMM  1024
#define NH    16
#define HD    64
#define SEQ   2048
#define NASS  8192
#define NEXP  32
#define FDIM  512
#define DSH   2048

// ---------------- scratch ----------------
__device__ __align__(16) __half g_xnormh[TOK*DIMM];
__device__ __align__(16) __half g_qkvh[TOK*3*DIMM];
__device__ __align__(16) __half g_qmh[NH*SEQ*HD];
__device__ __align__(16) __half g_kmh[NH*SEQ*HD];
__device__ __align__(16) unsigned g_vmP[NH*(SEQ/2)*HD];
__device__ __align__(16) __half g_orowsh[TOK*DIMM];
__device__ float g_xffni[TOK*DIMM];
__device__ __align__(16) __half g_xffnh[TOK*DIMM];
__device__ __align__(16) __half g_gateh[NASS*FDIM];
__device__ __align__(16) __half g_uph[NASS*FDIM];
__device__ __align__(16) __half g_Gh[NASS*FDIM];
__device__ __align__(16) __half g_slotsh[(size_t)NASS*DIMM];
__device__ __align__(16) __half g_suh[(size_t)TOK*2*DSH];
__device__ __align__(16) __half g_hsh[(size_t)TOK*DSH];
__device__ float g_scales[NASS];
__device__ int   g_eid[NASS];
__device__ int   g_tokof[NASS];
__device__ int   g_posof[NASS];
__device__ int   g_counts[NEXP];
__device__ int   g_offsets[NEXP];
__device__ int   g_cursors[NEXP];
// K-major packed fp16 weights: Wt[N][K]
__device__ __align__(16) __half g_wqkvT[3072*1024];
__device__ __align__(16) __half g_woT[1024*1024];
__device__ __align__(16) __half g_wupT[(size_t)4096*1024];
__device__ __align__(16) __half g_wdnT[(size_t)1024*2048];
__device__ __align__(16) __half g_wguT[(size_t)64*512*1024];
__device__ __align__(16) __half g_wdnM[(size_t)32*1024*512];

// ---------------- helpers ----------------
__device__ __forceinline__ unsigned f2h2(float a, float b) {
    __half2 h = __floats2half2_rn(a, b);
    return *reinterpret_cast<unsigned*>(&h);
}
__device__ __forceinline__ void mma16(float c[4], const unsigned a[4], const unsigned b[2]) {
    asm volatile("mma.sync.aligned.m16n8k16.row.col.f32.f16.f16.f32 "
                 "{%0,%1,%2,%3},{%4,%5,%6,%7},{%8,%9},{%0,%1,%2,%3};"
                 : "+f"(c[0]), "+f"(c[1]), "+f"(c[2]), "+f"(c[3])
                 : "r"(a[0]), "r"(a[1]), "r"(a[2]), "r"(a[3]), "r"(b[0]), "r"(b[1]));
}
__device__ __forceinline__ uint32_t s2u(const void* p) {
    uint32_t a;
    asm("{ .reg .u64 t; cvta.to.shared.u64 t, %1; cvt.u32.u64 %0, t; }" : "=r"(a) : "l"(p));
    return a;
}
__device__ __forceinline__ void cpa16(uint32_t dst, const void* src) {
    asm volatile("cp.async.ca.shared.global [%0], [%1], 16;" :: "r"(dst), "l"(src));
}
#define CPA_COMMIT() asm volatile("cp.async.commit_group;")
#define CPA_WAIT1()  asm volatile("cp.async.wait_group 1;")
#define CPA_WAIT0()  asm volatile("cp.async.wait_group 0;")

__device__ __forceinline__ void ldsm4(unsigned* r, uint32_t a) {
    asm volatile("ldmatrix.sync.aligned.m8n8.x4.shared.b16 {%0,%1,%2,%3}, [%4];"
                 : "=r"(r[0]), "=r"(r[1]), "=r"(r[2]), "=r"(r[3]) : "r"(a));
}
// byte offset for this lane's ldmatrix.x4 row address; tile rows stride `stride` words
__device__ __forceinline__ uint32_t frag_off(int rowBase, int stride, int lane) {
    int lr = lane & 7, lh = (lane >> 3) & 1, lq = lane >> 4;
    return (uint32_t)(((rowBase + lr + lh*8) * stride + lq*4) * 4);
}

// Both tiles [row][kpair] stride 20 words. A rows wm..wm+31, B rows wn..wn+63.
// aOff0/aOff1: frag_off(wm,20)/frag_off(wm+16,20); bOff[p]: frag_off(wn+p*16,20).
__device__ __forceinline__ void compute_tile_ldsm(uint32_t aS, uint32_t bS,
                                                  uint32_t aOff0, uint32_t aOff1,
                                                  const uint32_t* bOff,
                                                  float acc[16][4]) {
    #pragma unroll
    for (int ks = 0; ks < 2; ks++) {
        unsigned a0[4], a1[4], bq[4][4];
        ldsm4(a0, aS + aOff0 + ks*32);
        ldsm4(a1, aS + aOff1 + ks*32);
        #pragma unroll
        for (int p = 0; p < 4; p++) ldsm4(bq[p], bS + bOff[p] + ks*32);
        #pragma unroll
        for (int ni = 0; ni < 8; ni++) {
            unsigned bf[2] = { bq[ni>>1][ni&1], bq[ni>>1][(ni&1)+2] };
            mma16(acc[ni],   a0, bf);
            mma16(acc[8+ni], a1, bf);
        }
    }
}

// ---------------- transpose-pack: W [K][N] fp32 -> Wt [N][K] half ----------------
__device__ __forceinline__ void packT_body(const float* __restrict__ W,
                                           __half* __restrict__ Wt,
                                           int K, int N, int k0, int n0, int tid) {
    __shared__ __half tile[32][72];
    int nl = tid & 31, kl = tid >> 5;
    #pragma unroll
    for (int it = 0; it < 8; it++)
        tile[nl][kl + it*8] = __float2half(W[(size_t)(k0 + kl + it*8)*N + n0 + nl]);
    __syncthreads();
    int kq = (tid & 15)*4, nr = tid >> 4;
    #pragma unroll
    for (int it = 0; it < 2; it++) {
        int n = nr + it*16;
        *(uint2*)&Wt[(size_t)(n0 + n)*K + k0 + kq] = *(uint2*)&tile[n][kq];
    }
}
__global__ void __launch_bounds__(256) packT(const float* __restrict__ W,
                                             __half* __restrict__ Wt, int K, int N) {
    packT_body(W, Wt, K, N, blockIdx.x*64, blockIdx.y*32, threadIdx.x);
}
__global__ void __launch_bounds__(256) packT_moe(const float* __restrict__ pW,
                                                 const float* __restrict__ fW) {
    int z = blockIdx.z;
    int sel = z >> 5, e = z & 31;
    const float* W = (e < 16) ? pW + ((size_t)sel*16 + e)      * (size_t)DIMM*FDIM
                              : fW + ((size_t)sel*16 + (e-16)) * (size_t)DIMM*FDIM;
    __half* Wt = g_wguT + (size_t)z*512*1024;
    packT_body(W, Wt, DIMM, FDIM, blockIdx.x*64, blockIdx.y*32, threadIdx.x);
}
__global__ void __launch_bounds__(256) conv_moe_down(const float* __restrict__ pW,
                                                     const float* __restrict__ fW) {
    int z = blockIdx.z;
    const float* W = (z < 16) ? pW + ((size_t)2*16 + z)      * (size_t)DIMM*FDIM
                              : fW + ((size_t)2*16 + (z-16)) * (size_t)DIMM*FDIM;
    __half* Wh = g_wdnM + (size_t)z*1024*512;
    int idx = blockIdx.x*256 + threadIdx.x;
    float4 a = ((const float4*)W)[idx];
    ((uint2*)Wh)[idx] = make_uint2(f2h2(a.x,a.y), f2h2(a.z,a.w));
}

// ---------------- dense fp16 GEMM, 3-stage cp.async + ldmatrix ----------------
#define GEMM_SMEM (2560 * 2 * 3 * 4)
template<int OUT>
__global__ void __launch_bounds__(256) gemm_h(const __half* __restrict__ A,
                                              const __half* __restrict__ Bt,
                                              void* __restrict__ Cv,
                                              const float* __restrict__ D,
                                              int M, int N, int K) {
    extern __shared__ __align__(16) unsigned smem[];
    unsigned* As = smem;
    unsigned* Bs = smem + 3*2560;
    int tid = threadIdx.x, lane = tid & 31, wid = tid >> 5;
    int g = lane >> 2, t4 = lane & 3;
    int wm = (wid & 3)*32, wn = (wid >> 2)*64;
    size_t rowBase = (size_t)blockIdx.y * 128, colBase = (size_t)blockIdx.x * 128;
    int r_ = tid >> 1, sel = tid & 1;
    int sidx = r_*20 + sel*8;
    const __half* Ag = A  + (rowBase + r_)*K + sel*16;
    const __half* Bg = Bt + (colBase + r_)*K + sel*16;
    uint32_t aB = s2u(As), bB = s2u(Bs);
    uint32_t aOff0 = frag_off(wm, 20, lane), aOff1 = frag_off(wm+16, 20, lane);
    uint32_t bOff[4];
    #pragma unroll
    for (int p = 0; p < 4; p++) bOff[p] = frag_off(wn + p*16, 20, lane);
    int NC = K >> 5;

    auto issue = [&](int cc, int s) {
        uint32_t ad = aB + (s*2560 + sidx)*4;
        cpa16(ad,      Ag + cc*32);
        cpa16(ad + 16, Ag + cc*32 + 8);
        uint32_t bd = bB + (s*2560 + sidx)*4;
        cpa16(bd,      Bg + cc*32);
        cpa16(bd + 16, Bg + cc*32 + 8);
        CPA_COMMIT();
    };

    float acc[16][4];
    #pragma unroll
    for (int i = 0; i < 16; i++)
        #pragma unroll
        for (int j = 0; j < 4; j++) acc[i][j] = 0.f;

    issue(0, 0);
    issue(1, 1);
    for (int c = 0; c < NC; c++) {
        if (c + 2 < NC) CPA_WAIT1(); else CPA_WAIT0();
        __syncthreads();
        int s = c - (c/3)*3;
        compute_tile_ldsm(aB + s*2560*4, bB + s*2560*4, aOff0, aOff1, bOff, acc);
        if (c + 2 < NC) issue(c + 2, (c+2) - ((c+2)/3)*3);
        __syncthreads();
    }
    #pragma unroll
    for (int mi = 0; mi < 2; mi++)
        #pragma unroll
        for (int ni = 0; ni < 8; ni++) {
            float* c = acc[mi*8+ni];
            size_t r0 = rowBase + wm + mi*16 + g;
            size_t c0 = colBase + wn + ni*8 + 2*t4;
            if (OUT == 0) {
                float* C = (float*)Cv;
                size_t o0 = r0*N + c0, o1 = (r0+8)*N + c0;
                if (D) {
                    C[o0] = c[0] + D[o0]; C[o0+1] = c[1] + D[o0+1];
                    C[o1] = c[2] + D[o1]; C[o1+1] = c[3] + D[o1+1];
                } else {
                    C[o0] = c[0]; C[o0+1] = c[1];
                    C[o1] = c[2]; C[o1+1] = c[3];
                }
            } else {
                __half* C = (__half*)Cv;
                *(unsigned*)&C[r0*N + c0]     = f2h2(c[0], c[1]);
                *(unsigned*)&C[(r0+8)*N + c0] = f2h2(c[2], c[3]);
            }
        }
}

// ---------------- MoE gate+up grouped GEMM ----------------
__global__ void __launch_bounds__(256) moe_gu_h() {
    extern __shared__ __align__(16) unsigned smem[];
    unsigned* As = smem;
    unsigned* Bs = smem + 3*2560;
    __shared__ int rows[128];
    int e = blockIdx.z;
    int cnt = g_counts[e];
    int rowTile = blockIdx.y * 128;
    if (rowTile >= cnt) return;
    int base = g_offsets[e];
    int colBase = blockIdx.x * 128;
    int selGU = colBase >> 9;
    int wcol = colBase & 511;
    const __half* Wt = g_wguT + (size_t)(selGU*32 + e)*512*1024;
    __half* Out = selGU ? g_uph : g_gateh;
    int tid = threadIdx.x;
    if (tid < 128) {
        int rr = rowTile + tid;
        rows[tid] = (rr < cnt) ? g_tokof[base + rr] : 0;
    }
    __syncthreads();
    int lane = tid & 31, wid = tid >> 5;
    int g = lane >> 2, t4 = lane & 3;
    int wm = (wid & 3)*32, wn = (wid >> 2)*64;
    int r_ = tid >> 1, sel = tid & 1;
    int sidx = r_*20 + sel*8;
    const __half* Ag = g_xffnh + (size_t)rows[r_]*DIMM + sel*16;
    const __half* Bg = Wt + (size_t)(wcol + r_)*1024 + sel*16;
    uint32_t aB = s2u(As), bB = s2u(Bs);
    uint32_t aOff0 = frag_off(wm, 20, lane), aOff1 = frag_off(wm+16, 20, lane);
    uint32_t bOff[4];
    #pragma unroll
    for (int p = 0; p < 4; p++) bOff[p] = frag_off(wn + p*16, 20, lane);

    auto issue = [&](int cc, int s) {
        uint32_t ad = aB + (s*2560 + sidx)*4;
        cpa16(ad,      Ag + cc*32);
        cpa16(ad + 16, Ag + cc*32 + 8);
        uint32_t bd = bB + (s*2560 + sidx)*4;
        cpa16(bd,      Bg + cc*32);
        cpa16(bd + 16, Bg + cc*32 + 8);
        CPA_COMMIT();
    };

    float acc[16][4];
    #pragma unroll
    for (int i = 0; i < 16; i++)
        #pragma unroll
        for (int j = 0; j < 4; j++) acc[i][j] = 0.f;

    issue(0, 0);
    issue(1, 1);
    for (int c = 0; c < 32; c++) {
        if (c + 2 < 32) CPA_WAIT1(); else CPA_WAIT0();
        __syncthreads();
        int s = c - (c/3)*3;
        compute_tile_ldsm(aB + s*2560*4, bB + s*2560*4, aOff0, aOff1, bOff, acc);
        if (c + 2 < 32) issue(c + 2, (c+2) - ((c+2)/3)*3);
        __syncthreads();
    }
    #pragma unroll
    for (int mi = 0; mi < 2; mi++)
        #pragma unroll
        for (int ni = 0; ni < 8; ni++) {
            float* c = acc[mi*8+ni];
            int r = rowTile + wm + mi*16 + g;
            int cc = wcol + wn + ni*8 + 2*t4;
            if (r < cnt)
                *(unsigned*)&Out[(size_t)(base+r)*FDIM + cc] = f2h2(c[0], c[1]);
            if (r + 8 < cnt)
                *(unsigned*)&Out[(size_t)(base+r+8)*FDIM + cc] = f2h2(c[2], c[3]);
        }
}

// ---------------- MoE down grouped GEMM ----------------
__global__ void __launch_bounds__(256) moe_down_h() {
    extern __shared__ __align__(16) unsigned smem[];
    unsigned* As = smem;
    unsigned* Bs = smem + 3*2560;
    int e = blockIdx.z;
    int cnt = g_counts[e];
    int rowTile = blockIdx.y * 128;
    if (rowTile >= cnt) return;
    int base = g_offsets[e];
    int colBase = blockIdx.x * 128;
    const __half* W = g_wdnM + (size_t)e*1024*512;
    int tid = threadIdx.x, lane = tid & 31, wid = tid >> 5;
    int g = lane >> 2, t4 = lane & 3;
    int wm = (wid & 3)*32, wn = (wid >> 2)*64;
    int r_ = tid >> 1, sel = tid & 1;
    int sidx = r_*20 + sel*8;
    int arow = base + rowTile + r_;
    if (arow > NASS - 1) arow = NASS - 1;
    const __half* Ag = g_Gh + (size_t)arow*FDIM + sel*16;
    const __half* Bg = W + (size_t)(colBase + r_)*FDIM + sel*16;
    uint32_t aB = s2u(As), bB = s2u(Bs);
    uint32_t aOff0 = frag_off(wm, 20, lane), aOff1 = frag_off(wm+16, 20, lane);
    uint32_t bOff[4];
    #pragma unroll
    for (int p = 0; p < 4; p++) bOff[p] = frag_off(wn + p*16, 20, lane);

    auto issue = [&](int cc, int s) {
        uint32_t ad = aB + (s*2560 + sidx)*4;
        cpa16(ad,      Ag + cc*32);
        cpa16(ad + 16, Ag + cc*32 + 8);
        uint32_t bd = bB + (s*2560 + sidx)*4;
        cpa16(bd,      Bg + cc*32);
        cpa16(bd + 16, Bg + cc*32 + 8);
        CPA_COMMIT();
    };

    float acc[16][4];
    #pragma unroll
    for (int i = 0; i < 16; i++)
        #pragma unroll
        for (int j = 0; j < 4; j++) acc[i][j] = 0.f;

    issue(0, 0);
    issue(1, 1);
    for (int c = 0; c < 16; c++) {
        if (c + 2 < 16) CPA_WAIT1(); else CPA_WAIT0();
        __syncthreads();
        int s = c - (c/3)*3;
        compute_tile_ldsm(aB + s*2560*4, bB + s*2560*4, aOff0, aOff1, bOff, acc);
        if (c + 2 < 16) issue(c + 2, (c+2) - ((c+2)/3)*3);
        __syncthreads();
    }
    #pragma unroll
    for (int mi = 0; mi < 2; mi++)
        #pragma unroll
        for (int ni = 0; ni < 8; ni++) {
            float* c = acc[mi*8+ni];
            int r = rowTile + wm + mi*16 + g;
            int cc = colBase + wn + ni*8 + 2*t4;
            if (r < cnt)
                *(unsigned*)&g_slotsh[(size_t)(base+r)*DIMM + cc] = f2h2(c[0], c[1]);
            if (r + 8 < cnt)
                *(unsigned*)&g_slotsh[(size_t)(base+r+8)*DIMM + cc] = f2h2(c[2], c[3]);
        }
}

// ---------------- rmsnorm (half out) ----------------
__global__ void rmsnorm_h(const float* __restrict__ x, const float* __restrict__ w,
                          __half* __restrict__ out) {
    int r = blockIdx.x;
    const float* xr = x + (size_t)r*DIMM;
    __shared__ float red[8];
    float s = 0.f;
    for (int d = threadIdx.x; d < DIMM; d += 256) { float v = xr[d]; s += v*v; }
    #pragma unroll
    for (int o = 16; o; o >>= 1) s += __shfl_xor_sync(0xffffffffu, s, o);
    if ((threadIdx.x & 31) == 0) red[threadIdx.x >> 5] = s;
    __syncthreads();
    if (threadIdx.x == 0) {
        float t = 0.f;
        #pragma unroll
        for (int i = 0; i < 8; i++) t += red[i];
        red[0] = rsqrtf(t / (float)DIMM + 1e-5f);
    }
    __syncthreads();
    float rms = red[0];
    for (int d = threadIdx.x; d < DIMM; d += 256)
        out[(size_t)r*DIMM + d] = __float2half(xr[d] * rms * w[d]);
}

// ---------------- rope + dual interleave ----------------
__global__ void rope_interleave_kernel() {
    int r = blockIdx.x, h = blockIdx.y, d = threadIdx.x;
    int bi = r >> 10, si = r & 1023;
    int t = 2*si + bi;
    size_t src = (size_t)r*3072 + h*64;
    float q = __half2float(g_qkvh[src + d]);
    float k = __half2float(g_qkvh[src + 1024 + d]);
    float v = __half2float(g_qkvh[src + 2048 + d]);
    ((__half*)g_vmP)[(((size_t)h*1024 + (t >> 1))*64 + d)*2 + (t & 1)] = __float2half(v);
    __shared__ float qs[64], ks[64];
    qs[d] = q; ks[d] = k;
    __syncthreads();
    if (d < 32) {
        float inv = powf(10000.0f, -(float)(2*d) / 64.0f);
        float fr = (float)si * inv;
        float sn, cs;
        sincosf(fr, &sn, &cs);
        size_t dst = ((size_t)h*SEQ + t)*64;
        float x1 = qs[d], x2 = qs[d+32];
        g_qmh[dst + d]      = __float2half( x1*cs + x2*sn);
        g_qmh[dst + d + 32] = __float2half(-x1*sn + x2*cs);
        x1 = ks[d]; x2 = ks[d+32];
        g_kmh[dst + d]      = __float2half( x1*cs + x2*sn);
        g_kmh[dst + d + 32] = __float2half(-x1*sn + x2*cs);
    }
}

// ---------------- fp16 flash attention (ldmatrix frags) ----------------
#define ATT_SMEM_W (4608 + 2304 + 4608 + 2304)
__global__ void __launch_bounds__(256) attn_h() {
    extern __shared__ __align__(16) unsigned asm_[];
    unsigned* Qs = asm_;
    unsigned* Ks = asm_ + 4608;
    unsigned* Ps = asm_ + 6912;
    unsigned* Vt = asm_ + 11520;
    int h = blockIdx.y;
    int t0 = ((int)gridDim.x - 1 - (int)blockIdx.x) * 128;
    int tid = threadIdx.x, lane = tid & 31, wid = tid >> 5;
    int g = lane >> 2, t4 = lane & 3;
    int wm = wid * 16;
    uint32_t qB = s2u(Qs), kB = s2u(Ks), pB = s2u(Ps), vB = s2u(Vt);
    uint32_t aOffQ = frag_off(wm, 36, lane);
    uint32_t bOffK[4];
    #pragma unroll
    for (int p = 0; p < 4; p++) bOffK[p] = frag_off(p*16, 36, lane);

    const __half* qb = g_qmh + ((size_t)h*SEQ + t0)*64;
    for (int i = tid; i < 128*8; i += 256) {
        int r = i >> 3, j = i & 7;
        *(uint4*)&Qs[r*36 + j*4] = ((const uint4*)(qb + (size_t)r*64))[j];
    }

    float o[8][4];
    #pragma unroll
    for (int n = 0; n < 8; n++)
        #pragma unroll
        for (int j = 0; j < 4; j++) o[n][j] = 0.f;
    float m0 = -1e30f, m1 = -1e30f, l0 = 0.f, l1 = 0.f;
    int row0 = t0 + wm + g, row1 = row0 + 8;
    int wmax = t0 + wm + 15;

    for (int kt = 0; kt <= t0 + 127; kt += 64) {
        __syncthreads();
        const __half* kb = g_kmh + ((size_t)h*SEQ + kt)*64;
        for (int i = tid; i < 64*8; i += 256) {
            int r = i >> 3, j = i & 7;
            *(uint4*)&Ks[r*36 + j*4] = ((const uint4*)(kb + (size_t)r*64))[j];
        }
        const unsigned* vp = g_vmP + ((size_t)h*1024 + (kt >> 1))*64;
        for (int w = tid; w < 64*32; w += 256) {
            int d = w & 63, p = w >> 6;
            Vt[d*36 + p] = vp[(size_t)p*64 + d];
        }
        __syncthreads();
        if (kt > wmax) continue;

        float s[8][4];
        #pragma unroll
        for (int n = 0; n < 8; n++)
            #pragma unroll
            for (int j = 0; j < 4; j++) s[n][j] = 0.f;
        #pragma unroll
        for (int ks = 0; ks < 4; ks++) {
            unsigned aq[4], bq[4][4];
            ldsm4(aq, qB + aOffQ + ks*32);
            #pragma unroll
            for (int p = 0; p < 4; p++) ldsm4(bq[p], kB + bOffK[p] + ks*32);
            #pragma unroll
            for (int n = 0; n < 8; n++) {
                unsigned bf[2] = { bq[n>>1][n&1], bq[n>>1][(n&1)+2] };
                mma16(s[n], aq, bf);
            }
        }
        float mx0 = -1e30f, mx1 = -1e30f;
        #pragma unroll
        for (int n = 0; n < 8; n++) {
            int c0 = kt + n*8 + 2*t4, c1 = c0 + 1;
            s[n][0] = (c0 <= row0) ? s[n][0]*0.125f : -1e30f;
            s[n][1] = (c1 <= row0) ? s[n][1]*0.125f : -1e30f;
            s[n][2] = (c0 <= row1) ? s[n][2]*0.125f : -1e30f;
            s[n][3] = (c1 <= row1) ? s[n][3]*0.125f : -1e30f;
            mx0 = fmaxf(mx0, fmaxf(s[n][0], s[n][1]));
            mx1 = fmaxf(mx1, fmaxf(s[n][2], s[n][3]));
        }
        mx0 = fmaxf(mx0, __shfl_xor_sync(0xffffffffu, mx0, 1));
        mx0 = fmaxf(mx0, __shfl_xor_sync(0xffffffffu, mx0, 2));
        mx1 = fmaxf(mx1, __shfl_xor_sync(0xffffffffu, mx1, 1));
        mx1 = fmaxf(mx1, __shfl_xor_sync(0xffffffffu, mx1, 2));
        float nm0 = fmaxf(m0, mx0), nm1 = fmaxf(m1, mx1);
        float cor0 = __expf(m0 - nm0), cor1 = __expf(m1 - nm1);
        m0 = nm0; m1 = nm1;
        l0 *= cor0; l1 *= cor1;
        float sum0 = 0.f, sum1 = 0.f;
        #pragma unroll
        for (int n = 0; n < 8; n++) {
            float p00 = __expf(s[n][0] - nm0), p01 = __expf(s[n][1] - nm0);
            float p10 = __expf(s[n][2] - nm1), p11 = __expf(s[n][3] - nm1);
            sum0 += p00 + p01; sum1 += p10 + p11;
            Ps[(wm+g)*36 + n*4 + t4]   = f2h2(p00, p01);
            Ps[(wm+g+8)*36 + n*4 + t4] = f2h2(p10, p11);
            #pragma unroll
            for (int j = 0; j < 2; j++) { o[n][j] *= cor0; o[n][2+j] *= cor1; }
        }
        sum0 += __shfl_xor_sync(0xffffffffu, sum0, 1);
        sum0 += __shfl_xor_sync(0xffffffffu, sum0, 2);
        sum1 += __shfl_xor_sync(0xffffffffu, sum1, 1);
        sum1 += __shfl_xor_sync(0xffffffffu, sum1, 2);
        l0 += sum0; l1 += sum1;
        __syncwarp();

        #pragma unroll
        for (int ks = 0; ks < 4; ks++) {
            unsigned ap[4], bq[4][4];
            ldsm4(ap, pB + aOffQ + ks*32);
            #pragma unroll
            for (int p = 0; p < 4; p++) ldsm4(bq[p], vB + bOffK[p] + ks*32);
            #pragma unroll
            for (int n = 0; n < 8; n++) {
                unsigned bf[2] = { bq[n>>1][n&1], bq[n>>1][(n&1)+2] };
                mma16(o[n], ap, bf);
            }
        }
    }

    float inv0 = 1.f / l0, inv1 = 1.f / l1;
    int tok0 = (row0 & 1)*1024 + (row0 >> 1);
    int tok1 = (row1 & 1)*1024 + (row1 >> 1);
    #pragma unroll
    for (int n = 0; n < 8; n++) {
        int col = h*64 + n*8 + 2*t4;
        *(unsigned*)&g_orowsh[(size_t)tok0*DIMM + col] = f2h2(o[n][0]*inv0, o[n][1]*inv0);
        *(unsigned*)&g_orowsh[(size_t)tok1*DIMM + col] = f2h2(o[n][2]*inv1, o[n][3]*inv1);
    }
}

// ---------------- router ----------------
__global__ void router_kernel(const float* __restrict__ pkeys, const float* __restrict__ fkeys,
                              const float* __restrict__ pbias, const float* __restrict__ fbias,
                              const int* __restrict__ pidx, const float* __restrict__ pval,
                              const int* __restrict__ fidx, const float* __restrict__ fval) {
    int tok = blockIdx.x, tid = threadIdx.x;
    bool isf = tok >= 1024;
    const float* keys = isf ? fkeys : pkeys;
    const __half* x = g_xffnh + (size_t)tok*DIMM;
    __shared__ float part[8][16];
    __shared__ float logit[16];
    int e = tid & 15, ch = tid >> 4;
    float s = 0.f;
    int d0 = ch * 128;
    for (int d = d0; d < d0 + 128; d++)
        s = fmaf(__half2float(x[d]), keys[d*16 + e], s);
    part[ch][e] = s;
    __syncthreads();
    if (tid < 16) {
        float t = 0.f;
        #pragma unroll
        for (int c = 0; c < 8; c++) t += part[c][tid];
        logit[tid] = t;
    }
    __syncthreads();
    if (tid == 0) {
        int lt = isf ? tok - 1024 : tok;
        const int*   idx  = isf ? fidx  : pidx;
        const float* val  = isf ? fval  : pval;
        const float* bias = isf ? fbias : pbias;
        float sc[4]; int id[4]; float sum = 0.f;
        #pragma unroll
        for (int k = 0; k < 4; k++) {
            int ix = idx[lt*4 + k];
            float v = val[lt*4 + k] + logit[ix] + bias[ix];
            float s2 = 1.f / (1.f + expf(-v));
            sc[k] = s2; sum += s2;
            id[k] = ix + (isf ? 16 : 0);
        }
        #pragma unroll
        for (int k = 0; k < 4; k++) {
            g_scales[tok*4 + k] = sc[k] / sum;
            g_eid[tok*4 + k] = id[k];
            atomicAdd(&g_counts[id[k]], 1);
        }
    }
}

__global__ void zero32_kernel() {
    int i = threadIdx.x;
    if (i < NEXP) { g_counts[i] = 0; g_cursors[i] = 0; }
}

__global__ void prefix_kernel() {
    int acc = 0;
    for (int e = 0; e < NEXP; e++) { g_offsets[e] = acc; acc += g_counts[e]; }
}

__global__ void scatter_kernel() {
    int a = blockIdx.x * blockDim.x + threadIdx.x;
    if (a >= NASS) return;
    int e = g_eid[a];
    int p = g_offsets[e] + atomicAdd(&g_cursors[e], 1);
    g_tokof[p] = a >> 2;
    g_posof[a] = p;
}

__global__ void swiglu_moe_kernel() {
    int i = blockIdx.x*256 + threadIdx.x;
    __half2 g2 = ((const __half2*)g_gateh)[i];
    __half2 u2 = ((const __half2*)g_uph)[i];
    float2 gf = __half22float2(g2), uf = __half22float2(u2);
    float a = gf.x / (1.f + __expf(-gf.x)) * uf.x;
    float b = gf.y / (1.f + __expf(-gf.y)) * uf.y;
    ((__half2*)g_Gh)[i] = __floats2half2_rn(a, b);
}

__global__ void combine_kernel(float* __restrict__ y) {
    int tok = blockIdx.x;
    __shared__ int pos[4];
    __shared__ float sc[4];
    if (threadIdx.x < 4) {
        pos[threadIdx.x] = g_posof[tok*4 + threadIdx.x];
        sc[threadIdx.x]  = g_scales[tok*4 + threadIdx.x];
    }
    __syncthreads();
    for (int d = threadIdx.x; d < DIMM; d += 256) {
        float v = g_xffni[(size_t)tok*DIMM + d];
        #pragma unroll
        for (int k = 0; k < 4; k++)
            v = fmaf(sc[k], __half2float(g_slotsh[(size_t)pos[k]*DIMM + d]), v);
        y[(size_t)tok*DIMM + d] = v;
    }
}

__global__ void swiglu_shared_kernel() {
    int t = blockIdx.x;
    for (int j = threadIdx.x; j < DSH; j += 256) {
        float a = __half2float(g_suh[(size_t)t*2*DSH + j]);
        float b = __half2float(g_suh[(size_t)t*2*DSH + DSH + j]);
        g_hsh[(size_t)t*DSH + j] = __float2half((a / (1.f + __expf(-a))) * b);
    }
}

// ---------------- launch ----------------
extern "C" void kernel_launch(void* const* d_in, const int* in_sizes, int n_in,
                              void* d_out, int out_size) {
    const float* x_input  = (const float*)d_in[0];
    const int*   p_idx    = (const int*)  d_in[1];
    const float* p_val    = (const float*)d_in[2];
    const int*   f_idx    = (const int*)  d_in[3];
    const float* f_val    = (const float*)d_in[4];
    const float* attn_nw  = (const float*)d_in[5];
    const float* ffn_nw   = (const float*)d_in[6];
    const float* W_attn   = (const float*)d_in[7];
    const float* W_attn_o = (const float*)d_in[8];
    const float* ffn_up   = (const float*)d_in[9];
    const float* ffn_down = (const float*)d_in[10];
    const float* pW       = (const float*)d_in[11];
    const float* fW       = (const float*)d_in[12];
    const float* pkeys    = (const float*)d_in[13];
    const float* fkeys    = (const float*)d_in[14];
    const float* pbias    = (const float*)d_in[15];
    const float* fbias    = (const float*)d_in[16];
    float* out = (float*)d_out;

    __half *xnormh, *qkvh, *orowsh, *xffnh, *suh, *hsh;
    __half *wqkvT, *woT, *wupT, *wdnT;
    float *xffni;
    cudaGetSymbolAddress((void**)&xnormh, g_xnormh);
    cudaGetSymbolAddress((void**)&qkvh,   g_qkvh);
    cudaGetSymbolAddress((void**)&orowsh, g_orowsh);
    cudaGetSymbolAddress((void**)&xffni,  g_xffni);
    cudaGetSymbolAddress((void**)&xffnh,  g_xffnh);
    cudaGetSymbolAddress((void**)&suh,    g_suh);
    cudaGetSymbolAddress((void**)&hsh,    g_hsh);
    cudaGetSymbolAddress((void**)&wqkvT,  g_wqkvT);
    cudaGetSymbolAddress((void**)&woT,    g_woT);
    cudaGetSymbolAddress((void**)&wupT,   g_wupT);
    cudaGetSymbolAddress((void**)&wdnT,   g_wdnT);

    static bool attr_set = false;
    if (!attr_set) {
        cudaFuncSetAttribute(attn_h, cudaFuncAttributeMaxDynamicSharedMemorySize,
                             ATT_SMEM_W * 4);
        cudaFuncSetAttribute(gemm_h<0>, cudaFuncAttributeMaxDynamicSharedMemorySize,
                             GEMM_SMEM);
        cudaFuncSetAttribute(gemm_h<1>, cudaFuncAttributeMaxDynamicSharedMemorySize,
                             GEMM_SMEM);
        cudaFuncSetAttribute(moe_gu_h, cudaFuncAttributeMaxDynamicSharedMemorySize,
                             GEMM_SMEM);
        cudaFuncSetAttribute(moe_down_h, cudaFuncAttributeMaxDynamicSharedMemorySize,
                             GEMM_SMEM);
        attr_set = true;
    }

    // weight packing to K-major fp16
    packT<<<dim3(16, 96),  256>>>(W_attn,   wqkvT, DIMM, 3*DIMM);
    packT<<<dim3(16, 32),  256>>>(W_attn_o, woT,   DIMM, DIMM);
    packT<<<dim3(16, 128), 256>>>(ffn_up,   wupT,  DIMM, 2*DSH);
    packT<<<dim3(32, 32),  256>>>(ffn_down, wdnT,  DSH,  DIMM);
    packT_moe<<<dim3(16, 16, 64), 256>>>(pW, fW);
    conv_moe_down<<<dim3(512, 1, 32), 256>>>(pW, fW);

    // attention block
    rmsnorm_h<<<TOK, 256>>>(x_input, attn_nw, xnormh);
    gemm_h<1><<<dim3(24, 16), 256, GEMM_SMEM>>>(xnormh, wqkvT, qkvh, nullptr, TOK, 3*DIMM, DIMM);
    rope_interleave_kernel<<<dim3(TOK, NH), 64>>>();
    attn_h<<<dim3(SEQ/128, NH), 256, ATT_SMEM_W*4>>>();
    gemm_h<0><<<dim3(8, 16), 256, GEMM_SMEM>>>(orowsh, woT, xffni, x_input, TOK, DIMM, DIMM);
    rmsnorm_h<<<TOK, 256>>>(xffni, ffn_nw, xffnh);

    // routing
    zero32_kernel<<<1, 32>>>();
    router_kernel<<<TOK, 128>>>(pkeys, fkeys, pbias, fbias, p_idx, p_val, f_idx, f_val);
    prefix_kernel<<<1, 1>>>();
    scatter_kernel<<<32, 256>>>();

    // grouped MoE
    moe_gu_h<<<dim3(8, 16, NEXP), 256, GEMM_SMEM>>>();
    swiglu_moe_kernel<<<(NASS*FDIM/2)/256, 256>>>();
    moe_down_h<<<dim3(8, 16, NEXP), 256, GEMM_SMEM>>>();
    combine_kernel<<<TOK, 256>>>(out);

    // shared expert (adds into out)
    gemm_h<1><<<dim3(32, 16), 256, GEMM_SMEM>>>(xffnh, wupT, suh, nullptr, TOK, 2*DSH, DIMM);
    swiglu_shared_kernel<<<TOK, 256>>>();
    gemm_h<0><<<dim3(8, 16), 256, GEMM_SMEM>>>(hsh, wdnT, out, out, TOK, DIMM, DSH);
}

// round 12
// speedup vs baseline: 6.4518x; 1.0100x over previous
#include <cuda_runtime.h>
#include <cuda_fp16.h>
#include <math.h>
#include <stdint.h>

// ---------------- problem constants ----------------
#define TOK   2048
#define DIMM  1024
#define NH    16
#define HD    64
#define SEQ   2048
#define NASS  8192
#define NEXP  32
#define FDIM  512
#define DSH   2048

// ---------------- scratch ----------------
__device__ __align__(16) __half g_xnormh[TOK*DIMM];
__device__ __align__(16) __half g_qkvh[TOK*3*DIMM];
__device__ __align__(16) __half g_qmh[NH*SEQ*HD];
__device__ __align__(16) __half g_kmh[NH*SEQ*HD];
__device__ __align__(16) unsigned g_vmP[NH*(SEQ/2)*HD];
__device__ __align__(16) __half g_orowsh[TOK*DIMM];
__device__ float g_xffni[TOK*DIMM];
__device__ __align__(16) __half g_xffnh[TOK*DIMM];
__device__ __align__(16) __half g_Gh[NASS*FDIM];
__device__ __align__(16) __half g_slotsh[(size_t)NASS*DIMM];
__device__ __align__(16) __half g_hsh[(size_t)TOK*DSH];
__device__ float g_scales[NASS];
__device__ int   g_eid[NASS];
__device__ int   g_tokof[NASS];
__device__ int   g_posof[NASS];
__device__ int   g_counts[NEXP];
__device__ int   g_offsets[NEXP];
__device__ int   g_cursors[NEXP];
// K-major packed fp16 weights: Wt[N][K]
__device__ __align__(16) __half g_wqkvT[3072*1024];
__device__ __align__(16) __half g_woT[1024*1024];
__device__ __align__(16) __half g_wupT[(size_t)4096*1024];   // gate/up interleaved tiles
__device__ __align__(16) __half g_wdnT[(size_t)1024*2048];
__device__ __align__(16) __half g_wguT[(size_t)32*1024*1024]; // per-expert gate/up interleaved
__device__ __align__(16) __half g_wdnM[(size_t)32*1024*512];

// ---------------- helpers ----------------
__device__ __forceinline__ unsigned f2h2(float a, float b) {
    __half2 h = __floats2half2_rn(a, b);
    return *reinterpret_cast<unsigned*>(&h);
}
__device__ __forceinline__ void mma16(float c[4], const unsigned a[4], const unsigned b[2]) {
    asm volatile("mma.sync.aligned.m16n8k16.row.col.f32.f16.f16.f32 "
                 "{%0,%1,%2,%3},{%4,%5,%6,%7},{%8,%9},{%0,%1,%2,%3};"
                 : "+f"(c[0]), "+f"(c[1]), "+f"(c[2]), "+f"(c[3])
                 : "r"(a[0]), "r"(a[1]), "r"(a[2]), "r"(a[3]), "r"(b[0]), "r"(b[1]));
}
__device__ __forceinline__ uint32_t s2u(const void* p) {
    uint32_t a;
    asm("{ .reg .u64 t; cvta.to.shared.u64 t, %1; cvt.u32.u64 %0, t; }" : "=r"(a) : "l"(p));
    return a;
}
__device__ __forceinline__ void cpa16(uint32_t dst, const void* src) {
    asm volatile("cp.async.ca.shared.global [%0], [%1], 16;" :: "r"(dst), "l"(src));
}
#define CPA_COMMIT() asm volatile("cp.async.commit_group;")
#define CPA_WAIT1()  asm volatile("cp.async.wait_group 1;")
#define CPA_WAIT0()  asm volatile("cp.async.wait_group 0;")

__device__ __forceinline__ void ldsm4(unsigned* r, uint32_t a) {
    asm volatile("ldmatrix.sync.aligned.m8n8.x4.shared.b16 {%0,%1,%2,%3}, [%4];"
                 : "=r"(r[0]), "=r"(r[1]), "=r"(r[2]), "=r"(r[3]) : "r"(a));
}
__device__ __forceinline__ uint32_t frag_off(int rowBase, int stride, int lane) {
    int lr = lane & 7, lh = (lane >> 3) & 1, lq = lane >> 4;
    return (uint32_t)(((rowBase + lr + lh*8) * stride + lq*4) * 4);
}

__device__ __forceinline__ void compute_tile_ldsm(uint32_t aS, uint32_t bS,
                                                  uint32_t aOff0, uint32_t aOff1,
                                                  const uint32_t* bOff,
                                                  float acc[16][4]) {
    #pragma unroll
    for (int ks = 0; ks < 2; ks++) {
        unsigned a0[4], a1[4], bq[4][4];
        ldsm4(a0, aS + aOff0 + ks*32);
        ldsm4(a1, aS + aOff1 + ks*32);
        #pragma unroll
        for (int p = 0; p < 4; p++) ldsm4(bq[p], bS + bOff[p] + ks*32);
        #pragma unroll
        for (int ni = 0; ni < 8; ni++) {
            unsigned bf[2] = { bq[ni>>1][ni&1], bq[ni>>1][(ni&1)+2] };
            mma16(acc[ni],   a0, bf);
            mma16(acc[8+ni], a1, bf);
        }
    }
}

// ---------------- transpose-pack: W [K][N] fp32 -> Wt [dest(n)][K] half ----------------
// MODE 0: dest = n.  MODE 1 (dense gate/up interleave, NH=N/2): c<NH: (c>>6)*128+(c&63),
//         else m=c-NH: (m>>6)*128+64+(m&63).
template<int MODE>
__device__ __forceinline__ void packT_body(const float* __restrict__ W,
                                           __half* __restrict__ Wt,
                                           int K, int N, int k0, int n0, int tid) {
    __shared__ __half tile[32][72];
    int nl = tid & 31, kl = tid >> 5;
    #pragma unroll
    for (int it = 0; it < 8; it++)
        tile[nl][kl + it*8] = __float2half(W[(size_t)(k0 + kl + it*8)*N + n0 + nl]);
    __syncthreads();
    int kq8 = (tid & 7)*8, nr = tid >> 3;
    int c = n0 + nr;
    int drow;
    if (MODE == 0) drow = c;
    else {
        int NHf = N >> 1;
        drow = (c < NHf) ? ((c >> 6)*128 + (c & 63))
                         : (((c - NHf) >> 6)*128 + 64 + ((c - NHf) & 63));
    }
    *(uint4*)&Wt[(size_t)drow*K + k0 + kq8] = *(uint4*)&tile[nr][kq8];
}
__global__ void __launch_bounds__(256) packT(const float* __restrict__ W,
                                             __half* __restrict__ Wt, int K, int N) {
    packT_body<0>(W, Wt, K, N, blockIdx.x*64, blockIdx.y*32, threadIdx.x);
}
__global__ void __launch_bounds__(256) packT_gu(const float* __restrict__ W,
                                                __half* __restrict__ Wt, int K, int N) {
    packT_body<1>(W, Wt, K, N, blockIdx.x*64, blockIdx.y*32, threadIdx.x);
}
// MoE gate/up: z = sel*32+e; dest row for source col c: (c>>6)*128 + sel*64 + (c&63)
__global__ void __launch_bounds__(256) packT_moe(const float* __restrict__ pW,
                                                 const float* __restrict__ fW) {
    __shared__ __half tile[32][72];
    int z = blockIdx.z;
    int sel = z >> 5, e = z & 31;
    const float* W = (e < 16) ? pW + ((size_t)sel*16 + e)      * (size_t)DIMM*FDIM
                              : fW + ((size_t)sel*16 + (e-16)) * (size_t)DIMM*FDIM;
    __half* Wt = g_wguT + (size_t)e*1024*1024;
    int k0 = blockIdx.x*64, n0 = blockIdx.y*32;
    int tid = threadIdx.x;
    int nl = tid & 31, kl = tid >> 5;
    #pragma unroll
    for (int it = 0; it < 8; it++)
        tile[nl][kl + it*8] = __float2half(W[(size_t)(k0 + kl + it*8)*FDIM + n0 + nl]);
    __syncthreads();
    int kq8 = (tid & 7)*8, nr = tid >> 3;
    int c = n0 + nr;
    int drow = (c >> 6)*128 + sel*64 + (c & 63);
    *(uint4*)&Wt[(size_t)drow*DIMM + k0 + kq8] = *(uint4*)&tile[nr][kq8];
}
__global__ void __launch_bounds__(256) conv_moe_down(const float* __restrict__ pW,
                                                     const float* __restrict__ fW) {
    int z = blockIdx.z;
    const float* W = (z < 16) ? pW + ((size_t)2*16 + z)      * (size_t)DIMM*FDIM
                              : fW + ((size_t)2*16 + (z-16)) * (size_t)DIMM*FDIM;
    __half* Wh = g_wdnM + (size_t)z*1024*512;
    int idx = blockIdx.x*256 + threadIdx.x;        // 65536 per z, 8 elems each
    float4 a = ((const float4*)W)[idx*2];
    float4 b = ((const float4*)W)[idx*2 + 1];
    ((uint4*)Wh)[idx] = make_uint4(f2h2(a.x,a.y), f2h2(a.z,a.w), f2h2(b.x,b.y), f2h2(b.z,b.w));
}

// ---------------- dense fp16 GEMM, 3-stage cp.async + ldmatrix ----------------
// OUT 0: float out (+D)   OUT 1: half out   OUT 2: fused swiglu -> half out (N'=2*outN)
#define GEMM_SMEM (2560 * 2 * 3 * 4)
template<int OUT>
__global__ void __launch_bounds__(256) gemm_h(const __half* __restrict__ A,
                                              const __half* __restrict__ Bt,
                                              void* __restrict__ Cv,
                                              const float* __restrict__ D,
                                              int M, int N, int K) {
    extern __shared__ __align__(16) unsigned smem[];
    unsigned* As = smem;
    unsigned* Bs = smem + 3*2560;
    int tid = threadIdx.x, lane = tid & 31, wid = tid >> 5;
    int g = lane >> 2, t4 = lane & 3;
    int wm = (wid & 3)*32, wn = (wid >> 2)*64;
    size_t rowBase = (size_t)blockIdx.y * 128, colBase = (size_t)blockIdx.x * 128;
    int r_ = tid >> 1, sel = tid & 1;
    int sidx = r_*20 + sel*8;
    const __half* Ag = A  + (rowBase + r_)*K + sel*16;
    const __half* Bg = Bt + (colBase + r_)*K + sel*16;
    uint32_t aB = s2u(As), bB = s2u(Bs);
    uint32_t aOff0 = frag_off(wm, 20, lane), aOff1 = frag_off(wm+16, 20, lane);
    uint32_t bOff[4];
    #pragma unroll
    for (int p = 0; p < 4; p++) bOff[p] = frag_off(wn + p*16, 20, lane);
    int NC = K >> 5;

    auto issue = [&](int cc, int s) {
        uint32_t ad = aB + (s*2560 + sidx)*4;
        cpa16(ad,      Ag + cc*32);
        cpa16(ad + 16, Ag + cc*32 + 8);
        uint32_t bd = bB + (s*2560 + sidx)*4;
        cpa16(bd,      Bg + cc*32);
        cpa16(bd + 16, Bg + cc*32 + 8);
        CPA_COMMIT();
    };

    float acc[16][4];
    #pragma unroll
    for (int i = 0; i < 16; i++)
        #pragma unroll
        for (int j = 0; j < 4; j++) acc[i][j] = 0.f;

    issue(0, 0);
    issue(1, 1);
    for (int c = 0; c < NC; c++) {
        if (c + 2 < NC) CPA_WAIT1(); else CPA_WAIT0();
        __syncthreads();
        int s = c - (c/3)*3;
        compute_tile_ldsm(aB + s*2560*4, bB + s*2560*4, aOff0, aOff1, bOff, acc);
        if (c + 2 < NC) issue(c + 2, (c+2) - ((c+2)/3)*3);
    }
    if (OUT == 2) {
        // fused swiglu: stage 128x128 half tile, combine gate/up halves
        __syncthreads();
        unsigned* sm = smem;                    // 128 x 66 u32
        #pragma unroll
        for (int mi = 0; mi < 2; mi++)
            #pragma unroll
            for (int ni = 0; ni < 8; ni++) {
                float* c = acc[mi*8+ni];
                int r = wm + mi*16 + g;
                int cw = (wn >> 1) + ni*4 + t4;
                sm[r*66 + cw]     = f2h2(c[0], c[1]);
                sm[(r+8)*66 + cw] = f2h2(c[2], c[3]);
            }
        __syncthreads();
        __half* C = (__half*)Cv;
        int outN = N >> 1;
        size_t fBase = colBase >> 1;
        for (int idx = tid; idx < 128*32; idx += 256) {
            int r = idx >> 5, cw = idx & 31;
            float2 gf = __half22float2(*(__half2*)&sm[r*66 + cw]);
            float2 uf = __half22float2(*(__half2*)&sm[r*66 + 32 + cw]);
            float a = gf.x / (1.f + __expf(-gf.x)) * uf.x;
            float b = gf.y / (1.f + __expf(-gf.y)) * uf.y;
            *(unsigned*)&C[(rowBase + r)*outN + fBase + 2*cw] = f2h2(a, b);
        }
        return;
    }
    #pragma unroll
    for (int mi = 0; mi < 2; mi++)
        #pragma unroll
        for (int ni = 0; ni < 8; ni++) {
            float* c = acc[mi*8+ni];
            size_t r0 = rowBase + wm + mi*16 + g;
            size_t c0 = colBase + wn + ni*8 + 2*t4;
            if (OUT == 0) {
                float* C = (float*)Cv;
                size_t o0 = r0*N + c0, o1 = (r0+8)*N + c0;
                if (D) {
                    C[o0] = c[0] + D[o0]; C[o0+1] = c[1] + D[o0+1];
                    C[o1] = c[2] + D[o1]; C[o1+1] = c[3] + D[o1+1];
                } else {
                    C[o0] = c[0]; C[o0+1] = c[1];
                    C[o1] = c[2]; C[o1+1] = c[3];
                }
            } else {
                __half* C = (__half*)Cv;
                *(unsigned*)&C[r0*N + c0]     = f2h2(c[0], c[1]);
                *(unsigned*)&C[(r0+8)*N + c0] = f2h2(c[2], c[3]);
            }
        }
}

// ---------------- MoE gate+up grouped GEMM, fused swiglu -> g_Gh ----------------
__global__ void __launch_bounds__(256) moe_gu_h() {
    extern __shared__ __align__(16) unsigned smem[];
    unsigned* As = smem;
    unsigned* Bs = smem + 3*2560;
    __shared__ int rows[128];
    int e = blockIdx.z;
    int cnt = g_counts[e];
    int rowTile = blockIdx.y * 128;
    if (rowTile >= cnt) return;
    int base = g_offsets[e];
    int colBase = blockIdx.x * 128;             // over N'=1024 interleaved
    const __half* Wt = g_wguT + (size_t)e*1024*1024;
    int tid = threadIdx.x;
    if (tid < 128) {
        int rr = rowTile + tid;
        rows[tid] = (rr < cnt) ? g_tokof[base + rr] : 0;
    }
    __syncthreads();
    int lane = tid & 31, wid = tid >> 5;
    int g = lane >> 2, t4 = lane & 3;
    int wm = (wid & 3)*32, wn = (wid >> 2)*64;
    int r_ = tid >> 1, sel = tid & 1;
    int sidx = r_*20 + sel*8;
    const __half* Ag = g_xffnh + (size_t)rows[r_]*DIMM + sel*16;
    const __half* Bg = Wt + (size_t)(colBase + r_)*1024 + sel*16;
    uint32_t aB = s2u(As), bB = s2u(Bs);
    uint32_t aOff0 = frag_off(wm, 20, lane), aOff1 = frag_off(wm+16, 20, lane);
    uint32_t bOff[4];
    #pragma unroll
    for (int p = 0; p < 4; p++) bOff[p] = frag_off(wn + p*16, 20, lane);

    auto issue = [&](int cc, int s) {
        uint32_t ad = aB + (s*2560 + sidx)*4;
        cpa16(ad,      Ag + cc*32);
        cpa16(ad + 16, Ag + cc*32 + 8);
        uint32_t bd = bB + (s*2560 + sidx)*4;
        cpa16(bd,      Bg + cc*32);
        cpa16(bd + 16, Bg + cc*32 + 8);
        CPA_COMMIT();
    };

    float acc[16][4];
    #pragma unroll
    for (int i = 0; i < 16; i++)
        #pragma unroll
        for (int j = 0; j < 4; j++) acc[i][j] = 0.f;

    issue(0, 0);
    issue(1, 1);
    for (int c = 0; c < 32; c++) {
        if (c + 2 < 32) CPA_WAIT1(); else CPA_WAIT0();
        __syncthreads();
        int s = c - (c/3)*3;
        compute_tile_ldsm(aB + s*2560*4, bB + s*2560*4, aOff0, aOff1, bOff, acc);
        if (c + 2 < 32) issue(c + 2, (c+2) - ((c+2)/3)*3);
    }
    // fused swiglu epilogue
    __syncthreads();
    unsigned* sm = smem;
    #pragma unroll
    for (int mi = 0; mi < 2; mi++)
        #pragma unroll
        for (int ni = 0; ni < 8; ni++) {
            float* c = acc[mi*8+ni];
            int r = wm + mi*16 + g;
            int cw = (wn >> 1) + ni*4 + t4;
            sm[r*66 + cw]     = f2h2(c[0], c[1]);
            sm[(r+8)*66 + cw] = f2h2(c[2], c[3]);
        }
    __syncthreads();
    int fBase = colBase >> 1;
    for (int idx = tid; idx < 128*32; idx += 256) {
        int r = idx >> 5, cw = idx & 31;
        if (rowTile + r >= cnt) continue;
        float2 gf = __half22float2(*(__half2*)&sm[r*66 + cw]);
        float2 uf = __half22float2(*(__half2*)&sm[r*66 + 32 + cw]);
        float a = gf.x / (1.f + __expf(-gf.x)) * uf.x;
        float b = gf.y / (1.f + __expf(-gf.y)) * uf.y;
        *(unsigned*)&g_Gh[(size_t)(base + rowTile + r)*FDIM + fBase + 2*cw] = f2h2(a, b);
    }
}

// ---------------- MoE down grouped GEMM ----------------
__global__ void __launch_bounds__(256) moe_down_h() {
    extern __shared__ __align__(16) unsigned smem[];
    unsigned* As = smem;
    unsigned* Bs = smem + 3*2560;
    int e = blockIdx.z;
    int cnt = g_counts[e];
    int rowTile = blockIdx.y * 128;
    if (rowTile >= cnt) return;
    int base = g_offsets[e];
    int colBase = blockIdx.x * 128;
    const __half* W = g_wdnM + (size_t)e*1024*512;
    int tid = threadIdx.x, lane = tid & 31, wid = tid >> 5;
    int g = lane >> 2, t4 = lane & 3;
    int wm = (wid & 3)*32, wn = (wid >> 2)*64;
    int r_ = tid >> 1, sel = tid & 1;
    int sidx = r_*20 + sel*8;
    int arow = base + rowTile + r_;
    if (arow > NASS - 1) arow = NASS - 1;
    const __half* Ag = g_Gh + (size_t)arow*FDIM + sel*16;
    const __half* Bg = W + (size_t)(colBase + r_)*FDIM + sel*16;
    uint32_t aB = s2u(As), bB = s2u(Bs);
    uint32_t aOff0 = frag_off(wm, 20, lane), aOff1 = frag_off(wm+16, 20, lane);
    uint32_t bOff[4];
    #pragma unroll
    for (int p = 0; p < 4; p++) bOff[p] = frag_off(wn + p*16, 20, lane);

    auto issue = [&](int cc, int s) {
        uint32_t ad = aB + (s*2560 + sidx)*4;
        cpa16(ad,      Ag + cc*32);
        cpa16(ad + 16, Ag + cc*32 + 8);
        uint32_t bd = bB + (s*2560 + sidx)*4;
        cpa16(bd,      Bg + cc*32);
        cpa16(bd + 16, Bg + cc*32 + 8);
        CPA_COMMIT();
    };

    float acc[16][4];
    #pragma unroll
    for (int i = 0; i < 16; i++)
        #pragma unroll
        for (int j = 0; j < 4; j++) acc[i][j] = 0.f;

    issue(0, 0);
    issue(1, 1);
    for (int c = 0; c < 16; c++) {
        if (c + 2 < 16) CPA_WAIT1(); else CPA_WAIT0();
        __syncthreads();
        int s = c - (c/3)*3;
        compute_tile_ldsm(aB + s*2560*4, bB + s*2560*4, aOff0, aOff1, bOff, acc);
        if (c + 2 < 16) issue(c + 2, (c+2) - ((c+2)/3)*3);
    }
    #pragma unroll
    for (int mi = 0; mi < 2; mi++)
        #pragma unroll
        for (int ni = 0; ni < 8; ni++) {
            float* c = acc[mi*8+ni];
            int r = rowTile + wm + mi*16 + g;
            int cc = colBase + wn + ni*8 + 2*t4;
            if (r < cnt)
                *(unsigned*)&g_slotsh[(size_t)(base+r)*DIMM + cc] = f2h2(c[0], c[1]);
            if (r + 8 < cnt)
                *(unsigned*)&g_slotsh[(size_t)(base+r+8)*DIMM + cc] = f2h2(c[2], c[3]);
        }
}

// ---------------- rmsnorm (half out) ----------------
__global__ void rmsnorm_h(const float* __restrict__ x, const float* __restrict__ w,
                          __half* __restrict__ out) {
    int r = blockIdx.x;
    const float* xr = x + (size_t)r*DIMM;
    __shared__ float red[8];
    float s = 0.f;
    for (int d = threadIdx.x; d < DIMM; d += 256) { float v = xr[d]; s += v*v; }
    #pragma unroll
    for (int o = 16; o; o >>= 1) s += __shfl_xor_sync(0xffffffffu, s, o);
    if ((threadIdx.x & 31) == 0) red[threadIdx.x >> 5] = s;
    __syncthreads();
    if (threadIdx.x == 0) {
        float t = 0.f;
        #pragma unroll
        for (int i = 0; i < 8; i++) t += red[i];
        red[0] = rsqrtf(t / (float)DIMM + 1e-5f);
    }
    __syncthreads();
    float rms = red[0];
    for (int d = threadIdx.x; d < DIMM; d += 256)
        out[(size_t)r*DIMM + d] = __float2half(xr[d] * rms * w[d]);
}

// ---------------- rope + dual interleave ----------------
__global__ void rope_interleave_kernel() {
    int r = blockIdx.x, h = blockIdx.y, d = threadIdx.x;
    int bi = r >> 10, si = r & 1023;
    int t = 2*si + bi;
    size_t src = (size_t)r*3072 + h*64;
    float q = __half2float(g_qkvh[src + d]);
    float k = __half2float(g_qkvh[src + 1024 + d]);
    float v = __half2float(g_qkvh[src + 2048 + d]);
    ((__half*)g_vmP)[(((size_t)h*1024 + (t >> 1))*64 + d)*2 + (t & 1)] = __float2half(v);
    __shared__ float qs[64], ks[64];
    qs[d] = q; ks[d] = k;
    __syncthreads();
    if (d < 32) {
        float inv = powf(10000.0f, -(float)(2*d) / 64.0f);
        float fr = (float)si * inv;
        float sn, cs;
        sincosf(fr, &sn, &cs);
        size_t dst = ((size_t)h*SEQ + t)*64;
        float x1 = qs[d], x2 = qs[d+32];
        g_qmh[dst + d]      = __float2half( x1*cs + x2*sn);
        g_qmh[dst + d + 32] = __float2half(-x1*sn + x2*cs);
        x1 = ks[d]; x2 = ks[d+32];
        g_kmh[dst + d]      = __float2half( x1*cs + x2*sn);
        g_kmh[dst + d + 32] = __float2half(-x1*sn + x2*cs);
    }
}

// ---------------- fp16 flash attention (ldmatrix frags) ----------------
#define ATT_SMEM_W (4608 + 2304 + 4608 + 2304)
__global__ void __launch_bounds__(256) attn_h() {
    extern __shared__ __align__(16) unsigned asm_[];
    unsigned* Qs = asm_;
    unsigned* Ks = asm_ + 4608;
    unsigned* Ps = asm_ + 6912;
    unsigned* Vt = asm_ + 11520;
    int h = blockIdx.y;
    int t0 = ((int)gridDim.x - 1 - (int)blockIdx.x) * 128;
    int tid = threadIdx.x, lane = tid & 31, wid = tid >> 5;
    int g = lane >> 2, t4 = lane & 3;
    int wm = wid * 16;
    uint32_t qB = s2u(Qs), kB = s2u(Ks), pB = s2u(Ps), vB = s2u(Vt);
    uint32_t aOffQ = frag_off(wm, 36, lane);
    uint32_t bOffK[4];
    #pragma unroll
    for (int p = 0; p < 4; p++) bOffK[p] = frag_off(p*16, 36, lane);

    const __half* qb = g_qmh + ((size_t)h*SEQ + t0)*64;
    for (int i = tid; i < 128*8; i += 256) {
        int r = i >> 3, j = i & 7;
        *(uint4*)&Qs[r*36 + j*4] = ((const uint4*)(qb + (size_t)r*64))[j];
    }

    float o[8][4];
    #pragma unroll
    for (int n = 0; n < 8; n++)
        #pragma unroll
        for (int j = 0; j < 4; j++) o[n][j] = 0.f;
    float m0 = -1e30f, m1 = -1e30f, l0 = 0.f, l1 = 0.f;
    int row0 = t0 + wm + g, row1 = row0 + 8;
    int wmax = t0 + wm + 15;

    for (int kt = 0; kt <= t0 + 127; kt += 64) {
        __syncthreads();
        const __half* kb = g_kmh + ((size_t)h*SEQ + kt)*64;
        for (int i = tid; i < 64*8; i += 256) {
            int r = i >> 3, j = i & 7;
            *(uint4*)&Ks[r*36 + j*4] = ((const uint4*)(kb + (size_t)r*64))[j];
        }
        const unsigned* vp = g_vmP + ((size_t)h*1024 + (kt >> 1))*64;
        for (int w = tid; w < 64*32; w += 256) {
            int d = w & 63, p = w >> 6;
            Vt[d*36 + p] = vp[(size_t)p*64 + d];
        }
        __syncthreads();
        if (kt > wmax) continue;

        float s[8][4];
        #pragma unroll
        for (int n = 0; n < 8; n++)
            #pragma unroll
            for (int j = 0; j < 4; j++) s[n][j] = 0.f;
        #pragma unroll
        for (int ks = 0; ks < 4; ks++) {
            unsigned aq[4], bq[4][4];
            ldsm4(aq, qB + aOffQ + ks*32);
            #pragma unroll
            for (int p = 0; p < 4; p++) ldsm4(bq[p], kB + bOffK[p] + ks*32);
            #pragma unroll
            for (int n = 0; n < 8; n++) {
                unsigned bf[2] = { bq[n>>1][n&1], bq[n>>1][(n&1)+2] };
                mma16(s[n], aq, bf);
            }
        }
        float mx0 = -1e30f, mx1 = -1e30f;
        #pragma unroll
        for (int n = 0; n < 8; n++) {
            int c0 = kt + n*8 + 2*t4, c1 = c0 + 1;
            s[n][0] = (c0 <= row0) ? s[n][0]*0.125f : -1e30f;
            s[n][1] = (c1 <= row0) ? s[n][1]*0.125f : -1e30f;
            s[n][2] = (c0 <= row1) ? s[n][2]*0.125f : -1e30f;
            s[n][3] = (c1 <= row1) ? s[n][3]*0.125f : -1e30f;
            mx0 = fmaxf(mx0, fmaxf(s[n][0], s[n][1]));
            mx1 = fmaxf(mx1, fmaxf(s[n][2], s[n][3]));
        }
        mx0 = fmaxf(mx0, __shfl_xor_sync(0xffffffffu, mx0, 1));
        mx0 = fmaxf(mx0, __shfl_xor_sync(0xffffffffu, mx0, 2));
        mx1 = fmaxf(mx1, __shfl_xor_sync(0xffffffffu, mx1, 1));
        mx1 = fmaxf(mx1, __shfl_xor_sync(0xffffffffu, mx1, 2));
        float nm0 = fmaxf(m0, mx0), nm1 = fmaxf(m1, mx1);
        float cor0 = __expf(m0 - nm0), cor1 = __expf(m1 - nm1);
        m0 = nm0; m1 = nm1;
        l0 *= cor0; l1 *= cor1;
        float sum0 = 0.f, sum1 = 0.f;
        #pragma unroll
        for (int n = 0; n < 8; n++) {
            float p00 = __expf(s[n][0] - nm0), p01 = __expf(s[n][1] - nm0);
            float p10 = __expf(s[n][2] - nm1), p11 = __expf(s[n][3] - nm1);
            sum0 += p00 + p01; sum1 += p10 + p11;
            Ps[(wm+g)*36 + n*4 + t4]   = f2h2(p00, p01);
            Ps[(wm+g+8)*36 + n*4 + t4] = f2h2(p10, p11);
            #pragma unroll
            for (int j = 0; j < 2; j++) { o[n][j] *= cor0; o[n][2+j] *= cor1; }
        }
        sum0 += __shfl_xor_sync(0xffffffffu, sum0, 1);
        sum0 += __shfl_xor_sync(0xffffffffu, sum0, 2);
        sum1 += __shfl_xor_sync(0xffffffffu, sum1, 1);
        sum1 += __shfl_xor_sync(0xffffffffu, sum1, 2);
        l0 += sum0; l1 += sum1;
        __syncwarp();

        #pragma unroll
        for (int ks = 0; ks < 4; ks++) {
            unsigned ap[4], bq[4][4];
            ldsm4(ap, pB + aOffQ + ks*32);
            #pragma unroll
            for (int p = 0; p < 4; p++) ldsm4(bq[p], vB + bOffK[p] + ks*32);
            #pragma unroll
            for (int n = 0; n < 8; n++) {
                unsigned bf[2] = { bq[n>>1][n&1], bq[n>>1][(n&1)+2] };
                mma16(o[n], ap, bf);
            }
        }
    }

    float inv0 = 1.f / l0, inv1 = 1.f / l1;
    int tok0 = (row0 & 1)*1024 + (row0 >> 1);
    int tok1 = (row1 & 1)*1024 + (row1 >> 1);
    #pragma unroll
    for (int n = 0; n < 8; n++) {
        int col = h*64 + n*8 + 2*t4;
        *(unsigned*)&g_orowsh[(size_t)tok0*DIMM + col] = f2h2(o[n][0]*inv0, o[n][1]*inv0);
        *(unsigned*)&g_orowsh[(size_t)tok1*DIMM + col] = f2h2(o[n][2]*inv1, o[n][3]*inv1);
    }
}

// ---------------- router ----------------
__global__ void router_kernel(const float* __restrict__ pkeys, const float* __restrict__ fkeys,
                              const float* __restrict__ pbias, const float* __restrict__ fbias,
                              const int* __restrict__ pidx, const float* __restrict__ pval,
                              const int* __restrict__ fidx, const float* __restrict__ fval) {
    int tok = blockIdx.x, tid = threadIdx.x;
    bool isf = tok >= 1024;
    const float* keys = isf ? fkeys : pkeys;
    const __half* x = g_xffnh + (size_t)tok*DIMM;
    __shared__ float part[8][16];
    __shared__ float logit[16];
    int e = tid & 15, ch = tid >> 4;
    float s = 0.f;
    int d0 = ch * 128;
    for (int d = d0; d < d0 + 128; d++)
        s = fmaf(__half2float(x[d]), keys[d*16 + e], s);
    part[ch][e] = s;
    __syncthreads();
    if (tid < 16) {
        float t = 0.f;
        #pragma unroll
        for (int c = 0; c < 8; c++) t += part[c][tid];
        logit[tid] = t;
    }
    __syncthreads();
    if (tid == 0) {
        int lt = isf ? tok - 1024 : tok;
        const int*   idx  = isf ? fidx  : pidx;
        const float* val  = isf ? fval  : pval;
        const float* bias = isf ? fbias : pbias;
        float sc[4]; int id[4]; float sum = 0.f;
        #pragma unroll
        for (int k = 0; k < 4; k++) {
            int ix = idx[lt*4 + k];
            float v = val[lt*4 + k] + logit[ix] + bias[ix];
            float s2 = 1.f / (1.f + expf(-v));
            sc[k] = s2; sum += s2;
            id[k] = ix + (isf ? 16 : 0);
        }
        #pragma unroll
        for (int k = 0; k < 4; k++) {
            g_scales[tok*4 + k] = sc[k] / sum;
            g_eid[tok*4 + k] = id[k];
            atomicAdd(&g_counts[id[k]], 1);
        }
    }
}

__global__ void zero32_kernel() {
    int i = threadIdx.x;
    if (i < NEXP) { g_counts[i] = 0; g_cursors[i] = 0; }
}

__global__ void prefix_kernel() {
    int acc = 0;
    for (int e = 0; e < NEXP; e++) { g_offsets[e] = acc; acc += g_counts[e]; }
}

__global__ void scatter_kernel() {
    int a = blockIdx.x * blockDim.x + threadIdx.x;
    if (a >= NASS) return;
    int e = g_eid[a];
    int p = g_offsets[e] + atomicAdd(&g_cursors[e], 1);
    g_tokof[p] = a >> 2;
    g_posof[a] = p;
}

__global__ void combine_kernel(float* __restrict__ y) {
    int tok = blockIdx.x;
    __shared__ int pos[4];
    __shared__ float sc[4];
    if (threadIdx.x < 4) {
        pos[threadIdx.x] = g_posof[tok*4 + threadIdx.x];
        sc[threadIdx.x]  = g_scales[tok*4 + threadIdx.x];
    }
    __syncthreads();
    for (int d = threadIdx.x; d < DIMM; d += 256) {
        float v = g_xffni[(size_t)tok*DIMM + d];
        #pragma unroll
        for (int k = 0; k < 4; k++)
            v = fmaf(sc[k], __half2float(g_slotsh[(size_t)pos[k]*DIMM + d]), v);
        y[(size_t)tok*DIMM + d] = v;
    }
}

// ---------------- launch ----------------
extern "C" void kernel_launch(void* const* d_in, const int* in_sizes, int n_in,
                              void* d_out, int out_size) {
    const float* x_input  = (const float*)d_in[0];
    const int*   p_idx    = (const int*)  d_in[1];
    const float* p_val    = (const float*)d_in[2];
    const int*   f_idx    = (const int*)  d_in[3];
    const float* f_val    = (const float*)d_in[4];
    const float* attn_nw  = (const float*)d_in[5];
    const float* ffn_nw   = (const float*)d_in[6];
    const float* W_attn   = (const float*)d_in[7];
    const float* W_attn_o = (const float*)d_in[8];
    const float* ffn_up   = (const float*)d_in[9];
    const float* ffn_down = (const float*)d_in[10];
    const float* pW       = (const float*)d_in[11];
    const float* fW       = (const float*)d_in[12];
    const float* pkeys    = (const float*)d_in[13];
    const float* fkeys    = (const float*)d_in[14];
    const float* pbias    = (const float*)d_in[15];
    const float* fbias    = (const float*)d_in[16];
    float* out = (float*)d_out;

    __half *xnormh, *qkvh, *orowsh, *xffnh, *hsh;
    __half *wqkvT, *woT, *wupT, *wdnT;
    float *xffni;
    cudaGetSymbolAddress((void**)&xnormh, g_xnormh);
    cudaGetSymbolAddress((void**)&qkvh,   g_qkvh);
    cudaGetSymbolAddress((void**)&orowsh, g_orowsh);
    cudaGetSymbolAddress((void**)&xffni,  g_xffni);
    cudaGetSymbolAddress((void**)&xffnh,  g_xffnh);
    cudaGetSymbolAddress((void**)&hsh,    g_hsh);
    cudaGetSymbolAddress((void**)&wqkvT,  g_wqkvT);
    cudaGetSymbolAddress((void**)&woT,    g_woT);
    cudaGetSymbolAddress((void**)&wupT,   g_wupT);
    cudaGetSymbolAddress((void**)&wdnT,   g_wdnT);

    static bool attr_set = false;
    if (!attr_set) {
        cudaFuncSetAttribute(attn_h, cudaFuncAttributeMaxDynamicSharedMemorySize,
                             ATT_SMEM_W * 4);
        cudaFuncSetAttribute(gemm_h<0>, cudaFuncAttributeMaxDynamicSharedMemorySize,
                             GEMM_SMEM);
        cudaFuncSetAttribute(gemm_h<1>, cudaFuncAttributeMaxDynamicSharedMemorySize,
                             GEMM_SMEM);
        cudaFuncSetAttribute(gemm_h<2>, cudaFuncAttributeMaxDynamicSharedMemorySize,
                             GEMM_SMEM);
        cudaFuncSetAttribute(moe_gu_h, cudaFuncAttributeMaxDynamicSharedMemorySize,
                             GEMM_SMEM);
        cudaFuncSetAttribute(moe_down_h, cudaFuncAttributeMaxDynamicSharedMemorySize,
                             GEMM_SMEM);
        attr_set = true;
    }

    // weight packing to K-major fp16
    packT<<<dim3(16, 96),  256>>>(W_attn,   wqkvT, DIMM, 3*DIMM);
    packT<<<dim3(16, 32),  256>>>(W_attn_o, woT,   DIMM, DIMM);
    packT_gu<<<dim3(16, 128), 256>>>(ffn_up, wupT, DIMM, 2*DSH);
    packT<<<dim3(32, 32),  256>>>(ffn_down, wdnT,  DSH,  DIMM);
    packT_moe<<<dim3(16, 16, 64), 256>>>(pW, fW);
    conv_moe_down<<<dim3(256, 1, 32), 256>>>(pW, fW);

    // attention block
    rmsnorm_h<<<TOK, 256>>>(x_input, attn_nw, xnormh);
    gemm_h<1><<<dim3(24, 16), 256, GEMM_SMEM>>>(xnormh, wqkvT, qkvh, nullptr, TOK, 3*DIMM, DIMM);
    rope_interleave_kernel<<<dim3(TOK, NH), 64>>>();
    attn_h<<<dim3(SEQ/128, NH), 256, ATT_SMEM_W*4>>>();
    gemm_h<0><<<dim3(8, 16), 256, GEMM_SMEM>>>(orowsh, woT, xffni, x_input, TOK, DIMM, DIMM);
    rmsnorm_h<<<TOK, 256>>>(xffni, ffn_nw, xffnh);

    // routing
    zero32_kernel<<<1, 32>>>();
    router_kernel<<<TOK, 128>>>(pkeys, fkeys, pbias, fbias, p_idx, p_val, f_idx, f_val);
    prefix_kernel<<<1, 1>>>();
    scatter_kernel<<<32, 256>>>();

    // grouped MoE (fused swiglu in gate/up)
    moe_gu_h<<<dim3(8, 16, NEXP), 256, GEMM_SMEM>>>();
    moe_down_h<<<dim3(8, 16, NEXP), 256, GEMM_SMEM>>>();
    combine_kernel<<<TOK, 256>>>(out);

    // shared expert (fused swiglu up, then down adds into out)
    gemm_h<2><<<dim3(32, 16), 256, GEMM_SMEM>>>(xffnh, wupT, hsh, nullptr, TOK, 2*DSH, DIMM);
    gemm_h<0><<<dim3(8, 16), 256, GEMM_SMEM>>>(hsh, wdnT, out, out, TOK, DIMM, DSH);
}

// round 13
// speedup vs baseline: 6.7023x; 1.0388x over previous
#include <cuda_runtime.h>
#include <cuda_fp16.h>
#include <math.h>
#include <stdint.h>

// ---------------- problem constants ----------------
#define TOK   2048
#define DIMM  1024
#define NH    16
#define HD    64
#define SEQ   2048
#define NASS  8192
#define NEXP  32
#define FDIM  512
#define DSH   2048

// ---------------- scratch ----------------
__device__ __align__(16) __half g_xnormh[TOK*DIMM];
__device__ __align__(16) __half g_qkvh[TOK*3*DIMM];
__device__ __align__(16) __half g_qmh[NH*SEQ*HD];
__device__ __align__(16) __half g_kmh[NH*SEQ*HD];
__device__ __align__(16) unsigned g_vmP[NH*(SEQ/2)*HD];
__device__ __align__(16) __half g_orowsh[TOK*DIMM];
__device__ float g_xffni[TOK*DIMM];
__device__ __align__(16) __half g_xffnh[TOK*DIMM];
__device__ __align__(16) __half g_Gh[NASS*FDIM];
__device__ __align__(16) __half g_slotsh[(size_t)NASS*DIMM];
__device__ __align__(16) __half g_hsh[(size_t)TOK*DSH];
__device__ float g_scales[NASS];
__device__ int   g_eid[NASS];
__device__ int   g_tokof[NASS];
__device__ int   g_posof[NASS];
__device__ int   g_counts[NEXP];
__device__ int   g_offsets[NEXP];
__device__ int   g_cursors[NEXP];
// K-major packed fp16 weights: Wt[N][K]
__device__ __align__(16) __half g_wqkvT[3072*1024];
__device__ __align__(16) __half g_woT[1024*1024];
__device__ __align__(16) __half g_wupT[(size_t)4096*1024];
__device__ __align__(16) __half g_wdnT[(size_t)1024*2048];
__device__ __align__(16) __half g_wguT[(size_t)32*1024*1024];
__device__ __align__(16) __half g_wdnM[(size_t)32*1024*512];

// ---------------- helpers ----------------
__device__ __forceinline__ unsigned f2h2(float a, float b) {
    __half2 h = __floats2half2_rn(a, b);
    return *reinterpret_cast<unsigned*>(&h);
}
__device__ __forceinline__ void mma16(float c[4], const unsigned a[4], const unsigned b[2]) {
    asm volatile("mma.sync.aligned.m16n8k16.row.col.f32.f16.f16.f32 "
                 "{%0,%1,%2,%3},{%4,%5,%6,%7},{%8,%9},{%0,%1,%2,%3};"
                 : "+f"(c[0]), "+f"(c[1]), "+f"(c[2]), "+f"(c[3])
                 : "r"(a[0]), "r"(a[1]), "r"(a[2]), "r"(a[3]), "r"(b[0]), "r"(b[1]));
}
__device__ __forceinline__ uint32_t s2u(const void* p) {
    uint32_t a;
    asm("{ .reg .u64 t; cvta.to.shared.u64 t, %1; cvt.u32.u64 %0, t; }" : "=r"(a) : "l"(p));
    return a;
}
__device__ __forceinline__ void cpa16(uint32_t dst, const void* src) {
    asm volatile("cp.async.ca.shared.global [%0], [%1], 16;" :: "r"(dst), "l"(src));
}
#define CPA_COMMIT() asm volatile("cp.async.commit_group;")
#define CPA_WAIT1()  asm volatile("cp.async.wait_group 1;")
#define CPA_WAIT0()  asm volatile("cp.async.wait_group 0;")

__device__ __forceinline__ void ldsm4(unsigned* r, uint32_t a) {
    asm volatile("ldmatrix.sync.aligned.m8n8.x4.shared.b16 {%0,%1,%2,%3}, [%4];"
                 : "=r"(r[0]), "=r"(r[1]), "=r"(r[2]), "=r"(r[3]) : "r"(a));
}
__device__ __forceinline__ uint32_t frag_off(int rowBase, int stride, int lane) {
    int lr = lane & 7, lh = (lane >> 3) & 1, lq = lane >> 4;
    return (uint32_t)(((rowBase + lr + lh*8) * stride + lq*4) * 4);
}

__device__ __forceinline__ void compute_tile_ldsm(uint32_t aS, uint32_t bS,
                                                  uint32_t aOff0, uint32_t aOff1,
                                                  const uint32_t* bOff,
                                                  float acc[16][4]) {
    #pragma unroll
    for (int ks = 0; ks < 2; ks++) {
        unsigned a0[4], a1[4], bq[4][4];
        ldsm4(a0, aS + aOff0 + ks*32);
        ldsm4(a1, aS + aOff1 + ks*32);
        #pragma unroll
        for (int p = 0; p < 4; p++) ldsm4(bq[p], bS + bOff[p] + ks*32);
        #pragma unroll
        for (int ni = 0; ni < 8; ni++) {
            unsigned bf[2] = { bq[ni>>1][ni&1], bq[ni>>1][(ni&1)+2] };
            mma16(acc[ni],   a0, bf);
            mma16(acc[8+ni], a1, bf);
        }
    }
}

// ---------------- transpose-pack ----------------
template<int MODE>
__device__ __forceinline__ void packT_body(const float* __restrict__ W,
                                           __half* __restrict__ Wt,
                                           int K, int N, int k0, int n0, int tid) {
    __shared__ __half tile[32][72];
    int nl = tid & 31, kl = tid >> 5;
    #pragma unroll
    for (int it = 0; it < 8; it++)
        tile[nl][kl + it*8] = __float2half(W[(size_t)(k0 + kl + it*8)*N + n0 + nl]);
    __syncthreads();
    int kq8 = (tid & 7)*8, nr = tid >> 3;
    int c = n0 + nr;
    int drow;
    if (MODE == 0) drow = c;
    else {
        int NHf = N >> 1;
        drow = (c < NHf) ? ((c >> 6)*128 + (c & 63))
                         : (((c - NHf) >> 6)*128 + 64 + ((c - NHf) & 63));
    }
    *(uint4*)&Wt[(size_t)drow*K + k0 + kq8] = *(uint4*)&tile[nr][kq8];
}
__global__ void __launch_bounds__(256) packT(const float* __restrict__ W,
                                             __half* __restrict__ Wt, int K, int N) {
    packT_body<0>(W, Wt, K, N, blockIdx.x*64, blockIdx.y*32, threadIdx.x);
}
__global__ void __launch_bounds__(256) packT_gu(const float* __restrict__ W,
                                                __half* __restrict__ Wt, int K, int N) {
    packT_body<1>(W, Wt, K, N, blockIdx.x*64, blockIdx.y*32, threadIdx.x);
}
__global__ void __launch_bounds__(256) packT_moe(const float* __restrict__ pW,
                                                 const float* __restrict__ fW) {
    __shared__ __half tile[32][72];
    int z = blockIdx.z;
    int sel = z >> 5, e = z & 31;
    const float* W = (e < 16) ? pW + ((size_t)sel*16 + e)      * (size_t)DIMM*FDIM
                              : fW + ((size_t)sel*16 + (e-16)) * (size_t)DIMM*FDIM;
    __half* Wt = g_wguT + (size_t)e*1024*1024;
    int k0 = blockIdx.x*64, n0 = blockIdx.y*32;
    int tid = threadIdx.x;
    int nl = tid & 31, kl = tid >> 5;
    #pragma unroll
    for (int it = 0; it < 8; it++)
        tile[nl][kl + it*8] = __float2half(W[(size_t)(k0 + kl + it*8)*FDIM + n0 + nl]);
    __syncthreads();
    int kq8 = (tid & 7)*8, nr = tid >> 3;
    int c = n0 + nr;
    int drow = (c >> 6)*128 + sel*64 + (c & 63);
    *(uint4*)&Wt[(size_t)drow*DIMM + k0 + kq8] = *(uint4*)&tile[nr][kq8];
}
__global__ void __launch_bounds__(256) conv_moe_down(const float* __restrict__ pW,
                                                     const float* __restrict__ fW) {
    int z = blockIdx.z;
    const float* W = (z < 16) ? pW + ((size_t)2*16 + z)      * (size_t)DIMM*FDIM
                              : fW + ((size_t)2*16 + (z-16)) * (size_t)DIMM*FDIM;
    __half* Wh = g_wdnM + (size_t)z*1024*512;
    int idx = blockIdx.x*256 + threadIdx.x;
    float4 a = ((const float4*)W)[idx*2];
    float4 b = ((const float4*)W)[idx*2 + 1];
    ((uint4*)Wh)[idx] = make_uint4(f2h2(a.x,a.y), f2h2(a.z,a.w), f2h2(b.x,b.y), f2h2(b.z,b.w));
}

// ---------------- dense fp16 GEMM, 3-stage cp.async + ldmatrix ----------------
#define GEMM_SMEM (2560 * 2 * 3 * 4)
template<int OUT>
__global__ void __launch_bounds__(256) gemm_h(const __half* __restrict__ A,
                                              const __half* __restrict__ Bt,
                                              void* __restrict__ Cv,
                                              const float* __restrict__ D,
                                              int M, int N, int K) {
    extern __shared__ __align__(16) unsigned smem[];
    unsigned* As = smem;
    unsigned* Bs = smem + 3*2560;
    int tid = threadIdx.x, lane = tid & 31, wid = tid >> 5;
    int g = lane >> 2, t4 = lane & 3;
    int wm = (wid & 3)*32, wn = (wid >> 2)*64;
    size_t rowBase = (size_t)blockIdx.y * 128, colBase = (size_t)blockIdx.x * 128;
    int r_ = tid >> 1, sel = tid & 1;
    int sidx = r_*20 + sel*8;
    const __half* Ag = A  + (rowBase + r_)*K + sel*16;
    const __half* Bg = Bt + (colBase + r_)*K + sel*16;
    uint32_t aB = s2u(As), bB = s2u(Bs);
    uint32_t aOff0 = frag_off(wm, 20, lane), aOff1 = frag_off(wm+16, 20, lane);
    uint32_t bOff[4];
    #pragma unroll
    for (int p = 0; p < 4; p++) bOff[p] = frag_off(wn + p*16, 20, lane);
    int NC = K >> 5;

    auto issue = [&](int cc, int s) {
        uint32_t ad = aB + (s*2560 + sidx)*4;
        cpa16(ad,      Ag + cc*32);
        cpa16(ad + 16, Ag + cc*32 + 8);
        uint32_t bd = bB + (s*2560 + sidx)*4;
        cpa16(bd,      Bg + cc*32);
        cpa16(bd + 16, Bg + cc*32 + 8);
        CPA_COMMIT();
    };

    float acc[16][4];
    #pragma unroll
    for (int i = 0; i < 16; i++)
        #pragma unroll
        for (int j = 0; j < 4; j++) acc[i][j] = 0.f;

    issue(0, 0);
    issue(1, 1);
    for (int c = 0; c < NC; c++) {
        if (c + 2 < NC) CPA_WAIT1(); else CPA_WAIT0();
        __syncthreads();
        int s = c - (c/3)*3;
        compute_tile_ldsm(aB + s*2560*4, bB + s*2560*4, aOff0, aOff1, bOff, acc);
        if (c + 2 < NC) issue(c + 2, (c+2) - ((c+2)/3)*3);
    }
    if (OUT == 2) {
        __syncthreads();
        unsigned* sm = smem;
        #pragma unroll
        for (int mi = 0; mi < 2; mi++)
            #pragma unroll
            for (int ni = 0; ni < 8; ni++) {
                float* c = acc[mi*8+ni];
                int r = wm + mi*16 + g;
                int cw = (wn >> 1) + ni*4 + t4;
                sm[r*66 + cw]     = f2h2(c[0], c[1]);
                sm[(r+8)*66 + cw] = f2h2(c[2], c[3]);
            }
        __syncthreads();
        __half* C = (__half*)Cv;
        int outN = N >> 1;
        size_t fBase = colBase >> 1;
        for (int idx = tid; idx < 128*32; idx += 256) {
            int r = idx >> 5, cw = idx & 31;
            float2 gf = __half22float2(*(__half2*)&sm[r*66 + cw]);
            float2 uf = __half22float2(*(__half2*)&sm[r*66 + 32 + cw]);
            float a = gf.x / (1.f + __expf(-gf.x)) * uf.x;
            float b = gf.y / (1.f + __expf(-gf.y)) * uf.y;
            *(unsigned*)&C[(rowBase + r)*outN + fBase + 2*cw] = f2h2(a, b);
        }
        return;
    }
    #pragma unroll
    for (int mi = 0; mi < 2; mi++)
        #pragma unroll
        for (int ni = 0; ni < 8; ni++) {
            float* c = acc[mi*8+ni];
            size_t r0 = rowBase + wm + mi*16 + g;
            size_t c0 = colBase + wn + ni*8 + 2*t4;
            if (OUT == 0) {
                float* C = (float*)Cv;
                size_t o0 = r0*N + c0, o1 = (r0+8)*N + c0;
                if (D) {
                    C[o0] = c[0] + D[o0]; C[o0+1] = c[1] + D[o0+1];
                    C[o1] = c[2] + D[o1]; C[o1+1] = c[3] + D[o1+1];
                } else {
                    C[o0] = c[0]; C[o0+1] = c[1];
                    C[o1] = c[2]; C[o1+1] = c[3];
                }
            } else {
                __half* C = (__half*)Cv;
                *(unsigned*)&C[r0*N + c0]     = f2h2(c[0], c[1]);
                *(unsigned*)&C[(r0+8)*N + c0] = f2h2(c[2], c[3]);
            }
        }
}

// ---------------- MoE gate+up grouped GEMM, fused swiglu -> g_Gh ----------------
__global__ void __launch_bounds__(256) moe_gu_h() {
    extern __shared__ __align__(16) unsigned smem[];
    unsigned* As = smem;
    unsigned* Bs = smem + 3*2560;
    __shared__ int rows[128];
    int e = blockIdx.z;
    int cnt = g_counts[e];
    int rowTile = blockIdx.y * 128;
    if (rowTile >= cnt) return;
    int base = g_offsets[e];
    int colBase = blockIdx.x * 128;
    const __half* Wt = g_wguT + (size_t)e*1024*1024;
    int tid = threadIdx.x;
    if (tid < 128) {
        int rr = rowTile + tid;
        rows[tid] = (rr < cnt) ? g_tokof[base + rr] : 0;
    }
    __syncthreads();
    int lane = tid & 31, wid = tid >> 5;
    int g = lane >> 2, t4 = lane & 3;
    int wm = (wid & 3)*32, wn = (wid >> 2)*64;
    int r_ = tid >> 1, sel = tid & 1;
    int sidx = r_*20 + sel*8;
    const __half* Ag = g_xffnh + (size_t)rows[r_]*DIMM + sel*16;
    const __half* Bg = Wt + (size_t)(colBase + r_)*1024 + sel*16;
    uint32_t aB = s2u(As), bB = s2u(Bs);
    uint32_t aOff0 = frag_off(wm, 20, lane), aOff1 = frag_off(wm+16, 20, lane);
    uint32_t bOff[4];
    #pragma unroll
    for (int p = 0; p < 4; p++) bOff[p] = frag_off(wn + p*16, 20, lane);

    auto issue = [&](int cc, int s) {
        uint32_t ad = aB + (s*2560 + sidx)*4;
        cpa16(ad,      Ag + cc*32);
        cpa16(ad + 16, Ag + cc*32 + 8);
        uint32_t bd = bB + (s*2560 + sidx)*4;
        cpa16(bd,      Bg + cc*32);
        cpa16(bd + 16, Bg + cc*32 + 8);
        CPA_COMMIT();
    };

    float acc[16][4];
    #pragma unroll
    for (int i = 0; i < 16; i++)
        #pragma unroll
        for (int j = 0; j < 4; j++) acc[i][j] = 0.f;

    issue(0, 0);
    issue(1, 1);
    for (int c = 0; c < 32; c++) {
        if (c + 2 < 32) CPA_WAIT1(); else CPA_WAIT0();
        __syncthreads();
        int s = c - (c/3)*3;
        compute_tile_ldsm(aB + s*2560*4, bB + s*2560*4, aOff0, aOff1, bOff, acc);
        if (c + 2 < 32) issue(c + 2, (c+2) - ((c+2)/3)*3);
    }
    __syncthreads();
    unsigned* sm = smem;
    #pragma unroll
    for (int mi = 0; mi < 2; mi++)
        #pragma unroll
        for (int ni = 0; ni < 8; ni++) {
            float* c = acc[mi*8+ni];
            int r = wm + mi*16 + g;
            int cw = (wn >> 1) + ni*4 + t4;
            sm[r*66 + cw]     = f2h2(c[0], c[1]);
            sm[(r+8)*66 + cw] = f2h2(c[2], c[3]);
        }
    __syncthreads();
    int fBase = colBase >> 1;
    for (int idx = tid; idx < 128*32; idx += 256) {
        int r = idx >> 5, cw = idx & 31;
        if (rowTile + r >= cnt) continue;
        float2 gf = __half22float2(*(__half2*)&sm[r*66 + cw]);
        float2 uf = __half22float2(*(__half2*)&sm[r*66 + 32 + cw]);
        float a = gf.x / (1.f + __expf(-gf.x)) * uf.x;
        float b = gf.y / (1.f + __expf(-gf.y)) * uf.y;
        *(unsigned*)&g_Gh[(size_t)(base + rowTile + r)*FDIM + fBase + 2*cw] = f2h2(a, b);
    }
}

// ---------------- MoE down grouped GEMM ----------------
__global__ void __launch_bounds__(256) moe_down_h() {
    extern __shared__ __align__(16) unsigned smem[];
    unsigned* As = smem;
    unsigned* Bs = smem + 3*2560;
    int e = blockIdx.z;
    int cnt = g_counts[e];
    int rowTile = blockIdx.y * 128;
    if (rowTile >= cnt) return;
    int base = g_offsets[e];
    int colBase = blockIdx.x * 128;
    const __half* W = g_wdnM + (size_t)e*1024*512;
    int tid = threadIdx.x, lane = tid & 31, wid = tid >> 5;
    int g = lane >> 2, t4 = lane & 3;
    int wm = (wid & 3)*32, wn = (wid >> 2)*64;
    int r_ = tid >> 1, sel = tid & 1;
    int sidx = r_*20 + sel*8;
    int arow = base + rowTile + r_;
    if (arow > NASS - 1) arow = NASS - 1;
    const __half* Ag = g_Gh + (size_t)arow*FDIM + sel*16;
    const __half* Bg = W + (size_t)(colBase + r_)*FDIM + sel*16;
    uint32_t aB = s2u(As), bB = s2u(Bs);
    uint32_t aOff0 = frag_off(wm, 20, lane), aOff1 = frag_off(wm+16, 20, lane);
    uint32_t bOff[4];
    #pragma unroll
    for (int p = 0; p < 4; p++) bOff[p] = frag_off(wn + p*16, 20, lane);

    auto issue = [&](int cc, int s) {
        uint32_t ad = aB + (s*2560 + sidx)*4;
        cpa16(ad,      Ag + cc*32);
        cpa16(ad + 16, Ag + cc*32 + 8);
        uint32_t bd = bB + (s*2560 + sidx)*4;
        cpa16(bd,      Bg + cc*32);
        cpa16(bd + 16, Bg + cc*32 + 8);
        CPA_COMMIT();
    };

    float acc[16][4];
    #pragma unroll
    for (int i = 0; i < 16; i++)
        #pragma unroll
        for (int j = 0; j < 4; j++) acc[i][j] = 0.f;

    issue(0, 0);
    issue(1, 1);
    for (int c = 0; c < 16; c++) {
        if (c + 2 < 16) CPA_WAIT1(); else CPA_WAIT0();
        __syncthreads();
        int s = c - (c/3)*3;
        compute_tile_ldsm(aB + s*2560*4, bB + s*2560*4, aOff0, aOff1, bOff, acc);
        if (c + 2 < 16) issue(c + 2, (c+2) - ((c+2)/3)*3);
    }
    #pragma unroll
    for (int mi = 0; mi < 2; mi++)
        #pragma unroll
        for (int ni = 0; ni < 8; ni++) {
            float* c = acc[mi*8+ni];
            int r = rowTile + wm + mi*16 + g;
            int cc = colBase + wn + ni*8 + 2*t4;
            if (r < cnt)
                *(unsigned*)&g_slotsh[(size_t)(base+r)*DIMM + cc] = f2h2(c[0], c[1]);
            if (r + 8 < cnt)
                *(unsigned*)&g_slotsh[(size_t)(base+r+8)*DIMM + cc] = f2h2(c[2], c[3]);
        }
}

// ---------------- rmsnorm (half out) ----------------
__global__ void rmsnorm_h(const float* __restrict__ x, const float* __restrict__ w,
                          __half* __restrict__ out) {
    int r = blockIdx.x;
    const float* xr = x + (size_t)r*DIMM;
    __shared__ float red[8];
    float s = 0.f;
    for (int d = threadIdx.x; d < DIMM; d += 256) { float v = xr[d]; s += v*v; }
    #pragma unroll
    for (int o = 16; o; o >>= 1) s += __shfl_xor_sync(0xffffffffu, s, o);
    if ((threadIdx.x & 31) == 0) red[threadIdx.x >> 5] = s;
    __syncthreads();
    if (threadIdx.x == 0) {
        float t = 0.f;
        #pragma unroll
        for (int i = 0; i < 8; i++) t += red[i];
        red[0] = rsqrtf(t / (float)DIMM + 1e-5f);
    }
    __syncthreads();
    float rms = red[0];
    for (int d = threadIdx.x; d < DIMM; d += 256)
        out[(size_t)r*DIMM + d] = __float2half(xr[d] * rms * w[d]);
}

// ---------------- rope + dual interleave ----------------
__global__ void rope_interleave_kernel() {
    int r = blockIdx.x, h = blockIdx.y, d = threadIdx.x;
    int bi = r >> 10, si = r & 1023;
    int t = 2*si + bi;
    size_t src = (size_t)r*3072 + h*64;
    float q = __half2float(g_qkvh[src + d]);
    float k = __half2float(g_qkvh[src + 1024 + d]);
    float v = __half2float(g_qkvh[src + 2048 + d]);
    ((__half*)g_vmP)[(((size_t)h*1024 + (t >> 1))*64 + d)*2 + (t & 1)] = __float2half(v);
    __shared__ float qs[64], ks[64];
    qs[d] = q; ks[d] = k;
    __syncthreads();
    if (d < 32) {
        float inv = powf(10000.0f, -(float)(2*d) / 64.0f);
        float fr = (float)si * inv;
        float sn, cs;
        sincosf(fr, &sn, &cs);
        size_t dst = ((size_t)h*SEQ + t)*64;
        float x1 = qs[d], x2 = qs[d+32];
        g_qmh[dst + d]      = __float2half( x1*cs + x2*sn);
        g_qmh[dst + d + 32] = __float2half(-x1*sn + x2*cs);
        x1 = ks[d]; x2 = ks[d+32];
        g_kmh[dst + d]      = __float2half( x1*cs + x2*sn);
        g_kmh[dst + d + 32] = __float2half(-x1*sn + x2*cs);
    }
}

// ---------------- fp16 flash attention (ldmatrix frags) ----------------
#define ATT_SMEM_W (4608 + 2304 + 4608 + 2304)
__global__ void __launch_bounds__(256) attn_h() {
    extern __shared__ __align__(16) unsigned asm_[];
    unsigned* Qs = asm_;
    unsigned* Ks = asm_ + 4608;
    unsigned* Ps = asm_ + 6912;
    unsigned* Vt = asm_ + 11520;
    int h = blockIdx.y;
    int t0 = ((int)gridDim.x - 1 - (int)blockIdx.x) * 128;
    int tid = threadIdx.x, lane = tid & 31, wid = tid >> 5;
    int g = lane >> 2, t4 = lane & 3;
    int wm = wid * 16;
    uint32_t qB = s2u(Qs), kB = s2u(Ks), pB = s2u(Ps), vB = s2u(Vt);
    uint32_t aOffQ = frag_off(wm, 36, lane);
    uint32_t bOffK[4];
    #pragma unroll
    for (int p = 0; p < 4; p++) bOffK[p] = frag_off(p*16, 36, lane);

    const __half* qb = g_qmh + ((size_t)h*SEQ + t0)*64;
    for (int i = tid; i < 128*8; i += 256) {
        int r = i >> 3, j = i & 7;
        *(uint4*)&Qs[r*36 + j*4] = ((const uint4*)(qb + (size_t)r*64))[j];
    }

    float o[8][4];
    #pragma unroll
    for (int n = 0; n < 8; n++)
        #pragma unroll
        for (int j = 0; j < 4; j++) o[n][j] = 0.f;
    float m0 = -1e30f, m1 = -1e30f, l0 = 0.f, l1 = 0.f;
    int row0 = t0 + wm + g, row1 = row0 + 8;
    int wmax = t0 + wm + 15;

    for (int kt = 0; kt <= t0 + 127; kt += 64) {
        __syncthreads();
        const __half* kb = g_kmh + ((size_t)h*SEQ + kt)*64;
        for (int i = tid; i < 64*8; i += 256) {
            int r = i >> 3, j = i & 7;
            *(uint4*)&Ks[r*36 + j*4] = ((const uint4*)(kb + (size_t)r*64))[j];
        }
        const unsigned* vp = g_vmP + ((size_t)h*1024 + (kt >> 1))*64;
        for (int w = tid; w < 64*32; w += 256) {
            int d = w & 63, p = w >> 6;
            Vt[d*36 + p] = vp[(size_t)p*64 + d];
        }
        __syncthreads();
        if (kt > wmax) continue;

        float s[8][4];
        #pragma unroll
        for (int n = 0; n < 8; n++)
            #pragma unroll
            for (int j = 0; j < 4; j++) s[n][j] = 0.f;
        #pragma unroll
        for (int ks = 0; ks < 4; ks++) {
            unsigned aq[4], bq[4][4];
            ldsm4(aq, qB + aOffQ + ks*32);
            #pragma unroll
            for (int p = 0; p < 4; p++) ldsm4(bq[p], kB + bOffK[p] + ks*32);
            #pragma unroll
            for (int n = 0; n < 8; n++) {
                unsigned bf[2] = { bq[n>>1][n&1], bq[n>>1][(n&1)+2] };
                mma16(s[n], aq, bf);
            }
        }
        float mx0 = -1e30f, mx1 = -1e30f;
        #pragma unroll
        for (int n = 0; n < 8; n++) {
            int c0 = kt + n*8 + 2*t4, c1 = c0 + 1;
            s[n][0] = (c0 <= row0) ? s[n][0]*0.125f : -1e30f;
            s[n][1] = (c1 <= row0) ? s[n][1]*0.125f : -1e30f;
            s[n][2] = (c0 <= row1) ? s[n][2]*0.125f : -1e30f;
            s[n][3] = (c1 <= row1) ? s[n][3]*0.125f : -1e30f;
            mx0 = fmaxf(mx0, fmaxf(s[n][0], s[n][1]));
            mx1 = fmaxf(mx1, fmaxf(s[n][2], s[n][3]));
        }
        mx0 = fmaxf(mx0, __shfl_xor_sync(0xffffffffu, mx0, 1));
        mx0 = fmaxf(mx0, __shfl_xor_sync(0xffffffffu, mx0, 2));
        mx1 = fmaxf(mx1, __shfl_xor_sync(0xffffffffu, mx1, 1));
        mx1 = fmaxf(mx1, __shfl_xor_sync(0xffffffffu, mx1, 2));
        float nm0 = fmaxf(m0, mx0), nm1 = fmaxf(m1, mx1);
        float cor0 = __expf(m0 - nm0), cor1 = __expf(m1 - nm1);
        m0 = nm0; m1 = nm1;
        l0 *= cor0; l1 *= cor1;
        float sum0 = 0.f, sum1 = 0.f;
        #pragma unroll
        for (int n = 0; n < 8; n++) {
            float p00 = __expf(s[n][0] - nm0), p01 = __expf(s[n][1] - nm0);
            float p10 = __expf(s[n][2] - nm1), p11 = __expf(s[n][3] - nm1);
            sum0 += p00 + p01; sum1 += p10 + p11;
            Ps[(wm+g)*36 + n*4 + t4]   = f2h2(p00, p01);
            Ps[(wm+g+8)*36 + n*4 + t4] = f2h2(p10, p11);
            #pragma unroll
            for (int j = 0; j < 2; j++) { o[n][j] *= cor0; o[n][2+j] *= cor1; }
        }
        sum0 += __shfl_xor_sync(0xffffffffu, sum0, 1);
        sum0 += __shfl_xor_sync(0xffffffffu, sum0, 2);
        sum1 += __shfl_xor_sync(0xffffffffu, sum1, 1);
        sum1 += __shfl_xor_sync(0xffffffffu, sum1, 2);
        l0 += sum0; l1 += sum1;
        __syncwarp();

        #pragma unroll
        for (int ks = 0; ks < 4; ks++) {
            unsigned ap[4], bq[4][4];
            ldsm4(ap, pB + aOffQ + ks*32);
            #pragma unroll
            for (int p = 0; p < 4; p++) ldsm4(bq[p], vB + bOffK[p] + ks*32);
            #pragma unroll
            for (int n = 0; n < 8; n++) {
                unsigned bf[2] = { bq[n>>1][n&1], bq[n>>1][(n&1)+2] };
                mma16(o[n], ap, bf);
            }
        }
    }

    float inv0 = 1.f / l0, inv1 = 1.f / l1;
    int tok0 = (row0 & 1)*1024 + (row0 >> 1);
    int tok1 = (row1 & 1)*1024 + (row1 >> 1);
    #pragma unroll
    for (int n = 0; n < 8; n++) {
        int col = h*64 + n*8 + 2*t4;
        *(unsigned*)&g_orowsh[(size_t)tok0*DIMM + col] = f2h2(o[n][0]*inv0, o[n][1]*inv0);
        *(unsigned*)&g_orowsh[(size_t)tok1*DIMM + col] = f2h2(o[n][2]*inv1, o[n][3]*inv1);
    }
}

// ---------------- router ----------------
__global__ void router_kernel(const float* __restrict__ pkeys, const float* __restrict__ fkeys,
                              const float* __restrict__ pbias, const float* __restrict__ fbias,
                              const int* __restrict__ pidx, const float* __restrict__ pval,
                              const int* __restrict__ fidx, const float* __restrict__ fval) {
    int tok = blockIdx.x, tid = threadIdx.x;
    bool isf = tok >= 1024;
    const float* keys = isf ? fkeys : pkeys;
    const __half* x = g_xffnh + (size_t)tok*DIMM;
    __shared__ float part[8][16];
    __shared__ float logit[16];
    int e = tid & 15, ch = tid >> 4;
    float s = 0.f;
    int d0 = ch * 128;
    for (int d = d0; d < d0 + 128; d++)
        s = fmaf(__half2float(x[d]), keys[d*16 + e], s);
    part[ch][e] = s;
    __syncthreads();
    if (tid < 16) {
        float t = 0.f;
        #pragma unroll
        for (int c = 0; c < 8; c++) t += part[c][tid];
        logit[tid] = t;
    }
    __syncthreads();
    if (tid == 0) {
        int lt = isf ? tok - 1024 : tok;
        const int*   idx  = isf ? fidx  : pidx;
        const float* val  = isf ? fval  : pval;
        const float* bias = isf ? fbias : pbias;
        float sc[4]; int id[4]; float sum = 0.f;
        #pragma unroll
        for (int k = 0; k < 4; k++) {
            int ix = idx[lt*4 + k];
            float v = val[lt*4 + k] + logit[ix] + bias[ix];
            float s2 = 1.f / (1.f + expf(-v));
            sc[k] = s2; sum += s2;
            id[k] = ix + (isf ? 16 : 0);
        }
        #pragma unroll
        for (int k = 0; k < 4; k++) {
            g_scales[tok*4 + k] = sc[k] / sum;
            g_eid[tok*4 + k] = id[k];
            atomicAdd(&g_counts[id[k]], 1);
        }
    }
}

__global__ void zero32_kernel() {
    int i = threadIdx.x;
    if (i < NEXP) { g_counts[i] = 0; g_cursors[i] = 0; }
}

__global__ void prefix_kernel() {
    int acc = 0;
    for (int e = 0; e < NEXP; e++) { g_offsets[e] = acc; acc += g_counts[e]; }
}

__global__ void scatter_kernel() {
    int a = blockIdx.x * blockDim.x + threadIdx.x;
    if (a >= NASS) return;
    int e = g_eid[a];
    int p = g_offsets[e] + atomicAdd(&g_cursors[e], 1);
    g_tokof[p] = a >> 2;
    g_posof[a] = p;
}

__global__ void combine_kernel(float* __restrict__ y) {
    int tok = blockIdx.x;
    __shared__ int pos[4];
    __shared__ float sc[4];
    if (threadIdx.x < 4) {
        pos[threadIdx.x] = g_posof[tok*4 + threadIdx.x];
        sc[threadIdx.x]  = g_scales[tok*4 + threadIdx.x];
    }
    __syncthreads();
    for (int d = threadIdx.x; d < DIMM; d += 256) {
        float v = g_xffni[(size_t)tok*DIMM + d];
        #pragma unroll
        for (int k = 0; k < 4; k++)
            v = fmaf(sc[k], __half2float(g_slotsh[(size_t)pos[k]*DIMM + d]), v);
        y[(size_t)tok*DIMM + d] = v;
    }
}

// ---------------- launch ----------------
extern "C" void kernel_launch(void* const* d_in, const int* in_sizes, int n_in,
                              void* d_out, int out_size) {
    const float* x_input  = (const float*)d_in[0];
    const int*   p_idx    = (const int*)  d_in[1];
    const float* p_val    = (const float*)d_in[2];
    const int*   f_idx    = (const int*)  d_in[3];
    const float* f_val    = (const float*)d_in[4];
    const float* attn_nw  = (const float*)d_in[5];
    const float* ffn_nw   = (const float*)d_in[6];
    const float* W_attn   = (const float*)d_in[7];
    const float* W_attn_o = (const float*)d_in[8];
    const float* ffn_up   = (const float*)d_in[9];
    const float* ffn_down = (const float*)d_in[10];
    const float* pW       = (const float*)d_in[11];
    const float* fW       = (const float*)d_in[12];
    const float* pkeys    = (const float*)d_in[13];
    const float* fkeys    = (const float*)d_in[14];
    const float* pbias    = (const float*)d_in[15];
    const float* fbias    = (const float*)d_in[16];
    float* out = (float*)d_out;

    __half *xnormh, *qkvh, *orowsh, *xffnh, *hsh;
    __half *wqkvT, *woT, *wupT, *wdnT;
    float *xffni;
    cudaGetSymbolAddress((void**)&xnormh, g_xnormh);
    cudaGetSymbolAddress((void**)&qkvh,   g_qkvh);
    cudaGetSymbolAddress((void**)&orowsh, g_orowsh);
    cudaGetSymbolAddress((void**)&xffni,  g_xffni);
    cudaGetSymbolAddress((void**)&xffnh,  g_xffnh);
    cudaGetSymbolAddress((void**)&hsh,    g_hsh);
    cudaGetSymbolAddress((void**)&wqkvT,  g_wqkvT);
    cudaGetSymbolAddress((void**)&woT,    g_woT);
    cudaGetSymbolAddress((void**)&wupT,   g_wupT);
    cudaGetSymbolAddress((void**)&wdnT,   g_wdnT);

    static cudaStream_t s1 = nullptr, s2 = nullptr;
    static cudaEvent_t evFork, evQKVp, evWo, evWup, evMoeP, evXffn, evHsh;
    static bool init_done = false;
    if (!init_done) {
        cudaFuncSetAttribute(attn_h, cudaFuncAttributeMaxDynamicSharedMemorySize,
                             ATT_SMEM_W * 4);
        cudaFuncSetAttribute(gemm_h<0>, cudaFuncAttributeMaxDynamicSharedMemorySize, GEMM_SMEM);
        cudaFuncSetAttribute(gemm_h<1>, cudaFuncAttributeMaxDynamicSharedMemorySize, GEMM_SMEM);
        cudaFuncSetAttribute(gemm_h<2>, cudaFuncAttributeMaxDynamicSharedMemorySize, GEMM_SMEM);
        cudaFuncSetAttribute(moe_gu_h, cudaFuncAttributeMaxDynamicSharedMemorySize, GEMM_SMEM);
        cudaFuncSetAttribute(moe_down_h, cudaFuncAttributeMaxDynamicSharedMemorySize, GEMM_SMEM);
        cudaStreamCreateWithFlags(&s1, cudaStreamNonBlocking);
        cudaStreamCreateWithFlags(&s2, cudaStreamNonBlocking);
        cudaEventCreateWithFlags(&evFork, cudaEventDisableTiming);
        cudaEventCreateWithFlags(&evQKVp, cudaEventDisableTiming);
        cudaEventCreateWithFlags(&evWo,   cudaEventDisableTiming);
        cudaEventCreateWithFlags(&evWup,  cudaEventDisableTiming);
        cudaEventCreateWithFlags(&evMoeP, cudaEventDisableTiming);
        cudaEventCreateWithFlags(&evXffn, cudaEventDisableTiming);
        cudaEventCreateWithFlags(&evHsh,  cudaEventDisableTiming);
        init_done = true;
    }

    // fork side stream s1 for all weight packing
    cudaEventRecord(evFork, 0);
    cudaStreamWaitEvent(s1, evFork, 0);
    packT<<<dim3(16, 96),  256, 0, s1>>>(W_attn,   wqkvT, DIMM, 3*DIMM);
    cudaEventRecord(evQKVp, s1);
    packT<<<dim3(16, 32),  256, 0, s1>>>(W_attn_o, woT,   DIMM, DIMM);
    cudaEventRecord(evWo, s1);
    packT_gu<<<dim3(16, 128), 256, 0, s1>>>(ffn_up, wupT, DIMM, 2*DSH);
    packT<<<dim3(32, 32),  256, 0, s1>>>(ffn_down, wdnT,  DSH,  DIMM);
    cudaEventRecord(evWup, s1);
    packT_moe<<<dim3(16, 16, 64), 256, 0, s1>>>(pW, fW);
    conv_moe_down<<<dim3(256, 1, 32), 256, 0, s1>>>(pW, fW);
    cudaEventRecord(evMoeP, s1);

    // main stream: attention block (overlaps with packing)
    rmsnorm_h<<<TOK, 256>>>(x_input, attn_nw, xnormh);
    cudaStreamWaitEvent(0, evQKVp, 0);
    gemm_h<1><<<dim3(24, 16), 256, GEMM_SMEM>>>(xnormh, wqkvT, qkvh, nullptr, TOK, 3*DIMM, DIMM);
    rope_interleave_kernel<<<dim3(TOK, NH), 64>>>();
    attn_h<<<dim3(SEQ/128, NH), 256, ATT_SMEM_W*4>>>();
    cudaStreamWaitEvent(0, evWo, 0);
    gemm_h<0><<<dim3(8, 16), 256, GEMM_SMEM>>>(orowsh, woT, xffni, x_input, TOK, DIMM, DIMM);
    rmsnorm_h<<<TOK, 256>>>(xffni, ffn_nw, xffnh);
    cudaEventRecord(evXffn, 0);

    // s2: shared-expert up GEMM (fused swiglu), overlaps MoE chain
    cudaStreamWaitEvent(s2, evXffn, 0);
    cudaStreamWaitEvent(s2, evWup, 0);
    gemm_h<2><<<dim3(32, 16), 256, GEMM_SMEM, s2>>>(xffnh, wupT, hsh, nullptr, TOK, 2*DSH, DIMM);
    cudaEventRecord(evHsh, s2);

    // main: routing + grouped MoE
    zero32_kernel<<<1, 32>>>();
    router_kernel<<<TOK, 128>>>(pkeys, fkeys, pbias, fbias, p_idx, p_val, f_idx, f_val);
    prefix_kernel<<<1, 1>>>();
    scatter_kernel<<<32, 256>>>();
    cudaStreamWaitEvent(0, evMoeP, 0);
    moe_gu_h<<<dim3(8, 16, NEXP), 256, GEMM_SMEM>>>();
    moe_down_h<<<dim3(8, 16, NEXP), 256, GEMM_SMEM>>>();
    combine_kernel<<<TOK, 256>>>(out);

    // shared-expert down (accumulates into out) — join s2
    cudaStreamWaitEvent(0, evHsh, 0);
    gemm_h<0><<<dim3(8, 16), 256, GEMM_SMEM>>>(hsh, wdnT, out, out, TOK, DIMM, DSH);
}

// round 14
// speedup vs baseline: 7.1378x; 1.0650x over previous
#include <cuda_runtime.h>
#include <cuda_fp16.h>
#include <math.h>
#include <stdint.h>

// ---------------- problem constants ----------------
#define TOK   2048
#define DIMM  1024
#define NH    16
#define HD    64
#define SEQ   2048
#define NASS  8192
#define NEXP  32
#define FDIM  512
#define DSH   2048

// ---------------- scratch ----------------
__device__ __align__(16) __half g_xnormh[TOK*DIMM];
__device__ __align__(16) __half g_qkvh[TOK*3*DIMM];
__device__ __align__(16) __half g_qmh[NH*SEQ*HD];
__device__ __align__(16) __half g_kmh[NH*SEQ*HD];
__device__ __align__(16) unsigned g_vmP[NH*(SEQ/2)*HD];
__device__ __align__(16) __half g_orowsh[TOK*DIMM];
__device__ float g_xffni[TOK*DIMM];
__device__ __align__(16) __half g_xffnh[TOK*DIMM];
__device__ __align__(16) __half g_Gh[NASS*FDIM];
__device__ __align__(16) __half g_slotsh[(size_t)NASS*DIMM];
__device__ __align__(16) __half g_hsh[(size_t)TOK*DSH];
__device__ __align__(16) __half g_shdownh[(size_t)TOK*DIMM];
__device__ float g_scales[NASS];
__device__ int   g_eid[NASS];
__device__ int   g_tokof[NASS];
__device__ int   g_posof[NASS];
__device__ int   g_counts[NEXP];
__device__ int   g_offsets[NEXP];
__device__ int   g_cursors[NEXP];
// K-major packed fp16 weights: Wt[N][K]
__device__ __align__(16) __half g_wqkvT[3072*1024];
__device__ __align__(16) __half g_woT[1024*1024];
__device__ __align__(16) __half g_wupT[(size_t)4096*1024];
__device__ __align__(16) __half g_wdnT[(size_t)1024*2048];
__device__ __align__(16) __half g_wguT[(size_t)32*1024*1024];
__device__ __align__(16) __half g_wdnM[(size_t)32*1024*512];

// ---------------- helpers ----------------
__device__ __forceinline__ unsigned f2h2(float a, float b) {
    __half2 h = __floats2half2_rn(a, b);
    return *reinterpret_cast<unsigned*>(&h);
}
__device__ __forceinline__ void mma16(float c[4], const unsigned a[4], const unsigned b[2]) {
    asm volatile("mma.sync.aligned.m16n8k16.row.col.f32.f16.f16.f32 "
                 "{%0,%1,%2,%3},{%4,%5,%6,%7},{%8,%9},{%0,%1,%2,%3};"
                 : "+f"(c[0]), "+f"(c[1]), "+f"(c[2]), "+f"(c[3])
                 : "r"(a[0]), "r"(a[1]), "r"(a[2]), "r"(a[3]), "r"(b[0]), "r"(b[1]));
}
__device__ __forceinline__ uint32_t s2u(const void* p) {
    uint32_t a;
    asm("{ .reg .u64 t; cvta.to.shared.u64 t, %1; cvt.u32.u64 %0, t; }" : "=r"(a) : "l"(p));
    return a;
}
__device__ __forceinline__ void cpa16(uint32_t dst, const void* src) {
    asm volatile("cp.async.ca.shared.global [%0], [%1], 16;" :: "r"(dst), "l"(src));
}
#define CPA_COMMIT() asm volatile("cp.async.commit_group;")
#define CPA_WAIT1()  asm volatile("cp.async.wait_group 1;")
#define CPA_WAIT0()  asm volatile("cp.async.wait_group 0;")

__device__ __forceinline__ void ldsm4(unsigned* r, uint32_t a) {
    asm volatile("ldmatrix.sync.aligned.m8n8.x4.shared.b16 {%0,%1,%2,%3}, [%4];"
                 : "=r"(r[0]), "=r"(r[1]), "=r"(r[2]), "=r"(r[3]) : "r"(a));
}
__device__ __forceinline__ uint32_t frag_off(int rowBase, int stride, int lane) {
    int lr = lane & 7, lh = (lane >> 3) & 1, lq = lane >> 4;
    return (uint32_t)(((rowBase + lr + lh*8) * stride + lq*4) * 4);
}

__device__ __forceinline__ void compute_tile_ldsm(uint32_t aS, uint32_t bS,
                                                  uint32_t aOff0, uint32_t aOff1,
                                                  const uint32_t* bOff,
                                                  float acc[16][4]) {
    #pragma unroll
    for (int ks = 0; ks < 2; ks++) {
        unsigned a0[4], a1[4], bq[4][4];
        ldsm4(a0, aS + aOff0 + ks*32);
        ldsm4(a1, aS + aOff1 + ks*32);
        #pragma unroll
        for (int p = 0; p < 4; p++) ldsm4(bq[p], bS + bOff[p] + ks*32);
        #pragma unroll
        for (int ni = 0; ni < 8; ni++) {
            unsigned bf[2] = { bq[ni>>1][ni&1], bq[ni>>1][(ni&1)+2] };
            mma16(acc[ni],   a0, bf);
            mma16(acc[8+ni], a1, bf);
        }
    }
}

// ---------------- transpose-pack ----------------
template<int MODE>
__device__ __forceinline__ void packT_body(const float* __restrict__ W,
                                           __half* __restrict__ Wt,
                                           int K, int N, int k0, int n0, int tid) {
    __shared__ __half tile[32][72];
    int nl = tid & 31, kl = tid >> 5;
    #pragma unroll
    for (int it = 0; it < 8; it++)
        tile[nl][kl + it*8] = __float2half(W[(size_t)(k0 + kl + it*8)*N + n0 + nl]);
    __syncthreads();
    int kq8 = (tid & 7)*8, nr = tid >> 3;
    int c = n0 + nr;
    int drow;
    if (MODE == 0) drow = c;
    else {
        int NHf = N >> 1;
        drow = (c < NHf) ? ((c >> 6)*128 + (c & 63))
                         : (((c - NHf) >> 6)*128 + 64 + ((c - NHf) & 63));
    }
    *(uint4*)&Wt[(size_t)drow*K + k0 + kq8] = *(uint4*)&tile[nr][kq8];
}
__global__ void __launch_bounds__(256) packT(const float* __restrict__ W,
                                             __half* __restrict__ Wt, int K, int N) {
    packT_body<0>(W, Wt, K, N, blockIdx.x*64, blockIdx.y*32, threadIdx.x);
}
__global__ void __launch_bounds__(256) packT_gu(const float* __restrict__ W,
                                                __half* __restrict__ Wt, int K, int N) {
    packT_body<1>(W, Wt, K, N, blockIdx.x*64, blockIdx.y*32, threadIdx.x);
}
__global__ void __launch_bounds__(256) packT_moe(const float* __restrict__ pW,
                                                 const float* __restrict__ fW) {
    __shared__ __half tile[32][72];
    int z = blockIdx.z;
    int sel = z >> 5, e = z & 31;
    const float* W = (e < 16) ? pW + ((size_t)sel*16 + e)      * (size_t)DIMM*FDIM
                              : fW + ((size_t)sel*16 + (e-16)) * (size_t)DIMM*FDIM;
    __half* Wt = g_wguT + (size_t)e*1024*1024;
    int k0 = blockIdx.x*64, n0 = blockIdx.y*32;
    int tid = threadIdx.x;
    int nl = tid & 31, kl = tid >> 5;
    #pragma unroll
    for (int it = 0; it < 8; it++)
        tile[nl][kl + it*8] = __float2half(W[(size_t)(k0 + kl + it*8)*FDIM + n0 + nl]);
    __syncthreads();
    int kq8 = (tid & 7)*8, nr = tid >> 3;
    int c = n0 + nr;
    int drow = (c >> 6)*128 + sel*64 + (c & 63);
    *(uint4*)&Wt[(size_t)drow*DIMM + k0 + kq8] = *(uint4*)&tile[nr][kq8];
}
__global__ void __launch_bounds__(256) conv_moe_down(const float* __restrict__ pW,
                                                     const float* __restrict__ fW) {
    int z = blockIdx.z;
    const float* W = (z < 16) ? pW + ((size_t)2*16 + z)      * (size_t)DIMM*FDIM
                              : fW + ((size_t)2*16 + (z-16)) * (size_t)DIMM*FDIM;
    __half* Wh = g_wdnM + (size_t)z*1024*512;
    int idx = blockIdx.x*256 + threadIdx.x;
    float4 a = ((const float4*)W)[idx*2];
    float4 b = ((const float4*)W)[idx*2 + 1];
    ((uint4*)Wh)[idx] = make_uint4(f2h2(a.x,a.y), f2h2(a.z,a.w), f2h2(b.x,b.y), f2h2(b.z,b.w));
}

// ---------------- dense fp16 GEMM, 3-stage cp.async + ldmatrix ----------------
#define GEMM_SMEM (2560 * 2 * 3 * 4)
template<int OUT>
__global__ void __launch_bounds__(256) gemm_h(const __half* __restrict__ A,
                                              const __half* __restrict__ Bt,
                                              void* __restrict__ Cv,
                                              const float* __restrict__ D,
                                              int M, int N, int K) {
    extern __shared__ __align__(16) unsigned smem[];
    unsigned* As = smem;
    unsigned* Bs = smem + 3*2560;
    int tid = threadIdx.x, lane = tid & 31, wid = tid >> 5;
    int g = lane >> 2, t4 = lane & 3;
    int wm = (wid & 3)*32, wn = (wid >> 2)*64;
    size_t rowBase = (size_t)blockIdx.y * 128, colBase = (size_t)blockIdx.x * 128;
    int r_ = tid >> 1, sel = tid & 1;
    int sidx = r_*20 + sel*8;
    const __half* Ag = A  + (rowBase + r_)*K + sel*16;
    const __half* Bg = Bt + (colBase + r_)*K + sel*16;
    uint32_t aB = s2u(As), bB = s2u(Bs);
    uint32_t aOff0 = frag_off(wm, 20, lane), aOff1 = frag_off(wm+16, 20, lane);
    uint32_t bOff[4];
    #pragma unroll
    for (int p = 0; p < 4; p++) bOff[p] = frag_off(wn + p*16, 20, lane);
    int NC = K >> 5;

    auto issue = [&](int cc, int s) {
        uint32_t ad = aB + (s*2560 + sidx)*4;
        cpa16(ad,      Ag + cc*32);
        cpa16(ad + 16, Ag + cc*32 + 8);
        uint32_t bd = bB + (s*2560 + sidx)*4;
        cpa16(bd,      Bg + cc*32);
        cpa16(bd + 16, Bg + cc*32 + 8);
        CPA_COMMIT();
    };

    float acc[16][4];
    #pragma unroll
    for (int i = 0; i < 16; i++)
        #pragma unroll
        for (int j = 0; j < 4; j++) acc[i][j] = 0.f;

    issue(0, 0);
    issue(1, 1);
    for (int c = 0; c < NC; c++) {
        if (c + 2 < NC) CPA_WAIT1(); else CPA_WAIT0();
        __syncthreads();
        int s = c - (c/3)*3;
        compute_tile_ldsm(aB + s*2560*4, bB + s*2560*4, aOff0, aOff1, bOff, acc);
        if (c + 2 < NC) issue(c + 2, (c+2) - ((c+2)/3)*3);
    }
    if (OUT == 2) {
        __syncthreads();
        unsigned* sm = smem;
        #pragma unroll
        for (int mi = 0; mi < 2; mi++)
            #pragma unroll
            for (int ni = 0; ni < 8; ni++) {
                float* c = acc[mi*8+ni];
                int r = wm + mi*16 + g;
                int cw = (wn >> 1) + ni*4 + t4;
                sm[r*66 + cw]     = f2h2(c[0], c[1]);
                sm[(r+8)*66 + cw] = f2h2(c[2], c[3]);
            }
        __syncthreads();
        __half* C = (__half*)Cv;
        int outN = N >> 1;
        size_t fBase = colBase >> 1;
        for (int idx = tid; idx < 128*32; idx += 256) {
            int r = idx >> 5, cw = idx & 31;
            float2 gf = __half22float2(*(__half2*)&sm[r*66 + cw]);
            float2 uf = __half22float2(*(__half2*)&sm[r*66 + 32 + cw]);
            float a = gf.x / (1.f + __expf(-gf.x)) * uf.x;
            float b = gf.y / (1.f + __expf(-gf.y)) * uf.y;
            *(unsigned*)&C[(rowBase + r)*outN + fBase + 2*cw] = f2h2(a, b);
        }
        return;
    }
    #pragma unroll
    for (int mi = 0; mi < 2; mi++)
        #pragma unroll
        for (int ni = 0; ni < 8; ni++) {
            float* c = acc[mi*8+ni];
            size_t r0 = rowBase + wm + mi*16 + g;
            size_t c0 = colBase + wn + ni*8 + 2*t4;
            if (OUT == 0) {
                float* C = (float*)Cv;
                size_t o0 = r0*N + c0, o1 = (r0+8)*N + c0;
                if (D) {
                    C[o0] = c[0] + D[o0]; C[o0+1] = c[1] + D[o0+1];
                    C[o1] = c[2] + D[o1]; C[o1+1] = c[3] + D[o1+1];
                } else {
                    C[o0] = c[0]; C[o0+1] = c[1];
                    C[o1] = c[2]; C[o1+1] = c[3];
                }
            } else {
                __half* C = (__half*)Cv;
                *(unsigned*)&C[r0*N + c0]     = f2h2(c[0], c[1]);
                *(unsigned*)&C[(r0+8)*N + c0] = f2h2(c[2], c[3]);
            }
        }
}

// ---------------- MoE gate+up grouped GEMM, fused swiglu -> g_Gh ----------------
__global__ void __launch_bounds__(256) moe_gu_h() {
    extern __shared__ __align__(16) unsigned smem[];
    unsigned* As = smem;
    unsigned* Bs = smem + 3*2560;
    __shared__ int rows[128];
    int e = blockIdx.z;
    int cnt = g_counts[e];
    int rowTile = blockIdx.y * 128;
    if (rowTile >= cnt) return;
    int base = g_offsets[e];
    int colBase = blockIdx.x * 128;
    const __half* Wt = g_wguT + (size_t)e*1024*1024;
    int tid = threadIdx.x;
    if (tid < 128) {
        int rr = rowTile + tid;
        rows[tid] = (rr < cnt) ? g_tokof[base + rr] : 0;
    }
    __syncthreads();
    int lane = tid & 31, wid = tid >> 5;
    int g = lane >> 2, t4 = lane & 3;
    int wm = (wid & 3)*32, wn = (wid >> 2)*64;
    int r_ = tid >> 1, sel = tid & 1;
    int sidx = r_*20 + sel*8;
    const __half* Ag = g_xffnh + (size_t)rows[r_]*DIMM + sel*16;
    const __half* Bg = Wt + (size_t)(colBase + r_)*1024 + sel*16;
    uint32_t aB = s2u(As), bB = s2u(Bs);
    uint32_t aOff0 = frag_off(wm, 20, lane), aOff1 = frag_off(wm+16, 20, lane);
    uint32_t bOff[4];
    #pragma unroll
    for (int p = 0; p < 4; p++) bOff[p] = frag_off(wn + p*16, 20, lane);

    auto issue = [&](int cc, int s) {
        uint32_t ad = aB + (s*2560 + sidx)*4;
        cpa16(ad,      Ag + cc*32);
        cpa16(ad + 16, Ag + cc*32 + 8);
        uint32_t bd = bB + (s*2560 + sidx)*4;
        cpa16(bd,      Bg + cc*32);
        cpa16(bd + 16, Bg + cc*32 + 8);
        CPA_COMMIT();
    };

    float acc[16][4];
    #pragma unroll
    for (int i = 0; i < 16; i++)
        #pragma unroll
        for (int j = 0; j < 4; j++) acc[i][j] = 0.f;

    issue(0, 0);
    issue(1, 1);
    for (int c = 0; c < 32; c++) {
        if (c + 2 < 32) CPA_WAIT1(); else CPA_WAIT0();
        __syncthreads();
        int s = c - (c/3)*3;
        compute_tile_ldsm(aB + s*2560*4, bB + s*2560*4, aOff0, aOff1, bOff, acc);
        if (c + 2 < 32) issue(c + 2, (c+2) - ((c+2)/3)*3);
    }
    __syncthreads();
    unsigned* sm = smem;
    #pragma unroll
    for (int mi = 0; mi < 2; mi++)
        #pragma unroll
        for (int ni = 0; ni < 8; ni++) {
            float* c = acc[mi*8+ni];
            int r = wm + mi*16 + g;
            int cw = (wn >> 1) + ni*4 + t4;
            sm[r*66 + cw]     = f2h2(c[0], c[1]);
            sm[(r+8)*66 + cw] = f2h2(c[2], c[3]);
        }
    __syncthreads();
    int fBase = colBase >> 1;
    for (int idx = tid; idx < 128*32; idx += 256) {
        int r = idx >> 5, cw = idx & 31;
        if (rowTile + r >= cnt) continue;
        float2 gf = __half22float2(*(__half2*)&sm[r*66 + cw]);
        float2 uf = __half22float2(*(__half2*)&sm[r*66 + 32 + cw]);
        float a = gf.x / (1.f + __expf(-gf.x)) * uf.x;
        float b = gf.y / (1.f + __expf(-gf.y)) * uf.y;
        *(unsigned*)&g_Gh[(size_t)(base + rowTile + r)*FDIM + fBase + 2*cw] = f2h2(a, b);
    }
}

// ---------------- MoE down grouped GEMM ----------------
__global__ void __launch_bounds__(256) moe_down_h() {
    extern __shared__ __align__(16) unsigned smem[];
    unsigned* As = smem;
    unsigned* Bs = smem + 3*2560;
    int e = blockIdx.z;
    int cnt = g_counts[e];
    int rowTile = blockIdx.y * 128;
    if (rowTile >= cnt) return;
    int base = g_offsets[e];
    int colBase = blockIdx.x * 128;
    const __half* W = g_wdnM + (size_t)e*1024*512;
    int tid = threadIdx.x, lane = tid & 31, wid = tid >> 5;
    int g = lane >> 2, t4 = lane & 3;
    int wm = (wid & 3)*32, wn = (wid >> 2)*64;
    int r_ = tid >> 1, sel = tid & 1;
    int sidx = r_*20 + sel*8;
    int arow = base + rowTile + r_;
    if (arow > NASS - 1) arow = NASS - 1;
    const __half* Ag = g_Gh + (size_t)arow*FDIM + sel*16;
    const __half* Bg = W + (size_t)(colBase + r_)*FDIM + sel*16;
    uint32_t aB = s2u(As), bB = s2u(Bs);
    uint32_t aOff0 = frag_off(wm, 20, lane), aOff1 = frag_off(wm+16, 20, lane);
    uint32_t bOff[4];
    #pragma unroll
    for (int p = 0; p < 4; p++) bOff[p] = frag_off(wn + p*16, 20, lane);

    auto issue = [&](int cc, int s) {
        uint32_t ad = aB + (s*2560 + sidx)*4;
        cpa16(ad,      Ag + cc*32);
        cpa16(ad + 16, Ag + cc*32 + 8);
        uint32_t bd = bB + (s*2560 + sidx)*4;
        cpa16(bd,      Bg + cc*32);
        cpa16(bd + 16, Bg + cc*32 + 8);
        CPA_COMMIT();
    };

    float acc[16][4];
    #pragma unroll
    for (int i = 0; i < 16; i++)
        #pragma unroll
        for (int j = 0; j < 4; j++) acc[i][j] = 0.f;

    issue(0, 0);
    issue(1, 1);
    for (int c = 0; c < 16; c++) {
        if (c + 2 < 16) CPA_WAIT1(); else CPA_WAIT0();
        __syncthreads();
        int s = c - (c/3)*3;
        compute_tile_ldsm(aB + s*2560*4, bB + s*2560*4, aOff0, aOff1, bOff, acc);
        if (c + 2 < 16) issue(c + 2, (c+2) - ((c+2)/3)*3);
    }
    #pragma unroll
    for (int mi = 0; mi < 2; mi++)
        #pragma unroll
        for (int ni = 0; ni < 8; ni++) {
            float* c = acc[mi*8+ni];
            int r = rowTile + wm + mi*16 + g;
            int cc = colBase + wn + ni*8 + 2*t4;
            if (r < cnt)
                *(unsigned*)&g_slotsh[(size_t)(base+r)*DIMM + cc] = f2h2(c[0], c[1]);
            if (r + 8 < cnt)
                *(unsigned*)&g_slotsh[(size_t)(base+r+8)*DIMM + cc] = f2h2(c[2], c[3]);
        }
}

// ---------------- rmsnorm (half out) ----------------
__global__ void rmsnorm_h(const float* __restrict__ x, const float* __restrict__ w,
                          __half* __restrict__ out) {
    int r = blockIdx.x;
    const float* xr = x + (size_t)r*DIMM;
    __shared__ float red[8];
    float s = 0.f;
    for (int d = threadIdx.x; d < DIMM; d += 256) { float v = xr[d]; s += v*v; }
    #pragma unroll
    for (int o = 16; o; o >>= 1) s += __shfl_xor_sync(0xffffffffu, s, o);
    if ((threadIdx.x & 31) == 0) red[threadIdx.x >> 5] = s;
    __syncthreads();
    if (threadIdx.x == 0) {
        float t = 0.f;
        #pragma unroll
        for (int i = 0; i < 8; i++) t += red[i];
        red[0] = rsqrtf(t / (float)DIMM + 1e-5f);
    }
    __syncthreads();
    float rms = red[0];
    for (int d = threadIdx.x; d < DIMM; d += 256)
        out[(size_t)r*DIMM + d] = __float2half(xr[d] * rms * w[d]);
}

// ---------------- rope + dual interleave ----------------
__global__ void rope_interleave_kernel() {
    int r = blockIdx.x, h = blockIdx.y, d = threadIdx.x;
    int bi = r >> 10, si = r & 1023;
    int t = 2*si + bi;
    size_t src = (size_t)r*3072 + h*64;
    float q = __half2float(g_qkvh[src + d]);
    float k = __half2float(g_qkvh[src + 1024 + d]);
    float v = __half2float(g_qkvh[src + 2048 + d]);
    ((__half*)g_vmP)[(((size_t)h*1024 + (t >> 1))*64 + d)*2 + (t & 1)] = __float2half(v);
    __shared__ float qs[64], ks[64];
    qs[d] = q; ks[d] = k;
    __syncthreads();
    if (d < 32) {
        float inv = powf(10000.0f, -(float)(2*d) / 64.0f);
        float fr = (float)si * inv;
        float sn, cs;
        sincosf(fr, &sn, &cs);
        size_t dst = ((size_t)h*SEQ + t)*64;
        float x1 = qs[d], x2 = qs[d+32];
        g_qmh[dst + d]      = __float2half( x1*cs + x2*sn);
        g_qmh[dst + d + 32] = __float2half(-x1*sn + x2*cs);
        x1 = ks[d]; x2 = ks[d+32];
        g_kmh[dst + d]      = __float2half( x1*cs + x2*sn);
        g_kmh[dst + d + 32] = __float2half(-x1*sn + x2*cs);
    }
}

// ---------------- fp16 flash attention (ldmatrix frags) ----------------
#define ATT_SMEM_W (4608 + 2304 + 4608 + 2304)
__global__ void __launch_bounds__(256) attn_h() {
    extern __shared__ __align__(16) unsigned asm_[];
    unsigned* Qs = asm_;
    unsigned* Ks = asm_ + 4608;
    unsigned* Ps = asm_ + 6912;
    unsigned* Vt = asm_ + 11520;
    int h = blockIdx.y;
    int t0 = ((int)gridDim.x - 1 - (int)blockIdx.x) * 128;
    int tid = threadIdx.x, lane = tid & 31, wid = tid >> 5;
    int g = lane >> 2, t4 = lane & 3;
    int wm = wid * 16;
    uint32_t qB = s2u(Qs), kB = s2u(Ks), pB = s2u(Ps), vB = s2u(Vt);
    uint32_t aOffQ = frag_off(wm, 36, lane);
    uint32_t bOffK[4];
    #pragma unroll
    for (int p = 0; p < 4; p++) bOffK[p] = frag_off(p*16, 36, lane);

    const __half* qb = g_qmh + ((size_t)h*SEQ + t0)*64;
    for (int i = tid; i < 128*8; i += 256) {
        int r = i >> 3, j = i & 7;
        *(uint4*)&Qs[r*36 + j*4] = ((const uint4*)(qb + (size_t)r*64))[j];
    }

    float o[8][4];
    #pragma unroll
    for (int n = 0; n < 8; n++)
        #pragma unroll
        for (int j = 0; j < 4; j++) o[n][j] = 0.f;
    float m0 = -1e30f, m1 = -1e30f, l0 = 0.f, l1 = 0.f;
    int row0 = t0 + wm + g, row1 = row0 + 8;
    int wmax = t0 + wm + 15;

    for (int kt = 0; kt <= t0 + 127; kt += 64) {
        __syncthreads();
        const __half* kb = g_kmh + ((size_t)h*SEQ + kt)*64;
        for (int i = tid; i < 64*8; i += 256) {
            int r = i >> 3, j = i & 7;
            *(uint4*)&Ks[r*36 + j*4] = ((const uint4*)(kb + (size_t)r*64))[j];
        }
        const unsigned* vp = g_vmP + ((size_t)h*1024 + (kt >> 1))*64;
        for (int w = tid; w < 64*32; w += 256) {
            int d = w & 63, p = w >> 6;
            Vt[d*36 + p] = vp[(size_t)p*64 + d];
        }
        __syncthreads();
        if (kt > wmax) continue;

        float s[8][4];
        #pragma unroll
        for (int n = 0; n < 8; n++)
            #pragma unroll
            for (int j = 0; j < 4; j++) s[n][j] = 0.f;
        #pragma unroll
        for (int ks = 0; ks < 4; ks++) {
            unsigned aq[4], bq[4][4];
            ldsm4(aq, qB + aOffQ + ks*32);
            #pragma unroll
            for (int p = 0; p < 4; p++) ldsm4(bq[p], kB + bOffK[p] + ks*32);
            #pragma unroll
            for (int n = 0; n < 8; n++) {
                unsigned bf[2] = { bq[n>>1][n&1], bq[n>>1][(n&1)+2] };
                mma16(s[n], aq, bf);
            }
        }
        float mx0 = -1e30f, mx1 = -1e30f;
        #pragma unroll
        for (int n = 0; n < 8; n++) {
            int c0 = kt + n*8 + 2*t4, c1 = c0 + 1;
            s[n][0] = (c0 <= row0) ? s[n][0]*0.125f : -1e30f;
            s[n][1] = (c1 <= row0) ? s[n][1]*0.125f : -1e30f;
            s[n][2] = (c0 <= row1) ? s[n][2]*0.125f : -1e30f;
            s[n][3] = (c1 <= row1) ? s[n][3]*0.125f : -1e30f;
            mx0 = fmaxf(mx0, fmaxf(s[n][0], s[n][1]));
            mx1 = fmaxf(mx1, fmaxf(s[n][2], s[n][3]));
        }
        mx0 = fmaxf(mx0, __shfl_xor_sync(0xffffffffu, mx0, 1));
        mx0 = fmaxf(mx0, __shfl_xor_sync(0xffffffffu, mx0, 2));
        mx1 = fmaxf(mx1, __shfl_xor_sync(0xffffffffu, mx1, 1));
        mx1 = fmaxf(mx1, __shfl_xor_sync(0xffffffffu, mx1, 2));
        float nm0 = fmaxf(m0, mx0), nm1 = fmaxf(m1, mx1);
        float cor0 = __expf(m0 - nm0), cor1 = __expf(m1 - nm1);
        m0 = nm0; m1 = nm1;
        l0 *= cor0; l1 *= cor1;
        float sum0 = 0.f, sum1 = 0.f;
        #pragma unroll
        for (int n = 0; n < 8; n++) {
            float p00 = __expf(s[n][0] - nm0), p01 = __expf(s[n][1] - nm0);
            float p10 = __expf(s[n][2] - nm1), p11 = __expf(s[n][3] - nm1);
            sum0 += p00 + p01; sum1 += p10 + p11;
            Ps[(wm+g)*36 + n*4 + t4]   = f2h2(p00, p01);
            Ps[(wm+g+8)*36 + n*4 + t4] = f2h2(p10, p11);
            #pragma unroll
            for (int j = 0; j < 2; j++) { o[n][j] *= cor0; o[n][2+j] *= cor1; }
        }
        sum0 += __shfl_xor_sync(0xffffffffu, sum0, 1);
        sum0 += __shfl_xor_sync(0xffffffffu, sum0, 2);
        sum1 += __shfl_xor_sync(0xffffffffu, sum1, 1);
        sum1 += __shfl_xor_sync(0xffffffffu, sum1, 2);
        l0 += sum0; l1 += sum1;
        __syncwarp();

        #pragma unroll
        for (int ks = 0; ks < 4; ks++) {
            unsigned ap[4], bq[4][4];
            ldsm4(ap, pB + aOffQ + ks*32);
            #pragma unroll
            for (int p = 0; p < 4; p++) ldsm4(bq[p], vB + bOffK[p] + ks*32);
            #pragma unroll
            for (int n = 0; n < 8; n++) {
                unsigned bf[2] = { bq[n>>1][n&1], bq[n>>1][(n&1)+2] };
                mma16(o[n], ap, bf);
            }
        }
    }

    float inv0 = 1.f / l0, inv1 = 1.f / l1;
    int tok0 = (row0 & 1)*1024 + (row0 >> 1);
    int tok1 = (row1 & 1)*1024 + (row1 >> 1);
    #pragma unroll
    for (int n = 0; n < 8; n++) {
        int col = h*64 + n*8 + 2*t4;
        *(unsigned*)&g_orowsh[(size_t)tok0*DIMM + col] = f2h2(o[n][0]*inv0, o[n][1]*inv0);
        *(unsigned*)&g_orowsh[(size_t)tok1*DIMM + col] = f2h2(o[n][2]*inv1, o[n][3]*inv1);
    }
}

// ---------------- router ----------------
__global__ void router_kernel(const float* __restrict__ pkeys, const float* __restrict__ fkeys,
                              const float* __restrict__ pbias, const float* __restrict__ fbias,
                              const int* __restrict__ pidx, const float* __restrict__ pval,
                              const int* __restrict__ fidx, const float* __restrict__ fval) {
    int tok = blockIdx.x, tid = threadIdx.x;
    bool isf = tok >= 1024;
    const float* keys = isf ? fkeys : pkeys;
    const __half* x = g_xffnh + (size_t)tok*DIMM;
    __shared__ float part[8][16];
    __shared__ float logit[16];
    int e = tid & 15, ch = tid >> 4;
    float s = 0.f;
    int d0 = ch * 128;
    for (int d = d0; d < d0 + 128; d++)
        s = fmaf(__half2float(x[d]), keys[d*16 + e], s);
    part[ch][e] = s;
    __syncthreads();
    if (tid < 16) {
        float t = 0.f;
        #pragma unroll
        for (int c = 0; c < 8; c++) t += part[c][tid];
        logit[tid] = t;
    }
    __syncthreads();
    if (tid == 0) {
        int lt = isf ? tok - 1024 : tok;
        const int*   idx  = isf ? fidx  : pidx;
        const float* val  = isf ? fval  : pval;
        const float* bias = isf ? fbias : pbias;
        float sc[4]; int id[4]; float sum = 0.f;
        #pragma unroll
        for (int k = 0; k < 4; k++) {
            int ix = idx[lt*4 + k];
            float v = val[lt*4 + k] + logit[ix] + bias[ix];
            float s2 = 1.f / (1.f + expf(-v));
            sc[k] = s2; sum += s2;
            id[k] = ix + (isf ? 16 : 0);
        }
        #pragma unroll
        for (int k = 0; k < 4; k++) {
            g_scales[tok*4 + k] = sc[k] / sum;
            g_eid[tok*4 + k] = id[k];
            atomicAdd(&g_counts[id[k]], 1);
        }
    }
}

__global__ void zero32_kernel() {
    int i = threadIdx.x;
    if (i < NEXP) { g_counts[i] = 0; g_cursors[i] = 0; }
}

// fused prefix + scatter: single block, 256 threads
__global__ void __launch_bounds__(256) prefix_scatter_kernel() {
    __shared__ int soff[NEXP];
    if (threadIdx.x == 0) {
        int acc = 0;
        for (int e = 0; e < NEXP; e++) { soff[e] = acc; g_offsets[e] = acc; acc += g_counts[e]; }
    }
    __syncthreads();
    for (int a = threadIdx.x; a < NASS; a += 256) {
        int e = g_eid[a];
        int p = soff[e] + atomicAdd(&g_cursors[e], 1);
        g_tokof[p] = a >> 2;
        g_posof[a] = p;
    }
}

__global__ void combine_kernel(float* __restrict__ y) {
    int tok = blockIdx.x;
    __shared__ int pos[4];
    __shared__ float sc[4];
    if (threadIdx.x < 4) {
        pos[threadIdx.x] = g_posof[tok*4 + threadIdx.x];
        sc[threadIdx.x]  = g_scales[tok*4 + threadIdx.x];
    }
    __syncthreads();
    for (int d = threadIdx.x; d < DIMM; d += 256) {
        float v = g_xffni[(size_t)tok*DIMM + d]
                + __half2float(g_shdownh[(size_t)tok*DIMM + d]);
        #pragma unroll
        for (int k = 0; k < 4; k++)
            v = fmaf(sc[k], __half2float(g_slotsh[(size_t)pos[k]*DIMM + d]), v);
        y[(size_t)tok*DIMM + d] = v;
    }
}

// ---------------- launch ----------------
extern "C" void kernel_launch(void* const* d_in, const int* in_sizes, int n_in,
                              void* d_out, int out_size) {
    const float* x_input  = (const float*)d_in[0];
    const int*   p_idx    = (const int*)  d_in[1];
    const float* p_val    = (const float*)d_in[2];
    const int*   f_idx    = (const int*)  d_in[3];
    const float* f_val    = (const float*)d_in[4];
    const float* attn_nw  = (const float*)d_in[5];
    const float* ffn_nw   = (const float*)d_in[6];
    const float* W_attn   = (const float*)d_in[7];
    const float* W_attn_o = (const float*)d_in[8];
    const float* ffn_up   = (const float*)d_in[9];
    const float* ffn_down = (const float*)d_in[10];
    const float* pW       = (const float*)d_in[11];
    const float* fW       = (const float*)d_in[12];
    const float* pkeys    = (const float*)d_in[13];
    const float* fkeys    = (const float*)d_in[14];
    const float* pbias    = (const float*)d_in[15];
    const float* fbias    = (const float*)d_in[16];
    float* out = (float*)d_out;

    __half *xnormh, *qkvh, *orowsh, *xffnh, *hsh, *shdownh;
    __half *wqkvT, *woT, *wupT, *wdnT;
    float *xffni;
    cudaGetSymbolAddress((void**)&xnormh, g_xnormh);
    cudaGetSymbolAddress((void**)&qkvh,   g_qkvh);
    cudaGetSymbolAddress((void**)&orowsh, g_orowsh);
    cudaGetSymbolAddress((void**)&xffni,  g_xffni);
    cudaGetSymbolAddress((void**)&xffnh,  g_xffnh);
    cudaGetSymbolAddress((void**)&hsh,    g_hsh);
    cudaGetSymbolAddress((void**)&shdownh, g_shdownh);
    cudaGetSymbolAddress((void**)&wqkvT,  g_wqkvT);
    cudaGetSymbolAddress((void**)&woT,    g_woT);
    cudaGetSymbolAddress((void**)&wupT,   g_wupT);
    cudaGetSymbolAddress((void**)&wdnT,   g_wdnT);

    static cudaStream_t s1 = nullptr, s2 = nullptr;
    static cudaEvent_t evFork, evZero, evQKVp, evWo, evWup, evMoeP, evXffn, evSh;
    static bool init_done = false;
    if (!init_done) {
        cudaFuncSetAttribute(attn_h, cudaFuncAttributeMaxDynamicSharedMemorySize,
                             ATT_SMEM_W * 4);
        cudaFuncSetAttribute(gemm_h<0>, cudaFuncAttributeMaxDynamicSharedMemorySize, GEMM_SMEM);
        cudaFuncSetAttribute(gemm_h<1>, cudaFuncAttributeMaxDynamicSharedMemorySize, GEMM_SMEM);
        cudaFuncSetAttribute(gemm_h<2>, cudaFuncAttributeMaxDynamicSharedMemorySize, GEMM_SMEM);
        cudaFuncSetAttribute(moe_gu_h, cudaFuncAttributeMaxDynamicSharedMemorySize, GEMM_SMEM);
        cudaFuncSetAttribute(moe_down_h, cudaFuncAttributeMaxDynamicSharedMemorySize, GEMM_SMEM);
        cudaStreamCreateWithFlags(&s1, cudaStreamNonBlocking);
        cudaStreamCreateWithFlags(&s2, cudaStreamNonBlocking);
        cudaEventCreateWithFlags(&evFork, cudaEventDisableTiming);
        cudaEventCreateWithFlags(&evZero, cudaEventDisableTiming);
        cudaEventCreateWithFlags(&evQKVp, cudaEventDisableTiming);
        cudaEventCreateWithFlags(&evWo,   cudaEventDisableTiming);
        cudaEventCreateWithFlags(&evWup,  cudaEventDisableTiming);
        cudaEventCreateWithFlags(&evMoeP, cudaEventDisableTiming);
        cudaEventCreateWithFlags(&evXffn, cudaEventDisableTiming);
        cudaEventCreateWithFlags(&evSh,   cudaEventDisableTiming);
        init_done = true;
    }

    // fork side stream s1: zero + all weight packing
    cudaEventRecord(evFork, 0);
    cudaStreamWaitEvent(s1, evFork, 0);
    zero32_kernel<<<1, 32, 0, s1>>>();
    cudaEventRecord(evZero, s1);
    packT<<<dim3(16, 96),  256, 0, s1>>>(W_attn,   wqkvT, DIMM, 3*DIMM);
    cudaEventRecord(evQKVp, s1);
    packT<<<dim3(16, 32),  256, 0, s1>>>(W_attn_o, woT,   DIMM, DIMM);
    cudaEventRecord(evWo, s1);
    packT_gu<<<dim3(16, 128), 256, 0, s1>>>(ffn_up, wupT, DIMM, 2*DSH);
    packT<<<dim3(32, 32),  256, 0, s1>>>(ffn_down, wdnT,  DSH,  DIMM);
    cudaEventRecord(evWup, s1);
    packT_moe<<<dim3(16, 16, 64), 256, 0, s1>>>(pW, fW);
    conv_moe_down<<<dim3(256, 1, 32), 256, 0, s1>>>(pW, fW);
    cudaEventRecord(evMoeP, s1);

    // main stream: attention block (overlaps with packing)
    rmsnorm_h<<<TOK, 256>>>(x_input, attn_nw, xnormh);
    cudaStreamWaitEvent(0, evQKVp, 0);
    gemm_h<1><<<dim3(24, 16), 256, GEMM_SMEM>>>(xnormh, wqkvT, qkvh, nullptr, TOK, 3*DIMM, DIMM);
    rope_interleave_kernel<<<dim3(TOK, NH), 64>>>();
    attn_h<<<dim3(SEQ/128, NH), 256, ATT_SMEM_W*4>>>();
    cudaStreamWaitEvent(0, evWo, 0);
    gemm_h<0><<<dim3(8, 16), 256, GEMM_SMEM>>>(orowsh, woT, xffni, x_input, TOK, DIMM, DIMM);
    rmsnorm_h<<<TOK, 256>>>(xffni, ffn_nw, xffnh);
    cudaEventRecord(evXffn, 0);

    // s2: full shared-expert branch (up + down), overlaps router + MoE chain
    cudaStreamWaitEvent(s2, evXffn, 0);
    cudaStreamWaitEvent(s2, evWup, 0);
    gemm_h<2><<<dim3(32, 16), 256, GEMM_SMEM, s2>>>(xffnh, wupT, hsh, nullptr, TOK, 2*DSH, DIMM);
    gemm_h<1><<<dim3(8, 16), 256, GEMM_SMEM, s2>>>(hsh, wdnT, shdownh, nullptr, TOK, DIMM, DSH);
    cudaEventRecord(evSh, s2);

    // main: routing + grouped MoE
    cudaStreamWaitEvent(0, evZero, 0);
    router_kernel<<<TOK, 128>>>(pkeys, fkeys, pbias, fbias, p_idx, p_val, f_idx, f_val);
    prefix_scatter_kernel<<<1, 256>>>();
    cudaStreamWaitEvent(0, evMoeP, 0);
    moe_gu_h<<<dim3(8, 16, NEXP), 256, GEMM_SMEM>>>();
    moe_down_h<<<dim3(8, 16, NEXP), 256, GEMM_SMEM>>>();
    // final combine joins s2 and adds shared-expert output
    cudaStreamWaitEvent(0, evSh, 0);
    combine_kernel<<<TOK, 256>>>(out);
}

// round 15
// speedup vs baseline: 7.4593x; 1.0450x over previous
#include <cuda_runtime.h>
#include <cuda_fp16.h>
#include <math.h>
#include <stdint.h>

// ---------------- problem constants ----------------
#define TOK   2048
#define DIMM  1024
#define NH    16
#define HD    64
#define SEQ   2048
#define NASS  8192
#define NEXP  32
#define FDIM  512
#define DSH   2048

// ---------------- scratch ----------------
__device__ __align__(16) __half g_xnormh[TOK*DIMM];
__device__ __align__(16) __half g_qkvh[TOK*3*DIMM];
__device__ __align__(16) __half g_qmh[NH*SEQ*HD];
__device__ __align__(16) __half g_kmh[NH*SEQ*HD];
__device__ __align__(16) unsigned g_vmP[NH*(SEQ/2)*HD];
__device__ __align__(16) __half g_orowsh[TOK*DIMM];
__device__ float g_xffni[TOK*DIMM];
__device__ __align__(16) __half g_xffnh[TOK*DIMM];
__device__ __align__(16) __half g_Gh[NASS*FDIM];
__device__ __align__(16) __half g_slotsh[(size_t)NASS*DIMM];
__device__ __align__(16) __half g_hsh[(size_t)TOK*DSH];
__device__ __align__(16) __half g_shdownh[(size_t)TOK*DIMM];
__device__ float g_scales[NASS];
__device__ int   g_eid[NASS];
__device__ int   g_tokof[NASS];
__device__ int   g_posof[NASS];
__device__ int   g_counts[NEXP];
__device__ int   g_offsets[NEXP];
__device__ int   g_cursors[NEXP];
// K-major packed fp16 weights: Wt[N][K]
__device__ __align__(16) __half g_wqkvT[3072*1024];
__device__ __align__(16) __half g_woT[1024*1024];
__device__ __align__(16) __half g_wupT[(size_t)4096*1024];
__device__ __align__(16) __half g_wdnT[(size_t)1024*2048];
__device__ __align__(16) __half g_wguT[(size_t)32*1024*1024];
__device__ __align__(16) __half g_wdnM[(size_t)32*1024*512];

// ---------------- helpers ----------------
__device__ __forceinline__ unsigned f2h2(float a, float b) {
    __half2 h = __floats2half2_rn(a, b);
    return *reinterpret_cast<unsigned*>(&h);
}
__device__ __forceinline__ void mma16(float c[4], const unsigned a[4], const unsigned b[2]) {
    asm volatile("mma.sync.aligned.m16n8k16.row.col.f32.f16.f16.f32 "
                 "{%0,%1,%2,%3},{%4,%5,%6,%7},{%8,%9},{%0,%1,%2,%3};"
                 : "+f"(c[0]), "+f"(c[1]), "+f"(c[2]), "+f"(c[3])
                 : "r"(a[0]), "r"(a[1]), "r"(a[2]), "r"(a[3]), "r"(b[0]), "r"(b[1]));
}
__device__ __forceinline__ uint32_t s2u(const void* p) {
    uint32_t a;
    asm("{ .reg .u64 t; cvta.to.shared.u64 t, %1; cvt.u32.u64 %0, t; }" : "=r"(a) : "l"(p));
    return a;
}
__device__ __forceinline__ void cpa16(uint32_t dst, const void* src) {
    asm volatile("cp.async.ca.shared.global [%0], [%1], 16;" :: "r"(dst), "l"(src));
}
__device__ __forceinline__ void cpa4(uint32_t dst, const void* src) {
    asm volatile("cp.async.ca.shared.global [%0], [%1], 4;" :: "r"(dst), "l"(src));
}
#define CPA_COMMIT() asm volatile("cp.async.commit_group;")
#define CPA_WAIT1()  asm volatile("cp.async.wait_group 1;")
#define CPA_WAIT0()  asm volatile("cp.async.wait_group 0;")

__device__ __forceinline__ void ldsm4(unsigned* r, uint32_t a) {
    asm volatile("ldmatrix.sync.aligned.m8n8.x4.shared.b16 {%0,%1,%2,%3}, [%4];"
                 : "=r"(r[0]), "=r"(r[1]), "=r"(r[2]), "=r"(r[3]) : "r"(a));
}
__device__ __forceinline__ uint32_t frag_off(int rowBase, int stride, int lane) {
    int lr = lane & 7, lh = (lane >> 3) & 1, lq = lane >> 4;
    return (uint32_t)(((rowBase + lr + lh*8) * stride + lq*4) * 4);
}

__device__ __forceinline__ void compute_tile_ldsm(uint32_t aS, uint32_t bS,
                                                  uint32_t aOff0, uint32_t aOff1,
                                                  const uint32_t* bOff,
                                                  float acc[16][4]) {
    #pragma unroll
    for (int ks = 0; ks < 2; ks++) {
        unsigned a0[4], a1[4], bq[4][4];
        ldsm4(a0, aS + aOff0 + ks*32);
        ldsm4(a1, aS + aOff1 + ks*32);
        #pragma unroll
        for (int p = 0; p < 4; p++) ldsm4(bq[p], bS + bOff[p] + ks*32);
        #pragma unroll
        for (int ni = 0; ni < 8; ni++) {
            unsigned bf[2] = { bq[ni>>1][ni&1], bq[ni>>1][(ni&1)+2] };
            mma16(acc[ni],   a0, bf);
            mma16(acc[8+ni], a1, bf);
        }
    }
}

// ---------------- transpose-pack ----------------
template<int MODE>
__device__ __forceinline__ void packT_body(const float* __restrict__ W,
                                           __half* __restrict__ Wt,
                                           int K, int N, int k0, int n0, int tid) {
    __shared__ __half tile[32][72];
    int nl = tid & 31, kl = tid >> 5;
    #pragma unroll
    for (int it = 0; it < 8; it++)
        tile[nl][kl + it*8] = __float2half(W[(size_t)(k0 + kl + it*8)*N + n0 + nl]);
    __syncthreads();
    int kq8 = (tid & 7)*8, nr = tid >> 3;
    int c = n0 + nr;
    int drow;
    if (MODE == 0) drow = c;
    else {
        int NHf = N >> 1;
        drow = (c < NHf) ? ((c >> 6)*128 + (c & 63))
                         : (((c - NHf) >> 6)*128 + 64 + ((c - NHf) & 63));
    }
    *(uint4*)&Wt[(size_t)drow*K + k0 + kq8] = *(uint4*)&tile[nr][kq8];
}
__global__ void __launch_bounds__(256) packT(const float* __restrict__ W,
                                             __half* __restrict__ Wt, int K, int N) {
    packT_body<0>(W, Wt, K, N, blockIdx.x*64, blockIdx.y*32, threadIdx.x);
}
__global__ void __launch_bounds__(256) packT_gu(const float* __restrict__ W,
                                                __half* __restrict__ Wt, int K, int N) {
    packT_body<1>(W, Wt, K, N, blockIdx.x*64, blockIdx.y*32, threadIdx.x);
}
__global__ void __launch_bounds__(256) packT_moe(const float* __restrict__ pW,
                                                 const float* __restrict__ fW) {
    __shared__ __half tile[32][72];
    int z = blockIdx.z;
    int sel = z >> 5, e = z & 31;
    const float* W = (e < 16) ? pW + ((size_t)sel*16 + e)      * (size_t)DIMM*FDIM
                              : fW + ((size_t)sel*16 + (e-16)) * (size_t)DIMM*FDIM;
    __half* Wt = g_wguT + (size_t)e*1024*1024;
    int k0 = blockIdx.x*64, n0 = blockIdx.y*32;
    int tid = threadIdx.x;
    int nl = tid & 31, kl = tid >> 5;
    #pragma unroll
    for (int it = 0; it < 8; it++)
        tile[nl][kl + it*8] = __float2half(W[(size_t)(k0 + kl + it*8)*FDIM + n0 + nl]);
    __syncthreads();
    int kq8 = (tid & 7)*8, nr = tid >> 3;
    int c = n0 + nr;
    int drow = (c >> 6)*128 + sel*64 + (c & 63);
    *(uint4*)&Wt[(size_t)drow*DIMM + k0 + kq8] = *(uint4*)&tile[nr][kq8];
}
__global__ void __launch_bounds__(256) conv_moe_down(const float* __restrict__ pW,
                                                     const float* __restrict__ fW) {
    int z = blockIdx.z;
    const float* W = (z < 16) ? pW + ((size_t)2*16 + z)      * (size_t)DIMM*FDIM
                              : fW + ((size_t)2*16 + (z-16)) * (size_t)DIMM*FDIM;
    __half* Wh = g_wdnM + (size_t)z*1024*512;
    int idx = blockIdx.x*256 + threadIdx.x;
    float4 a = ((const float4*)W)[idx*2];
    float4 b = ((const float4*)W)[idx*2 + 1];
    ((uint4*)Wh)[idx] = make_uint4(f2h2(a.x,a.y), f2h2(a.z,a.w), f2h2(b.x,b.y), f2h2(b.z,b.w));
}

// ---------------- dense fp16 GEMM, 3-stage cp.async + ldmatrix ----------------
#define GEMM_SMEM (2560 * 2 * 3 * 4)
template<int OUT>
__global__ void __launch_bounds__(256) gemm_h(const __half* __restrict__ A,
                                              const __half* __restrict__ Bt,
                                              void* __restrict__ Cv,
                                              const float* __restrict__ D,
                                              int M, int N, int K) {
    extern __shared__ __align__(16) unsigned smem[];
    unsigned* As = smem;
    unsigned* Bs = smem + 3*2560;
    int tid = threadIdx.x, lane = tid & 31, wid = tid >> 5;
    int g = lane >> 2, t4 = lane & 3;
    int wm = (wid & 3)*32, wn = (wid >> 2)*64;
    size_t rowBase = (size_t)blockIdx.y * 128, colBase = (size_t)blockIdx.x * 128;
    int r_ = tid >> 1, sel = tid & 1;
    int sidx = r_*20 + sel*8;
    const __half* Ag = A  + (rowBase + r_)*K + sel*16;
    const __half* Bg = Bt + (colBase + r_)*K + sel*16;
    uint32_t aB = s2u(As), bB = s2u(Bs);
    uint32_t aOff0 = frag_off(wm, 20, lane), aOff1 = frag_off(wm+16, 20, lane);
    uint32_t bOff[4];
    #pragma unroll
    for (int p = 0; p < 4; p++) bOff[p] = frag_off(wn + p*16, 20, lane);
    int NC = K >> 5;

    auto issue = [&](int cc, int s) {
        uint32_t ad = aB + (s*2560 + sidx)*4;
        cpa16(ad,      Ag + cc*32);
        cpa16(ad + 16, Ag + cc*32 + 8);
        uint32_t bd = bB + (s*2560 + sidx)*4;
        cpa16(bd,      Bg + cc*32);
        cpa16(bd + 16, Bg + cc*32 + 8);
        CPA_COMMIT();
    };

    float acc[16][4];
    #pragma unroll
    for (int i = 0; i < 16; i++)
        #pragma unroll
        for (int j = 0; j < 4; j++) acc[i][j] = 0.f;

    issue(0, 0);
    issue(1, 1);
    for (int c = 0; c < NC; c++) {
        if (c + 2 < NC) CPA_WAIT1(); else CPA_WAIT0();
        __syncthreads();
        int s = c - (c/3)*3;
        compute_tile_ldsm(aB + s*2560*4, bB + s*2560*4, aOff0, aOff1, bOff, acc);
        if (c + 2 < NC) issue(c + 2, (c+2) - ((c+2)/3)*3);
    }
    if (OUT == 2) {
        __syncthreads();
        unsigned* sm = smem;
        #pragma unroll
        for (int mi = 0; mi < 2; mi++)
            #pragma unroll
            for (int ni = 0; ni < 8; ni++) {
                float* c = acc[mi*8+ni];
                int r = wm + mi*16 + g;
                int cw = (wn >> 1) + ni*4 + t4;
                sm[r*66 + cw]     = f2h2(c[0], c[1]);
                sm[(r+8)*66 + cw] = f2h2(c[2], c[3]);
            }
        __syncthreads();
        __half* C = (__half*)Cv;
        int outN = N >> 1;
        size_t fBase = colBase >> 1;
        for (int idx = tid; idx < 128*32; idx += 256) {
            int r = idx >> 5, cw = idx & 31;
            float2 gf = __half22float2(*(__half2*)&sm[r*66 + cw]);
            float2 uf = __half22float2(*(__half2*)&sm[r*66 + 32 + cw]);
            float a = gf.x / (1.f + __expf(-gf.x)) * uf.x;
            float b = gf.y / (1.f + __expf(-gf.y)) * uf.y;
            *(unsigned*)&C[(rowBase + r)*outN + fBase + 2*cw] = f2h2(a, b);
        }
        return;
    }
    #pragma unroll
    for (int mi = 0; mi < 2; mi++)
        #pragma unroll
        for (int ni = 0; ni < 8; ni++) {
            float* c = acc[mi*8+ni];
            size_t r0 = rowBase + wm + mi*16 + g;
            size_t c0 = colBase + wn + ni*8 + 2*t4;
            if (OUT == 0) {
                float* C = (float*)Cv;
                size_t o0 = r0*N + c0, o1 = (r0+8)*N + c0;
                if (D) {
                    C[o0] = c[0] + D[o0]; C[o0+1] = c[1] + D[o0+1];
                    C[o1] = c[2] + D[o1]; C[o1+1] = c[3] + D[o1+1];
                } else {
                    C[o0] = c[0]; C[o0+1] = c[1];
                    C[o1] = c[2]; C[o1+1] = c[3];
                }
            } else {
                __half* C = (__half*)Cv;
                *(unsigned*)&C[r0*N + c0]     = f2h2(c[0], c[1]);
                *(unsigned*)&C[(r0+8)*N + c0] = f2h2(c[2], c[3]);
            }
        }
}

// ---------------- MoE gate+up grouped GEMM, fused swiglu -> g_Gh ----------------
__global__ void __launch_bounds__(256) moe_gu_h() {
    extern __shared__ __align__(16) unsigned smem[];
    unsigned* As = smem;
    unsigned* Bs = smem + 3*2560;
    __shared__ int rows[128];
    int e = blockIdx.z;
    int cnt = g_counts[e];
    int rowTile = blockIdx.y * 128;
    if (rowTile >= cnt) return;
    int base = g_offsets[e];
    int colBase = blockIdx.x * 128;
    const __half* Wt = g_wguT + (size_t)e*1024*1024;
    int tid = threadIdx.x;
    if (tid < 128) {
        int rr = rowTile + tid;
        rows[tid] = (rr < cnt) ? g_tokof[base + rr] : 0;
    }
    __syncthreads();
    int lane = tid & 31, wid = tid >> 5;
    int g = lane >> 2, t4 = lane & 3;
    int wm = (wid & 3)*32, wn = (wid >> 2)*64;
    int r_ = tid >> 1, sel = tid & 1;
    int sidx = r_*20 + sel*8;
    const __half* Ag = g_xffnh + (size_t)rows[r_]*DIMM + sel*16;
    const __half* Bg = Wt + (size_t)(colBase + r_)*1024 + sel*16;
    uint32_t aB = s2u(As), bB = s2u(Bs);
    uint32_t aOff0 = frag_off(wm, 20, lane), aOff1 = frag_off(wm+16, 20, lane);
    uint32_t bOff[4];
    #pragma unroll
    for (int p = 0; p < 4; p++) bOff[p] = frag_off(wn + p*16, 20, lane);

    auto issue = [&](int cc, int s) {
        uint32_t ad = aB + (s*2560 + sidx)*4;
        cpa16(ad,      Ag + cc*32);
        cpa16(ad + 16, Ag + cc*32 + 8);
        uint32_t bd = bB + (s*2560 + sidx)*4;
        cpa16(bd,      Bg + cc*32);
        cpa16(bd + 16, Bg + cc*32 + 8);
        CPA_COMMIT();
    };

    float acc[16][4];
    #pragma unroll
    for (int i = 0; i < 16; i++)
        #pragma unroll
        for (int j = 0; j < 4; j++) acc[i][j] = 0.f;

    issue(0, 0);
    issue(1, 1);
    for (int c = 0; c < 32; c++) {
        if (c + 2 < 32) CPA_WAIT1(); else CPA_WAIT0();
        __syncthreads();
        int s = c - (c/3)*3;
        compute_tile_ldsm(aB + s*2560*4, bB + s*2560*4, aOff0, aOff1, bOff, acc);
        if (c + 2 < 32) issue(c + 2, (c+2) - ((c+2)/3)*3);
    }
    __syncthreads();
    unsigned* sm = smem;
    #pragma unroll
    for (int mi = 0; mi < 2; mi++)
        #pragma unroll
        for (int ni = 0; ni < 8; ni++) {
            float* c = acc[mi*8+ni];
            int r = wm + mi*16 + g;
            int cw = (wn >> 1) + ni*4 + t4;
            sm[r*66 + cw]     = f2h2(c[0], c[1]);
            sm[(r+8)*66 + cw] = f2h2(c[2], c[3]);
        }
    __syncthreads();
    int fBase = colBase >> 1;
    for (int idx = tid; idx < 128*32; idx += 256) {
        int r = idx >> 5, cw = idx & 31;
        if (rowTile + r >= cnt) continue;
        float2 gf = __half22float2(*(__half2*)&sm[r*66 + cw]);
        float2 uf = __half22float2(*(__half2*)&sm[r*66 + 32 + cw]);
        float a = gf.x / (1.f + __expf(-gf.x)) * uf.x;
        float b = gf.y / (1.f + __expf(-gf.y)) * uf.y;
        *(unsigned*)&g_Gh[(size_t)(base + rowTile + r)*FDIM + fBase + 2*cw] = f2h2(a, b);
    }
}

// ---------------- MoE down grouped GEMM ----------------
__global__ void __launch_bounds__(256) moe_down_h() {
    extern __shared__ __align__(16) unsigned smem[];
    unsigned* As = smem;
    unsigned* Bs = smem + 3*2560;
    int e = blockIdx.z;
    int cnt = g_counts[e];
    int rowTile = blockIdx.y * 128;
    if (rowTile >= cnt) return;
    int base = g_offsets[e];
    int colBase = blockIdx.x * 128;
    const __half* W = g_wdnM + (size_t)e*1024*512;
    int tid = threadIdx.x, lane = tid & 31, wid = tid >> 5;
    int g = lane >> 2, t4 = lane & 3;
    int wm = (wid & 3)*32, wn = (wid >> 2)*64;
    int r_ = tid >> 1, sel = tid & 1;
    int sidx = r_*20 + sel*8;
    int arow = base + rowTile + r_;
    if (arow > NASS - 1) arow = NASS - 1;
    const __half* Ag = g_Gh + (size_t)arow*FDIM + sel*16;
    const __half* Bg = W + (size_t)(colBase + r_)*FDIM + sel*16;
    uint32_t aB = s2u(As), bB = s2u(Bs);
    uint32_t aOff0 = frag_off(wm, 20, lane), aOff1 = frag_off(wm+16, 20, lane);
    uint32_t bOff[4];
    #pragma unroll
    for (int p = 0; p < 4; p++) bOff[p] = frag_off(wn + p*16, 20, lane);

    auto issue = [&](int cc, int s) {
        uint32_t ad = aB + (s*2560 + sidx)*4;
        cpa16(ad,      Ag + cc*32);
        cpa16(ad + 16, Ag + cc*32 + 8);
        uint32_t bd = bB + (s*2560 + sidx)*4;
        cpa16(bd,      Bg + cc*32);
        cpa16(bd + 16, Bg + cc*32 + 8);
        CPA_COMMIT();
    };

    float acc[16][4];
    #pragma unroll
    for (int i = 0; i < 16; i++)
        #pragma unroll
        for (int j = 0; j < 4; j++) acc[i][j] = 0.f;

    issue(0, 0);
    issue(1, 1);
    for (int c = 0; c < 16; c++) {
        if (c + 2 < 16) CPA_WAIT1(); else CPA_WAIT0();
        __syncthreads();
        int s = c - (c/3)*3;
        compute_tile_ldsm(aB + s*2560*4, bB + s*2560*4, aOff0, aOff1, bOff, acc);
        if (c + 2 < 16) issue(c + 2, (c+2) - ((c+2)/3)*3);
    }
    #pragma unroll
    for (int mi = 0; mi < 2; mi++)
        #pragma unroll
        for (int ni = 0; ni < 8; ni++) {
            float* c = acc[mi*8+ni];
            int r = rowTile + wm + mi*16 + g;
            int cc = colBase + wn + ni*8 + 2*t4;
            if (r < cnt)
                *(unsigned*)&g_slotsh[(size_t)(base+r)*DIMM + cc] = f2h2(c[0], c[1]);
            if (r + 8 < cnt)
                *(unsigned*)&g_slotsh[(size_t)(base+r+8)*DIMM + cc] = f2h2(c[2], c[3]);
        }
}

// ---------------- rmsnorm (half out) ----------------
__global__ void rmsnorm_h(const float* __restrict__ x, const float* __restrict__ w,
                          __half* __restrict__ out) {
    int r = blockIdx.x;
    const float* xr = x + (size_t)r*DIMM;
    __shared__ float red[8];
    float s = 0.f;
    for (int d = threadIdx.x; d < DIMM; d += 256) { float v = xr[d]; s += v*v; }
    #pragma unroll
    for (int o = 16; o; o >>= 1) s += __shfl_xor_sync(0xffffffffu, s, o);
    if ((threadIdx.x & 31) == 0) red[threadIdx.x >> 5] = s;
    __syncthreads();
    if (threadIdx.x == 0) {
        float t = 0.f;
        #pragma unroll
        for (int i = 0; i < 8; i++) t += red[i];
        red[0] = rsqrtf(t / (float)DIMM + 1e-5f);
    }
    __syncthreads();
    float rms = red[0];
    for (int d = threadIdx.x; d < DIMM; d += 256)
        out[(size_t)r*DIMM + d] = __float2half(xr[d] * rms * w[d]);
}

// ---------------- rope + dual interleave ----------------
__global__ void rope_interleave_kernel() {
    int r = blockIdx.x, h = blockIdx.y, d = threadIdx.x;
    int bi = r >> 10, si = r & 1023;
    int t = 2*si + bi;
    size_t src = (size_t)r*3072 + h*64;
    float q = __half2float(g_qkvh[src + d]);
    float k = __half2float(g_qkvh[src + 1024 + d]);
    float v = __half2float(g_qkvh[src + 2048 + d]);
    ((__half*)g_vmP)[(((size_t)h*1024 + (t >> 1))*64 + d)*2 + (t & 1)] = __float2half(v);
    __shared__ float qs[64], ks[64];
    qs[d] = q; ks[d] = k;
    __syncthreads();
    if (d < 32) {
        float inv = powf(10000.0f, -(float)(2*d) / 64.0f);
        float fr = (float)si * inv;
        float sn, cs;
        sincosf(fr, &sn, &cs);
        size_t dst = ((size_t)h*SEQ + t)*64;
        float x1 = qs[d], x2 = qs[d+32];
        g_qmh[dst + d]      = __float2half( x1*cs + x2*sn);
        g_qmh[dst + d + 32] = __float2half(-x1*sn + x2*cs);
        x1 = ks[d]; x2 = ks[d+32];
        g_kmh[dst + d]      = __float2half( x1*cs + x2*sn);
        g_kmh[dst + d + 32] = __float2half(-x1*sn + x2*cs);
    }
}

// ---------------- fp16 flash attention (ldmatrix frags, cp.async K/V pipeline) ----------------
// smem words: Qs 128*36=4608, Ps 4608, Ks 2x64*36=4608, Vt 2x64*36=4608 -> 18432 (73.7KB)
#define ATT_SMEM_W (4608*4)
__global__ void __launch_bounds__(256) attn_h() {
    extern __shared__ __align__(16) unsigned asm_[];
    unsigned* Qs = asm_;
    unsigned* Ps = asm_ + 4608;
    unsigned* Ks = asm_ + 9216;     // 2 stages x 2304
    unsigned* Vt = asm_ + 13824;    // 2 stages x 2304
    int h = blockIdx.y;
    int t0 = ((int)gridDim.x - 1 - (int)blockIdx.x) * 128;
    int tid = threadIdx.x, lane = tid & 31, wid = tid >> 5;
    int g = lane >> 2, t4 = lane & 3;
    int wm = wid * 16;
    uint32_t qB = s2u(Qs), kB = s2u(Ks), pB = s2u(Ps), vB = s2u(Vt);
    uint32_t aOffQ = frag_off(wm, 36, lane);
    uint32_t bOffK[4];
    #pragma unroll
    for (int p = 0; p < 4; p++) bOffK[p] = frag_off(p*16, 36, lane);

    const __half* qb = g_qmh + ((size_t)h*SEQ + t0)*64;
    for (int i = tid; i < 128*8; i += 256) {
        int r = i >> 3, j = i & 7;
        *(uint4*)&Qs[r*36 + j*4] = ((const uint4*)(qb + (size_t)r*64))[j];
    }

    // K/V tile loader via cp.async (stage s in {0,1})
    auto issueKV = [&](int kt, int s) {
        const __half* kb = g_kmh + ((size_t)h*SEQ + kt)*64;
        #pragma unroll
        for (int it = 0; it < 2; it++) {
            int i = tid + it*256;
            int r = i >> 3, j = i & 7;
            cpa16(kB + (s*2304 + r*36 + j*4)*4, (const uint4*)(kb + (size_t)r*64) + j);
        }
        const unsigned* vp = g_vmP + ((size_t)h*1024 + (kt >> 1))*64;
        #pragma unroll
        for (int it = 0; it < 8; it++) {
            int w = tid + it*256;
            int d = w & 63, p = w >> 6;
            cpa4(vB + (s*2304 + d*36 + p)*4, vp + (size_t)p*64 + d);
        }
        CPA_COMMIT();
    };

    float o[8][4];
    #pragma unroll
    for (int n = 0; n < 8; n++)
        #pragma unroll
        for (int j = 0; j < 4; j++) o[n][j] = 0.f;
    float m0 = -1e30f, m1 = -1e30f, l0 = 0.f, l1 = 0.f;
    int row0 = t0 + wm + g, row1 = row0 + 8;
    int wmax = t0 + wm + 15;
    int ntiles = (t0 + 128) >> 6;

    issueKV(0, 0);
    for (int it = 0; it < ntiles; it++) {
        int kt = it << 6;
        if (it + 1 < ntiles) { issueKV((it+1) << 6, (it+1) & 1); CPA_WAIT1(); }
        else CPA_WAIT0();
        __syncthreads();
        if (kt <= wmax) {
            uint32_t kBs = kB + ((it & 1)*2304)*4;
            uint32_t vBs = vB + ((it & 1)*2304)*4;

            float s[8][4];
            #pragma unroll
            for (int n = 0; n < 8; n++)
                #pragma unroll
                for (int j = 0; j < 4; j++) s[n][j] = 0.f;
            #pragma unroll
            for (int ks = 0; ks < 4; ks++) {
                unsigned aq[4], bq[4][4];
                ldsm4(aq, qB + aOffQ + ks*32);
                #pragma unroll
                for (int p = 0; p < 4; p++) ldsm4(bq[p], kBs + bOffK[p] + ks*32);
                #pragma unroll
                for (int n = 0; n < 8; n++) {
                    unsigned bf[2] = { bq[n>>1][n&1], bq[n>>1][(n&1)+2] };
                    mma16(s[n], aq, bf);
                }
            }
            float mx0 = -1e30f, mx1 = -1e30f;
            #pragma unroll
            for (int n = 0; n < 8; n++) {
                int c0 = kt + n*8 + 2*t4, c1 = c0 + 1;
                s[n][0] = (c0 <= row0) ? s[n][0]*0.125f : -1e30f;
                s[n][1] = (c1 <= row0) ? s[n][1]*0.125f : -1e30f;
                s[n][2] = (c0 <= row1) ? s[n][2]*0.125f : -1e30f;
                s[n][3] = (c1 <= row1) ? s[n][3]*0.125f : -1e30f;
                mx0 = fmaxf(mx0, fmaxf(s[n][0], s[n][1]));
                mx1 = fmaxf(mx1, fmaxf(s[n][2], s[n][3]));
            }
            mx0 = fmaxf(mx0, __shfl_xor_sync(0xffffffffu, mx0, 1));
            mx0 = fmaxf(mx0, __shfl_xor_sync(0xffffffffu, mx0, 2));
            mx1 = fmaxf(mx1, __shfl_xor_sync(0xffffffffu, mx1, 1));
            mx1 = fmaxf(mx1, __shfl_xor_sync(0xffffffffu, mx1, 2));
            float nm0 = fmaxf(m0, mx0), nm1 = fmaxf(m1, mx1);
            float cor0 = __expf(m0 - nm0), cor1 = __expf(m1 - nm1);
            m0 = nm0; m1 = nm1;
            l0 *= cor0; l1 *= cor1;
            float sum0 = 0.f, sum1 = 0.f;
            #pragma unroll
            for (int n = 0; n < 8; n++) {
                float p00 = __expf(s[n][0] - nm0), p01 = __expf(s[n][1] - nm0);
                float p10 = __expf(s[n][2] - nm1), p11 = __expf(s[n][3] - nm1);
                sum0 += p00 + p01; sum1 += p10 + p11;
                Ps[(wm+g)*36 + n*4 + t4]   = f2h2(p00, p01);
                Ps[(wm+g+8)*36 + n*4 + t4] = f2h2(p10, p11);
                #pragma unroll
                for (int j = 0; j < 2; j++) { o[n][j] *= cor0; o[n][2+j] *= cor1; }
            }
            sum0 += __shfl_xor_sync(0xffffffffu, sum0, 1);
            sum0 += __shfl_xor_sync(0xffffffffu, sum0, 2);
            sum1 += __shfl_xor_sync(0xffffffffu, sum1, 1);
            sum1 += __shfl_xor_sync(0xffffffffu, sum1, 2);
            l0 += sum0; l1 += sum1;
            __syncwarp();

            #pragma unroll
            for (int ks = 0; ks < 4; ks++) {
                unsigned ap[4], bq[4][4];
                ldsm4(ap, pB + aOffQ + ks*32);
                #pragma unroll
                for (int p = 0; p < 4; p++) ldsm4(bq[p], vBs + bOffK[p] + ks*32);
                #pragma unroll
                for (int n = 0; n < 8; n++) {
                    unsigned bf[2] = { bq[n>>1][n&1], bq[n>>1][(n&1)+2] };
                    mma16(o[n], ap, bf);
                }
            }
        }
        __syncthreads();
    }

    float inv0 = 1.f / l0, inv1 = 1.f / l1;
    int tok0 = (row0 & 1)*1024 + (row0 >> 1);
    int tok1 = (row1 & 1)*1024 + (row1 >> 1);
    #pragma unroll
    for (int n = 0; n < 8; n++) {
        int col = h*64 + n*8 + 2*t4;
        *(unsigned*)&g_orowsh[(size_t)tok0*DIMM + col] = f2h2(o[n][0]*inv0, o[n][1]*inv0);
        *(unsigned*)&g_orowsh[(size_t)tok1*DIMM + col] = f2h2(o[n][2]*inv1, o[n][3]*inv1);
    }
}

// ---------------- router ----------------
__global__ void router_kernel(const float* __restrict__ pkeys, const float* __restrict__ fkeys,
                              const float* __restrict__ pbias, const float* __restrict__ fbias,
                              const int* __restrict__ pidx, const float* __restrict__ pval,
                              const int* __restrict__ fidx, const float* __restrict__ fval) {
    int tok = blockIdx.x, tid = threadIdx.x;
    bool isf = tok >= 1024;
    const float* keys = isf ? fkeys : pkeys;
    const __half* x = g_xffnh + (size_t)tok*DIMM;
    __shared__ float part[8][16];
    __shared__ float logit[16];
    int e = tid & 15, ch = tid >> 4;
    float s = 0.f;
    int d0 = ch * 128;
    for (int d = d0; d < d0 + 128; d++)
        s = fmaf(__half2float(x[d]), keys[d*16 + e], s);
    part[ch][e] = s;
    __syncthreads();
    if (tid < 16) {
        float t = 0.f;
        #pragma unroll
        for (int c = 0; c < 8; c++) t += part[c][tid];
        logit[tid] = t;
    }
    __syncthreads();
    if (tid == 0) {
        int lt = isf ? tok - 1024 : tok;
        const int*   idx  = isf ? fidx  : pidx;
        const float* val  = isf ? fval  : pval;
        const float* bias = isf ? fbias : pbias;
        float sc[4]; int id[4]; float sum = 0.f;
        #pragma unroll
        for (int k = 0; k < 4; k++) {
            int ix = idx[lt*4 + k];
            float v = val[lt*4 + k] + logit[ix] + bias[ix];
            float s2 = 1.f / (1.f + expf(-v));
            sc[k] = s2; sum += s2;
            id[k] = ix + (isf ? 16 : 0);
        }
        #pragma unroll
        for (int k = 0; k < 4; k++) {
            g_scales[tok*4 + k] = sc[k] / sum;
            g_eid[tok*4 + k] = id[k];
            atomicAdd(&g_counts[id[k]], 1);
        }
    }
}

__global__ void zero32_kernel() {
    int i = threadIdx.x;
    if (i < NEXP) { g_counts[i] = 0; g_cursors[i] = 0; }
}

// fused prefix + scatter: single block, 256 threads
__global__ void __launch_bounds__(256) prefix_scatter_kernel() {
    __shared__ int soff[NEXP];
    if (threadIdx.x == 0) {
        int acc = 0;
        for (int e = 0; e < NEXP; e++) { soff[e] = acc; g_offsets[e] = acc; acc += g_counts[e]; }
    }
    __syncthreads();
    for (int a = threadIdx.x; a < NASS; a += 256) {
        int e = g_eid[a];
        int p = soff[e] + atomicAdd(&g_cursors[e], 1);
        g_tokof[p] = a >> 2;
        g_posof[a] = p;
    }
}

__global__ void combine_kernel(float* __restrict__ y) {
    int tok = blockIdx.x;
    __shared__ int pos[4];
    __shared__ float sc[4];
    if (threadIdx.x < 4) {
        pos[threadIdx.x] = g_posof[tok*4 + threadIdx.x];
        sc[threadIdx.x]  = g_scales[tok*4 + threadIdx.x];
    }
    __syncthreads();
    for (int d = threadIdx.x; d < DIMM; d += 256) {
        float v = g_xffni[(size_t)tok*DIMM + d]
                + __half2float(g_shdownh[(size_t)tok*DIMM + d]);
        #pragma unroll
        for (int k = 0; k < 4; k++)
            v = fmaf(sc[k], __half2float(g_slotsh[(size_t)pos[k]*DIMM + d]), v);
        y[(size_t)tok*DIMM + d] = v;
    }
}

// ---------------- launch ----------------
extern "C" void kernel_launch(void* const* d_in, const int* in_sizes, int n_in,
                              void* d_out, int out_size) {
    const float* x_input  = (const float*)d_in[0];
    const int*   p_idx    = (const int*)  d_in[1];
    const float* p_val    = (const float*)d_in[2];
    const int*   f_idx    = (const int*)  d_in[3];
    const float* f_val    = (const float*)d_in[4];
    const float* attn_nw  = (const float*)d_in[5];
    const float* ffn_nw   = (const float*)d_in[6];
    const float* W_attn   = (const float*)d_in[7];
    const float* W_attn_o = (const float*)d_in[8];
    const float* ffn_up   = (const float*)d_in[9];
    const float* ffn_down = (const float*)d_in[10];
    const float* pW       = (const float*)d_in[11];
    const float* fW       = (const float*)d_in[12];
    const float* pkeys    = (const float*)d_in[13];
    const float* fkeys    = (const float*)d_in[14];
    const float* pbias    = (const float*)d_in[15];
    const float* fbias    = (const float*)d_in[16];
    float* out = (float*)d_out;

    __half *xnormh, *qkvh, *orowsh, *xffnh, *hsh, *shdownh;
    __half *wqkvT, *woT, *wupT, *wdnT;
    float *xffni;
    cudaGetSymbolAddress((void**)&xnormh, g_xnormh);
    cudaGetSymbolAddress((void**)&qkvh,   g_qkvh);
    cudaGetSymbolAddress((void**)&orowsh, g_orowsh);
    cudaGetSymbolAddress((void**)&xffni,  g_xffni);
    cudaGetSymbolAddress((void**)&xffnh,  g_xffnh);
    cudaGetSymbolAddress((void**)&hsh,    g_hsh);
    cudaGetSymbolAddress((void**)&shdownh, g_shdownh);
    cudaGetSymbolAddress((void**)&wqkvT,  g_wqkvT);
    cudaGetSymbolAddress((void**)&woT,    g_woT);
    cudaGetSymbolAddress((void**)&wupT,   g_wupT);
    cudaGetSymbolAddress((void**)&wdnT,   g_wdnT);

    static cudaStream_t s1 = nullptr, s2 = nullptr;
    static cudaEvent_t evFork, evZero, evQKVp, evWo, evWup, evMoeP, evXffn, evSh;
    static bool init_done = false;
    if (!init_done) {
        cudaFuncSetAttribute(attn_h, cudaFuncAttributeMaxDynamicSharedMemorySize,
                             ATT_SMEM_W * 4);
        cudaFuncSetAttribute(gemm_h<0>, cudaFuncAttributeMaxDynamicSharedMemorySize, GEMM_SMEM);
        cudaFuncSetAttribute(gemm_h<1>, cudaFuncAttributeMaxDynamicSharedMemorySize, GEMM_SMEM);
        cudaFuncSetAttribute(gemm_h<2>, cudaFuncAttributeMaxDynamicSharedMemorySize, GEMM_SMEM);
        cudaFuncSetAttribute(moe_gu_h, cudaFuncAttributeMaxDynamicSharedMemorySize, GEMM_SMEM);
        cudaFuncSetAttribute(moe_down_h, cudaFuncAttributeMaxDynamicSharedMemorySize, GEMM_SMEM);
        cudaStreamCreateWithFlags(&s1, cudaStreamNonBlocking);
        cudaStreamCreateWithFlags(&s2, cudaStreamNonBlocking);
        cudaEventCreateWithFlags(&evFork, cudaEventDisableTiming);
        cudaEventCreateWithFlags(&evZero, cudaEventDisableTiming);
        cudaEventCreateWithFlags(&evQKVp, cudaEventDisableTiming);
        cudaEventCreateWithFlags(&evWo,   cudaEventDisableTiming);
        cudaEventCreateWithFlags(&evWup,  cudaEventDisableTiming);
        cudaEventCreateWithFlags(&evMoeP, cudaEventDisableTiming);
        cudaEventCreateWithFlags(&evXffn, cudaEventDisableTiming);
        cudaEventCreateWithFlags(&evSh,   cudaEventDisableTiming);
        init_done = true;
    }

    // fork side stream s1: zero + all weight packing
    cudaEventRecord(evFork, 0);
    cudaStreamWaitEvent(s1, evFork, 0);
    zero32_kernel<<<1, 32, 0, s1>>>();
    cudaEventRecord(evZero, s1);
    packT<<<dim3(16, 96),  256, 0, s1>>>(W_attn,   wqkvT, DIMM, 3*DIMM);
    cudaEventRecord(evQKVp, s1);
    packT<<<dim3(16, 32),  256, 0, s1>>>(W_attn_o, woT,   DIMM, DIMM);
    cudaEventRecord(evWo, s1);
    packT_gu<<<dim3(16, 128), 256, 0, s1>>>(ffn_up, wupT, DIMM, 2*DSH);
    packT<<<dim3(32, 32),  256, 0, s1>>>(ffn_down, wdnT,  DSH,  DIMM);
    cudaEventRecord(evWup, s1);
    packT_moe<<<dim3(16, 16, 64), 256, 0, s1>>>(pW, fW);
    conv_moe_down<<<dim3(256, 1, 32), 256, 0, s1>>>(pW, fW);
    cudaEventRecord(evMoeP, s1);

    // main stream: attention block (overlaps with packing)
    rmsnorm_h<<<TOK, 256>>>(x_input, attn_nw, xnormh);
    cudaStreamWaitEvent(0, evQKVp, 0);
    gemm_h<1><<<dim3(24, 16), 256, GEMM_SMEM>>>(xnormh, wqkvT, qkvh, nullptr, TOK, 3*DIMM, DIMM);
    rope_interleave_kernel<<<dim3(TOK, NH), 64>>>();
    attn_h<<<dim3(SEQ/128, NH), 256, ATT_SMEM_W*4>>>();
    cudaStreamWaitEvent(0, evWo, 0);
    gemm_h<0><<<dim3(8, 16), 256, GEMM_SMEM>>>(orowsh, woT, xffni, x_input, TOK, DIMM, DIMM);
    rmsnorm_h<<<TOK, 256>>>(xffni, ffn_nw, xffnh);
    cudaEventRecord(evXffn, 0);

    // s2: full shared-expert branch (up + down), overlaps router + MoE chain
    cudaStreamWaitEvent(s2, evXffn, 0);
    cudaStreamWaitEvent(s2, evWup, 0);
    gemm_h<2><<<dim3(32, 16), 256, GEMM_SMEM, s2>>>(xffnh, wupT, hsh, nullptr, TOK, 2*DSH, DIMM);
    gemm_h<1><<<dim3(8, 16), 256, GEMM_SMEM, s2>>>(hsh, wdnT, shdownh, nullptr, TOK, DIMM, DSH);
    cudaEventRecord(evSh, s2);

    // main: routing + grouped MoE
    cudaStreamWaitEvent(0, evZero, 0);
    router_kernel<<<TOK, 128>>>(pkeys, fkeys, pbias, fbias, p_idx, p_val, f_idx, f_val);
    prefix_scatter_kernel<<<1, 256>>>();
    cudaStreamWaitEvent(0, evMoeP, 0);
    moe_gu_h<<<dim3(8, 16, NEXP), 256, GEMM_SMEM>>>();
    moe_down_h<<<dim3(8, 16, NEXP), 256, GEMM_SMEM>>>();
    // final combine joins s2 and adds shared-expert output
    cudaStreamWaitEvent(0, evSh, 0);
    combine_kernel<<<TOK, 256>>>(out);
}

// round 16
// speedup vs baseline: 7.8931x; 1.0582x over previous
#include <cuda_runtime.h>
#include <cuda_fp16.h>
#include <math.h>
#include <stdint.h>

// ---------------- problem constants ----------------
#define TOK   2048
#define DIMM  1024
#define NH    16
#define HD    64
#define SEQ   2048
#define NASS  8192
#define NEXP  32
#define FDIM  512
#define DSH   2048

// ---------------- scratch ----------------
__device__ __align__(16) __half g_xnormh[TOK*DIMM];
__device__ __align__(16) __half g_qkvh[TOK*3*DIMM];
__device__ __align__(16) __half g_qmh[NH*SEQ*HD];
__device__ __align__(16) __half g_kmh[NH*SEQ*HD];
__device__ __align__(16) unsigned g_vmP[NH*(SEQ/2)*HD];
__device__ __align__(16) __half g_orowsh[TOK*DIMM];
__device__ float g_xffni[TOK*DIMM];
__device__ __align__(16) __half g_xffnh[TOK*DIMM];
__device__ __align__(16) __half g_Gh[NASS*FDIM];
__device__ __align__(16) __half g_slotsh[(size_t)NASS*DIMM];
__device__ __align__(16) __half g_hsh[(size_t)TOK*DSH];
__device__ __align__(16) __half g_shdownh[(size_t)TOK*DIMM];
// split-KV attention partials
__device__ __align__(16) float  g_attO[(size_t)256*8192];   // [h*8+bb][split][128][64]
__device__ __align__(16) float2 g_attML[256*128];
__device__ float g_scales[NASS];
__device__ int   g_eid[NASS];
__device__ int   g_tokof[NASS];
__device__ int   g_posof[NASS];
__device__ int   g_counts[NEXP];
__device__ int   g_offsets[NEXP];
__device__ int   g_cursors[NEXP];
// K-major packed fp16 weights: Wt[N][K]
__device__ __align__(16) __half g_wqkvT[3072*1024];
__device__ __align__(16) __half g_woT[1024*1024];
__device__ __align__(16) __half g_wupT[(size_t)4096*1024];
__device__ __align__(16) __half g_wdnT[(size_t)1024*2048];
__device__ __align__(16) __half g_wguT[(size_t)32*1024*1024];
__device__ __align__(16) __half g_wdnM[(size_t)32*1024*512];

// ---------------- helpers ----------------
__device__ __forceinline__ unsigned f2h2(float a, float b) {
    __half2 h = __floats2half2_rn(a, b);
    return *reinterpret_cast<unsigned*>(&h);
}
__device__ __forceinline__ void mma16(float c[4], const unsigned a[4], const unsigned b[2]) {
    asm volatile("mma.sync.aligned.m16n8k16.row.col.f32.f16.f16.f32 "
                 "{%0,%1,%2,%3},{%4,%5,%6,%7},{%8,%9},{%0,%1,%2,%3};"
                 : "+f"(c[0]), "+f"(c[1]), "+f"(c[2]), "+f"(c[3])
                 : "r"(a[0]), "r"(a[1]), "r"(a[2]), "r"(a[3]), "r"(b[0]), "r"(b[1]));
}
__device__ __forceinline__ uint32_t s2u(const void* p) {
    uint32_t a;
    asm("{ .reg .u64 t; cvta.to.shared.u64 t, %1; cvt.u32.u64 %0, t; }" : "=r"(a) : "l"(p));
    return a;
}
__device__ __forceinline__ void cpa16(uint32_t dst, const void* src) {
    asm volatile("cp.async.ca.shared.global [%0], [%1], 16;" :: "r"(dst), "l"(src));
}
__device__ __forceinline__ void cpa4(uint32_t dst, const void* src) {
    asm volatile("cp.async.ca.shared.global [%0], [%1], 4;" :: "r"(dst), "l"(src));
}
#define CPA_COMMIT() asm volatile("cp.async.commit_group;")
#define CPA_WAIT1()  asm volatile("cp.async.wait_group 1;")
#define CPA_WAIT0()  asm volatile("cp.async.wait_group 0;")

__device__ __forceinline__ void ldsm4(unsigned* r, uint32_t a) {
    asm volatile("ldmatrix.sync.aligned.m8n8.x4.shared.b16 {%0,%1,%2,%3}, [%4];"
                 : "=r"(r[0]), "=r"(r[1]), "=r"(r[2]), "=r"(r[3]) : "r"(a));
}
__device__ __forceinline__ uint32_t frag_off(int rowBase, int stride, int lane) {
    int lr = lane & 7, lh = (lane >> 3) & 1, lq = lane >> 4;
    return (uint32_t)(((rowBase + lr + lh*8) * stride + lq*4) * 4);
}

__device__ __forceinline__ void compute_tile_ldsm(uint32_t aS, uint32_t bS,
                                                  uint32_t aOff0, uint32_t aOff1,
                                                  const uint32_t* bOff,
                                                  float acc[16][4]) {
    #pragma unroll
    for (int ks = 0; ks < 2; ks++) {
        unsigned a0[4], a1[4], bq[4][4];
        ldsm4(a0, aS + aOff0 + ks*32);
        ldsm4(a1, aS + aOff1 + ks*32);
        #pragma unroll
        for (int p = 0; p < 4; p++) ldsm4(bq[p], bS + bOff[p] + ks*32);
        #pragma unroll
        for (int ni = 0; ni < 8; ni++) {
            unsigned bf[2] = { bq[ni>>1][ni&1], bq[ni>>1][(ni&1)+2] };
            mma16(acc[ni],   a0, bf);
            mma16(acc[8+ni], a1, bf);
        }
    }
}

// ---------------- transpose-pack ----------------
template<int MODE>
__device__ __forceinline__ void packT_body(const float* __restrict__ W,
                                           __half* __restrict__ Wt,
                                           int K, int N, int k0, int n0, int tid) {
    __shared__ __half tile[32][72];
    int nl = tid & 31, kl = tid >> 5;
    #pragma unroll
    for (int it = 0; it < 8; it++)
        tile[nl][kl + it*8] = __float2half(W[(size_t)(k0 + kl + it*8)*N + n0 + nl]);
    __syncthreads();
    int kq8 = (tid & 7)*8, nr = tid >> 3;
    int c = n0 + nr;
    int drow;
    if (MODE == 0) drow = c;
    else {
        int NHf = N >> 1;
        drow = (c < NHf) ? ((c >> 6)*128 + (c & 63))
                         : (((c - NHf) >> 6)*128 + 64 + ((c - NHf) & 63));
    }
    *(uint4*)&Wt[(size_t)drow*K + k0 + kq8] = *(uint4*)&tile[nr][kq8];
}
__global__ void __launch_bounds__(256) packT(const float* __restrict__ W,
                                             __half* __restrict__ Wt, int K, int N) {
    packT_body<0>(W, Wt, K, N, blockIdx.x*64, blockIdx.y*32, threadIdx.x);
}
__global__ void __launch_bounds__(256) packT_gu(const float* __restrict__ W,
                                                __half* __restrict__ Wt, int K, int N) {
    packT_body<1>(W, Wt, K, N, blockIdx.x*64, blockIdx.y*32, threadIdx.x);
}
__global__ void __launch_bounds__(256) packT_moe(const float* __restrict__ pW,
                                                 const float* __restrict__ fW) {
    __shared__ __half tile[32][72];
    int z = blockIdx.z;
    int sel = z >> 5, e = z & 31;
    const float* W = (e < 16) ? pW + ((size_t)sel*16 + e)      * (size_t)DIMM*FDIM
                              : fW + ((size_t)sel*16 + (e-16)) * (size_t)DIMM*FDIM;
    __half* Wt = g_wguT + (size_t)e*1024*1024;
    int k0 = blockIdx.x*64, n0 = blockIdx.y*32;
    int tid = threadIdx.x;
    int nl = tid & 31, kl = tid >> 5;
    #pragma unroll
    for (int it = 0; it < 8; it++)
        tile[nl][kl + it*8] = __float2half(W[(size_t)(k0 + kl + it*8)*FDIM + n0 + nl]);
    __syncthreads();
    int kq8 = (tid & 7)*8, nr = tid >> 3;
    int c = n0 + nr;
    int drow = (c >> 6)*128 + sel*64 + (c & 63);
    *(uint4*)&Wt[(size_t)drow*DIMM + k0 + kq8] = *(uint4*)&tile[nr][kq8];
}
__global__ void __launch_bounds__(256) conv_moe_down(const float* __restrict__ pW,
                                                     const float* __restrict__ fW) {
    int z = blockIdx.z;
    const float* W = (z < 16) ? pW + ((size_t)2*16 + z)      * (size_t)DIMM*FDIM
                              : fW + ((size_t)2*16 + (z-16)) * (size_t)DIMM*FDIM;
    __half* Wh = g_wdnM + (size_t)z*1024*512;
    int idx = blockIdx.x*256 + threadIdx.x;
    float4 a = ((const float4*)W)[idx*2];
    float4 b = ((const float4*)W)[idx*2 + 1];
    ((uint4*)Wh)[idx] = make_uint4(f2h2(a.x,a.y), f2h2(a.z,a.w), f2h2(b.x,b.y), f2h2(b.z,b.w));
}

// ---------------- dense fp16 GEMM, 3-stage cp.async + ldmatrix ----------------
#define GEMM_SMEM (2560 * 2 * 3 * 4)
template<int OUT>
__global__ void __launch_bounds__(256) gemm_h(const __half* __restrict__ A,
                                              const __half* __restrict__ Bt,
                                              void* __restrict__ Cv,
                                              const float* __restrict__ D,
                                              int M, int N, int K) {
    extern __shared__ __align__(16) unsigned smem[];
    unsigned* As = smem;
    unsigned* Bs = smem + 3*2560;
    int tid = threadIdx.x, lane = tid & 31, wid = tid >> 5;
    int g = lane >> 2, t4 = lane & 3;
    int wm = (wid & 3)*32, wn = (wid >> 2)*64;
    size_t rowBase = (size_t)blockIdx.y * 128, colBase = (size_t)blockIdx.x * 128;
    int r_ = tid >> 1, sel = tid & 1;
    int sidx = r_*20 + sel*8;
    const __half* Ag = A  + (rowBase + r_)*K + sel*16;
    const __half* Bg = Bt + (colBase + r_)*K + sel*16;
    uint32_t aB = s2u(As), bB = s2u(Bs);
    uint32_t aOff0 = frag_off(wm, 20, lane), aOff1 = frag_off(wm+16, 20, lane);
    uint32_t bOff[4];
    #pragma unroll
    for (int p = 0; p < 4; p++) bOff[p] = frag_off(wn + p*16, 20, lane);
    int NC = K >> 5;

    auto issue = [&](int cc, int s) {
        uint32_t ad = aB + (s*2560 + sidx)*4;
        cpa16(ad,      Ag + cc*32);
        cpa16(ad + 16, Ag + cc*32 + 8);
        uint32_t bd = bB + (s*2560 + sidx)*4;
        cpa16(bd,      Bg + cc*32);
        cpa16(bd + 16, Bg + cc*32 + 8);
        CPA_COMMIT();
    };

    float acc[16][4];
    #pragma unroll
    for (int i = 0; i < 16; i++)
        #pragma unroll
        for (int j = 0; j < 4; j++) acc[i][j] = 0.f;

    issue(0, 0);
    issue(1, 1);
    for (int c = 0; c < NC; c++) {
        if (c + 2 < NC) CPA_WAIT1(); else CPA_WAIT0();
        __syncthreads();
        int s = c - (c/3)*3;
        compute_tile_ldsm(aB + s*2560*4, bB + s*2560*4, aOff0, aOff1, bOff, acc);
        if (c + 2 < NC) issue(c + 2, (c+2) - ((c+2)/3)*3);
    }
    if (OUT == 2) {
        __syncthreads();
        unsigned* sm = smem;
        #pragma unroll
        for (int mi = 0; mi < 2; mi++)
            #pragma unroll
            for (int ni = 0; ni < 8; ni++) {
                float* c = acc[mi*8+ni];
                int r = wm + mi*16 + g;
                int cw = (wn >> 1) + ni*4 + t4;
                sm[r*66 + cw]     = f2h2(c[0], c[1]);
                sm[(r+8)*66 + cw] = f2h2(c[2], c[3]);
            }
        __syncthreads();
        __half* C = (__half*)Cv;
        int outN = N >> 1;
        size_t fBase = colBase >> 1;
        for (int idx = tid; idx < 128*32; idx += 256) {
            int r = idx >> 5, cw = idx & 31;
            float2 gf = __half22float2(*(__half2*)&sm[r*66 + cw]);
            float2 uf = __half22float2(*(__half2*)&sm[r*66 + 32 + cw]);
            float a = gf.x / (1.f + __expf(-gf.x)) * uf.x;
            float b = gf.y / (1.f + __expf(-gf.y)) * uf.y;
            *(unsigned*)&C[(rowBase + r)*outN + fBase + 2*cw] = f2h2(a, b);
        }
        return;
    }
    #pragma unroll
    for (int mi = 0; mi < 2; mi++)
        #pragma unroll
        for (int ni = 0; ni < 8; ni++) {
            float* c = acc[mi*8+ni];
            size_t r0 = rowBase + wm + mi*16 + g;
            size_t c0 = colBase + wn + ni*8 + 2*t4;
            if (OUT == 0) {
                float* C = (float*)Cv;
                size_t o0 = r0*N + c0, o1 = (r0+8)*N + c0;
                if (D) {
                    C[o0] = c[0] + D[o0]; C[o0+1] = c[1] + D[o0+1];
                    C[o1] = c[2] + D[o1]; C[o1+1] = c[3] + D[o1+1];
                } else {
                    C[o0] = c[0]; C[o0+1] = c[1];
                    C[o1] = c[2]; C[o1+1] = c[3];
                }
            } else {
                __half* C = (__half*)Cv;
                *(unsigned*)&C[r0*N + c0]     = f2h2(c[0], c[1]);
                *(unsigned*)&C[(r0+8)*N + c0] = f2h2(c[2], c[3]);
            }
        }
}

// ---------------- MoE gate+up grouped GEMM, fused swiglu -> g_Gh ----------------
__global__ void __launch_bounds__(256) moe_gu_h() {
    extern __shared__ __align__(16) unsigned smem[];
    unsigned* As = smem;
    unsigned* Bs = smem + 3*2560;
    __shared__ int rows[128];
    int e = blockIdx.z;
    int cnt = g_counts[e];
    int rowTile = blockIdx.y * 128;
    if (rowTile >= cnt) return;
    int base = g_offsets[e];
    int colBase = blockIdx.x * 128;
    const __half* Wt = g_wguT + (size_t)e*1024*1024;
    int tid = threadIdx.x;
    if (tid < 128) {
        int rr = rowTile + tid;
        rows[tid] = (rr < cnt) ? g_tokof[base + rr] : 0;
    }
    __syncthreads();
    int lane = tid & 31, wid = tid >> 5;
    int g = lane >> 2, t4 = lane & 3;
    int wm = (wid & 3)*32, wn = (wid >> 2)*64;
    int r_ = tid >> 1, sel = tid & 1;
    int sidx = r_*20 + sel*8;
    const __half* Ag = g_xffnh + (size_t)rows[r_]*DIMM + sel*16;
    const __half* Bg = Wt + (size_t)(colBase + r_)*1024 + sel*16;
    uint32_t aB = s2u(As), bB = s2u(Bs);
    uint32_t aOff0 = frag_off(wm, 20, lane), aOff1 = frag_off(wm+16, 20, lane);
    uint32_t bOff[4];
    #pragma unroll
    for (int p = 0; p < 4; p++) bOff[p] = frag_off(wn + p*16, 20, lane);

    auto issue = [&](int cc, int s) {
        uint32_t ad = aB + (s*2560 + sidx)*4;
        cpa16(ad,      Ag + cc*32);
        cpa16(ad + 16, Ag + cc*32 + 8);
        uint32_t bd = bB + (s*2560 + sidx)*4;
        cpa16(bd,      Bg + cc*32);
        cpa16(bd + 16, Bg + cc*32 + 8);
        CPA_COMMIT();
    };

    float acc[16][4];
    #pragma unroll
    for (int i = 0; i < 16; i++)
        #pragma unroll
        for (int j = 0; j < 4; j++) acc[i][j] = 0.f;

    issue(0, 0);
    issue(1, 1);
    for (int c = 0; c < 32; c++) {
        if (c + 2 < 32) CPA_WAIT1(); else CPA_WAIT0();
        __syncthreads();
        int s = c - (c/3)*3;
        compute_tile_ldsm(aB + s*2560*4, bB + s*2560*4, aOff0, aOff1, bOff, acc);
        if (c + 2 < 32) issue(c + 2, (c+2) - ((c+2)/3)*3);
    }
    __syncthreads();
    unsigned* sm = smem;
    #pragma unroll
    for (int mi = 0; mi < 2; mi++)
        #pragma unroll
        for (int ni = 0; ni < 8; ni++) {
            float* c = acc[mi*8+ni];
            int r = wm + mi*16 + g;
            int cw = (wn >> 1) + ni*4 + t4;
            sm[r*66 + cw]     = f2h2(c[0], c[1]);
            sm[(r+8)*66 + cw] = f2h2(c[2], c[3]);
        }
    __syncthreads();
    int fBase = colBase >> 1;
    for (int idx = tid; idx < 128*32; idx += 256) {
        int r = idx >> 5, cw = idx & 31;
        if (rowTile + r >= cnt) continue;
        float2 gf = __half22float2(*(__half2*)&sm[r*66 + cw]);
        float2 uf = __half22float2(*(__half2*)&sm[r*66 + 32 + cw]);
        float a = gf.x / (1.f + __expf(-gf.x)) * uf.x;
        float b = gf.y / (1.f + __expf(-gf.y)) * uf.y;
        *(unsigned*)&g_Gh[(size_t)(base + rowTile + r)*FDIM + fBase + 2*cw] = f2h2(a, b);
    }
}

// ---------------- MoE down grouped GEMM ----------------
__global__ void __launch_bounds__(256) moe_down_h() {
    extern __shared__ __align__(16) unsigned smem[];
    unsigned* As = smem;
    unsigned* Bs = smem + 3*2560;
    int e = blockIdx.z;
    int cnt = g_counts[e];
    int rowTile = blockIdx.y * 128;
    if (rowTile >= cnt) return;
    int base = g_offsets[e];
    int colBase = blockIdx.x * 128;
    const __half* W = g_wdnM + (size_t)e*1024*512;
    int tid = threadIdx.x, lane = tid & 31, wid = tid >> 5;
    int g = lane >> 2, t4 = lane & 3;
    int wm = (wid & 3)*32, wn = (wid >> 2)*64;
    int r_ = tid >> 1, sel = tid & 1;
    int sidx = r_*20 + sel*8;
    int arow = base + rowTile + r_;
    if (arow > NASS - 1) arow = NASS - 1;
    const __half* Ag = g_Gh + (size_t)arow*FDIM + sel*16;
    const __half* Bg = W + (size_t)(colBase + r_)*FDIM + sel*16;
    uint32_t aB = s2u(As), bB = s2u(Bs);
    uint32_t aOff0 = frag_off(wm, 20, lane), aOff1 = frag_off(wm+16, 20, lane);
    uint32_t bOff[4];
    #pragma unroll
    for (int p = 0; p < 4; p++) bOff[p] = frag_off(wn + p*16, 20, lane);

    auto issue = [&](int cc, int s) {
        uint32_t ad = aB + (s*2560 + sidx)*4;
        cpa16(ad,      Ag + cc*32);
        cpa16(ad + 16, Ag + cc*32 + 8);
        uint32_t bd = bB + (s*2560 + sidx)*4;
        cpa16(bd,      Bg + cc*32);
        cpa16(bd + 16, Bg + cc*32 + 8);
        CPA_COMMIT();
    };

    float acc[16][4];
    #pragma unroll
    for (int i = 0; i < 16; i++)
        #pragma unroll
        for (int j = 0; j < 4; j++) acc[i][j] = 0.f;

    issue(0, 0);
    issue(1, 1);
    for (int c = 0; c < 16; c++) {
        if (c + 2 < 16) CPA_WAIT1(); else CPA_WAIT0();
        __syncthreads();
        int s = c - (c/3)*3;
        compute_tile_ldsm(aB + s*2560*4, bB + s*2560*4, aOff0, aOff1, bOff, acc);
        if (c + 2 < 16) issue(c + 2, (c+2) - ((c+2)/3)*3);
    }
    #pragma unroll
    for (int mi = 0; mi < 2; mi++)
        #pragma unroll
        for (int ni = 0; ni < 8; ni++) {
            float* c = acc[mi*8+ni];
            int r = rowTile + wm + mi*16 + g;
            int cc = colBase + wn + ni*8 + 2*t4;
            if (r < cnt)
                *(unsigned*)&g_slotsh[(size_t)(base+r)*DIMM + cc] = f2h2(c[0], c[1]);
            if (r + 8 < cnt)
                *(unsigned*)&g_slotsh[(size_t)(base+r+8)*DIMM + cc] = f2h2(c[2], c[3]);
        }
}

// ---------------- rmsnorm (half out) ----------------
__global__ void rmsnorm_h(const float* __restrict__ x, const float* __restrict__ w,
                          __half* __restrict__ out) {
    int r = blockIdx.x;
    const float* xr = x + (size_t)r*DIMM;
    __shared__ float red[8];
    float s = 0.f;
    for (int d = threadIdx.x; d < DIMM; d += 256) { float v = xr[d]; s += v*v; }
    #pragma unroll
    for (int o = 16; o; o >>= 1) s += __shfl_xor_sync(0xffffffffu, s, o);
    if ((threadIdx.x & 31) == 0) red[threadIdx.x >> 5] = s;
    __syncthreads();
    if (threadIdx.x == 0) {
        float t = 0.f;
        #pragma unroll
        for (int i = 0; i < 8; i++) t += red[i];
        red[0] = rsqrtf(t / (float)DIMM + 1e-5f);
    }
    __syncthreads();
    float rms = red[0];
    for (int d = threadIdx.x; d < DIMM; d += 256)
        out[(size_t)r*DIMM + d] = __float2half(xr[d] * rms * w[d]);
}

// ---------------- fused rmsnorm + router ----------------
__global__ void __launch_bounds__(256) rmsnorm_router(
    const float* __restrict__ x, const float* __restrict__ w,
    const float* __restrict__ pkeys, const float* __restrict__ fkeys,
    const float* __restrict__ pbias, const float* __restrict__ fbias,
    const int* __restrict__ pidx, const float* __restrict__ pval,
    const int* __restrict__ fidx, const float* __restrict__ fval,
    __half* __restrict__ out) {
    int tok = blockIdx.x, tid = threadIdx.x;
    const float* xr = x + (size_t)tok*DIMM;
    __shared__ float red[8];
    __shared__ __half xs[DIMM];
    __shared__ float part[16][17];
    __shared__ float logit[16];
    float s = 0.f;
    for (int d = tid; d < DIMM; d += 256) { float v = xr[d]; s += v*v; }
    #pragma unroll
    for (int o = 16; o; o >>= 1) s += __shfl_xor_sync(0xffffffffu, s, o);
    if ((tid & 31) == 0) red[tid >> 5] = s;
    __syncthreads();
    if (tid == 0) {
        float t = 0.f;
        #pragma unroll
        for (int i = 0; i < 8; i++) t += red[i];
        red[0] = rsqrtf(t / (float)DIMM + 1e-5f);
    }
    __syncthreads();
    float rms = red[0];
    for (int d = tid; d < DIMM; d += 256) {
        __half hv = __float2half(xr[d] * rms * w[d]);
        xs[d] = hv;
        out[(size_t)tok*DIMM + d] = hv;
    }
    __syncthreads();
    bool isf = tok >= 1024;
    const float* keys = isf ? fkeys : pkeys;
    int e = tid & 15, ch = tid >> 4;
    float sl = 0.f;
    int d0 = ch * 64;
    for (int d = d0; d < d0 + 64; d++)
        sl = fmaf(__half2float(xs[d]), keys[d*16 + e], sl);
    part[ch][e] = sl;
    __syncthreads();
    if (tid < 16) {
        float t = 0.f;
        #pragma unroll
        for (int c = 0; c < 16; c++) t += part[c][tid];
        logit[tid] = t;
    }
    __syncthreads();
    if (tid == 0) {
        int lt = isf ? tok - 1024 : tok;
        const int*   idx  = isf ? fidx  : pidx;
        const float* val  = isf ? fval  : pval;
        const float* bias = isf ? fbias : pbias;
        float sc[4]; int id[4]; float sum = 0.f;
        #pragma unroll
        for (int k = 0; k < 4; k++) {
            int ix = idx[lt*4 + k];
            float v = val[lt*4 + k] + logit[ix] + bias[ix];
            float s2 = 1.f / (1.f + expf(-v));
            sc[k] = s2; sum += s2;
            id[k] = ix + (isf ? 16 : 0);
        }
        #pragma unroll
        for (int k = 0; k < 4; k++) {
            g_scales[tok*4 + k] = sc[k] / sum;
            g_eid[tok*4 + k] = id[k];
            atomicAdd(&g_counts[id[k]], 1);
        }
    }
}

// ---------------- rope + dual interleave ----------------
__global__ void rope_interleave_kernel() {
    int r = blockIdx.x, h = blockIdx.y, d = threadIdx.x;
    int bi = r >> 10, si = r & 1023;
    int t = 2*si + bi;
    size_t src = (size_t)r*3072 + h*64;
    float q = __half2float(g_qkvh[src + d]);
    float k = __half2float(g_qkvh[src + 1024 + d]);
    float v = __half2float(g_qkvh[src + 2048 + d]);
    ((__half*)g_vmP)[(((size_t)h*1024 + (t >> 1))*64 + d)*2 + (t & 1)] = __float2half(v);
    __shared__ float qs[64], ks[64];
    qs[d] = q; ks[d] = k;
    __syncthreads();
    if (d < 32) {
        float inv = powf(10000.0f, -(float)(2*d) / 64.0f);
        float fr = (float)si * inv;
        float sn, cs;
        sincosf(fr, &sn, &cs);
        size_t dst = ((size_t)h*SEQ + t)*64;
        float x1 = qs[d], x2 = qs[d+32];
        g_qmh[dst + d]      = __float2half( x1*cs + x2*sn);
        g_qmh[dst + d + 32] = __float2half(-x1*sn + x2*cs);
        x1 = ks[d]; x2 = ks[d+32];
        g_kmh[dst + d]      = __float2half( x1*cs + x2*sn);
        g_kmh[dst + d + 32] = __float2half(-x1*sn + x2*cs);
    }
}

// ---------------- fp16 flash attention (split-KV load-balanced) ----------------
// work items per head: i<16 -> split halves of query tiles b=8..15; i>=16 -> singles b=7..0
#define ATT_SMEM_W (4608*4)
__global__ void __launch_bounds__(256) attn_h() {
    extern __shared__ __align__(16) unsigned asm_[];
    unsigned* Qs = asm_;
    unsigned* Ps = asm_ + 4608;
    unsigned* Ks = asm_ + 9216;
    unsigned* Vt = asm_ + 13824;
    int i = blockIdx.x, h = blockIdx.y;
    int b, split, nsplit;
    if (i < 16) { b = 15 - (i >> 1); split = i & 1; nsplit = 2; }
    else        { b = 23 - i;        split = 0;     nsplit = 1; }
    int t0 = b * 128;
    int ntot = (t0 + 128) >> 6;
    int half = ntot >> 1;
    int tlo = (nsplit == 2 && split == 1) ? half : 0;
    int thi = (nsplit == 2 && split == 0) ? half : ntot;
    int tid = threadIdx.x, lane = tid & 31, wid = tid >> 5;
    int g = lane >> 2, t4 = lane & 3;
    int wm = wid * 16;
    uint32_t qB = s2u(Qs), kB = s2u(Ks), pB = s2u(Ps), vB = s2u(Vt);
    uint32_t aOffQ = frag_off(wm, 36, lane);
    uint32_t bOffK[4];
    #pragma unroll
    for (int p = 0; p < 4; p++) bOffK[p] = frag_off(p*16, 36, lane);

    const __half* qb = g_qmh + ((size_t)h*SEQ + t0)*64;
    for (int ii = tid; ii < 128*8; ii += 256) {
        int r = ii >> 3, j = ii & 7;
        *(uint4*)&Qs[r*36 + j*4] = ((const uint4*)(qb + (size_t)r*64))[j];
    }

    auto issueKV = [&](int kt, int s) {
        const __half* kb = g_kmh + ((size_t)h*SEQ + kt)*64;
        #pragma unroll
        for (int it = 0; it < 2; it++) {
            int ii = tid + it*256;
            int r = ii >> 3, j = ii & 7;
            cpa16(kB + (s*2304 + r*36 + j*4)*4, (const uint4*)(kb + (size_t)r*64) + j);
        }
        const unsigned* vp = g_vmP + ((size_t)h*1024 + (kt >> 1))*64;
        #pragma unroll
        for (int it = 0; it < 8; it++) {
            int w = tid + it*256;
            int d = w & 63, p = w >> 6;
            cpa4(vB + (s*2304 + d*36 + p)*4, vp + (size_t)p*64 + d);
        }
        CPA_COMMIT();
    };

    float o[8][4];
    #pragma unroll
    for (int n = 0; n < 8; n++)
        #pragma unroll
        for (int j = 0; j < 4; j++) o[n][j] = 0.f;
    float m0 = -1e30f, m1 = -1e30f, l0 = 0.f, l1 = 0.f;
    int row0 = t0 + wm + g, row1 = row0 + 8;
    int wmax = t0 + wm + 15;

    issueKV(tlo << 6, tlo & 1);
    for (int it = tlo; it < thi; it++) {
        int kt = it << 6;
        if (it + 1 < thi) { issueKV((it+1) << 6, (it+1) & 1); CPA_WAIT1(); }
        else CPA_WAIT0();
        __syncthreads();
        if (kt <= wmax) {
            uint32_t kBs = kB + ((it & 1)*2304)*4;
            uint32_t vBs = vB + ((it & 1)*2304)*4;

            float s[8][4];
            #pragma unroll
            for (int n = 0; n < 8; n++)
                #pragma unroll
                for (int j = 0; j < 4; j++) s[n][j] = 0.f;
            #pragma unroll
            for (int ks = 0; ks < 4; ks++) {
                unsigned aq[4], bq[4][4];
                ldsm4(aq, qB + aOffQ + ks*32);
                #pragma unroll
                for (int p = 0; p < 4; p++) ldsm4(bq[p], kBs + bOffK[p] + ks*32);
                #pragma unroll
                for (int n = 0; n < 8; n++) {
                    unsigned bf[2] = { bq[n>>1][n&1], bq[n>>1][(n&1)+2] };
                    mma16(s[n], aq, bf);
                }
            }
            float mx0 = -1e30f, mx1 = -1e30f;
            #pragma unroll
            for (int n = 0; n < 8; n++) {
                int c0 = kt + n*8 + 2*t4, c1 = c0 + 1;
                s[n][0] = (c0 <= row0) ? s[n][0]*0.125f : -1e30f;
                s[n][1] = (c1 <= row0) ? s[n][1]*0.125f : -1e30f;
                s[n][2] = (c0 <= row1) ? s[n][2]*0.125f : -1e30f;
                s[n][3] = (c1 <= row1) ? s[n][3]*0.125f : -1e30f;
                mx0 = fmaxf(mx0, fmaxf(s[n][0], s[n][1]));
                mx1 = fmaxf(mx1, fmaxf(s[n][2], s[n][3]));
            }
            mx0 = fmaxf(mx0, __shfl_xor_sync(0xffffffffu, mx0, 1));
            mx0 = fmaxf(mx0, __shfl_xor_sync(0xffffffffu, mx0, 2));
            mx1 = fmaxf(mx1, __shfl_xor_sync(0xffffffffu, mx1, 1));
            mx1 = fmaxf(mx1, __shfl_xor_sync(0xffffffffu, mx1, 2));
            float nm0 = fmaxf(m0, mx0), nm1 = fmaxf(m1, mx1);
            float cor0 = __expf(m0 - nm0), cor1 = __expf(m1 - nm1);
            m0 = nm0; m1 = nm1;
            l0 *= cor0; l1 *= cor1;
            float sum0 = 0.f, sum1 = 0.f;
            #pragma unroll
            for (int n = 0; n < 8; n++) {
                float p00 = __expf(s[n][0] - nm0), p01 = __expf(s[n][1] - nm0);
                float p10 = __expf(s[n][2] - nm1), p11 = __expf(s[n][3] - nm1);
                sum0 += p00 + p01; sum1 += p10 + p11;
                Ps[(wm+g)*36 + n*4 + t4]   = f2h2(p00, p01);
                Ps[(wm+g+8)*36 + n*4 + t4] = f2h2(p10, p11);
                #pragma unroll
                for (int j = 0; j < 2; j++) { o[n][j] *= cor0; o[n][2+j] *= cor1; }
            }
            sum0 += __shfl_xor_sync(0xffffffffu, sum0, 1);
            sum0 += __shfl_xor_sync(0xffffffffu, sum0, 2);
            sum1 += __shfl_xor_sync(0xffffffffu, sum1, 1);
            sum1 += __shfl_xor_sync(0xffffffffu, sum1, 2);
            l0 += sum0; l1 += sum1;
            __syncwarp();

            #pragma unroll
            for (int ks = 0; ks < 4; ks++) {
                unsigned ap[4], bq[4][4];
                ldsm4(ap, pB + aOffQ + ks*32);
                #pragma unroll
                for (int p = 0; p < 4; p++) ldsm4(bq[p], vBs + bOffK[p] + ks*32);
                #pragma unroll
                for (int n = 0; n < 8; n++) {
                    unsigned bf[2] = { bq[n>>1][n&1], bq[n>>1][(n&1)+2] };
                    mma16(o[n], ap, bf);
                }
            }
        }
        __syncthreads();
    }

    if (nsplit == 1) {
        float inv0 = 1.f / l0, inv1 = 1.f / l1;
        int tok0 = (row0 & 1)*1024 + (row0 >> 1);
        int tok1 = (row1 & 1)*1024 + (row1 >> 1);
        #pragma unroll
        for (int n = 0; n < 8; n++) {
            int col = h*64 + n*8 + 2*t4;
            *(unsigned*)&g_orowsh[(size_t)tok0*DIMM + col] = f2h2(o[n][0]*inv0, o[n][1]*inv0);
            *(unsigned*)&g_orowsh[(size_t)tok1*DIMM + col] = f2h2(o[n][2]*inv1, o[n][3]*inv1);
        }
    } else {
        size_t pidxg = (size_t)((h*8 + (b-8))*2 + split);
        float* oP = g_attO + pidxg*8192;
        float2* mlP = g_attML + pidxg*128;
        int lr0 = wm + g, lr1 = lr0 + 8;
        #pragma unroll
        for (int n = 0; n < 8; n++) {
            int col = n*8 + 2*t4;
            *(float2*)&oP[lr0*64 + col] = make_float2(o[n][0], o[n][1]);
            *(float2*)&oP[lr1*64 + col] = make_float2(o[n][2], o[n][3]);
        }
        if (t4 == 0) {
            mlP[lr0] = make_float2(m0, l0);
            mlP[lr1] = make_float2(m1, l1);
        }
    }
}

// merge split-KV partials for query tiles b=8..15
__global__ void __launch_bounds__(256) attn_merge() {
    int bb = blockIdx.x;           // 0..7 -> b = 8+bb
    int h = blockIdx.y;
    int t0 = (8 + bb) * 128;
    size_t base = (size_t)((h*8 + bb)*2);
    const float* o0 = g_attO + base*8192;
    const float* o1 = o0 + 8192;
    const float2* ml0 = g_attML + base*128;
    const float2* ml1 = ml0 + 128;
    for (int idx = threadIdx.x; idx < 128*32; idx += 256) {
        int r = idx >> 5, cw = (idx & 31)*2;
        float2 a = ml0[r], c = ml1[r];
        float m = fmaxf(a.x, c.x);
        float w0 = __expf(a.x - m), w1 = __expf(c.x - m);
        float invl = 1.f / (a.y*w0 + c.y*w1);
        float x0 = (o0[r*64 + cw]   * w0 + o1[r*64 + cw]   * w1) * invl;
        float x1 = (o0[r*64 + cw+1] * w0 + o1[r*64 + cw+1] * w1) * invl;
        int row = t0 + r;
        int tok = (row & 1)*1024 + (row >> 1);
        *(unsigned*)&g_orowsh[(size_t)tok*DIMM + h*64 + cw] = f2h2(x0, x1);
    }
}

__global__ void zero32_kernel() {
    int i = threadIdx.x;
    if (i < NEXP) { g_counts[i] = 0; g_cursors[i] = 0; }
}

// fused prefix + scatter: single block, 256 threads
__global__ void __launch_bounds__(256) prefix_scatter_kernel() {
    __shared__ int soff[NEXP];
    if (threadIdx.x == 0) {
        int acc = 0;
        for (int e = 0; e < NEXP; e++) { soff[e] = acc; g_offsets[e] = acc; acc += g_counts[e]; }
    }
    __syncthreads();
    for (int a = threadIdx.x; a < NASS; a += 256) {
        int e = g_eid[a];
        int p = soff[e] + atomicAdd(&g_cursors[e], 1);
        g_tokof[p] = a >> 2;
        g_posof[a] = p;
    }
}

__global__ void combine_kernel(float* __restrict__ y) {
    int tok = blockIdx.x;
    __shared__ int pos[4];
    __shared__ float sc[4];
    if (threadIdx.x < 4) {
        pos[threadIdx.x] = g_posof[tok*4 + threadIdx.x];
        sc[threadIdx.x]  = g_scales[tok*4 + threadIdx.x];
    }
    __syncthreads();
    for (int d = threadIdx.x; d < DIMM; d += 256) {
        float v = g_xffni[(size_t)tok*DIMM + d]
                + __half2float(g_shdownh[(size_t)tok*DIMM + d]);
        #pragma unroll
        for (int k = 0; k < 4; k++)
            v = fmaf(sc[k], __half2float(g_slotsh[(size_t)pos[k]*DIMM + d]), v);
        y[(size_t)tok*DIMM + d] = v;
    }
}

// ---------------- launch ----------------
extern "C" void kernel_launch(void* const* d_in, const int* in_sizes, int n_in,
                              void* d_out, int out_size) {
    const float* x_input  = (const float*)d_in[0];
    const int*   p_idx    = (const int*)  d_in[1];
    const float* p_val    = (const float*)d_in[2];
    const int*   f_idx    = (const int*)  d_in[3];
    const float* f_val    = (const float*)d_in[4];
    const float* attn_nw  = (const float*)d_in[5];
    const float* ffn_nw   = (const float*)d_in[6];
    const float* W_attn   = (const float*)d_in[7];
    const float* W_attn_o = (const float*)d_in[8];
    const float* ffn_up   = (const float*)d_in[9];
    const float* ffn_down = (const float*)d_in[10];
    const float* pW       = (const float*)d_in[11];
    const float* fW       = (const float*)d_in[12];
    const float* pkeys    = (const float*)d_in[13];
    const float* fkeys    = (const float*)d_in[14];
    const float* pbias    = (const float*)d_in[15];
    const float* fbias    = (const float*)d_in[16];
    float* out = (float*)d_out;

    __half *xnormh, *qkvh, *orowsh, *xffnh, *hsh, *shdownh;
    __half *wqkvT, *woT, *wupT, *wdnT;
    float *xffni;
    cudaGetSymbolAddress((void**)&xnormh, g_xnormh);
    cudaGetSymbolAddress((void**)&qkvh,   g_qkvh);
    cudaGetSymbolAddress((void**)&orowsh, g_orowsh);
    cudaGetSymbolAddress((void**)&xffni,  g_xffni);
    cudaGetSymbolAddress((void**)&xffnh,  g_xffnh);
    cudaGetSymbolAddress((void**)&hsh,    g_hsh);
    cudaGetSymbolAddress((void**)&shdownh, g_shdownh);
    cudaGetSymbolAddress((void**)&wqkvT,  g_wqkvT);
    cudaGetSymbolAddress((void**)&woT,    g_woT);
    cudaGetSymbolAddress((void**)&wupT,   g_wupT);
    cudaGetSymbolAddress((void**)&wdnT,   g_wdnT);

    static cudaStream_t s1 = nullptr, s2 = nullptr;
    static cudaEvent_t evFork, evZero, evQKVp, evWo, evWup, evMoeP, evXffn, evSh;
    static bool init_done = false;
    if (!init_done) {
        cudaFuncSetAttribute(attn_h, cudaFuncAttributeMaxDynamicSharedMemorySize,
                             ATT_SMEM_W * 4);
        cudaFuncSetAttribute(gemm_h<0>, cudaFuncAttributeMaxDynamicSharedMemorySize, GEMM_SMEM);
        cudaFuncSetAttribute(gemm_h<1>, cudaFuncAttributeMaxDynamicSharedMemorySize, GEMM_SMEM);
        cudaFuncSetAttribute(gemm_h<2>, cudaFuncAttributeMaxDynamicSharedMemorySize, GEMM_SMEM);
        cudaFuncSetAttribute(moe_gu_h, cudaFuncAttributeMaxDynamicSharedMemorySize, GEMM_SMEM);
        cudaFuncSetAttribute(moe_down_h, cudaFuncAttributeMaxDynamicSharedMemorySize, GEMM_SMEM);
        cudaStreamCreateWithFlags(&s1, cudaStreamNonBlocking);
        cudaStreamCreateWithFlags(&s2, cudaStreamNonBlocking);
        cudaEventCreateWithFlags(&evFork, cudaEventDisableTiming);
        cudaEventCreateWithFlags(&evZero, cudaEventDisableTiming);
        cudaEventCreateWithFlags(&evQKVp, cudaEventDisableTiming);
        cudaEventCreateWithFlags(&evWo,   cudaEventDisableTiming);
        cudaEventCreateWithFlags(&evWup,  cudaEventDisableTiming);
        cudaEventCreateWithFlags(&evMoeP, cudaEventDisableTiming);
        cudaEventCreateWithFlags(&evXffn, cudaEventDisableTiming);
        cudaEventCreateWithFlags(&evSh,   cudaEventDisableTiming);
        init_done = true;
    }

    // fork side stream s1: zero + all weight packing
    cudaEventRecord(evFork, 0);
    cudaStreamWaitEvent(s1, evFork, 0);
    zero32_kernel<<<1, 32, 0, s1>>>();
    cudaEventRecord(evZero, s1);
    packT<<<dim3(16, 96),  256, 0, s1>>>(W_attn,   wqkvT, DIMM, 3*DIMM);
    cudaEventRecord(evQKVp, s1);
    packT<<<dim3(16, 32),  256, 0, s1>>>(W_attn_o, woT,   DIMM, DIMM);
    cudaEventRecord(evWo, s1);
    packT_gu<<<dim3(16, 128), 256, 0, s1>>>(ffn_up, wupT, DIMM, 2*DSH);
    packT<<<dim3(32, 32),  256, 0, s1>>>(ffn_down, wdnT,  DSH,  DIMM);
    cudaEventRecord(evWup, s1);
    packT_moe<<<dim3(16, 16, 64), 256, 0, s1>>>(pW, fW);
    conv_moe_down<<<dim3(256, 1, 32), 256, 0, s1>>>(pW, fW);
    cudaEventRecord(evMoeP, s1);

    // main stream: attention block (overlaps with packing)
    rmsnorm_h<<<TOK, 256>>>(x_input, attn_nw, xnormh);
    cudaStreamWaitEvent(0, evQKVp, 0);
    gemm_h<1><<<dim3(24, 16), 256, GEMM_SMEM>>>(xnormh, wqkvT, qkvh, nullptr, TOK, 3*DIMM, DIMM);
    rope_interleave_kernel<<<dim3(TOK, NH), 64>>>();
    attn_h<<<dim3(24, NH), 256, ATT_SMEM_W*4>>>();
    attn_merge<<<dim3(8, NH), 256>>>();
    cudaStreamWaitEvent(0, evWo, 0);
    gemm_h<0><<<dim3(8, 16), 256, GEMM_SMEM>>>(orowsh, woT, xffni, x_input, TOK, DIMM, DIMM);
    cudaStreamWaitEvent(0, evZero, 0);
    rmsnorm_router<<<TOK, 256>>>(xffni, ffn_nw, pkeys, fkeys, pbias, fbias,
                                 p_idx, p_val, f_idx, f_val, xffnh);
    cudaEventRecord(evXffn, 0);

    // s2: full shared-expert branch (up + down), overlaps MoE chain
    cudaStreamWaitEvent(s2, evXffn, 0);
    cudaStreamWaitEvent(s2, evWup, 0);
    gemm_h<2><<<dim3(32, 16), 256, GEMM_SMEM, s2>>>(xffnh, wupT, hsh, nullptr, TOK, 2*DSH, DIMM);
    gemm_h<1><<<dim3(8, 16), 256, GEMM_SMEM, s2>>>(hsh, wdnT, shdownh, nullptr, TOK, DIMM, DSH);
    cudaEventRecord(evSh, s2);

    // main: routing + grouped MoE
    prefix_scatter_kernel<<<1, 256>>>();
    cudaStreamWaitEvent(0, evMoeP, 0);
    moe_gu_h<<<dim3(8, 16, NEXP), 256, GEMM_SMEM>>>();
    moe_down_h<<<dim3(8, 16, NEXP), 256, GEMM_SMEM>>>();
    // final combine joins s2 and adds shared-expert output
    cudaStreamWaitEvent(0, evSh, 0);
    combine_kernel<<<TOK, 256>>>(out);
}